// round 2
// baseline (speedup 1.0000x reference)
#include <cuda_runtime.h>
#include <math.h>

#define B_    4
#define NTOK  8192
#define D_    512
#define H_    8
#define DH_   64
#define MLM   256
#define LSEG  32
#define BH    (B_*H_)
#define KER_  33

// ---------------- scratch buffers ----------------
__device__ float g_normed[(size_t)B_*NTOK*D_];
__device__ float g_q [(size_t)BH*NTOK*DH_];
__device__ float g_k [(size_t)BH*NTOK*DH_];
__device__ float g_v [(size_t)BH*NTOK*DH_];
__device__ float g_ql[(size_t)BH*MLM*DH_];
__device__ float g_kl[(size_t)BH*MLM*DH_];
__device__ float g_X [(size_t)BH*MLM*MLM];
__device__ float g_Za[(size_t)BH*MLM*MLM];
__device__ float g_Zb[(size_t)BH*MLM*MLM];
__device__ float g_XZ[(size_t)BH*MLM*MLM];
__device__ float g_W [(size_t)BH*MLM*MLM];
__device__ float g_W2[(size_t)BH*MLM*MLM];
__device__ float g_A3V[(size_t)BH*MLM*DH_];
__device__ float g_Y  [(size_t)BH*MLM*DH_];
__device__ float g_O  [(size_t)B_*NTOK*D_];
__device__ unsigned g_maxbits[2];

// ---------------- LayerNorm ----------------
__global__ void ln_kernel(const float* __restrict__ x, const float* __restrict__ gamma,
                          const float* __restrict__ beta, float* __restrict__ out) {
    int row = blockIdx.x;
    int tid = threadIdx.x;                 // 256 threads, 2 elems each
    const float* xr = x + (size_t)row * D_;
    float v0 = xr[tid], v1 = xr[tid + 256];
    float s = v0 + v1, s2 = v0*v0 + v1*v1;
    #pragma unroll
    for (int o = 16; o > 0; o >>= 1) {
        s  += __shfl_xor_sync(0xffffffffu, s,  o);
        s2 += __shfl_xor_sync(0xffffffffu, s2, o);
    }
    __shared__ float sh[16];
    int w = tid >> 5, l = tid & 31;
    if (l == 0) { sh[w] = s; sh[w + 8] = s2; }
    __syncthreads();
    if (tid == 0) {
        float a = 0.f, b2 = 0.f;
        #pragma unroll
        for (int i = 0; i < 8; i++) { a += sh[i]; b2 += sh[i + 8]; }
        sh[0] = a; sh[8] = b2;
    }
    __syncthreads();
    float mu  = sh[0] * (1.f / D_);
    float var = sh[8] * (1.f / D_) - mu * mu;
    float inv = rsqrtf(var + 1e-5f);
    float* orow = out + (size_t)row * D_;
    orow[tid]       = (v0 - mu) * inv * gamma[tid]       + beta[tid];
    orow[tid + 256] = (v1 - mu) * inv * gamma[tid + 256] + beta[tid + 256];
}

// ---------------- SGEMM 128x128x8, 256 thr, 8x8 micro-tile ----------------
// mode 0: C = alpha*(A@B)
// mode 1: qkv scatter into q/k/v head layout (q scaled by 1/8)
// mode 2: C = A@B + bias[col] + addx[elem]   (final out-proj + residual)
__global__ void __launch_bounds__(256) sgemm_kernel(
        const float* __restrict__ A, const float* __restrict__ B, float* __restrict__ C,
        int M, int N, int K, size_t sA, size_t sB, size_t sC,
        float alpha, int mode,
        const float* __restrict__ addx, const float* __restrict__ bias,
        float* __restrict__ qp, float* __restrict__ kp, float* __restrict__ vp)
{
    int bz = blockIdx.z;
    A += (size_t)bz * sA; B += (size_t)bz * sB; C += (size_t)bz * sC;
    int m0 = blockIdx.y * 128, n0 = blockIdx.x * 128;
    __shared__ float As[8][128];
    __shared__ float Bs[8][128];
    int tid = threadIdx.x;
    int tx = tid & 15, ty = tid >> 4;
    float acc[8][8];
    #pragma unroll
    for (int i = 0; i < 8; i++)
        #pragma unroll
        for (int j = 0; j < 8; j++) acc[i][j] = 0.f;

    for (int k0 = 0; k0 < K; k0 += 8) {
        #pragma unroll
        for (int i = 0; i < 4; i++) {
            int lin = tid + i * 256;
            int kk = lin & 7, mm = lin >> 3;
            int gm = m0 + mm, gk = k0 + kk;
            As[kk][mm] = (gm < M && gk < K) ? A[(size_t)gm * K + gk] : 0.f;
        }
        #pragma unroll
        for (int i = 0; i < 4; i++) {
            int lin = tid + i * 256;
            int nn = lin & 127, kk = lin >> 7;
            int gn = n0 + nn, gk = k0 + kk;
            Bs[kk][nn] = (gn < N && gk < K) ? B[(size_t)gk * N + gn] : 0.f;
        }
        __syncthreads();
        #pragma unroll
        for (int kk = 0; kk < 8; kk++) {
            float a[8], b[8];
            *(float4*)&a[0] = *(const float4*)&As[kk][ty * 8];
            *(float4*)&a[4] = *(const float4*)&As[kk][ty * 8 + 4];
            *(float4*)&b[0] = *(const float4*)&Bs[kk][tx * 8];
            *(float4*)&b[4] = *(const float4*)&Bs[kk][tx * 8 + 4];
            #pragma unroll
            for (int i = 0; i < 8; i++)
                #pragma unroll
                for (int j = 0; j < 8; j++) acc[i][j] += a[i] * b[j];
        }
        __syncthreads();
    }

    #pragma unroll
    for (int i = 0; i < 8; i++) {
        int gm = m0 + ty * 8 + i;
        if (gm >= M) continue;
        #pragma unroll
        for (int j = 0; j < 8; j++) {
            int gn = n0 + tx * 8 + j;
            if (gn >= N) continue;
            float val = acc[i][j];
            if (mode == 0) {
                C[(size_t)gm * N + gn] = alpha * val;
            } else if (mode == 2) {
                C[(size_t)gm * N + gn] = val + bias[gn] + addx[(size_t)gm * N + gn];
            } else { // mode 1: qkv scatter
                int b_  = gm >> 13;
                int n_  = gm & 8191;
                int sec = gn >> 9;
                int cc  = gn & 511;
                int h_  = cc >> 6;
                int dh  = cc & 63;
                size_t idx = ((((size_t)b_ * H_ + h_) * NTOK) + n_) * DH_ + dh;
                if (sec == 0)      qp[idx] = val * 0.125f;
                else if (sec == 1) kp[idx] = val;
                else               vp[idx] = val;
            }
        }
    }
}

// ---------------- landmark means ----------------
__global__ void landmark_kernel(const float* __restrict__ q, const float* __restrict__ k,
                                float* __restrict__ ql, float* __restrict__ kl) {
    int bh = blockIdx.x, m = blockIdx.y;
    int dh = threadIdx.x;                  // 64 threads
    size_t base = ((size_t)bh * NTOK + (size_t)m * LSEG) * DH_ + dh;
    float aq = 0.f, ak = 0.f;
    #pragma unroll
    for (int i = 0; i < LSEG; i++) {
        aq += q[base + (size_t)i * DH_];
        ak += k[base + (size_t)i * DH_];
    }
    size_t o = ((size_t)bh * MLM + m) * DH_ + dh;
    ql[o] = aq * (1.f / LSEG);
    kl[o] = ak * (1.f / LSEG);
}

// ---------------- attn2 = softmax(q_l @ k_l^T) ----------------
__global__ void attn2_kernel(const float* __restrict__ ql, const float* __restrict__ kl,
                             float* __restrict__ X) {
    int bh = blockIdx.x, m = blockIdx.y;
    int j = threadIdx.x;                   // 256 threads
    __shared__ float qrow[DH_];
    __shared__ float wsum[8];
    if (j < DH_) qrow[j] = ql[((size_t)bh * MLM + m) * DH_ + j];
    __syncthreads();
    const float* kr = kl + ((size_t)bh * MLM + j) * DH_;
    float s = 0.f;
    #pragma unroll
    for (int d = 0; d < DH_; d++) s += qrow[d] * __ldg(&kr[d]);
    float e = __expf(s);
    float t = e;
    #pragma unroll
    for (int o = 16; o > 0; o >>= 1) t += __shfl_xor_sync(0xffffffffu, t, o);
    if ((j & 31) == 0) wsum[j >> 5] = t;
    __syncthreads();
    float S = 0.f;
    #pragma unroll
    for (int w = 0; w < 8; w++) S += wsum[w];
    X[((size_t)bh * MLM + m) * MLM + j] = e / S;
}

// ---------------- pinv helpers ----------------
__global__ void initmax_kernel(unsigned* mb) { mb[0] = 0u; mb[1] = 0u; }

__global__ void rowcol_kernel(const float* __restrict__ X, unsigned* mb) {
    int bh = blockIdx.x;
    int i = threadIdx.x;                   // 256 threads
    const float* Xm = X + (size_t)bh * MLM * MLM;
    float rs = 0.f, cs = 0.f;
    for (int j = 0; j < MLM; j++) {
        rs += fabsf(Xm[(size_t)i * MLM + j]);
        cs += fabsf(Xm[(size_t)j * MLM + i]);
    }
    #pragma unroll
    for (int o = 16; o > 0; o >>= 1) {
        rs = fmaxf(rs, __shfl_xor_sync(0xffffffffu, rs, o));
        cs = fmaxf(cs, __shfl_xor_sync(0xffffffffu, cs, o));
    }
    __shared__ float shr[8], shc[8];
    int w = i >> 5;
    if ((i & 31) == 0) { shr[w] = rs; shc[w] = cs; }
    __syncthreads();
    if (i == 0) {
        float mr = shr[0], mc = shc[0];
        #pragma unroll
        for (int k2 = 1; k2 < 8; k2++) { mr = fmaxf(mr, shr[k2]); mc = fmaxf(mc, shc[k2]); }
        atomicMax(&mb[0], __float_as_uint(mr));  // values >= 0: uint order == float order
        atomicMax(&mb[1], __float_as_uint(mc));
    }
}

__global__ void zinit_kernel(const float* __restrict__ X, float* __restrict__ Z,
                             const unsigned* __restrict__ mb) {
    float denom = __uint_as_float(mb[0]) * __uint_as_float(mb[1]);
    float inv = 1.f / denom;
    size_t idx = (size_t)blockIdx.x * 256 + threadIdx.x;   // over 32*256*256
    int bh = (int)(idx >> 16);
    int r = (int)((idx >> 8) & 255);
    int c = (int)(idx & 255);
    Z[idx] = X[((size_t)bh << 16) + ((size_t)c << 8) + r] * inv;
}

__global__ void diagsub_kernel(float* __restrict__ dst, const float* __restrict__ src, float c) {
    size_t idx = (size_t)blockIdx.x * 256 + threadIdx.x;
    int r = (int)((idx >> 8) & 255);
    int cc = (int)(idx & 255);
    dst[idx] = (r == cc ? c : 0.f) - src[idx];
}

// ---------------- attn3 @ v (streaming softmax over n) ----------------
__global__ void attn3v_kernel(const float* __restrict__ ql, const float* __restrict__ k,
                              const float* __restrict__ v, float* __restrict__ out) {
    // grid (BH, 8), block 128: 32 queries x 4 lanes of 16 dims
    int bh = blockIdx.x, qg = blockIdx.y;
    int tid = threadIdx.x;
    int q = tid >> 2, s = tid & 3;
    int m = qg * 32 + q;
    __shared__ float ks[64][64];
    __shared__ float vs[64][64];
    float qr[16];
    const float* qlp = ql + ((size_t)bh * MLM + m) * DH_ + s * 16;
    #pragma unroll
    for (int j = 0; j < 16; j++) qr[j] = qlp[j];
    float acc[16];
    #pragma unroll
    for (int j = 0; j < 16; j++) acc[j] = 0.f;
    float lsum = 0.f;
    const float* kbase = k + (size_t)bh * NTOK * DH_;
    const float* vbase = v + (size_t)bh * NTOK * DH_;

    for (int nt = 0; nt < NTOK; nt += 64) {
        __syncthreads();
        #pragma unroll
        for (int i = 0; i < 8; i++) {
            int f4 = tid + i * 128;
            int row = f4 >> 4, c4 = f4 & 15;
            ((float4*)ks)[f4] = ((const float4*)(kbase + (size_t)(nt + row) * DH_))[c4];
            ((float4*)vs)[f4] = ((const float4*)(vbase + (size_t)(nt + row) * DH_))[c4];
        }
        __syncthreads();
        #pragma unroll 4
        for (int n = 0; n < 64; n++) {
            const float* kr = &ks[n][s * 16];
            float p = 0.f;
            #pragma unroll
            for (int j = 0; j < 16; j++) p += qr[j] * kr[j];
            p += __shfl_xor_sync(0xffffffffu, p, 1);
            p += __shfl_xor_sync(0xffffffffu, p, 2);
            float e = __expf(p);   // scores are tiny (|s| < ~1.5): no max-subtraction needed
            lsum += e;
            const float* vr = &vs[n][s * 16];
            #pragma unroll
            for (int j = 0; j < 16; j++) acc[j] += e * vr[j];
        }
    }
    float invl = 1.f / lsum;
    float* op = out + ((size_t)bh * MLM + m) * DH_ + s * 16;
    #pragma unroll
    for (int j = 0; j < 16; j++) op[j] = acc[j] * invl;
}

// ---------------- depthwise conv (kernel 33 along n), writes O ----------------
__global__ void conv_kernel(const float* __restrict__ v, const float* __restrict__ ker,
                            float* __restrict__ O) {
    // grid (64 ntiles, H_, B_), 256 threads
    int nt = blockIdx.x, h = blockIdx.y, b = blockIdx.z;
    int n0 = nt * 128;
    __shared__ float vsh[160][64];
    __shared__ float kw[KER_];
    int tid = threadIdx.x;
    if (tid < KER_) kw[tid] = ker[h * KER_ + tid];
    const float* vb = v + ((size_t)b * H_ + h) * NTOK * DH_;
    #pragma unroll
    for (int i = 0; i < 10; i++) {
        int f4 = tid + i * 256;
        int row = f4 >> 4, c4 = f4 & 15;
        int n = n0 - 16 + row;
        float4 val = make_float4(0.f, 0.f, 0.f, 0.f);
        if (n >= 0 && n < NTOK) val = ((const float4*)(vb + (size_t)n * DH_))[c4];
        ((float4*)vsh)[f4] = val;
    }
    __syncthreads();
    int dh = tid & 63, g = tid >> 6;       // g: 0..3
    for (int ii = 0; ii < 32; ii++) {
        int nn = g * 32 + ii;
        float o = 0.f;
        #pragma unroll
        for (int t = 0; t < KER_; t++) o += kw[t] * vsh[nn + t][dh];
        O[((size_t)b * NTOK + (n0 + nn)) * D_ + h * DH_ + dh] = o;
    }
}

// ---------------- attn1 apply: O += softmax(q @ k_l^T) @ Y ----------------
__global__ void attn1_kernel(const float* __restrict__ q, const float* __restrict__ kl,
                             const float* __restrict__ Y, float* __restrict__ O) {
    // grid (32 chunks, H_, B_), 256 threads, dynamic shared
    extern __shared__ float sh[];
    float* kls   = sh;                       // 256*65 (padded vs bank conflicts)
    float* Ys    = kls + 256 * 65;           // 256*64
    float* qrow  = Ys + 256 * 64;            // 64
    float* ps    = qrow + 64;                // 256
    float* wsum  = ps + 256;                 // 8
    float* opart = wsum + 8;                 // 256
    int chunk = blockIdx.x, h = blockIdx.y, b = blockIdx.z;
    int bh = b * H_ + h;
    int tid = threadIdx.x;
    for (int i = tid; i < MLM * DH_; i += 256) {
        int r = i >> 6, c = i & 63;
        kls[r * 65 + c] = kl[((size_t)bh * MLM + r) * DH_ + c];
        Ys[i] = Y[(size_t)bh * MLM * DH_ + i];
    }
    __syncthreads();
    int n0 = chunk * 256;
    const float* qb = q + (size_t)bh * NTOK * DH_;
    int wid = tid >> 5, lane = tid & 31;
    int g = tid >> 6, dh = tid & 63;
    for (int nn = 0; nn < 256; nn++) {
        int n = n0 + nn;
        if (tid < 64) qrow[tid] = qb[(size_t)n * DH_ + tid];
        __syncthreads();
        const float* kr = &kls[tid * 65];
        float s = 0.f;
        #pragma unroll
        for (int d = 0; d < 64; d++) s += qrow[d] * kr[d];
        float e = __expf(s);
        ps[tid] = e;
        float t = e;
        #pragma unroll
        for (int o = 16; o > 0; o >>= 1) t += __shfl_xor_sync(0xffffffffu, t, o);
        if (lane == 0) wsum[wid] = t;
        __syncthreads();
        float S = 0.f;
        #pragma unroll
        for (int w = 0; w < 8; w++) S += wsum[w];
        const float* pp = &ps[g * 64];
        const float* Yp = &Ys[(size_t)g * 64 * 64 + dh];
        float o = 0.f;
        #pragma unroll 16
        for (int jj = 0; jj < 64; jj++) o += pp[jj] * Yp[(size_t)jj * 64];
        opart[tid] = o;
        __syncthreads();
        if (tid < 64) {
            float oo = opart[tid] + opart[64 + tid] + opart[128 + tid] + opart[192 + tid];
            O[((size_t)b * NTOK + n) * D_ + h * DH_ + tid] += oo / S;
        }
        __syncthreads();
    }
}

// ---------------- host launcher ----------------
extern "C" void kernel_launch(void* const* d_in, const int* in_sizes, int n_in,
                              void* d_out, int out_size) {
    const float* x      = (const float*)d_in[0];
    const float* gamma  = (const float*)d_in[1];
    const float* beta   = (const float*)d_in[2];
    const float* w_qkv  = (const float*)d_in[3];
    const float* res_k  = (const float*)d_in[4];
    const float* w_out  = (const float*)d_in[5];
    const float* b_out  = (const float*)d_in[6];
    float* out = (float*)d_out;

    float *normed, *q, *k, *v, *ql, *kl, *X, *Za, *Zb, *XZ, *W, *W2, *A3V, *Y, *O;
    unsigned* mb;
    cudaGetSymbolAddress((void**)&normed, g_normed);
    cudaGetSymbolAddress((void**)&q,  g_q);
    cudaGetSymbolAddress((void**)&k,  g_k);
    cudaGetSymbolAddress((void**)&v,  g_v);
    cudaGetSymbolAddress((void**)&ql, g_ql);
    cudaGetSymbolAddress((void**)&kl, g_kl);
    cudaGetSymbolAddress((void**)&X,  g_X);
    cudaGetSymbolAddress((void**)&Za, g_Za);
    cudaGetSymbolAddress((void**)&Zb, g_Zb);
    cudaGetSymbolAddress((void**)&XZ, g_XZ);
    cudaGetSymbolAddress((void**)&W,  g_W);
    cudaGetSymbolAddress((void**)&W2, g_W2);
    cudaGetSymbolAddress((void**)&A3V, g_A3V);
    cudaGetSymbolAddress((void**)&Y,  g_Y);
    cudaGetSymbolAddress((void**)&O,  g_O);
    cudaGetSymbolAddress((void**)&mb, g_maxbits);

    const int attn1_smem = (256 * 65 + 256 * 64 + 64 + 256 + 8 + 256) * (int)sizeof(float);
    cudaFuncSetAttribute(attn1_kernel, cudaFuncAttributeMaxDynamicSharedMemorySize, attn1_smem);

    // 1. LayerNorm
    ln_kernel<<<B_ * NTOK, 256>>>(x, gamma, beta, normed);

    // 2. QKV GEMM with head scatter
    sgemm_kernel<<<dim3(12, 256, 1), 256>>>(normed, w_qkv, nullptr,
        B_ * NTOK, 3 * D_, D_, 0, 0, 0, 1.f, 1, nullptr, nullptr, q, k, v);

    // 3. Landmarks
    landmark_kernel<<<dim3(BH, MLM), 64>>>(q, k, ql, kl);

    // 4. attn2
    attn2_kernel<<<dim3(BH, MLM), 256>>>(ql, kl, X);

    // 5. pinv init
    initmax_kernel<<<1, 1>>>(mb);
    rowcol_kernel<<<BH, 256>>>(X, mb);
    zinit_kernel<<<8192, 256>>>(X, Za, mb);

    // 6. Newton iterations: z = 0.25 z (13I - xz(15I - xz(7I - xz)))
    float* zc = Za; float* zn = Zb;
    const size_t sM = (size_t)MLM * MLM;
    for (int it = 0; it < 6; it++) {
        sgemm_kernel<<<dim3(2, 2, BH), 256>>>(X, zc, XZ, MLM, MLM, MLM, sM, sM, sM,
            1.f, 0, nullptr, nullptr, nullptr, nullptr, nullptr);
        diagsub_kernel<<<8192, 256>>>(W, XZ, 7.f);
        sgemm_kernel<<<dim3(2, 2, BH), 256>>>(XZ, W, W2, MLM, MLM, MLM, sM, sM, sM,
            1.f, 0, nullptr, nullptr, nullptr, nullptr, nullptr);
        diagsub_kernel<<<8192, 256>>>(W, W2, 15.f);
        sgemm_kernel<<<dim3(2, 2, BH), 256>>>(XZ, W, W2, MLM, MLM, MLM, sM, sM, sM,
            1.f, 0, nullptr, nullptr, nullptr, nullptr, nullptr);
        diagsub_kernel<<<8192, 256>>>(W, W2, 13.f);
        sgemm_kernel<<<dim3(2, 2, BH), 256>>>(zc, W, zn, MLM, MLM, MLM, sM, sM, sM,
            0.25f, 0, nullptr, nullptr, nullptr, nullptr, nullptr);
        float* tmp = zc; zc = zn; zn = tmp;
    }

    // 7. attn3 @ v
    attn3v_kernel<<<dim3(BH, 8), 128>>>(ql, k, v, A3V);

    // 8. Y = pinv(attn2) @ (attn3 @ v)
    sgemm_kernel<<<dim3(1, 2, BH), 256>>>(zc, A3V, Y, MLM, DH_, MLM,
        sM, (size_t)MLM * DH_, (size_t)MLM * DH_,
        1.f, 0, nullptr, nullptr, nullptr, nullptr, nullptr);

    // 9. conv writes O
    conv_kernel<<<dim3(64, H_, B_), 256>>>(v, res_k, O);

    // 10. attn1 applied, accumulated into O
    attn1_kernel<<<dim3(32, H_, B_), 256, attn1_smem>>>(q, kl, Y, O);

    // 11. out = x + O @ w_out + b_out
    sgemm_kernel<<<dim3(4, 256, 1), 256>>>(O, w_out, out, B_ * NTOK, D_, D_, 0, 0, 0,
        1.f, 2, x, b_out, nullptr, nullptr, nullptr);
}

// round 4
// speedup vs baseline: 1.3324x; 1.3324x over previous
#include <cuda_runtime.h>
#include <cuda_bf16.h>
#include <math.h>
#include <stdint.h>

#define B_    4
#define NTOK  8192
#define D_    512
#define H_    8
#define DH_   64
#define MLM   256
#define LSEG  32
#define BH    (B_*H_)
#define KER_  33

// ================= warp MMA helpers (plain sm_103: mma.sync + ldmatrix) =================
__device__ __forceinline__ uint32_t smem_to_u32(const void* p) {
    uint32_t a;
    asm("{ .reg .u64 t; cvta.to.shared.u64 t, %1; cvt.u32.u64 %0, t; }" : "=r"(a) : "l"(p));
    return a;
}
__device__ __forceinline__ void mma_bf16(float (&d)[4], const uint32_t (&a)[4], const uint32_t (&b)[2]) {
    asm volatile("mma.sync.aligned.m16n8k16.row.col.f32.bf16.bf16.f32 "
        "{%0,%1,%2,%3}, {%4,%5,%6,%7}, {%8,%9}, {%0,%1,%2,%3};"
        : "+f"(d[0]), "+f"(d[1]), "+f"(d[2]), "+f"(d[3])
        : "r"(a[0]), "r"(a[1]), "r"(a[2]), "r"(a[3]), "r"(b[0]), "r"(b[1]));
}
__device__ __forceinline__ void ldsm4(uint32_t (&r)[4], uint32_t a) {
    asm volatile("ldmatrix.sync.aligned.m8n8.x4.shared.b16 {%0,%1,%2,%3}, [%4];"
        : "=r"(r[0]), "=r"(r[1]), "=r"(r[2]), "=r"(r[3]) : "r"(a));
}
__device__ __forceinline__ void ldsm2(uint32_t (&r)[2], uint32_t a) {
    asm volatile("ldmatrix.sync.aligned.m8n8.x2.shared.b16 {%0,%1}, [%2];"
        : "=r"(r[0]), "=r"(r[1]) : "r"(a));
}

// ================= scratch buffers =================
__device__ __nv_bfloat16 g_nh[(size_t)B_*NTOK*D_];
__device__ __nv_bfloat16 g_nl[(size_t)B_*NTOK*D_];
__device__ __nv_bfloat16 g_wqh[(size_t)3*D_*D_];
__device__ __nv_bfloat16 g_wql[(size_t)3*D_*D_];
__device__ __nv_bfloat16 g_woh[(size_t)D_*D_];
__device__ __nv_bfloat16 g_wol[(size_t)D_*D_];
__device__ __nv_bfloat16 g_Oh[(size_t)B_*NTOK*D_];
__device__ __nv_bfloat16 g_Ol[(size_t)B_*NTOK*D_];
__device__ float g_q [(size_t)BH*NTOK*DH_];
__device__ float g_k [(size_t)BH*NTOK*DH_];
__device__ float g_v [(size_t)BH*NTOK*DH_];
__device__ float g_ql[(size_t)BH*MLM*DH_];
__device__ float g_kl[(size_t)BH*MLM*DH_];
__device__ float g_X [(size_t)BH*MLM*MLM];
__device__ __nv_bfloat16 g_Xh[(size_t)BH*MLM*MLM];
__device__ __nv_bfloat16 g_Xl[(size_t)BH*MLM*MLM];
__device__ __nv_bfloat16 g_Znh[2][(size_t)BH*MLM*MLM];
__device__ __nv_bfloat16 g_Znl[2][(size_t)BH*MLM*MLM];
__device__ __nv_bfloat16 g_Zth[2][(size_t)BH*MLM*MLM];
__device__ __nv_bfloat16 g_Ztl[2][(size_t)BH*MLM*MLM];
__device__ __nv_bfloat16 g_XZh[(size_t)BH*MLM*MLM];
__device__ __nv_bfloat16 g_XZl[(size_t)BH*MLM*MLM];
__device__ __nv_bfloat16 g_WtAh[(size_t)BH*MLM*MLM];
__device__ __nv_bfloat16 g_WtAl[(size_t)BH*MLM*MLM];
__device__ __nv_bfloat16 g_WtBh[(size_t)BH*MLM*MLM];
__device__ __nv_bfloat16 g_WtBl[(size_t)BH*MLM*MLM];
__device__ float g_Zf[(size_t)BH*MLM*MLM];
__device__ float g_A3V[(size_t)BH*MLM*DH_];
__device__ float g_Y  [(size_t)BH*MLM*DH_];
__device__ float g_O  [(size_t)B_*NTOK*D_];
__device__ unsigned g_maxbits[2];

// ================= LayerNorm -> bf16 hi/lo =================
__global__ void ln_kernel(const float* __restrict__ x, const float* __restrict__ gamma,
                          const float* __restrict__ beta,
                          __nv_bfloat16* __restrict__ ohi, __nv_bfloat16* __restrict__ olo) {
    int row = blockIdx.x;
    int tid = threadIdx.x;
    const float* xr = x + (size_t)row * D_;
    float v0 = xr[tid], v1 = xr[tid + 256];
    float s = v0 + v1, s2 = v0*v0 + v1*v1;
    #pragma unroll
    for (int o = 16; o > 0; o >>= 1) {
        s  += __shfl_xor_sync(0xffffffffu, s,  o);
        s2 += __shfl_xor_sync(0xffffffffu, s2, o);
    }
    __shared__ float sh[16];
    int w = tid >> 5, l = tid & 31;
    if (l == 0) { sh[w] = s; sh[w + 8] = s2; }
    __syncthreads();
    if (tid == 0) {
        float a = 0.f, b2 = 0.f;
        #pragma unroll
        for (int i = 0; i < 8; i++) { a += sh[i]; b2 += sh[i + 8]; }
        sh[0] = a; sh[8] = b2;
    }
    __syncthreads();
    float mu  = sh[0] * (1.f / D_);
    float var = sh[8] * (1.f / D_) - mu * mu;
    float inv = rsqrtf(var + 1e-5f);
    size_t base = (size_t)row * D_;
    #pragma unroll
    for (int half = 0; half < 2; half++) {
        int c = tid + half * 256;
        float v = (half == 0 ? v0 : v1);
        float nv = (v - mu) * inv * gamma[c] + beta[c];
        __nv_bfloat16 hi = __float2bfloat16(nv);
        ohi[base + c] = hi;
        olo[base + c] = __float2bfloat16(nv - __bfloat162float(hi));
    }
}

// ================= transpose+split: W[K,N] -> T[N,K] bf16 hi/lo =================
__global__ void tsplit_kernel(const float* __restrict__ W, __nv_bfloat16* __restrict__ Thi,
                              __nv_bfloat16* __restrict__ Tlo, int K, int N) {
    int idx = blockIdx.x * 256 + threadIdx.x;
    if (idx >= K * N) return;
    int k = idx / N, n = idx % N;
    float v = W[idx];
    __nv_bfloat16 hi = __float2bfloat16(v);
    Thi[(size_t)n * K + k] = hi;
    Tlo[(size_t)n * K + k] = __float2bfloat16(v - __bfloat162float(hi));
}

__global__ void osplit_kernel(const float* __restrict__ O, __nv_bfloat16* __restrict__ hi,
                              __nv_bfloat16* __restrict__ lo) {
    size_t idx = (size_t)blockIdx.x * 256 + threadIdx.x;
    float v = O[idx];
    __nv_bfloat16 h = __float2bfloat16(v);
    hi[idx] = h;
    lo[idx] = __float2bfloat16(v - __bfloat162float(h));
}

// ================= bf16-split MMA GEMM: D[m,n] = sum_k A[m,k]*B[n,k] =================
// 128x128 tile, 256 threads (8 warps, warp tile 32m x 64n), K-chunk 32.
// mode 0: QKV scatter (q*0.125)
// mode 1: Cout = D + bias[n] + addx[m,n]  (row width 512)
// mode 2: pinv epilogue: Nhi/Nlo = split(alpha*D); Thi/Tlo = split((diag?diagc:0) - beta*D) transposed; Cf32 = alpha*D
#define TCG_SMEM (128 * 132 * 4)
__global__ void __launch_bounds__(256) tc_gemm(
        const __nv_bfloat16* __restrict__ Ahi, const __nv_bfloat16* __restrict__ Alo,
        const __nv_bfloat16* __restrict__ Bhi, const __nv_bfloat16* __restrict__ Blo,
        int K, size_t strA, size_t strB, int mode,
        float* __restrict__ qp, float* __restrict__ kp, float* __restrict__ vp,
        float* __restrict__ Cout, const float* __restrict__ bias, const float* __restrict__ addx,
        __nv_bfloat16* __restrict__ Nhi, __nv_bfloat16* __restrict__ Nlo,
        __nv_bfloat16* __restrict__ Thi, __nv_bfloat16* __restrict__ Tlo,
        float* __restrict__ Cf32, float alpha, float diagc, float beta)
{
    extern __shared__ __align__(16) char smem[];
    __nv_bfloat16* tiles = reinterpret_cast<__nv_bfloat16*>(smem);  // 4 x [128][40]
    uint32_t sbase = smem_to_u32(smem);
    int tid = threadIdx.x;
    int wid = tid >> 5, lane = tid & 31;
    int wm = (wid & 3) * 32, wn = (wid >> 2) * 64;
    int bz = blockIdx.z;
    int m0 = blockIdx.y * 128, n0 = blockIdx.x * 128;
    size_t oz = (size_t)bz * 65536;
    Ahi += (size_t)bz * strA; Alo += (size_t)bz * strA;
    Bhi += (size_t)bz * strB; Blo += (size_t)bz * strB;

    const __nv_bfloat16* srcs[4] = {Ahi, Alo, Bhi, Blo};
    const int row0s[4] = {m0, m0, n0, n0};

    float acc[2][8][4];
    #pragma unroll
    for (int a = 0; a < 2; a++)
        #pragma unroll
        for (int b = 0; b < 8; b++)
            #pragma unroll
            for (int c = 0; c < 4; c++) acc[a][b][c] = 0.f;

    int nch = K >> 5;
    for (int ch = 0; ch < nch; ch++) {
        int k0 = ch << 5;
        #pragma unroll
        for (int bsel = 0; bsel < 4; bsel++) {
            const __nv_bfloat16* src = srcs[bsel];
            int row0 = row0s[bsel];
            #pragma unroll
            for (int i = 0; i < 2; i++) {
                int lin = tid + i * 256;
                int r = lin >> 2, c16 = lin & 3;
                uint4 val = *reinterpret_cast<const uint4*>(src + (size_t)(row0 + r) * K + k0 + c16 * 8);
                *reinterpret_cast<uint4*>(tiles + bsel * 5120 + r * 40 + c16 * 8) = val;
            }
        }
        __syncthreads();
        #pragma unroll
        for (int ks = 0; ks < 32; ks += 16) {
            uint32_t Ah[2][4], Al[2][4];
            #pragma unroll
            for (int mf = 0; mf < 2; mf++) {
                int row = wm + mf * 16 + (lane & 15);
                int col = ks + ((lane >> 4) << 3);
                ldsm4(Ah[mf], sbase + (uint32_t)(0 * 5120 + row * 40 + col) * 2);
                ldsm4(Al[mf], sbase + (uint32_t)(1 * 5120 + row * 40 + col) * 2);
            }
            #pragma unroll
            for (int nf = 0; nf < 8; nf++) {
                int rowb = wn + nf * 8 + (lane & 7);
                int colb = ks + ((lane >> 3) & 1) * 8;
                uint32_t Bh2[2], Bl2[2];
                ldsm2(Bh2, sbase + (uint32_t)(2 * 5120 + rowb * 40 + colb) * 2);
                ldsm2(Bl2, sbase + (uint32_t)(3 * 5120 + rowb * 40 + colb) * 2);
                #pragma unroll
                for (int mf = 0; mf < 2; mf++) {
                    mma_bf16(acc[mf][nf], Ah[mf], Bh2);
                    mma_bf16(acc[mf][nf], Ah[mf], Bl2);
                    mma_bf16(acc[mf][nf], Al[mf], Bh2);
                }
            }
        }
        __syncthreads();
    }

    // stage accumulators to smem [128][132]
    float* stg = reinterpret_cast<float*>(smem);
    {
        int r = lane >> 2, c = (lane & 3) * 2;
        #pragma unroll
        for (int mf = 0; mf < 2; mf++)
            #pragma unroll
            for (int nf = 0; nf < 8; nf++) {
                int rr = wm + mf * 16 + r, cc = wn + nf * 8 + c;
                *reinterpret_cast<float2*>(&stg[rr * 132 + cc]) = make_float2(acc[mf][nf][0], acc[mf][nf][1]);
                *reinterpret_cast<float2*>(&stg[(rr + 8) * 132 + cc]) = make_float2(acc[mf][nf][2], acc[mf][nf][3]);
            }
    }
    __syncthreads();

    if (mode == 0) {
        #pragma unroll 4
        for (int i = 0; i < 16; i++) {
            int lin = tid + (i << 8);
            int token = lin >> 5, c4 = lin & 31;
            int gn = n0 + (c4 << 2);
            float4 v = *reinterpret_cast<float4*>(&stg[token * 132 + (c4 << 2)]);
            int gmm = m0 + token;
            int b_ = gmm >> 13, n_ = gmm & 8191;
            int sec = gn >> 9, cc = gn & 511, h_ = cc >> 6, dh = cc & 63;
            size_t idx = ((((size_t)b_ * H_ + h_) * NTOK) + n_) * DH_ + dh;
            if (sec == 0) {
                v.x *= 0.125f; v.y *= 0.125f; v.z *= 0.125f; v.w *= 0.125f;
                *reinterpret_cast<float4*>(&qp[idx]) = v;
            } else if (sec == 1) {
                *reinterpret_cast<float4*>(&kp[idx]) = v;
            } else {
                *reinterpret_cast<float4*>(&vp[idx]) = v;
            }
        }
    } else if (mode == 1) {
        #pragma unroll 4
        for (int i = 0; i < 16; i++) {
            int lin = tid + (i << 8);
            int token = lin >> 5, c4 = lin & 31;
            int gn = n0 + (c4 << 2);
            int gmm = m0 + token;
            float4 v = *reinterpret_cast<float4*>(&stg[token * 132 + (c4 << 2)]);
            float4 bb = *reinterpret_cast<const float4*>(&bias[gn]);
            float4 xx = *reinterpret_cast<const float4*>(&addx[(size_t)gmm * 512 + gn]);
            v.x += bb.x + xx.x; v.y += bb.y + xx.y; v.z += bb.z + xx.z; v.w += bb.w + xx.w;
            *reinterpret_cast<float4*>(&Cout[(size_t)gmm * 512 + gn]) = v;
        }
    } else {
        if (Thi) {
            #pragma unroll 4
            for (int i = 0; i < 64; i++) {
                int idx = tid + (i << 8);
                int gn_l = idx >> 7, gm_l = idx & 127;
                int gmm = m0 + gm_l, gn = n0 + gn_l;
                float v = stg[gm_l * 132 + gn_l];
                float t = (gmm == gn ? diagc : 0.f) - beta * v;
                __nv_bfloat16 h = __float2bfloat16(t);
                Thi[oz + (size_t)gn * 256 + gmm] = h;
                Tlo[oz + (size_t)gn * 256 + gmm] = __float2bfloat16(t - __bfloat162float(h));
            }
        }
        if (Nhi) {
            #pragma unroll 4
            for (int i = 0; i < 16; i++) {
                int lin = tid + (i << 8);
                int token = lin >> 5, c4 = lin & 31;
                int gn = n0 + (c4 << 2);
                int gmm = m0 + token;
                float4 v = *reinterpret_cast<float4*>(&stg[token * 132 + (c4 << 2)]);
                float vv[4] = {v.x * alpha, v.y * alpha, v.z * alpha, v.w * alpha};
                __nv_bfloat16 h[4], l2[4];
                #pragma unroll
                for (int t2 = 0; t2 < 4; t2++) {
                    h[t2] = __float2bfloat16(vv[t2]);
                    l2[t2] = __float2bfloat16(vv[t2] - __bfloat162float(h[t2]));
                }
                *reinterpret_cast<uint2*>(&Nhi[oz + (size_t)gmm * 256 + gn]) = *reinterpret_cast<uint2*>(h);
                *reinterpret_cast<uint2*>(&Nlo[oz + (size_t)gmm * 256 + gn]) = *reinterpret_cast<uint2*>(l2);
            }
        }
        if (Cf32) {
            #pragma unroll 4
            for (int i = 0; i < 16; i++) {
                int lin = tid + (i << 8);
                int token = lin >> 5, c4 = lin & 31;
                int gn = n0 + (c4 << 2);
                int gmm = m0 + token;
                float4 v = *reinterpret_cast<float4*>(&stg[token * 132 + (c4 << 2)]);
                v.x *= alpha; v.y *= alpha; v.z *= alpha; v.w *= alpha;
                *reinterpret_cast<float4*>(&Cf32[oz + (size_t)gmm * 256 + gn]) = v;
            }
        }
    }
}

// ================= SIMT SGEMM (Y only): C = A@B, B in [K,N] =================
__global__ void __launch_bounds__(256) sgemm_kernel(
        const float* __restrict__ A, const float* __restrict__ B, float* __restrict__ C,
        int M, int N, int K, size_t sA, size_t sB, size_t sC)
{
    int bz = blockIdx.z;
    A += (size_t)bz * sA; B += (size_t)bz * sB; C += (size_t)bz * sC;
    int m0 = blockIdx.y * 128, n0 = blockIdx.x * 128;
    __shared__ float As[8][128];
    __shared__ float Bs[8][128];
    int tid = threadIdx.x;
    int tx = tid & 15, ty = tid >> 4;
    float acc[8][8];
    #pragma unroll
    for (int i = 0; i < 8; i++)
        #pragma unroll
        for (int j = 0; j < 8; j++) acc[i][j] = 0.f;

    for (int k0 = 0; k0 < K; k0 += 8) {
        #pragma unroll
        for (int i = 0; i < 4; i++) {
            int lin = tid + i * 256;
            int kk = lin & 7, mm = lin >> 3;
            int gmm = m0 + mm, gk = k0 + kk;
            As[kk][mm] = (gmm < M && gk < K) ? A[(size_t)gmm * K + gk] : 0.f;
        }
        #pragma unroll
        for (int i = 0; i < 4; i++) {
            int lin = tid + i * 256;
            int nn = lin & 127, kk = lin >> 7;
            int gn = n0 + nn, gk = k0 + kk;
            Bs[kk][nn] = (gn < N && gk < K) ? B[(size_t)gk * N + gn] : 0.f;
        }
        __syncthreads();
        #pragma unroll
        for (int kk = 0; kk < 8; kk++) {
            float a[8], b[8];
            *(float4*)&a[0] = *(const float4*)&As[kk][ty * 8];
            *(float4*)&a[4] = *(const float4*)&As[kk][ty * 8 + 4];
            *(float4*)&b[0] = *(const float4*)&Bs[kk][tx * 8];
            *(float4*)&b[4] = *(const float4*)&Bs[kk][tx * 8 + 4];
            #pragma unroll
            for (int i = 0; i < 8; i++)
                #pragma unroll
                for (int j = 0; j < 8; j++) acc[i][j] += a[i] * b[j];
        }
        __syncthreads();
    }
    #pragma unroll
    for (int i = 0; i < 8; i++) {
        int gmm = m0 + ty * 8 + i;
        if (gmm >= M) continue;
        #pragma unroll
        for (int j = 0; j < 8; j++) {
            int gn = n0 + tx * 8 + j;
            if (gn >= N) continue;
            C[(size_t)gmm * N + gn] = acc[i][j];
        }
    }
}

// ================= landmark means =================
__global__ void landmark_kernel(const float* __restrict__ q, const float* __restrict__ k,
                                float* __restrict__ ql, float* __restrict__ kl) {
    int bh = blockIdx.x, m = blockIdx.y;
    int dh = threadIdx.x;
    size_t base = ((size_t)bh * NTOK + (size_t)m * LSEG) * DH_ + dh;
    float aq = 0.f, ak = 0.f;
    #pragma unroll
    for (int i = 0; i < LSEG; i++) {
        aq += q[base + (size_t)i * DH_];
        ak += k[base + (size_t)i * DH_];
    }
    size_t o = ((size_t)bh * MLM + m) * DH_ + dh;
    ql[o] = aq * (1.f / LSEG);
    kl[o] = ak * (1.f / LSEG);
}

// ================= attn2 (tiled): X = softmax(q_l @ k_l^T), + bf16 split =================
#define ATTN2_SMEM ((256 * 68 + 32 * 64 + 8) * 4)
__global__ void attn2_kernel(const float* __restrict__ ql, const float* __restrict__ kl,
                             float* __restrict__ X,
                             __nv_bfloat16* __restrict__ Xh, __nv_bfloat16* __restrict__ Xl) {
    extern __shared__ __align__(16) float sh2[];
    float* kls  = sh2;               // [256][68]
    float* qs   = sh2 + 256 * 68;    // [32][64]
    float* wsum = qs + 32 * 64;      // [8]
    int bh = blockIdx.x, mt = blockIdx.y;
    int tid = threadIdx.x;
    #pragma unroll
    for (int i = 0; i < 16; i++) {
        int lin = tid + i * 256;
        int r = lin >> 4, c = lin & 15;
        *(float4*)&kls[r * 68 + c * 4] = *(const float4*)&kl[((size_t)bh * MLM + r) * DH_ + c * 4];
    }
    #pragma unroll
    for (int i = 0; i < 2; i++) {
        int lin = tid + i * 256;
        int r = lin >> 4, c = lin & 15;
        *(float4*)&qs[r * 64 + c * 4] = *(const float4*)&ql[((size_t)bh * MLM + mt * 32 + r) * DH_ + c * 4];
    }
    __syncthreads();
    int j = tid;
    int wid = tid >> 5, lane = tid & 31;
    const float* kr = &kls[j * 68];
    for (int ml = 0; ml < 32; ml++) {
        const float* qr = &qs[ml * 64];
        float a0 = 0.f, a1 = 0.f, a2 = 0.f, a3 = 0.f;
        #pragma unroll
        for (int d4 = 0; d4 < 16; d4++) {
            float4 kv = *(const float4*)&kr[d4 * 4];
            float4 qv = *(const float4*)&qr[d4 * 4];
            a0 += qv.x * kv.x; a1 += qv.y * kv.y; a2 += qv.z * kv.z; a3 += qv.w * kv.w;
        }
        float e = __expf(a0 + a1 + a2 + a3);
        float t = e;
        #pragma unroll
        for (int o = 16; o > 0; o >>= 1) t += __shfl_xor_sync(0xffffffffu, t, o);
        if (lane == 0) wsum[wid] = t;
        __syncthreads();
        float S = 0.f;
        #pragma unroll
        for (int w = 0; w < 8; w++) S += wsum[w];
        float val = e * (1.f / S);
        size_t o = ((size_t)bh * MLM + mt * 32 + ml) * MLM + j;
        X[o] = val;
        __nv_bfloat16 h = __float2bfloat16(val);
        Xh[o] = h;
        Xl[o] = __float2bfloat16(val - __bfloat162float(h));
        __syncthreads();
    }
}

// ================= pinv init =================
__global__ void initmax_kernel(unsigned* mb) { mb[0] = 0u; mb[1] = 0u; }

__global__ void rowcol_kernel(const float* __restrict__ X, unsigned* mb) {
    int bh = blockIdx.x;
    int i = threadIdx.x;
    const float* Xm = X + (size_t)bh * MLM * MLM;
    float rs = 0.f, cs = 0.f;
    for (int j = 0; j < MLM; j++) {
        rs += fabsf(Xm[(size_t)i * MLM + j]);
        cs += fabsf(Xm[(size_t)j * MLM + i]);
    }
    #pragma unroll
    for (int o = 16; o > 0; o >>= 1) {
        rs = fmaxf(rs, __shfl_xor_sync(0xffffffffu, rs, o));
        cs = fmaxf(cs, __shfl_xor_sync(0xffffffffu, cs, o));
    }
    __shared__ float shr[8], shc[8];
    int w = i >> 5;
    if ((i & 31) == 0) { shr[w] = rs; shc[w] = cs; }
    __syncthreads();
    if (i == 0) {
        float mr = shr[0], mc = shc[0];
        #pragma unroll
        for (int k2 = 1; k2 < 8; k2++) { mr = fmaxf(mr, shr[k2]); mc = fmaxf(mc, shc[k2]); }
        atomicMax(&mb[0], __float_as_uint(mr));
        atomicMax(&mb[1], __float_as_uint(mc));
    }
}

// Z0 = X^T / denom : norm split (transposed read) and trans split (natural read)
__global__ void zinit_kernel(const float* __restrict__ X, const unsigned* __restrict__ mb,
                             __nv_bfloat16* __restrict__ Znh, __nv_bfloat16* __restrict__ Znl,
                             __nv_bfloat16* __restrict__ Zth, __nv_bfloat16* __restrict__ Ztl) {
    float inv = 1.f / (__uint_as_float(mb[0]) * __uint_as_float(mb[1]));
    size_t idx = (size_t)blockIdx.x * 256 + threadIdx.x;
    int bh = (int)(idx >> 16);
    int r = (int)((idx >> 8) & 255);
    int c = (int)(idx & 255);
    float tv = X[idx] * inv;                                        // Zt[r][c] = X[r][c]*inv
    __nv_bfloat16 th = __float2bfloat16(tv);
    Zth[idx] = th; Ztl[idx] = __float2bfloat16(tv - __bfloat162float(th));
    float nv = X[((size_t)bh << 16) + ((size_t)c << 8) + r] * inv;  // Zn[r][c] = X[c][r]*inv
    __nv_bfloat16 nh = __float2bfloat16(nv);
    Znh[idx] = nh; Znl[idx] = __float2bfloat16(nv - __bfloat162float(nh));
}

// ================= attn3 @ v (streaming softmax over n) =================
__global__ void attn3v_kernel(const float* __restrict__ ql, const float* __restrict__ k,
                              const float* __restrict__ v, float* __restrict__ out) {
    int bh = blockIdx.x, qg = blockIdx.y;
    int tid = threadIdx.x;
    int q = tid >> 2, s = tid & 3;
    int m = qg * 32 + q;
    __shared__ float ks[64][64];
    __shared__ float vs[64][64];
    float qr[16];
    const float* qlp = ql + ((size_t)bh * MLM + m) * DH_ + s * 16;
    #pragma unroll
    for (int j = 0; j < 16; j++) qr[j] = qlp[j];
    float acc[16];
    #pragma unroll
    for (int j = 0; j < 16; j++) acc[j] = 0.f;
    float lsum = 0.f;
    const float* kbase = k + (size_t)bh * NTOK * DH_;
    const float* vbase = v + (size_t)bh * NTOK * DH_;

    for (int nt = 0; nt < NTOK; nt += 64) {
        __syncthreads();
        #pragma unroll
        for (int i = 0; i < 8; i++) {
            int f4 = tid + i * 128;
            int row2 = f4 >> 4, c4 = f4 & 15;
            ((float4*)ks)[f4] = ((const float4*)(kbase + (size_t)(nt + row2) * DH_))[c4];
            ((float4*)vs)[f4] = ((const float4*)(vbase + (size_t)(nt + row2) * DH_))[c4];
        }
        __syncthreads();
        #pragma unroll 4
        for (int n = 0; n < 64; n++) {
            const float* kr = &ks[n][s * 16];
            float p0 = 0.f, p1 = 0.f;
            #pragma unroll
            for (int j = 0; j < 8; j++) { p0 += qr[j] * kr[j]; p1 += qr[j + 8] * kr[j + 8]; }
            float p = p0 + p1;
            p += __shfl_xor_sync(0xffffffffu, p, 1);
            p += __shfl_xor_sync(0xffffffffu, p, 2);
            float e = __expf(p);
            lsum += e;
            const float* vr = &vs[n][s * 16];
            #pragma unroll
            for (int j = 0; j < 16; j++) acc[j] += e * vr[j];
        }
    }
    float invl = 1.f / lsum;
    float* op = out + ((size_t)bh * MLM + m) * DH_ + s * 16;
    #pragma unroll
    for (int j = 0; j < 16; j++) op[j] = acc[j] * invl;
}

// ================= depthwise conv, writes O =================
__global__ void conv_kernel(const float* __restrict__ v, const float* __restrict__ ker,
                            float* __restrict__ O) {
    int nt = blockIdx.x, h = blockIdx.y, b = blockIdx.z;
    int n0 = nt * 128;
    __shared__ float vsh[160][64];
    __shared__ float kw[KER_];
    int tid = threadIdx.x;
    if (tid < KER_) kw[tid] = ker[h * KER_ + tid];
    const float* vb = v + ((size_t)b * H_ + h) * NTOK * DH_;
    #pragma unroll
    for (int i = 0; i < 10; i++) {
        int f4 = tid + i * 256;
        int row2 = f4 >> 4, c4 = f4 & 15;
        int n = n0 - 16 + row2;
        float4 val = make_float4(0.f, 0.f, 0.f, 0.f);
        if (n >= 0 && n < NTOK) val = ((const float4*)(vb + (size_t)n * DH_))[c4];
        ((float4*)vsh)[f4] = val;
    }
    __syncthreads();
    int dh = tid & 63, g = tid >> 6;
    for (int ii = 0; ii < 32; ii++) {
        int nn = g * 32 + ii;
        float o = 0.f;
        #pragma unroll
        for (int t = 0; t < KER_; t++) o += kw[t] * vsh[nn + t][dh];
        O[((size_t)b * NTOK + (n0 + nn)) * D_ + h * DH_ + dh] = o;
    }
}

// ================= attn1 apply: O += softmax(q @ k_l^T) @ Y =================
__global__ void attn1_kernel(const float* __restrict__ q, const float* __restrict__ kl,
                             const float* __restrict__ Y, float* __restrict__ O) {
    extern __shared__ float sh[];
    float* kls   = sh;                       // 256*65
    float* Ys    = kls + 256 * 65;           // 256*64
    float* qrow  = Ys + 256 * 64;            // 64
    float* ps    = qrow + 64;                // 256
    float* wsum  = ps + 256;                 // 8
    float* opart = wsum + 8;                 // 256
    int chunk = blockIdx.x, h = blockIdx.y, b = blockIdx.z;
    int bh = b * H_ + h;
    int tid = threadIdx.x;
    for (int i = tid; i < MLM * DH_; i += 256) {
        int r = i >> 6, c = i & 63;
        kls[r * 65 + c] = kl[((size_t)bh * MLM + r) * DH_ + c];
        Ys[i] = Y[(size_t)bh * MLM * DH_ + i];
    }
    __syncthreads();
    int n0 = chunk * 256;
    const float* qb = q + (size_t)bh * NTOK * DH_;
    int wid = tid >> 5, lane = tid & 31;
    int g = tid >> 6, dh = tid & 63;
    for (int nn = 0; nn < 256; nn++) {
        int n = n0 + nn;
        if (tid < 64) qrow[tid] = qb[(size_t)n * DH_ + tid];
        __syncthreads();
        const float* kr = &kls[tid * 65];
        float s0 = 0.f, s1 = 0.f, s2 = 0.f, s3 = 0.f;
        #pragma unroll
        for (int d = 0; d < 64; d += 4) {
            s0 += qrow[d] * kr[d]; s1 += qrow[d+1] * kr[d+1];
            s2 += qrow[d+2] * kr[d+2]; s3 += qrow[d+3] * kr[d+3];
        }
        float e = __expf(s0 + s1 + s2 + s3);
        ps[tid] = e;
        float t = e;
        #pragma unroll
        for (int o = 16; o > 0; o >>= 1) t += __shfl_xor_sync(0xffffffffu, t, o);
        if (lane == 0) wsum[wid] = t;
        __syncthreads();
        float S = 0.f;
        #pragma unroll
        for (int w = 0; w < 8; w++) S += wsum[w];
        const float* pp = &ps[g * 64];
        const float* Yp = &Ys[(size_t)g * 64 * 64 + dh];
        float o = 0.f;
        #pragma unroll 16
        for (int jj = 0; jj < 64; jj++) o += pp[jj] * Yp[(size_t)jj * 64];
        opart[tid] = o;
        __syncthreads();
        if (tid < 64) {
            float oo = opart[tid] + opart[64 + tid] + opart[128 + tid] + opart[192 + tid];
            O[((size_t)b * NTOK + n) * D_ + h * DH_ + tid] += oo / S;
        }
        __syncthreads();
    }
}

// ================= host launcher =================
extern "C" void kernel_launch(void* const* d_in, const int* in_sizes, int n_in,
                              void* d_out, int out_size) {
    const float* x      = (const float*)d_in[0];
    const float* gamma  = (const float*)d_in[1];
    const float* beta   = (const float*)d_in[2];
    const float* w_qkv  = (const float*)d_in[3];
    const float* res_k  = (const float*)d_in[4];
    const float* w_out  = (const float*)d_in[5];
    const float* b_out  = (const float*)d_in[6];
    float* out = (float*)d_out;

    __nv_bfloat16 *nh, *nl, *wqh, *wql, *woh, *wol, *Oh, *Ol, *Xh, *Xl;
    __nv_bfloat16 *Znh[2], *Znl[2], *Zth[2], *Ztl[2], *XZh, *XZl, *WtAh, *WtAl, *WtBh, *WtBl;
    float *q, *k, *v, *ql, *kl, *X, *Zf, *A3V, *Y, *O;
    unsigned* mb;
    cudaGetSymbolAddress((void**)&nh, g_nh);
    cudaGetSymbolAddress((void**)&nl, g_nl);
    cudaGetSymbolAddress((void**)&wqh, g_wqh);
    cudaGetSymbolAddress((void**)&wql, g_wql);
    cudaGetSymbolAddress((void**)&woh, g_woh);
    cudaGetSymbolAddress((void**)&wol, g_wol);
    cudaGetSymbolAddress((void**)&Oh, g_Oh);
    cudaGetSymbolAddress((void**)&Ol, g_Ol);
    cudaGetSymbolAddress((void**)&Xh, g_Xh);
    cudaGetSymbolAddress((void**)&Xl, g_Xl);
    {
        __nv_bfloat16* p;
        cudaGetSymbolAddress((void**)&p, g_Znh); Znh[0] = p; Znh[1] = p + (size_t)BH*MLM*MLM;
        cudaGetSymbolAddress((void**)&p, g_Znl); Znl[0] = p; Znl[1] = p + (size_t)BH*MLM*MLM;
        cudaGetSymbolAddress((void**)&p, g_Zth); Zth[0] = p; Zth[1] = p + (size_t)BH*MLM*MLM;
        cudaGetSymbolAddress((void**)&p, g_Ztl); Ztl[0] = p; Ztl[1] = p + (size_t)BH*MLM*MLM;
    }
    cudaGetSymbolAddress((void**)&XZh, g_XZh);
    cudaGetSymbolAddress((void**)&XZl, g_XZl);
    cudaGetSymbolAddress((void**)&WtAh, g_WtAh);
    cudaGetSymbolAddress((void**)&WtAl, g_WtAl);
    cudaGetSymbolAddress((void**)&WtBh, g_WtBh);
    cudaGetSymbolAddress((void**)&WtBl, g_WtBl);
    cudaGetSymbolAddress((void**)&q,  g_q);
    cudaGetSymbolAddress((void**)&k,  g_k);
    cudaGetSymbolAddress((void**)&v,  g_v);
    cudaGetSymbolAddress((void**)&ql, g_ql);
    cudaGetSymbolAddress((void**)&kl, g_kl);
    cudaGetSymbolAddress((void**)&X,  g_X);
    cudaGetSymbolAddress((void**)&Zf, g_Zf);
    cudaGetSymbolAddress((void**)&A3V, g_A3V);
    cudaGetSymbolAddress((void**)&Y,  g_Y);
    cudaGetSymbolAddress((void**)&O,  g_O);
    cudaGetSymbolAddress((void**)&mb, g_maxbits);

    const int attn1_smem = (256 * 65 + 256 * 64 + 64 + 256 + 8 + 256) * (int)sizeof(float);
    cudaFuncSetAttribute(attn1_kernel, cudaFuncAttributeMaxDynamicSharedMemorySize, attn1_smem);
    cudaFuncSetAttribute(attn2_kernel, cudaFuncAttributeMaxDynamicSharedMemorySize, ATTN2_SMEM);
    cudaFuncSetAttribute(tc_gemm, cudaFuncAttributeMaxDynamicSharedMemorySize, TCG_SMEM);

    const size_t sM = (size_t)MLM * MLM;

    // 1. LayerNorm -> bf16 split
    ln_kernel<<<B_ * NTOK, 256>>>(x, gamma, beta, nh, nl);

    // 2. weight transpose+split
    tsplit_kernel<<<(D_ * 3 * D_ + 255) / 256, 256>>>(w_qkv, wqh, wql, D_, 3 * D_);
    tsplit_kernel<<<(D_ * D_ + 255) / 256, 256>>>(w_out, woh, wol, D_, D_);

    // 3. QKV on tensor cores (mma.sync), scatter to head layout
    tc_gemm<<<dim3(12, 256, 1), 256, TCG_SMEM>>>(nh, nl, wqh, wql, D_, 0, 0, 0,
        q, k, v, nullptr, nullptr, nullptr,
        nullptr, nullptr, nullptr, nullptr, nullptr, 1.f, 0.f, 1.f);

    // 4. Landmarks
    landmark_kernel<<<dim3(BH, MLM), 64>>>(q, k, ql, kl);

    // 5. attn2 (+ bf16 split)
    attn2_kernel<<<dim3(BH, 8), 256, ATTN2_SMEM>>>(ql, kl, X, Xh, Xl);

    // 6. pinv init
    initmax_kernel<<<1, 1>>>(mb);
    rowcol_kernel<<<BH, 256>>>(X, mb);
    zinit_kernel<<<8192, 256>>>(X, mb, Znh[0], Znl[0], Zth[0], Ztl[0]);

    // 7. Newton iterations on tensor cores
    int cur = 0;
    for (int it = 0; it < 6; it++) {
        int nxt = cur ^ 1;
        // XZ = X@Z (norm split out), WtA = (7I - XZ)^T (trans split out)
        tc_gemm<<<dim3(2, 2, BH), 256, TCG_SMEM>>>(Xh, Xl, Zth[cur], Ztl[cur], MLM, sM, sM, 2,
            nullptr, nullptr, nullptr, nullptr, nullptr, nullptr,
            XZh, XZl, WtAh, WtAl, nullptr, 1.f, 7.f, 1.f);
        // WtB = (15I - XZ@W7)^T
        tc_gemm<<<dim3(2, 2, BH), 256, TCG_SMEM>>>(XZh, XZl, WtAh, WtAl, MLM, sM, sM, 2,
            nullptr, nullptr, nullptr, nullptr, nullptr, nullptr,
            nullptr, nullptr, WtBh, WtBl, nullptr, 1.f, 15.f, 1.f);
        // WtA = (13I - XZ@W15)^T
        tc_gemm<<<dim3(2, 2, BH), 256, TCG_SMEM>>>(XZh, XZl, WtBh, WtBl, MLM, sM, sM, 2,
            nullptr, nullptr, nullptr, nullptr, nullptr, nullptr,
            nullptr, nullptr, WtAh, WtAl, nullptr, 1.f, 13.f, 1.f);
        // Z_next = 0.25 * Z@W13 (norm + trans splits; fp32 copy on last iter)
        tc_gemm<<<dim3(2, 2, BH), 256, TCG_SMEM>>>(Znh[cur], Znl[cur], WtAh, WtAl, MLM, sM, sM, 2,
            nullptr, nullptr, nullptr, nullptr, nullptr, nullptr,
            Znh[nxt], Znl[nxt], Zth[nxt], Ztl[nxt], (it == 5) ? Zf : nullptr, 0.25f, 0.f, -0.25f);
        cur = nxt;
    }

    // 8. attn3 @ v
    attn3v_kernel<<<dim3(BH, 8), 128>>>(ql, k, v, A3V);

    // 9. Y = pinv(attn2) @ (attn3 @ v)
    sgemm_kernel<<<dim3(1, 2, BH), 256>>>(Zf, A3V, Y, MLM, DH_, MLM,
        sM, (size_t)MLM * DH_, (size_t)MLM * DH_);

    // 10. conv -> O ; 11. attn1 accumulates into O
    conv_kernel<<<dim3(64, H_, B_), 256>>>(v, res_k, O);
    attn1_kernel<<<dim3(32, H_, B_), 256, attn1_smem>>>(q, kl, Y, O);

    // 12. split O ; 13. out = x + O@w_out + b_out on tensor cores
    osplit_kernel<<<(int)(((size_t)B_*NTOK*D_) / 256), 256>>>(O, Oh, Ol);
    tc_gemm<<<dim3(4, 256, 1), 256, TCG_SMEM>>>(Oh, Ol, woh, wol, D_, 0, 0, 1,
        nullptr, nullptr, nullptr, out, b_out, x,
        nullptr, nullptr, nullptr, nullptr, nullptr, 1.f, 0.f, 1.f);
}

// round 5
// speedup vs baseline: 1.3332x; 1.0006x over previous
#include <cuda_runtime.h>
#include <cuda_bf16.h>
#include <math.h>
#include <stdint.h>

#define B_    4
#define NTOK  8192
#define D_    512
#define H_    8
#define DH_   64
#define MLM   256
#define LSEG  32
#define BH    (B_*H_)
#define KER_  33

// ================= warp MMA helpers (plain sm_103: mma.sync + ldmatrix) =================
__device__ __forceinline__ uint32_t smem_to_u32(const void* p) {
    uint32_t a;
    asm("{ .reg .u64 t; cvta.to.shared.u64 t, %1; cvt.u32.u64 %0, t; }" : "=r"(a) : "l"(p));
    return a;
}
__device__ __forceinline__ void mma_bf16(float (&d)[4], const uint32_t (&a)[4], const uint32_t (&b)[2]) {
    asm volatile("mma.sync.aligned.m16n8k16.row.col.f32.bf16.bf16.f32 "
        "{%0,%1,%2,%3}, {%4,%5,%6,%7}, {%8,%9}, {%0,%1,%2,%3};"
        : "+f"(d[0]), "+f"(d[1]), "+f"(d[2]), "+f"(d[3])
        : "r"(a[0]), "r"(a[1]), "r"(a[2]), "r"(a[3]), "r"(b[0]), "r"(b[1]));
}
__device__ __forceinline__ void ldsm4(uint32_t (&r)[4], uint32_t a) {
    asm volatile("ldmatrix.sync.aligned.m8n8.x4.shared.b16 {%0,%1,%2,%3}, [%4];"
        : "=r"(r[0]), "=r"(r[1]), "=r"(r[2]), "=r"(r[3]) : "r"(a));
}
__device__ __forceinline__ void ldsm2(uint32_t (&r)[2], uint32_t a) {
    asm volatile("ldmatrix.sync.aligned.m8n8.x2.shared.b16 {%0,%1}, [%2];"
        : "=r"(r[0]), "=r"(r[1]) : "r"(a));
}

// ================= scratch buffers =================
__device__ __nv_bfloat16 g_nh[(size_t)B_*NTOK*D_];
__device__ __nv_bfloat16 g_nl[(size_t)B_*NTOK*D_];
__device__ __nv_bfloat16 g_wqh[(size_t)3*D_*D_];
__device__ __nv_bfloat16 g_wql[(size_t)3*D_*D_];
__device__ __nv_bfloat16 g_woh[(size_t)D_*D_];
__device__ __nv_bfloat16 g_wol[(size_t)D_*D_];
__device__ __nv_bfloat16 g_Oh[(size_t)B_*NTOK*D_];
__device__ __nv_bfloat16 g_Ol[(size_t)B_*NTOK*D_];
__device__ float g_q [(size_t)BH*NTOK*DH_];
__device__ float g_k [(size_t)BH*NTOK*DH_];
__device__ float g_v [(size_t)BH*NTOK*DH_];
__device__ float g_ql[(size_t)BH*MLM*DH_];
__device__ float g_kl[(size_t)BH*MLM*DH_];
__device__ float g_X [(size_t)BH*MLM*MLM];
__device__ __nv_bfloat16 g_Xh[(size_t)BH*MLM*MLM];
__device__ __nv_bfloat16 g_Xl[(size_t)BH*MLM*MLM];
__device__ __nv_bfloat16 g_Znh[2][(size_t)BH*MLM*MLM];
__device__ __nv_bfloat16 g_Znl[2][(size_t)BH*MLM*MLM];
__device__ __nv_bfloat16 g_Zth[2][(size_t)BH*MLM*MLM];
__device__ __nv_bfloat16 g_Ztl[2][(size_t)BH*MLM*MLM];
__device__ __nv_bfloat16 g_XZh[(size_t)BH*MLM*MLM];
__device__ __nv_bfloat16 g_XZl[(size_t)BH*MLM*MLM];
__device__ __nv_bfloat16 g_WtAh[(size_t)BH*MLM*MLM];
__device__ __nv_bfloat16 g_WtAl[(size_t)BH*MLM*MLM];
__device__ __nv_bfloat16 g_WtBh[(size_t)BH*MLM*MLM];
__device__ __nv_bfloat16 g_WtBl[(size_t)BH*MLM*MLM];
__device__ float g_Zf[(size_t)BH*MLM*MLM];
__device__ float g_A3V[(size_t)BH*MLM*DH_];
__device__ float g_Y  [(size_t)BH*MLM*DH_];
__device__ float g_O  [(size_t)B_*NTOK*D_];
__device__ unsigned g_maxbits[2];

// ================= LayerNorm -> bf16 hi/lo =================
__global__ void ln_kernel(const float* __restrict__ x, const float* __restrict__ gamma,
                          const float* __restrict__ beta,
                          __nv_bfloat16* __restrict__ ohi, __nv_bfloat16* __restrict__ olo) {
    int row = blockIdx.x;
    int tid = threadIdx.x;
    const float* xr = x + (size_t)row * D_;
    float v0 = xr[tid], v1 = xr[tid + 256];
    float s = v0 + v1, s2 = v0*v0 + v1*v1;
    #pragma unroll
    for (int o = 16; o > 0; o >>= 1) {
        s  += __shfl_xor_sync(0xffffffffu, s,  o);
        s2 += __shfl_xor_sync(0xffffffffu, s2, o);
    }
    __shared__ float sh[16];
    int w = tid >> 5, l = tid & 31;
    if (l == 0) { sh[w] = s; sh[w + 8] = s2; }
    __syncthreads();
    if (tid == 0) {
        float a = 0.f, b2 = 0.f;
        #pragma unroll
        for (int i = 0; i < 8; i++) { a += sh[i]; b2 += sh[i + 8]; }
        sh[0] = a; sh[8] = b2;
    }
    __syncthreads();
    float mu  = sh[0] * (1.f / D_);
    float var = sh[8] * (1.f / D_) - mu * mu;
    float inv = rsqrtf(var + 1e-5f);
    size_t base = (size_t)row * D_;
    #pragma unroll
    for (int half = 0; half < 2; half++) {
        int c = tid + half * 256;
        float v = (half == 0 ? v0 : v1);
        float nv = (v - mu) * inv * gamma[c] + beta[c];
        __nv_bfloat16 hi = __float2bfloat16(nv);
        ohi[base + c] = hi;
        olo[base + c] = __float2bfloat16(nv - __bfloat162float(hi));
    }
}

// ================= transpose+split: W[K,N] -> T[N,K] bf16 hi/lo =================
__global__ void tsplit_kernel(const float* __restrict__ W, __nv_bfloat16* __restrict__ Thi,
                              __nv_bfloat16* __restrict__ Tlo, int K, int N) {
    int idx = blockIdx.x * 256 + threadIdx.x;
    if (idx >= K * N) return;
    int k = idx / N, n = idx % N;
    float v = W[idx];
    __nv_bfloat16 hi = __float2bfloat16(v);
    Thi[(size_t)n * K + k] = hi;
    Tlo[(size_t)n * K + k] = __float2bfloat16(v - __bfloat162float(hi));
}

__global__ void osplit_kernel(const float* __restrict__ O, __nv_bfloat16* __restrict__ hi,
                              __nv_bfloat16* __restrict__ lo) {
    size_t idx = (size_t)blockIdx.x * 256 + threadIdx.x;
    float v = O[idx];
    __nv_bfloat16 h = __float2bfloat16(v);
    hi[idx] = h;
    lo[idx] = __float2bfloat16(v - __bfloat162float(h));
}

// ================= bf16-split MMA GEMM: D[m,n] = sum_k A[m,k]*B[n,k] =================
// 128x128 tile, 256 threads (8 warps, warp tile 32m x 64n), K-chunk 32.
// mode 0: QKV scatter (q*0.125)
// mode 1: Cout = D + bias[n] + addx[m,n]  (row width 512)
// mode 2: pinv epilogue: Nhi/Nlo = split(alpha*D); Thi/Tlo = split((diag?diagc:0) - beta*D) transposed; Cf32 = alpha*D
#define TCG_SMEM (128 * 132 * 4)
__global__ void __launch_bounds__(256) tc_gemm(
        const __nv_bfloat16* __restrict__ Ahi, const __nv_bfloat16* __restrict__ Alo,
        const __nv_bfloat16* __restrict__ Bhi, const __nv_bfloat16* __restrict__ Blo,
        int K, size_t strA, size_t strB, int mode,
        float* __restrict__ qp, float* __restrict__ kp, float* __restrict__ vp,
        float* __restrict__ Cout, const float* __restrict__ bias, const float* __restrict__ addx,
        __nv_bfloat16* __restrict__ Nhi, __nv_bfloat16* __restrict__ Nlo,
        __nv_bfloat16* __restrict__ Thi, __nv_bfloat16* __restrict__ Tlo,
        float* __restrict__ Cf32, float alpha, float diagc, float beta)
{
    extern __shared__ __align__(16) char smem[];
    __nv_bfloat16* tiles = reinterpret_cast<__nv_bfloat16*>(smem);  // 4 x [128][40]
    uint32_t sbase = smem_to_u32(smem);
    int tid = threadIdx.x;
    int wid = tid >> 5, lane = tid & 31;
    int wm = (wid & 3) * 32, wn = (wid >> 2) * 64;
    int bz = blockIdx.z;
    int m0 = blockIdx.y * 128, n0 = blockIdx.x * 128;
    size_t oz = (size_t)bz * 65536;
    Ahi += (size_t)bz * strA; Alo += (size_t)bz * strA;
    Bhi += (size_t)bz * strB; Blo += (size_t)bz * strB;

    const __nv_bfloat16* srcs[4] = {Ahi, Alo, Bhi, Blo};
    const int row0s[4] = {m0, m0, n0, n0};

    float acc[2][8][4];
    #pragma unroll
    for (int a = 0; a < 2; a++)
        #pragma unroll
        for (int b = 0; b < 8; b++)
            #pragma unroll
            for (int c = 0; c < 4; c++) acc[a][b][c] = 0.f;

    int nch = K >> 5;
    for (int ch = 0; ch < nch; ch++) {
        int k0 = ch << 5;
        #pragma unroll
        for (int bsel = 0; bsel < 4; bsel++) {
            const __nv_bfloat16* src = srcs[bsel];
            int row0 = row0s[bsel];
            #pragma unroll
            for (int i = 0; i < 2; i++) {
                int lin = tid + i * 256;
                int r = lin >> 2, c16 = lin & 3;
                uint4 val = *reinterpret_cast<const uint4*>(src + (size_t)(row0 + r) * K + k0 + c16 * 8);
                *reinterpret_cast<uint4*>(tiles + bsel * 5120 + r * 40 + c16 * 8) = val;
            }
        }
        __syncthreads();
        #pragma unroll
        for (int ks = 0; ks < 32; ks += 16) {
            uint32_t Ah[2][4], Al[2][4];
            #pragma unroll
            for (int mf = 0; mf < 2; mf++) {
                int row = wm + mf * 16 + (lane & 15);
                int col = ks + ((lane >> 4) << 3);
                ldsm4(Ah[mf], sbase + (uint32_t)(0 * 5120 + row * 40 + col) * 2);
                ldsm4(Al[mf], sbase + (uint32_t)(1 * 5120 + row * 40 + col) * 2);
            }
            #pragma unroll
            for (int nf = 0; nf < 8; nf++) {
                int rowb = wn + nf * 8 + (lane & 7);
                int colb = ks + ((lane >> 3) & 1) * 8;
                uint32_t Bh2[2], Bl2[2];
                ldsm2(Bh2, sbase + (uint32_t)(2 * 5120 + rowb * 40 + colb) * 2);
                ldsm2(Bl2, sbase + (uint32_t)(3 * 5120 + rowb * 40 + colb) * 2);
                #pragma unroll
                for (int mf = 0; mf < 2; mf++) {
                    mma_bf16(acc[mf][nf], Ah[mf], Bh2);
                    mma_bf16(acc[mf][nf], Ah[mf], Bl2);
                    mma_bf16(acc[mf][nf], Al[mf], Bh2);
                }
            }
        }
        __syncthreads();
    }

    // stage accumulators to smem [128][132]
    float* stg = reinterpret_cast<float*>(smem);
    {
        int r = lane >> 2, c = (lane & 3) * 2;
        #pragma unroll
        for (int mf = 0; mf < 2; mf++)
            #pragma unroll
            for (int nf = 0; nf < 8; nf++) {
                int rr = wm + mf * 16 + r, cc = wn + nf * 8 + c;
                *reinterpret_cast<float2*>(&stg[rr * 132 + cc]) = make_float2(acc[mf][nf][0], acc[mf][nf][1]);
                *reinterpret_cast<float2*>(&stg[(rr + 8) * 132 + cc]) = make_float2(acc[mf][nf][2], acc[mf][nf][3]);
            }
    }
    __syncthreads();

    if (mode == 0) {
        #pragma unroll 4
        for (int i = 0; i < 16; i++) {
            int lin = tid + (i << 8);
            int token = lin >> 5, c4 = lin & 31;
            int gn = n0 + (c4 << 2);
            float4 v = *reinterpret_cast<float4*>(&stg[token * 132 + (c4 << 2)]);
            int gmm = m0 + token;
            int b_ = gmm >> 13, n_ = gmm & 8191;
            int sec = gn >> 9, cc = gn & 511, h_ = cc >> 6, dh = cc & 63;
            size_t idx = ((((size_t)b_ * H_ + h_) * NTOK) + n_) * DH_ + dh;
            if (sec == 0) {
                v.x *= 0.125f; v.y *= 0.125f; v.z *= 0.125f; v.w *= 0.125f;
                *reinterpret_cast<float4*>(&qp[idx]) = v;
            } else if (sec == 1) {
                *reinterpret_cast<float4*>(&kp[idx]) = v;
            } else {
                *reinterpret_cast<float4*>(&vp[idx]) = v;
            }
        }
    } else if (mode == 1) {
        #pragma unroll 4
        for (int i = 0; i < 16; i++) {
            int lin = tid + (i << 8);
            int token = lin >> 5, c4 = lin & 31;
            int gn = n0 + (c4 << 2);
            int gmm = m0 + token;
            float4 v = *reinterpret_cast<float4*>(&stg[token * 132 + (c4 << 2)]);
            float4 bb = *reinterpret_cast<const float4*>(&bias[gn]);
            float4 xx = *reinterpret_cast<const float4*>(&addx[(size_t)gmm * 512 + gn]);
            v.x += bb.x + xx.x; v.y += bb.y + xx.y; v.z += bb.z + xx.z; v.w += bb.w + xx.w;
            *reinterpret_cast<float4*>(&Cout[(size_t)gmm * 512 + gn]) = v;
        }
    } else {
        if (Thi) {
            #pragma unroll 4
            for (int i = 0; i < 64; i++) {
                int idx = tid + (i << 8);
                int gn_l = idx >> 7, gm_l = idx & 127;
                int gmm = m0 + gm_l, gn = n0 + gn_l;
                float v = stg[gm_l * 132 + gn_l];
                float t = (gmm == gn ? diagc : 0.f) - beta * v;
                __nv_bfloat16 h = __float2bfloat16(t);
                Thi[oz + (size_t)gn * 256 + gmm] = h;
                Tlo[oz + (size_t)gn * 256 + gmm] = __float2bfloat16(t - __bfloat162float(h));
            }
        }
        if (Nhi) {
            #pragma unroll 4
            for (int i = 0; i < 16; i++) {
                int lin = tid + (i << 8);
                int token = lin >> 5, c4 = lin & 31;
                int gn = n0 + (c4 << 2);
                int gmm = m0 + token;
                float4 v = *reinterpret_cast<float4*>(&stg[token * 132 + (c4 << 2)]);
                float vv[4] = {v.x * alpha, v.y * alpha, v.z * alpha, v.w * alpha};
                __nv_bfloat16 h[4], l2[4];
                #pragma unroll
                for (int t2 = 0; t2 < 4; t2++) {
                    h[t2] = __float2bfloat16(vv[t2]);
                    l2[t2] = __float2bfloat16(vv[t2] - __bfloat162float(h[t2]));
                }
                *reinterpret_cast<uint2*>(&Nhi[oz + (size_t)gmm * 256 + gn]) = *reinterpret_cast<uint2*>(h);
                *reinterpret_cast<uint2*>(&Nlo[oz + (size_t)gmm * 256 + gn]) = *reinterpret_cast<uint2*>(l2);
            }
        }
        if (Cf32) {
            #pragma unroll 4
            for (int i = 0; i < 16; i++) {
                int lin = tid + (i << 8);
                int token = lin >> 5, c4 = lin & 31;
                int gn = n0 + (c4 << 2);
                int gmm = m0 + token;
                float4 v = *reinterpret_cast<float4*>(&stg[token * 132 + (c4 << 2)]);
                v.x *= alpha; v.y *= alpha; v.z *= alpha; v.w *= alpha;
                *reinterpret_cast<float4*>(&Cf32[oz + (size_t)gmm * 256 + gn]) = v;
            }
        }
    }
}

// ================= SIMT SGEMM (Y only): C = A@B, B in [K,N] =================
__global__ void __launch_bounds__(256) sgemm_kernel(
        const float* __restrict__ A, const float* __restrict__ B, float* __restrict__ C,
        int M, int N, int K, size_t sA, size_t sB, size_t sC)
{
    int bz = blockIdx.z;
    A += (size_t)bz * sA; B += (size_t)bz * sB; C += (size_t)bz * sC;
    int m0 = blockIdx.y * 128, n0 = blockIdx.x * 128;
    __shared__ float As[8][128];
    __shared__ float Bs[8][128];
    int tid = threadIdx.x;
    int tx = tid & 15, ty = tid >> 4;
    float acc[8][8];
    #pragma unroll
    for (int i = 0; i < 8; i++)
        #pragma unroll
        for (int j = 0; j < 8; j++) acc[i][j] = 0.f;

    for (int k0 = 0; k0 < K; k0 += 8) {
        #pragma unroll
        for (int i = 0; i < 4; i++) {
            int lin = tid + i * 256;
            int kk = lin & 7, mm = lin >> 3;
            int gmm = m0 + mm, gk = k0 + kk;
            As[kk][mm] = (gmm < M && gk < K) ? A[(size_t)gmm * K + gk] : 0.f;
        }
        #pragma unroll
        for (int i = 0; i < 4; i++) {
            int lin = tid + i * 256;
            int nn = lin & 127, kk = lin >> 7;
            int gn = n0 + nn, gk = k0 + kk;
            Bs[kk][nn] = (gn < N && gk < K) ? B[(size_t)gk * N + gn] : 0.f;
        }
        __syncthreads();
        #pragma unroll
        for (int kk = 0; kk < 8; kk++) {
            float a[8], b[8];
            *(float4*)&a[0] = *(const float4*)&As[kk][ty * 8];
            *(float4*)&a[4] = *(const float4*)&As[kk][ty * 8 + 4];
            *(float4*)&b[0] = *(const float4*)&Bs[kk][tx * 8];
            *(float4*)&b[4] = *(const float4*)&Bs[kk][tx * 8 + 4];
            #pragma unroll
            for (int i = 0; i < 8; i++)
                #pragma unroll
                for (int j = 0; j < 8; j++) acc[i][j] += a[i] * b[j];
        }
        __syncthreads();
    }
    #pragma unroll
    for (int i = 0; i < 8; i++) {
        int gmm = m0 + ty * 8 + i;
        if (gmm >= M) continue;
        #pragma unroll
        for (int j = 0; j < 8; j++) {
            int gn = n0 + tx * 8 + j;
            if (gn >= N) continue;
            C[(size_t)gmm * N + gn] = acc[i][j];
        }
    }
}

// ================= landmark means =================
__global__ void landmark_kernel(const float* __restrict__ q, const float* __restrict__ k,
                                float* __restrict__ ql, float* __restrict__ kl) {
    int bh = blockIdx.x, m = blockIdx.y;
    int dh = threadIdx.x;
    size_t base = ((size_t)bh * NTOK + (size_t)m * LSEG) * DH_ + dh;
    float aq = 0.f, ak = 0.f;
    #pragma unroll
    for (int i = 0; i < LSEG; i++) {
        aq += q[base + (size_t)i * DH_];
        ak += k[base + (size_t)i * DH_];
    }
    size_t o = ((size_t)bh * MLM + m) * DH_ + dh;
    ql[o] = aq * (1.f / LSEG);
    kl[o] = ak * (1.f / LSEG);
}

// ================= attn2 (tiled): X = softmax(q_l @ k_l^T), + bf16 split =================
#define ATTN2_SMEM ((256 * 68 + 32 * 64 + 8) * 4)
__global__ void attn2_kernel(const float* __restrict__ ql, const float* __restrict__ kl,
                             float* __restrict__ X,
                             __nv_bfloat16* __restrict__ Xh, __nv_bfloat16* __restrict__ Xl) {
    extern __shared__ __align__(16) float sh2[];
    float* kls  = sh2;               // [256][68]
    float* qs   = sh2 + 256 * 68;    // [32][64]
    float* wsum = qs + 32 * 64;      // [8]
    int bh = blockIdx.x, mt = blockIdx.y;
    int tid = threadIdx.x;
    #pragma unroll
    for (int i = 0; i < 16; i++) {
        int lin = tid + i * 256;
        int r = lin >> 4, c = lin & 15;
        *(float4*)&kls[r * 68 + c * 4] = *(const float4*)&kl[((size_t)bh * MLM + r) * DH_ + c * 4];
    }
    #pragma unroll
    for (int i = 0; i < 2; i++) {
        int lin = tid + i * 256;
        int r = lin >> 4, c = lin & 15;
        *(float4*)&qs[r * 64 + c * 4] = *(const float4*)&ql[((size_t)bh * MLM + mt * 32 + r) * DH_ + c * 4];
    }
    __syncthreads();
    int j = tid;
    int wid = tid >> 5, lane = tid & 31;
    const float* kr = &kls[j * 68];
    for (int ml = 0; ml < 32; ml++) {
        const float* qr = &qs[ml * 64];
        float a0 = 0.f, a1 = 0.f, a2 = 0.f, a3 = 0.f;
        #pragma unroll
        for (int d4 = 0; d4 < 16; d4++) {
            float4 kv = *(const float4*)&kr[d4 * 4];
            float4 qv = *(const float4*)&qr[d4 * 4];
            a0 += qv.x * kv.x; a1 += qv.y * kv.y; a2 += qv.z * kv.z; a3 += qv.w * kv.w;
        }
        float e = __expf(a0 + a1 + a2 + a3);
        float t = e;
        #pragma unroll
        for (int o = 16; o > 0; o >>= 1) t += __shfl_xor_sync(0xffffffffu, t, o);
        if (lane == 0) wsum[wid] = t;
        __syncthreads();
        float S = 0.f;
        #pragma unroll
        for (int w = 0; w < 8; w++) S += wsum[w];
        float val = e * (1.f / S);
        size_t o = ((size_t)bh * MLM + mt * 32 + ml) * MLM + j;
        X[o] = val;
        __nv_bfloat16 h = __float2bfloat16(val);
        Xh[o] = h;
        Xl[o] = __float2bfloat16(val - __bfloat162float(h));
        __syncthreads();
    }
}

// ================= pinv init =================
__global__ void initmax_kernel(unsigned* mb) { mb[0] = 0u; mb[1] = 0u; }

__global__ void rowcol_kernel(const float* __restrict__ X, unsigned* mb) {
    int bh = blockIdx.x;
    int i = threadIdx.x;
    const float* Xm = X + (size_t)bh * MLM * MLM;
    float rs = 0.f, cs = 0.f;
    for (int j = 0; j < MLM; j++) {
        rs += fabsf(Xm[(size_t)i * MLM + j]);
        cs += fabsf(Xm[(size_t)j * MLM + i]);
    }
    #pragma unroll
    for (int o = 16; o > 0; o >>= 1) {
        rs = fmaxf(rs, __shfl_xor_sync(0xffffffffu, rs, o));
        cs = fmaxf(cs, __shfl_xor_sync(0xffffffffu, cs, o));
    }
    __shared__ float shr[8], shc[8];
    int w = i >> 5;
    if ((i & 31) == 0) { shr[w] = rs; shc[w] = cs; }
    __syncthreads();
    if (i == 0) {
        float mr = shr[0], mc = shc[0];
        #pragma unroll
        for (int k2 = 1; k2 < 8; k2++) { mr = fmaxf(mr, shr[k2]); mc = fmaxf(mc, shc[k2]); }
        atomicMax(&mb[0], __float_as_uint(mr));
        atomicMax(&mb[1], __float_as_uint(mc));
    }
}

// Z0 = X^T / denom : norm split (transposed read) and trans split (natural read)
__global__ void zinit_kernel(const float* __restrict__ X, const unsigned* __restrict__ mb,
                             __nv_bfloat16* __restrict__ Znh, __nv_bfloat16* __restrict__ Znl,
                             __nv_bfloat16* __restrict__ Zth, __nv_bfloat16* __restrict__ Ztl) {
    float inv = 1.f / (__uint_as_float(mb[0]) * __uint_as_float(mb[1]));
    size_t idx = (size_t)blockIdx.x * 256 + threadIdx.x;
    int bh = (int)(idx >> 16);
    int r = (int)((idx >> 8) & 255);
    int c = (int)(idx & 255);
    float tv = X[idx] * inv;                                        // Zt[r][c] = X[r][c]*inv
    __nv_bfloat16 th = __float2bfloat16(tv);
    Zth[idx] = th; Ztl[idx] = __float2bfloat16(tv - __bfloat162float(th));
    float nv = X[((size_t)bh << 16) + ((size_t)c << 8) + r] * inv;  // Zn[r][c] = X[c][r]*inv
    __nv_bfloat16 nh = __float2bfloat16(nv);
    Znh[idx] = nh; Znl[idx] = __float2bfloat16(nv - __bfloat162float(nh));
}

// ================= attn3 @ v (streaming softmax over n) =================
__global__ void attn3v_kernel(const float* __restrict__ ql, const float* __restrict__ k,
                              const float* __restrict__ v, float* __restrict__ out) {
    int bh = blockIdx.x, qg = blockIdx.y;
    int tid = threadIdx.x;
    int q = tid >> 2, s = tid & 3;
    int m = qg * 32 + q;
    __shared__ float ks[64][64];
    __shared__ float vs[64][64];
    float qr[16];
    const float* qlp = ql + ((size_t)bh * MLM + m) * DH_ + s * 16;
    #pragma unroll
    for (int j = 0; j < 16; j++) qr[j] = qlp[j];
    float acc[16];
    #pragma unroll
    for (int j = 0; j < 16; j++) acc[j] = 0.f;
    float lsum = 0.f;
    const float* kbase = k + (size_t)bh * NTOK * DH_;
    const float* vbase = v + (size_t)bh * NTOK * DH_;

    for (int nt = 0; nt < NTOK; nt += 64) {
        __syncthreads();
        #pragma unroll
        for (int i = 0; i < 8; i++) {
            int f4 = tid + i * 128;
            int row2 = f4 >> 4, c4 = f4 & 15;
            ((float4*)ks)[f4] = ((const float4*)(kbase + (size_t)(nt + row2) * DH_))[c4];
            ((float4*)vs)[f4] = ((const float4*)(vbase + (size_t)(nt + row2) * DH_))[c4];
        }
        __syncthreads();
        #pragma unroll 4
        for (int n = 0; n < 64; n++) {
            const float* kr = &ks[n][s * 16];
            float p0 = 0.f, p1 = 0.f;
            #pragma unroll
            for (int j = 0; j < 8; j++) { p0 += qr[j] * kr[j]; p1 += qr[j + 8] * kr[j + 8]; }
            float p = p0 + p1;
            p += __shfl_xor_sync(0xffffffffu, p, 1);
            p += __shfl_xor_sync(0xffffffffu, p, 2);
            float e = __expf(p);
            lsum += e;
            const float* vr = &vs[n][s * 16];
            #pragma unroll
            for (int j = 0; j < 16; j++) acc[j] += e * vr[j];
        }
    }
    float invl = 1.f / lsum;
    float* op = out + ((size_t)bh * MLM + m) * DH_ + s * 16;
    #pragma unroll
    for (int j = 0; j < 16; j++) op[j] = acc[j] * invl;
}

// ================= depthwise conv, writes O =================
__global__ void conv_kernel(const float* __restrict__ v, const float* __restrict__ ker,
                            float* __restrict__ O) {
    int nt = blockIdx.x, h = blockIdx.y, b = blockIdx.z;
    int n0 = nt * 128;
    __shared__ float vsh[160][64];
    __shared__ float kw[KER_];
    int tid = threadIdx.x;
    if (tid < KER_) kw[tid] = ker[h * KER_ + tid];
    const float* vb = v + ((size_t)b * H_ + h) * NTOK * DH_;
    #pragma unroll
    for (int i = 0; i < 10; i++) {
        int f4 = tid + i * 256;
        int row2 = f4 >> 4, c4 = f4 & 15;
        int n = n0 - 16 + row2;
        float4 val = make_float4(0.f, 0.f, 0.f, 0.f);
        if (n >= 0 && n < NTOK) val = ((const float4*)(vb + (size_t)n * DH_))[c4];
        ((float4*)vsh)[f4] = val;
    }
    __syncthreads();
    int dh = tid & 63, g = tid >> 6;
    for (int ii = 0; ii < 32; ii++) {
        int nn = g * 32 + ii;
        float o = 0.f;
        #pragma unroll
        for (int t = 0; t < KER_; t++) o += kw[t] * vsh[nn + t][dh];
        O[((size_t)b * NTOK + (n0 + nn)) * D_ + h * DH_ + dh] = o;
    }
}

// ================= attn1 apply: O += softmax(q @ k_l^T) @ Y =================
__global__ void attn1_kernel(const float* __restrict__ q, const float* __restrict__ kl,
                             const float* __restrict__ Y, float* __restrict__ O) {
    extern __shared__ float sh[];
    float* kls   = sh;                       // 256*65
    float* Ys    = kls + 256 * 65;           // 256*64
    float* qrow  = Ys + 256 * 64;            // 64
    float* ps    = qrow + 64;                // 256
    float* wsum  = ps + 256;                 // 8
    float* opart = wsum + 8;                 // 256
    int chunk = blockIdx.x, h = blockIdx.y, b = blockIdx.z;
    int bh = b * H_ + h;
    int tid = threadIdx.x;
    for (int i = tid; i < MLM * DH_; i += 256) {
        int r = i >> 6, c = i & 63;
        kls[r * 65 + c] = kl[((size_t)bh * MLM + r) * DH_ + c];
        Ys[i] = Y[(size_t)bh * MLM * DH_ + i];
    }
    __syncthreads();
    int n0 = chunk * 256;
    const float* qb = q + (size_t)bh * NTOK * DH_;
    int wid = tid >> 5, lane = tid & 31;
    int g = tid >> 6, dh = tid & 63;
    for (int nn = 0; nn < 256; nn++) {
        int n = n0 + nn;
        if (tid < 64) qrow[tid] = qb[(size_t)n * DH_ + tid];
        __syncthreads();
        const float* kr = &kls[tid * 65];
        float s0 = 0.f, s1 = 0.f, s2 = 0.f, s3 = 0.f;
        #pragma unroll
        for (int d = 0; d < 64; d += 4) {
            s0 += qrow[d] * kr[d]; s1 += qrow[d+1] * kr[d+1];
            s2 += qrow[d+2] * kr[d+2]; s3 += qrow[d+3] * kr[d+3];
        }
        float e = __expf(s0 + s1 + s2 + s3);
        ps[tid] = e;
        float t = e;
        #pragma unroll
        for (int o = 16; o > 0; o >>= 1) t += __shfl_xor_sync(0xffffffffu, t, o);
        if (lane == 0) wsum[wid] = t;
        __syncthreads();
        float S = 0.f;
        #pragma unroll
        for (int w = 0; w < 8; w++) S += wsum[w];
        const float* pp = &ps[g * 64];
        const float* Yp = &Ys[(size_t)g * 64 * 64 + dh];
        float o = 0.f;
        #pragma unroll 16
        for (int jj = 0; jj < 64; jj++) o += pp[jj] * Yp[(size_t)jj * 64];
        opart[tid] = o;
        __syncthreads();
        if (tid < 64) {
            float oo = opart[tid] + opart[64 + tid] + opart[128 + tid] + opart[192 + tid];
            O[((size_t)b * NTOK + n) * D_ + h * DH_ + tid] += oo / S;
        }
        __syncthreads();
    }
}

// ================= host launcher =================
extern "C" void kernel_launch(void* const* d_in, const int* in_sizes, int n_in,
                              void* d_out, int out_size) {
    const float* x      = (const float*)d_in[0];
    const float* gamma  = (const float*)d_in[1];
    const float* beta   = (const float*)d_in[2];
    const float* w_qkv  = (const float*)d_in[3];
    const float* res_k  = (const float*)d_in[4];
    const float* w_out  = (const float*)d_in[5];
    const float* b_out  = (const float*)d_in[6];
    float* out = (float*)d_out;

    __nv_bfloat16 *nh, *nl, *wqh, *wql, *woh, *wol, *Oh, *Ol, *Xh, *Xl;
    __nv_bfloat16 *Znh[2], *Znl[2], *Zth[2], *Ztl[2], *XZh, *XZl, *WtAh, *WtAl, *WtBh, *WtBl;
    float *q, *k, *v, *ql, *kl, *X, *Zf, *A3V, *Y, *O;
    unsigned* mb;
    cudaGetSymbolAddress((void**)&nh, g_nh);
    cudaGetSymbolAddress((void**)&nl, g_nl);
    cudaGetSymbolAddress((void**)&wqh, g_wqh);
    cudaGetSymbolAddress((void**)&wql, g_wql);
    cudaGetSymbolAddress((void**)&woh, g_woh);
    cudaGetSymbolAddress((void**)&wol, g_wol);
    cudaGetSymbolAddress((void**)&Oh, g_Oh);
    cudaGetSymbolAddress((void**)&Ol, g_Ol);
    cudaGetSymbolAddress((void**)&Xh, g_Xh);
    cudaGetSymbolAddress((void**)&Xl, g_Xl);
    {
        __nv_bfloat16* p;
        cudaGetSymbolAddress((void**)&p, g_Znh); Znh[0] = p; Znh[1] = p + (size_t)BH*MLM*MLM;
        cudaGetSymbolAddress((void**)&p, g_Znl); Znl[0] = p; Znl[1] = p + (size_t)BH*MLM*MLM;
        cudaGetSymbolAddress((void**)&p, g_Zth); Zth[0] = p; Zth[1] = p + (size_t)BH*MLM*MLM;
        cudaGetSymbolAddress((void**)&p, g_Ztl); Ztl[0] = p; Ztl[1] = p + (size_t)BH*MLM*MLM;
    }
    cudaGetSymbolAddress((void**)&XZh, g_XZh);
    cudaGetSymbolAddress((void**)&XZl, g_XZl);
    cudaGetSymbolAddress((void**)&WtAh, g_WtAh);
    cudaGetSymbolAddress((void**)&WtAl, g_WtAl);
    cudaGetSymbolAddress((void**)&WtBh, g_WtBh);
    cudaGetSymbolAddress((void**)&WtBl, g_WtBl);
    cudaGetSymbolAddress((void**)&q,  g_q);
    cudaGetSymbolAddress((void**)&k,  g_k);
    cudaGetSymbolAddress((void**)&v,  g_v);
    cudaGetSymbolAddress((void**)&ql, g_ql);
    cudaGetSymbolAddress((void**)&kl, g_kl);
    cudaGetSymbolAddress((void**)&X,  g_X);
    cudaGetSymbolAddress((void**)&Zf, g_Zf);
    cudaGetSymbolAddress((void**)&A3V, g_A3V);
    cudaGetSymbolAddress((void**)&Y,  g_Y);
    cudaGetSymbolAddress((void**)&O,  g_O);
    cudaGetSymbolAddress((void**)&mb, g_maxbits);

    const int attn1_smem = (256 * 65 + 256 * 64 + 64 + 256 + 8 + 256) * (int)sizeof(float);
    cudaFuncSetAttribute(attn1_kernel, cudaFuncAttributeMaxDynamicSharedMemorySize, attn1_smem);
    cudaFuncSetAttribute(attn2_kernel, cudaFuncAttributeMaxDynamicSharedMemorySize, ATTN2_SMEM);
    cudaFuncSetAttribute(tc_gemm, cudaFuncAttributeMaxDynamicSharedMemorySize, TCG_SMEM);

    const size_t sM = (size_t)MLM * MLM;

    // 1. LayerNorm -> bf16 split
    ln_kernel<<<B_ * NTOK, 256>>>(x, gamma, beta, nh, nl);

    // 2. weight transpose+split
    tsplit_kernel<<<(D_ * 3 * D_ + 255) / 256, 256>>>(w_qkv, wqh, wql, D_, 3 * D_);
    tsplit_kernel<<<(D_ * D_ + 255) / 256, 256>>>(w_out, woh, wol, D_, D_);

    // 3. QKV on tensor cores (mma.sync), scatter to head layout
    tc_gemm<<<dim3(12, 256, 1), 256, TCG_SMEM>>>(nh, nl, wqh, wql, D_, 0, 0, 0,
        q, k, v, nullptr, nullptr, nullptr,
        nullptr, nullptr, nullptr, nullptr, nullptr, 1.f, 0.f, 1.f);

    // 4. Landmarks
    landmark_kernel<<<dim3(BH, MLM), 64>>>(q, k, ql, kl);

    // 5. attn2 (+ bf16 split)
    attn2_kernel<<<dim3(BH, 8), 256, ATTN2_SMEM>>>(ql, kl, X, Xh, Xl);

    // 6. pinv init
    initmax_kernel<<<1, 1>>>(mb);
    rowcol_kernel<<<BH, 256>>>(X, mb);
    zinit_kernel<<<8192, 256>>>(X, mb, Znh[0], Znl[0], Zth[0], Ztl[0]);

    // 7. Newton iterations on tensor cores
    int cur = 0;
    for (int it = 0; it < 6; it++) {
        int nxt = cur ^ 1;
        // XZ = X@Z (norm split out), WtA = (7I - XZ)^T (trans split out)
        tc_gemm<<<dim3(2, 2, BH), 256, TCG_SMEM>>>(Xh, Xl, Zth[cur], Ztl[cur], MLM, sM, sM, 2,
            nullptr, nullptr, nullptr, nullptr, nullptr, nullptr,
            XZh, XZl, WtAh, WtAl, nullptr, 1.f, 7.f, 1.f);
        // WtB = (15I - XZ@W7)^T
        tc_gemm<<<dim3(2, 2, BH), 256, TCG_SMEM>>>(XZh, XZl, WtAh, WtAl, MLM, sM, sM, 2,
            nullptr, nullptr, nullptr, nullptr, nullptr, nullptr,
            nullptr, nullptr, WtBh, WtBl, nullptr, 1.f, 15.f, 1.f);
        // WtA = (13I - XZ@W15)^T
        tc_gemm<<<dim3(2, 2, BH), 256, TCG_SMEM>>>(XZh, XZl, WtBh, WtBl, MLM, sM, sM, 2,
            nullptr, nullptr, nullptr, nullptr, nullptr, nullptr,
            nullptr, nullptr, WtAh, WtAl, nullptr, 1.f, 13.f, 1.f);
        // Z_next = 0.25 * Z@W13 (norm + trans splits; fp32 copy on last iter)
        tc_gemm<<<dim3(2, 2, BH), 256, TCG_SMEM>>>(Znh[cur], Znl[cur], WtAh, WtAl, MLM, sM, sM, 2,
            nullptr, nullptr, nullptr, nullptr, nullptr, nullptr,
            Znh[nxt], Znl[nxt], Zth[nxt], Ztl[nxt], (it == 5) ? Zf : nullptr, 0.25f, 0.f, -0.25f);
        cur = nxt;
    }

    // 8. attn3 @ v
    attn3v_kernel<<<dim3(BH, 8), 128>>>(ql, k, v, A3V);

    // 9. Y = pinv(attn2) @ (attn3 @ v)
    sgemm_kernel<<<dim3(1, 2, BH), 256>>>(Zf, A3V, Y, MLM, DH_, MLM,
        sM, (size_t)MLM * DH_, (size_t)MLM * DH_);

    // 10. conv -> O ; 11. attn1 accumulates into O
    conv_kernel<<<dim3(64, H_, B_), 256>>>(v, res_k, O);
    attn1_kernel<<<dim3(32, H_, B_), 256, attn1_smem>>>(q, kl, Y, O);

    // 12. split O ; 13. out = x + O@w_out + b_out on tensor cores
    osplit_kernel<<<(int)(((size_t)B_*NTOK*D_) / 256), 256>>>(O, Oh, Ol);
    tc_gemm<<<dim3(4, 256, 1), 256, TCG_SMEM>>>(Oh, Ol, woh, wol, D_, 0, 0, 1,
        nullptr, nullptr, nullptr, out, b_out, x,
        nullptr, nullptr, nullptr, nullptr, nullptr, 1.f, 0.f, 1.f);
}

// round 7
// speedup vs baseline: 4.7467x; 3.5604x over previous
#include <cuda_runtime.h>
#include <cuda_bf16.h>
#include <math.h>
#include <stdint.h>

#define B_    4
#define NTOK  8192
#define D_    512
#define H_    8
#define DH_   64
#define MLM   256
#define LSEG  32
#define BH    (B_*H_)
#define KER_  33
#define NCHK  8

__device__ __forceinline__ uint32_t smem_to_u32(const void* p) {
    uint32_t a;
    asm("{ .reg .u64 t; cvta.to.shared.u64 t, %1; cvt.u32.u64 %0, t; }" : "=r"(a) : "l"(p));
    return a;
}
__device__ __forceinline__ void mma_bf16(float (&d)[4], const uint32_t (&a)[4], const uint32_t (&b)[2]) {
    asm volatile("mma.sync.aligned.m16n8k16.row.col.f32.bf16.bf16.f32 "
        "{%0,%1,%2,%3}, {%4,%5,%6,%7}, {%8,%9}, {%0,%1,%2,%3};"
        : "+f"(d[0]), "+f"(d[1]), "+f"(d[2]), "+f"(d[3])
        : "r"(a[0]), "r"(a[1]), "r"(a[2]), "r"(a[3]), "r"(b[0]), "r"(b[1]));
}
__device__ __forceinline__ void mma_bf16p(float (&d)[4], const uint32_t (&a)[4], uint32_t b0, uint32_t b1) {
    asm volatile("mma.sync.aligned.m16n8k16.row.col.f32.bf16.bf16.f32 "
        "{%0,%1,%2,%3}, {%4,%5,%6,%7}, {%8,%9}, {%0,%1,%2,%3};"
        : "+f"(d[0]), "+f"(d[1]), "+f"(d[2]), "+f"(d[3])
        : "r"(a[0]), "r"(a[1]), "r"(a[2]), "r"(a[3]), "r"(b0), "r"(b1));
}
__device__ __forceinline__ void ldsm4(uint32_t (&r)[4], uint32_t a) {
    asm volatile("ldmatrix.sync.aligned.m8n8.x4.shared.b16 {%0,%1,%2,%3}, [%4];"
        : "=r"(r[0]), "=r"(r[1]), "=r"(r[2]), "=r"(r[3]) : "r"(a));
}
__device__ __forceinline__ void ldsm2(uint32_t (&r)[2], uint32_t a) {
    asm volatile("ldmatrix.sync.aligned.m8n8.x2.shared.b16 {%0,%1}, [%2];"
        : "=r"(r[0]), "=r"(r[1]) : "r"(a));
}
__device__ __forceinline__ float fexp(float s) {
    float t = s * 1.44269504088896341f;
    float i = rintf(t);
    float f = t - i;
    float p = 1.54035303933816e-4f;
    p = p * f + 1.33335581464284e-3f;
    p = p * f + 9.61812910762848e-3f;
    p = p * f + 5.55041086648216e-2f;
    p = p * f + 2.40226506959101e-1f;
    p = p * f + 6.93147180559945e-1f;
    p = p * f + 1.0f;
    return p * __int_as_float(((int)i + 127) << 23);
}

// scratch
__device__ __nv_bfloat16 g_nh[(size_t)B_*NTOK*D_];
__device__ __nv_bfloat16 g_nl[(size_t)B_*NTOK*D_];
__device__ __nv_bfloat16 g_wqh[(size_t)3*D_*D_];
__device__ __nv_bfloat16 g_wql[(size_t)3*D_*D_];
__device__ __nv_bfloat16 g_woh[(size_t)D_*D_];
__device__ __nv_bfloat16 g_wol[(size_t)D_*D_];
__device__ __nv_bfloat16 g_Oh[(size_t)B_*NTOK*D_];
__device__ __nv_bfloat16 g_Ol[(size_t)B_*NTOK*D_];
__device__ float g_q [(size_t)BH*NTOK*DH_];
__device__ float g_k [(size_t)BH*NTOK*DH_];
__device__ float g_v [(size_t)BH*NTOK*DH_];
__device__ __nv_bfloat16 g_qbh[(size_t)BH*NTOK*DH_];
__device__ __nv_bfloat16 g_qbl[(size_t)BH*NTOK*DH_];
__device__ __nv_bfloat16 g_kbh[(size_t)BH*NTOK*DH_];
__device__ __nv_bfloat16 g_kbl[(size_t)BH*NTOK*DH_];
__device__ __nv_bfloat16 g_vth[(size_t)BH*NTOK*DH_];
__device__ __nv_bfloat16 g_vtl[(size_t)BH*NTOK*DH_];
__device__ float g_ql[(size_t)BH*MLM*DH_];
__device__ float g_kl[(size_t)BH*MLM*DH_];
__device__ __nv_bfloat16 g_qlh[(size_t)BH*MLM*DH_];
__device__ __nv_bfloat16 g_qll[(size_t)BH*MLM*DH_];
__device__ __nv_bfloat16 g_klh[(size_t)BH*MLM*DH_];
__device__ __nv_bfloat16 g_kll[(size_t)BH*MLM*DH_];
__device__ __nv_bfloat16 g_yth[(size_t)BH*MLM*DH_];
__device__ __nv_bfloat16 g_ytl[(size_t)BH*MLM*DH_];
__device__ float g_X [(size_t)BH*MLM*MLM];
__device__ __nv_bfloat16 g_Xh[(size_t)BH*MLM*MLM];
__device__ __nv_bfloat16 g_Xl[(size_t)BH*MLM*MLM];
__device__ __nv_bfloat16 g_Znh[2][(size_t)BH*MLM*MLM];
__device__ __nv_bfloat16 g_Znl[2][(size_t)BH*MLM*MLM];
__device__ __nv_bfloat16 g_Zth[2][(size_t)BH*MLM*MLM];
__device__ __nv_bfloat16 g_Ztl[2][(size_t)BH*MLM*MLM];
__device__ __nv_bfloat16 g_XZh[(size_t)BH*MLM*MLM];
__device__ __nv_bfloat16 g_XZl[(size_t)BH*MLM*MLM];
__device__ __nv_bfloat16 g_WtAh[(size_t)BH*MLM*MLM];
__device__ __nv_bfloat16 g_WtAl[(size_t)BH*MLM*MLM];
__device__ __nv_bfloat16 g_WtBh[(size_t)BH*MLM*MLM];
__device__ __nv_bfloat16 g_WtBl[(size_t)BH*MLM*MLM];
__device__ float g_Zf[(size_t)BH*MLM*MLM];
__device__ float g_Opart[(size_t)NCHK*BH*MLM*DH_];
__device__ float g_dpart[(size_t)NCHK*BH*MLM];
__device__ float g_A3V[(size_t)BH*MLM*DH_];
__device__ float g_Y  [(size_t)BH*MLM*DH_];
__device__ float g_O  [(size_t)B_*NTOK*D_];
__device__ unsigned g_maxbits[2];

__global__ void ln_kernel(const float* __restrict__ x, const float* __restrict__ gamma,
                          const float* __restrict__ beta,
                          __nv_bfloat16* __restrict__ ohi, __nv_bfloat16* __restrict__ olo) {
    int row = blockIdx.x, tid = threadIdx.x;
    const float* xr = x + (size_t)row * D_;
    float v0 = xr[tid], v1 = xr[tid + 256];
    float s = v0 + v1, s2 = v0*v0 + v1*v1;
    #pragma unroll
    for (int o = 16; o > 0; o >>= 1) {
        s  += __shfl_xor_sync(0xffffffffu, s,  o);
        s2 += __shfl_xor_sync(0xffffffffu, s2, o);
    }
    __shared__ float sh[16];
    int w = tid >> 5;
    if ((tid & 31) == 0) { sh[w] = s; sh[w + 8] = s2; }
    __syncthreads();
    if (tid == 0) {
        float a = 0.f, b2 = 0.f;
        #pragma unroll
        for (int i = 0; i < 8; i++) { a += sh[i]; b2 += sh[i + 8]; }
        sh[0] = a; sh[8] = b2;
    }
    __syncthreads();
    float mu  = sh[0] * (1.f / D_);
    float var = sh[8] * (1.f / D_) - mu * mu;
    float inv = rsqrtf(var + 1e-5f);
    size_t base = (size_t)row * D_;
    #pragma unroll
    for (int half = 0; half < 2; half++) {
        int c = tid + half * 256;
        float v = (half == 0 ? v0 : v1);
        float nv = (v - mu) * inv * gamma[c] + beta[c];
        __nv_bfloat16 hi = __float2bfloat16(nv);
        ohi[base + c] = hi;
        olo[base + c] = __float2bfloat16(nv - __bfloat162float(hi));
    }
}

__global__ void tsplit_kernel(const float* __restrict__ W, __nv_bfloat16* __restrict__ Thi,
                              __nv_bfloat16* __restrict__ Tlo, int K, int N) {
    int idx = blockIdx.x * 256 + threadIdx.x;
    if (idx >= K * N) return;
    int k = idx / N, n = idx % N;
    float v = W[idx];
    __nv_bfloat16 hi = __float2bfloat16(v);
    Thi[(size_t)n * K + k] = hi;
    Tlo[(size_t)n * K + k] = __float2bfloat16(v - __bfloat162float(hi));
}
__global__ void bsplit_kernel(const float* __restrict__ s, __nv_bfloat16* __restrict__ h,
                              __nv_bfloat16* __restrict__ l) {
    size_t i = ((size_t)blockIdx.x * 256 + threadIdx.x) * 4;
    float4 v = *(const float4*)(s + i);
    __nv_bfloat16 hh[4], ll[4];
    float vv[4] = {v.x, v.y, v.z, v.w};
    #pragma unroll
    for (int t = 0; t < 4; t++) {
        hh[t] = __float2bfloat16(vv[t]);
        ll[t] = __float2bfloat16(vv[t] - __bfloat162float(hh[t]));
    }
    *(uint2*)(h + i) = *(uint2*)hh;
    *(uint2*)(l + i) = *(uint2*)ll;
}
__global__ void vtrans_kernel(const float* __restrict__ v, __nv_bfloat16* __restrict__ vth,
                              __nv_bfloat16* __restrict__ vtl) {
    __shared__ float ts[64][68];   // pitch 68 floats = 272B (16B multiple) — float4-safe
    int bh = blockIdx.y, k0 = blockIdx.x * 64;
    int tid = threadIdx.x;
    const float* vb = v + ((size_t)bh * NTOK + k0) * DH_;
    #pragma unroll
    for (int i = 0; i < 4; i++) {
        int lin = tid + i * 256;
        int r = lin >> 4, c4 = lin & 15;
        *(float4*)&ts[r][c4 * 4] = *(const float4*)(vb + r * 64 + c4 * 4);
    }
    __syncthreads();
    #pragma unroll
    for (int i = 0; i < 16; i++) {
        int lin = tid + i * 256;
        int dh = lin >> 6, ky = lin & 63;
        float val = ts[ky][dh];
        __nv_bfloat16 h = __float2bfloat16(val);
        size_t o = ((size_t)bh * 64 + dh) * NTOK + k0 + ky;
        vth[o] = h;
        vtl[o] = __float2bfloat16(val - __bfloat162float(h));
    }
}
__global__ void ytrans_kernel(const float* __restrict__ Y, __nv_bfloat16* __restrict__ yth,
                              __nv_bfloat16* __restrict__ ytl) {
    int bh = blockIdx.x, tid = threadIdx.x;
    #pragma unroll
    for (int i = 0; i < 64; i++) {
        int lin = tid + i * 256;
        int dh = lin >> 8, lm = lin & 255;
        float val = Y[(size_t)bh * 16384 + lm * 64 + dh];
        __nv_bfloat16 h = __float2bfloat16(val);
        size_t o = (size_t)bh * 16384 + dh * 256 + lm;
        yth[o] = h;
        ytl[o] = __float2bfloat16(val - __bfloat162float(h));
    }
}

// bf16-split MMA GEMM, D[m,n]=sum_k A[m,k]B[n,k]; modes 0/1/2; npass 1=hi only
#define TCG_SMEM (128 * 132 * 4)
__global__ void __launch_bounds__(256) tc_gemm(
        const __nv_bfloat16* __restrict__ Ahi, const __nv_bfloat16* __restrict__ Alo,
        const __nv_bfloat16* __restrict__ Bhi, const __nv_bfloat16* __restrict__ Blo,
        int K, size_t strA, size_t strB, int mode, int npass,
        float* __restrict__ qp, float* __restrict__ kp, float* __restrict__ vp,
        float* __restrict__ Cout, const float* __restrict__ bias, const float* __restrict__ addx,
        __nv_bfloat16* __restrict__ Nhi, __nv_bfloat16* __restrict__ Nlo,
        __nv_bfloat16* __restrict__ Thi, __nv_bfloat16* __restrict__ Tlo,
        float* __restrict__ Cf32, float alpha, float diagc, float beta)
{
    extern __shared__ __align__(16) char smem[];
    __nv_bfloat16* tiles = reinterpret_cast<__nv_bfloat16*>(smem);
    uint32_t sbase = smem_to_u32(smem);
    int tid = threadIdx.x;
    int wid = tid >> 5, lane = tid & 31;
    int wm = (wid & 3) * 32, wn = (wid >> 2) * 64;
    int bz = blockIdx.z;
    int m0 = blockIdx.y * 128, n0 = blockIdx.x * 128;
    size_t oz = (size_t)bz * 65536;
    Ahi += (size_t)bz * strA; Alo += (size_t)bz * strA;
    Bhi += (size_t)bz * strB; Blo += (size_t)bz * strB;
    const __nv_bfloat16* srcs[4] = {Ahi, Alo, Bhi, Blo};
    const int row0s[4] = {m0, m0, n0, n0};

    float acc[2][8][4];
    #pragma unroll
    for (int a = 0; a < 2; a++)
        #pragma unroll
        for (int b = 0; b < 8; b++)
            #pragma unroll
            for (int c = 0; c < 4; c++) acc[a][b][c] = 0.f;

    int nbuf = (npass == 1) ? 2 : 4;
    int nch = K >> 5;
    for (int ch = 0; ch < nch; ch++) {
        int k0 = ch << 5;
        for (int bs = 0; bs < nbuf; bs++) {
            int bsel = (npass == 1) ? bs * 2 : bs;
            const __nv_bfloat16* src = srcs[bsel];
            int row0 = row0s[bsel];
            #pragma unroll
            for (int i = 0; i < 2; i++) {
                int lin = tid + i * 256;
                int r = lin >> 2, c16 = lin & 3;
                uint4 val = *reinterpret_cast<const uint4*>(src + (size_t)(row0 + r) * K + k0 + c16 * 8);
                *reinterpret_cast<uint4*>(tiles + bsel * 5120 + r * 40 + c16 * 8) = val;
            }
        }
        __syncthreads();
        #pragma unroll
        for (int ks = 0; ks < 32; ks += 16) {
            uint32_t Ah[2][4], Al[2][4];
            #pragma unroll
            for (int mf = 0; mf < 2; mf++) {
                int row = wm + mf * 16 + (lane & 15);
                int col = ks + ((lane >> 4) << 3);
                ldsm4(Ah[mf], sbase + (uint32_t)(row * 40 + col) * 2);
                if (npass > 1) ldsm4(Al[mf], sbase + (uint32_t)(5120 + row * 40 + col) * 2);
            }
            #pragma unroll
            for (int nf = 0; nf < 8; nf++) {
                int rowb = wn + nf * 8 + (lane & 7);
                int colb = ks + ((lane >> 3) & 1) * 8;
                uint32_t Bh2[2], Bl2[2];
                ldsm2(Bh2, sbase + (uint32_t)(2 * 5120 + rowb * 40 + colb) * 2);
                if (npass > 1) ldsm2(Bl2, sbase + (uint32_t)(3 * 5120 + rowb * 40 + colb) * 2);
                #pragma unroll
                for (int mf = 0; mf < 2; mf++) {
                    mma_bf16(acc[mf][nf], Ah[mf], Bh2);
                    if (npass > 1) {
                        mma_bf16(acc[mf][nf], Ah[mf], Bl2);
                        mma_bf16(acc[mf][nf], Al[mf], Bh2);
                    }
                }
            }
        }
        __syncthreads();
    }

    float* stg = reinterpret_cast<float*>(smem);
    {
        int r = lane >> 2, c = (lane & 3) * 2;
        #pragma unroll
        for (int mf = 0; mf < 2; mf++)
            #pragma unroll
            for (int nf = 0; nf < 8; nf++) {
                int rr = wm + mf * 16 + r, cc = wn + nf * 8 + c;
                *reinterpret_cast<float2*>(&stg[rr * 132 + cc]) = make_float2(acc[mf][nf][0], acc[mf][nf][1]);
                *reinterpret_cast<float2*>(&stg[(rr + 8) * 132 + cc]) = make_float2(acc[mf][nf][2], acc[mf][nf][3]);
            }
    }
    __syncthreads();

    if (mode == 0) {
        #pragma unroll 4
        for (int i = 0; i < 16; i++) {
            int lin = tid + (i << 8);
            int token = lin >> 5, c4 = lin & 31;
            int gn = n0 + (c4 << 2);
            float4 v = *reinterpret_cast<float4*>(&stg[token * 132 + (c4 << 2)]);
            int gmm = m0 + token;
            int b_ = gmm >> 13, n_ = gmm & 8191;
            int sec = gn >> 9, cc = gn & 511, h_ = cc >> 6, dh = cc & 63;
            size_t idx = ((((size_t)b_ * H_ + h_) * NTOK) + n_) * DH_ + dh;
            if (sec == 0) {
                v.x *= 0.125f; v.y *= 0.125f; v.z *= 0.125f; v.w *= 0.125f;
                *reinterpret_cast<float4*>(&qp[idx]) = v;
            } else if (sec == 1) {
                *reinterpret_cast<float4*>(&kp[idx]) = v;
            } else {
                *reinterpret_cast<float4*>(&vp[idx]) = v;
            }
        }
    } else if (mode == 1) {
        #pragma unroll 4
        for (int i = 0; i < 16; i++) {
            int lin = tid + (i << 8);
            int token = lin >> 5, c4 = lin & 31;
            int gn = n0 + (c4 << 2);
            int gmm = m0 + token;
            float4 v = *reinterpret_cast<float4*>(&stg[token * 132 + (c4 << 2)]);
            float4 bb = *reinterpret_cast<const float4*>(&bias[gn]);
            float4 xx = *reinterpret_cast<const float4*>(&addx[(size_t)gmm * 512 + gn]);
            v.x += bb.x + xx.x; v.y += bb.y + xx.y; v.z += bb.z + xx.z; v.w += bb.w + xx.w;
            *reinterpret_cast<float4*>(&Cout[(size_t)gmm * 512 + gn]) = v;
        }
    } else {
        if (Thi) {
            #pragma unroll 4
            for (int i = 0; i < 64; i++) {
                int idx = tid + (i << 8);
                int gn_l = idx >> 7, gm_l = idx & 127;
                int gmm = m0 + gm_l, gn = n0 + gn_l;
                float v = stg[gm_l * 132 + gn_l];
                float t = (gmm == gn ? diagc : 0.f) - beta * v;
                __nv_bfloat16 h = __float2bfloat16(t);
                Thi[oz + (size_t)gn * 256 + gmm] = h;
                Tlo[oz + (size_t)gn * 256 + gmm] = __float2bfloat16(t - __bfloat162float(h));
            }
        }
        if (Nhi) {
            #pragma unroll 4
            for (int i = 0; i < 16; i++) {
                int lin = tid + (i << 8);
                int token = lin >> 5, c4 = lin & 31;
                int gn = n0 + (c4 << 2);
                int gmm = m0 + token;
                float4 v = *reinterpret_cast<float4*>(&stg[token * 132 + (c4 << 2)]);
                float vv[4] = {v.x * alpha, v.y * alpha, v.z * alpha, v.w * alpha};
                __nv_bfloat16 h[4], l2[4];
                #pragma unroll
                for (int t2 = 0; t2 < 4; t2++) {
                    h[t2] = __float2bfloat16(vv[t2]);
                    l2[t2] = __float2bfloat16(vv[t2] - __bfloat162float(h[t2]));
                }
                *reinterpret_cast<uint2*>(&Nhi[oz + (size_t)gmm * 256 + gn]) = *reinterpret_cast<uint2*>(h);
                *reinterpret_cast<uint2*>(&Nlo[oz + (size_t)gmm * 256 + gn]) = *reinterpret_cast<uint2*>(l2);
            }
        }
        if (Cf32) {
            #pragma unroll 4
            for (int i = 0; i < 16; i++) {
                int lin = tid + (i << 8);
                int token = lin >> 5, c4 = lin & 31;
                int gn = n0 + (c4 << 2);
                int gmm = m0 + token;
                float4 v = *reinterpret_cast<float4*>(&stg[token * 132 + (c4 << 2)]);
                v.x *= alpha; v.y *= alpha; v.z *= alpha; v.w *= alpha;
                *reinterpret_cast<float4*>(&Cf32[oz + (size_t)gmm * 256 + gn]) = v;
            }
        }
    }
}

// SIMT SGEMM for Y = Zf @ A3V
__global__ void __launch_bounds__(256) sgemm_kernel(
        const float* __restrict__ A, const float* __restrict__ B, float* __restrict__ C,
        int M, int N, int K, size_t sA, size_t sB, size_t sC)
{
    int bz = blockIdx.z;
    A += (size_t)bz * sA; B += (size_t)bz * sB; C += (size_t)bz * sC;
    int m0 = blockIdx.y * 128, n0 = blockIdx.x * 128;
    __shared__ float As[8][128];
    __shared__ float Bs[8][128];
    int tid = threadIdx.x;
    int tx = tid & 15, ty = tid >> 4;
    float acc[8][8];
    #pragma unroll
    for (int i = 0; i < 8; i++)
        #pragma unroll
        for (int j = 0; j < 8; j++) acc[i][j] = 0.f;
    for (int k0 = 0; k0 < K; k0 += 8) {
        #pragma unroll
        for (int i = 0; i < 4; i++) {
            int lin = tid + i * 256;
            int kk = lin & 7, mm = lin >> 3;
            int gmm = m0 + mm, gk = k0 + kk;
            As[kk][mm] = (gmm < M && gk < K) ? A[(size_t)gmm * K + gk] : 0.f;
        }
        #pragma unroll
        for (int i = 0; i < 4; i++) {
            int lin = tid + i * 256;
            int nn = lin & 127, kk = lin >> 7;
            int gn = n0 + nn, gk = k0 + kk;
            Bs[kk][nn] = (gn < N && gk < K) ? B[(size_t)gk * N + gn] : 0.f;
        }
        __syncthreads();
        #pragma unroll
        for (int kk = 0; kk < 8; kk++) {
            float a[8], b[8];
            *(float4*)&a[0] = *(const float4*)&As[kk][ty * 8];
            *(float4*)&a[4] = *(const float4*)&As[kk][ty * 8 + 4];
            *(float4*)&b[0] = *(const float4*)&Bs[kk][tx * 8];
            *(float4*)&b[4] = *(const float4*)&Bs[kk][tx * 8 + 4];
            #pragma unroll
            for (int i = 0; i < 8; i++)
                #pragma unroll
                for (int j = 0; j < 8; j++) acc[i][j] += a[i] * b[j];
        }
        __syncthreads();
    }
    #pragma unroll
    for (int i = 0; i < 8; i++) {
        int gmm = m0 + ty * 8 + i;
        if (gmm >= M) continue;
        #pragma unroll
        for (int j = 0; j < 8; j++) {
            int gn = n0 + tx * 8 + j;
            if (gn >= N) continue;
            C[(size_t)gmm * N + gn] = acc[i][j];
        }
    }
}

__global__ void landmark_kernel(const float* __restrict__ q, const float* __restrict__ k,
                                float* __restrict__ ql, float* __restrict__ kl) {
    int bh = blockIdx.x, m = blockIdx.y;
    int dh = threadIdx.x;
    size_t base = ((size_t)bh * NTOK + (size_t)m * LSEG) * DH_ + dh;
    float aq = 0.f, ak = 0.f;
    #pragma unroll
    for (int i = 0; i < LSEG; i++) {
        aq += q[base + (size_t)i * DH_];
        ak += k[base + (size_t)i * DH_];
    }
    size_t o = ((size_t)bh * MLM + m) * DH_ + dh;
    ql[o] = aq * (1.f / LSEG);
    kl[o] = ak * (1.f / LSEG);
}

#define ATTN2_SMEM ((256 * 68 + 32 * 64 + 8) * 4)
__global__ void attn2_kernel(const float* __restrict__ ql, const float* __restrict__ kl,
                             float* __restrict__ X,
                             __nv_bfloat16* __restrict__ Xh, __nv_bfloat16* __restrict__ Xl) {
    extern __shared__ __align__(16) float sh2[];
    float* kls  = sh2;
    float* qs   = sh2 + 256 * 68;
    float* wsum = qs + 32 * 64;
    int bh = blockIdx.x, mt = blockIdx.y;
    int tid = threadIdx.x;
    #pragma unroll
    for (int i = 0; i < 16; i++) {
        int lin = tid + i * 256;
        int r = lin >> 4, c = lin & 15;
        *(float4*)&kls[r * 68 + c * 4] = *(const float4*)&kl[((size_t)bh * MLM + r) * DH_ + c * 4];
    }
    #pragma unroll
    for (int i = 0; i < 2; i++) {
        int lin = tid + i * 256;
        int r = lin >> 4, c = lin & 15;
        *(float4*)&qs[r * 64 + c * 4] = *(const float4*)&ql[((size_t)bh * MLM + mt * 32 + r) * DH_ + c * 4];
    }
    __syncthreads();
    int j = tid, wid = tid >> 5, lane = tid & 31;
    const float* kr = &kls[j * 68];
    for (int ml = 0; ml < 32; ml++) {
        const float* qr = &qs[ml * 64];
        float a0 = 0.f, a1 = 0.f, a2 = 0.f, a3 = 0.f;
        #pragma unroll
        for (int d4 = 0; d4 < 16; d4++) {
            float4 kv = *(const float4*)&kr[d4 * 4];
            float4 qv = *(const float4*)&qr[d4 * 4];
            a0 += qv.x * kv.x; a1 += qv.y * kv.y; a2 += qv.z * kv.z; a3 += qv.w * kv.w;
        }
        float e = fexp(a0 + a1 + a2 + a3);
        float t = e;
        #pragma unroll
        for (int o = 16; o > 0; o >>= 1) t += __shfl_xor_sync(0xffffffffu, t, o);
        if (lane == 0) wsum[wid] = t;
        __syncthreads();
        float S = 0.f;
        #pragma unroll
        for (int w = 0; w < 8; w++) S += wsum[w];
        float val = e * (1.f / S);
        size_t o = ((size_t)bh * MLM + mt * 32 + ml) * MLM + j;
        X[o] = val;
        __nv_bfloat16 h = __float2bfloat16(val);
        Xh[o] = h;
        Xl[o] = __float2bfloat16(val - __bfloat162float(h));
        __syncthreads();
    }
}

__global__ void initmax_kernel(unsigned* mb) { mb[0] = 0u; mb[1] = 0u; }
__global__ void rowcol_kernel(const float* __restrict__ X, unsigned* mb) {
    int bh = blockIdx.x, i = threadIdx.x;
    const float* Xm = X + (size_t)bh * MLM * MLM;
    float rs = 0.f, cs = 0.f;
    for (int j = 0; j < MLM; j++) {
        rs += fabsf(Xm[(size_t)i * MLM + j]);
        cs += fabsf(Xm[(size_t)j * MLM + i]);
    }
    #pragma unroll
    for (int o = 16; o > 0; o >>= 1) {
        rs = fmaxf(rs, __shfl_xor_sync(0xffffffffu, rs, o));
        cs = fmaxf(cs, __shfl_xor_sync(0xffffffffu, cs, o));
    }
    __shared__ float shr[8], shc[8];
    int w = i >> 5;
    if ((i & 31) == 0) { shr[w] = rs; shc[w] = cs; }
    __syncthreads();
    if (i == 0) {
        float mr = shr[0], mc = shc[0];
        #pragma unroll
        for (int k2 = 1; k2 < 8; k2++) { mr = fmaxf(mr, shr[k2]); mc = fmaxf(mc, shc[k2]); }
        atomicMax(&mb[0], __float_as_uint(mr));
        atomicMax(&mb[1], __float_as_uint(mc));
    }
}
__global__ void zinit_kernel(const float* __restrict__ X, const unsigned* __restrict__ mb,
                             __nv_bfloat16* __restrict__ Znh, __nv_bfloat16* __restrict__ Znl,
                             __nv_bfloat16* __restrict__ Zth, __nv_bfloat16* __restrict__ Ztl) {
    float inv = 1.f / (__uint_as_float(mb[0]) * __uint_as_float(mb[1]));
    size_t idx = (size_t)blockIdx.x * 256 + threadIdx.x;
    int bh = (int)(idx >> 16);
    int r = (int)((idx >> 8) & 255);
    int c = (int)(idx & 255);
    float tv = X[idx] * inv;
    __nv_bfloat16 th = __float2bfloat16(tv);
    Zth[idx] = th; Ztl[idx] = __float2bfloat16(tv - __bfloat162float(th));
    float nv = X[((size_t)bh << 16) + ((size_t)c << 8) + r] * inv;
    __nv_bfloat16 nh = __float2bfloat16(nv);
    Znh[idx] = nh; Znl[idx] = __float2bfloat16(nv - __bfloat162float(nh));
}

// attn3@v via MMA: chunked keys, unnormalized partials
#define A3_SMEM 93184
__global__ void __launch_bounds__(256, 1) attn3v_mma(
        const __nv_bfloat16* __restrict__ qlh_, const __nv_bfloat16* __restrict__ qll_,
        const __nv_bfloat16* __restrict__ kh_, const __nv_bfloat16* __restrict__ klo_,
        const __nv_bfloat16* __restrict__ vth_, const __nv_bfloat16* __restrict__ vtl_,
        float* __restrict__ Opart, float* __restrict__ denpart)
{
    extern __shared__ __align__(16) __nv_bfloat16 sm3[];
    uint32_t sb = smem_to_u32(sm3);
    int tid = threadIdx.x, wid = tid >> 5, lane = tid & 31;
    int chunk = blockIdx.x, bh = blockIdx.y;
    int key0 = chunk * (NTOK / NCHK);
    {
        size_t qb = (size_t)bh * MLM * DH_;
        #pragma unroll
        for (int i = 0; i < 8; i++) {
            int lin = tid + i * 256;
            int r = lin >> 3, c = lin & 7;
            *(uint4*)(sm3 + r * 72 + c * 8) = *(const uint4*)(qlh_ + qb + r * 64 + c * 8);
            *(uint4*)(sm3 + 18432 + r * 72 + c * 8) = *(const uint4*)(qll_ + qb + r * 64 + c * 8);
        }
    }
    __syncthreads();
    uint32_t Ah[2][4][4], Al[2][4][4];
    #pragma unroll
    for (int mf = 0; mf < 2; mf++) {
        int row = wid * 32 + mf * 16 + (lane & 15);
        #pragma unroll
        for (int ks = 0; ks < 4; ks++) {
            int col = ks * 16 + ((lane >> 4) << 3);
            ldsm4(Ah[mf][ks], sb + (uint32_t)(row * 72 + col) * 2);
            ldsm4(Al[mf][ks], sb + (uint32_t)(18432 + row * 72 + col) * 2);
        }
    }
    float Oacc[2][8][4];
    #pragma unroll
    for (int a = 0; a < 2; a++)
        #pragma unroll
        for (int b = 0; b < 8; b++)
            #pragma unroll
            for (int c = 0; c < 4; c++) Oacc[a][b][c] = 0.f;
    float den[2][2] = {{0.f, 0.f}, {0.f, 0.f}};

    for (int t32 = 0; t32 < (NTOK / NCHK) / 32; t32++) {
        int kt0 = key0 + t32 * 32;
        __syncthreads();
        {
            int r = tid >> 3, c = tid & 7;
            *(uint4*)(sm3 + 36864 + r * 72 + c * 8) = *(const uint4*)(kh_ + ((size_t)bh * NTOK + kt0 + r) * 64 + c * 8);
            *(uint4*)(sm3 + 39168 + r * 72 + c * 8) = *(const uint4*)(klo_ + ((size_t)bh * NTOK + kt0 + r) * 64 + c * 8);
            int r2 = tid >> 2, c2 = tid & 3;
            *(uint4*)(sm3 + 41472 + r2 * 40 + c2 * 8) = *(const uint4*)(vth_ + ((size_t)bh * 64 + r2) * NTOK + kt0 + c2 * 8);
            *(uint4*)(sm3 + 44032 + r2 * 40 + c2 * 8) = *(const uint4*)(vtl_ + ((size_t)bh * 64 + r2) * NTOK + kt0 + c2 * 8);
        }
        __syncthreads();
        float S[2][4][4];
        #pragma unroll
        for (int a = 0; a < 2; a++)
            #pragma unroll
            for (int b = 0; b < 4; b++)
                #pragma unroll
                for (int c = 0; c < 4; c++) S[a][b][c] = 0.f;
        #pragma unroll
        for (int ks = 0; ks < 4; ks++) {
            #pragma unroll
            for (int np = 0; np < 2; np++) {
                int row = np * 16 + ((lane >> 4) & 1) * 8 + (lane & 7);
                int col = ks * 16 + ((lane >> 3) & 1) * 8;
                uint32_t bh4[4], bl4[4];
                ldsm4(bh4, sb + (uint32_t)(36864 + row * 72 + col) * 2);
                ldsm4(bl4, sb + (uint32_t)(39168 + row * 72 + col) * 2);
                #pragma unroll
                for (int mf = 0; mf < 2; mf++) {
                    mma_bf16p(S[mf][2*np],   Ah[mf][ks], bh4[0], bh4[1]);
                    mma_bf16p(S[mf][2*np],   Ah[mf][ks], bl4[0], bl4[1]);
                    mma_bf16p(S[mf][2*np],   Al[mf][ks], bh4[0], bh4[1]);
                    mma_bf16p(S[mf][2*np+1], Ah[mf][ks], bh4[2], bh4[3]);
                    mma_bf16p(S[mf][2*np+1], Ah[mf][ks], bl4[2], bl4[3]);
                    mma_bf16p(S[mf][2*np+1], Al[mf][ks], bh4[2], bh4[3]);
                }
            }
        }
        #pragma unroll
        for (int kt = 0; kt < 2; kt++) {
            uint32_t pah[2][4], pal[2][4];
            #pragma unroll
            for (int mf = 0; mf < 2; mf++) {
                float e[8];
                #pragma unroll
                for (int j = 0; j < 4; j++) { e[j] = fexp(S[mf][2*kt][j]); e[4+j] = fexp(S[mf][2*kt+1][j]); }
                den[mf][0] += e[0] + e[1] + e[4] + e[5];
                den[mf][1] += e[2] + e[3] + e[6] + e[7];
                #pragma unroll
                for (int j = 0; j < 4; j++) {
                    __nv_bfloat162 h2 = __floats2bfloat162_rn(e[2*j], e[2*j+1]);
                    pah[mf][j] = *(uint32_t*)&h2;
                    float r0 = e[2*j]   - __bfloat162float(__low2bfloat16(h2));
                    float r1 = e[2*j+1] - __bfloat162float(__high2bfloat16(h2));
                    __nv_bfloat162 l2 = __floats2bfloat162_rn(r0, r1);
                    pal[mf][j] = *(uint32_t*)&l2;
                }
            }
            #pragma unroll
            for (int np = 0; np < 4; np++) {
                int row = np * 16 + ((lane >> 4) & 1) * 8 + (lane & 7);
                int col = kt * 16 + ((lane >> 3) & 1) * 8;
                uint32_t vh4[4], vl4[4];
                ldsm4(vh4, sb + (uint32_t)(41472 + row * 40 + col) * 2);
                ldsm4(vl4, sb + (uint32_t)(44032 + row * 40 + col) * 2);
                #pragma unroll
                for (int mf = 0; mf < 2; mf++) {
                    mma_bf16p(Oacc[mf][2*np],   pah[mf], vh4[0], vh4[1]);
                    mma_bf16p(Oacc[mf][2*np],   pah[mf], vl4[0], vl4[1]);
                    mma_bf16p(Oacc[mf][2*np],   pal[mf], vh4[0], vh4[1]);
                    mma_bf16p(Oacc[mf][2*np+1], pah[mf], vh4[2], vh4[3]);
                    mma_bf16p(Oacc[mf][2*np+1], pah[mf], vl4[2], vl4[3]);
                    mma_bf16p(Oacc[mf][2*np+1], pal[mf], vh4[2], vh4[3]);
                }
            }
        }
    }
    #pragma unroll
    for (int mf = 0; mf < 2; mf++)
        #pragma unroll
        for (int j = 0; j < 2; j++) {
            den[mf][j] += __shfl_xor_sync(0xffffffffu, den[mf][j], 1);
            den[mf][j] += __shfl_xor_sync(0xffffffffu, den[mf][j], 2);
        }
    int g = lane >> 2, t = lane & 3;
    size_t ob = ((size_t)chunk * BH + bh) * MLM * 64;
    #pragma unroll
    for (int mf = 0; mf < 2; mf++) {
        int lm0 = wid * 32 + mf * 16 + g;
        #pragma unroll
        for (int nf = 0; nf < 8; nf++) {
            int c = nf * 8 + t * 2;
            *(float2*)&Opart[ob + (size_t)lm0 * 64 + c] = make_float2(Oacc[mf][nf][0], Oacc[mf][nf][1]);
            *(float2*)&Opart[ob + (size_t)(lm0 + 8) * 64 + c] = make_float2(Oacc[mf][nf][2], Oacc[mf][nf][3]);
        }
        if (t == 0) {
            denpart[((size_t)chunk * BH + bh) * MLM + lm0] = den[mf][0];
            denpart[((size_t)chunk * BH + bh) * MLM + lm0 + 8] = den[mf][1];
        }
    }
}

__global__ void a3v_reduce(const float* __restrict__ Opart, const float* __restrict__ denpart,
                           float* __restrict__ A3V) {
    int idx = blockIdx.x * 256 + threadIdx.x;
    int bh = idx >> 14, lm = (idx >> 6) & 255;
    float s = 0.f, d = 0.f;
    #pragma unroll
    for (int c = 0; c < NCHK; c++) {
        s += Opart[((size_t)c * BH + bh) * 16384 + (idx & 16383)];
        d += denpart[((size_t)c * BH + bh) * 256 + lm];
    }
    A3V[idx] = s / d;
}

__global__ void conv_kernel(const float* __restrict__ v, const float* __restrict__ ker,
                            float* __restrict__ O) {
    int nt = blockIdx.x, h = blockIdx.y, b = blockIdx.z;
    int n0 = nt * 128;
    __shared__ float vsh[160][64];
    __shared__ float kw[KER_];
    int tid = threadIdx.x;
    if (tid < KER_) kw[tid] = ker[h * KER_ + tid];
    const float* vb = v + ((size_t)b * H_ + h) * NTOK * DH_;
    #pragma unroll
    for (int i = 0; i < 10; i++) {
        int f4 = tid + i * 256;
        int row2 = f4 >> 4, c4 = f4 & 15;
        int n = n0 - 16 + row2;
        float4 val = make_float4(0.f, 0.f, 0.f, 0.f);
        if (n >= 0 && n < NTOK) val = ((const float4*)(vb + (size_t)n * DH_))[c4];
        ((float4*)vsh)[f4] = val;
    }
    __syncthreads();
    int dh = tid & 63, g = tid >> 6;
    for (int ii = 0; ii < 32; ii++) {
        int nn = g * 32 + ii;
        float o = 0.f;
        #pragma unroll
        for (int t = 0; t < KER_; t++) o += kw[t] * vsh[nn + t][dh];
        O[((size_t)b * NTOK + (n0 + nn)) * D_ + h * DH_ + dh] = o;
    }
}

// attn1 via MMA: O += softmax(q@kl^T)@Y
#define A1_SMEM 178176
__global__ void __launch_bounds__(256, 1) attn1_mma(
        const __nv_bfloat16* __restrict__ qh_, const __nv_bfloat16* __restrict__ qlo_,
        const __nv_bfloat16* __restrict__ klh_, const __nv_bfloat16* __restrict__ kll_,
        const __nv_bfloat16* __restrict__ yth_, const __nv_bfloat16* __restrict__ ytl_,
        float* __restrict__ O)
{
    extern __shared__ __align__(16) __nv_bfloat16 sm1[];
    uint32_t sb = smem_to_u32(sm1);
    int tid = threadIdx.x, wid = tid >> 5, lane = tid & 31;
    int bh = blockIdx.y;
    int tile0 = blockIdx.x * 128;
    {
        size_t qb = ((size_t)bh * NTOK + tile0) * DH_;
        #pragma unroll
        for (int i = 0; i < 4; i++) {
            int lin = tid + i * 256;
            int r = lin >> 3, c = lin & 7;
            *(uint4*)(sm1 + r * 72 + c * 8) = *(const uint4*)(qh_ + qb + r * 64 + c * 8);
            *(uint4*)(sm1 + 9216 + r * 72 + c * 8) = *(const uint4*)(qlo_ + qb + r * 64 + c * 8);
        }
        size_t kb = (size_t)bh * MLM * DH_;
        #pragma unroll
        for (int i = 0; i < 8; i++) {
            int lin = tid + i * 256;
            int r = lin >> 3, c = lin & 7;
            *(uint4*)(sm1 + 18432 + r * 72 + c * 8) = *(const uint4*)(klh_ + kb + r * 64 + c * 8);
            *(uint4*)(sm1 + 36864 + r * 72 + c * 8) = *(const uint4*)(kll_ + kb + r * 64 + c * 8);
        }
        size_t yb = (size_t)bh * 64 * MLM;
        #pragma unroll
        for (int i = 0; i < 8; i++) {
            int lin = tid + i * 256;
            int r = lin >> 5, c = lin & 31;
            *(uint4*)(sm1 + 55296 + r * 264 + c * 8) = *(const uint4*)(yth_ + yb + r * 256 + c * 8);
            *(uint4*)(sm1 + 72192 + r * 264 + c * 8) = *(const uint4*)(ytl_ + yb + r * 256 + c * 8);
        }
    }
    __syncthreads();
    uint32_t Ah[4][4], Al[4][4];
    {
        int row = wid * 16 + (lane & 15);
        #pragma unroll
        for (int ks = 0; ks < 4; ks++) {
            int col = ks * 16 + ((lane >> 4) << 3);
            ldsm4(Ah[ks], sb + (uint32_t)(row * 72 + col) * 2);
            ldsm4(Al[ks], sb + (uint32_t)(9216 + row * 72 + col) * 2);
        }
    }
    float Oacc[8][4];
    #pragma unroll
    for (int b = 0; b < 8; b++)
        #pragma unroll
        for (int c = 0; c < 4; c++) Oacc[b][c] = 0.f;
    float dlo = 0.f, dhi = 0.f;

    #pragma unroll
    for (int half = 0; half < 2; half++) {
        int lmb = half * 128;
        float S[16][4];
        #pragma unroll
        for (int b = 0; b < 16; b++)
            #pragma unroll
            for (int c = 0; c < 4; c++) S[b][c] = 0.f;
        #pragma unroll
        for (int ks = 0; ks < 4; ks++) {
            #pragma unroll
            for (int np = 0; np < 8; np++) {
                int row = lmb + np * 16 + ((lane >> 4) & 1) * 8 + (lane & 7);
                int col = ks * 16 + ((lane >> 3) & 1) * 8;
                uint32_t bh4[4], bl4[4];
                ldsm4(bh4, sb + (uint32_t)(18432 + row * 72 + col) * 2);
                ldsm4(bl4, sb + (uint32_t)(36864 + row * 72 + col) * 2);
                mma_bf16p(S[2*np],   Ah[ks], bh4[0], bh4[1]);
                mma_bf16p(S[2*np],   Ah[ks], bl4[0], bl4[1]);
                mma_bf16p(S[2*np],   Al[ks], bh4[0], bh4[1]);
                mma_bf16p(S[2*np+1], Ah[ks], bh4[2], bh4[3]);
                mma_bf16p(S[2*np+1], Ah[ks], bl4[2], bl4[3]);
                mma_bf16p(S[2*np+1], Al[ks], bh4[2], bh4[3]);
            }
        }
        #pragma unroll
        for (int kt = 0; kt < 8; kt++) {
            float e[8];
            #pragma unroll
            for (int j = 0; j < 4; j++) { e[j] = fexp(S[2*kt][j]); e[4+j] = fexp(S[2*kt+1][j]); }
            dlo += e[0] + e[1] + e[4] + e[5];
            dhi += e[2] + e[3] + e[6] + e[7];
            uint32_t pah[4], pal[4];
            #pragma unroll
            for (int j = 0; j < 4; j++) {
                __nv_bfloat162 h2 = __floats2bfloat162_rn(e[2*j], e[2*j+1]);
                pah[j] = *(uint32_t*)&h2;
                float r0 = e[2*j]   - __bfloat162float(__low2bfloat16(h2));
                float r1 = e[2*j+1] - __bfloat162float(__high2bfloat16(h2));
                __nv_bfloat162 l2 = __floats2bfloat162_rn(r0, r1);
                pal[j] = *(uint32_t*)&l2;
            }
            #pragma unroll
            for (int np = 0; np < 4; np++) {
                int row = np * 16 + ((lane >> 4) & 1) * 8 + (lane & 7);
                int col = lmb + kt * 16 + ((lane >> 3) & 1) * 8;
                uint32_t yh4[4], yl4[4];
                ldsm4(yh4, sb + (uint32_t)(55296 + row * 264 + col) * 2);
                ldsm4(yl4, sb + (uint32_t)(72192 + row * 264 + col) * 2);
                mma_bf16p(Oacc[2*np],   pah, yh4[0], yh4[1]);
                mma_bf16p(Oacc[2*np],   pah, yl4[0], yl4[1]);
                mma_bf16p(Oacc[2*np],   pal, yh4[0], yh4[1]);
                mma_bf16p(Oacc[2*np+1], pah, yh4[2], yh4[3]);
                mma_bf16p(Oacc[2*np+1], pah, yl4[2], yl4[3]);
                mma_bf16p(Oacc[2*np+1], pal, yh4[2], yh4[3]);
            }
        }
    }
    dlo += __shfl_xor_sync(0xffffffffu, dlo, 1);
    dlo += __shfl_xor_sync(0xffffffffu, dlo, 2);
    dhi += __shfl_xor_sync(0xffffffffu, dhi, 1);
    dhi += __shfl_xor_sync(0xffffffffu, dhi, 2);
    float ilo = 1.f / dlo, ihi = 1.f / dhi;
    int g = lane >> 2, t = lane & 3;
    int tok0 = tile0 + wid * 16 + g;
    int b = bh >> 3, h = bh & 7;
    size_t ob = ((size_t)b * NTOK + tok0) * D_ + h * DH_;
    #pragma unroll
    for (int nf = 0; nf < 8; nf++) {
        int c = nf * 8 + t * 2;
        float2* p0 = (float2*)&O[ob + c];
        float2 v0 = *p0;
        v0.x += Oacc[nf][0] * ilo; v0.y += Oacc[nf][1] * ilo;
        *p0 = v0;
        float2* p1 = (float2*)&O[ob + (size_t)8 * D_ + c];
        float2 v1 = *p1;
        v1.x += Oacc[nf][2] * ihi; v1.y += Oacc[nf][3] * ihi;
        *p1 = v1;
    }
}

__global__ void osplit_kernel(const float* __restrict__ O, __nv_bfloat16* __restrict__ hi,
                              __nv_bfloat16* __restrict__ lo) {
    size_t idx = (size_t)blockIdx.x * 256 + threadIdx.x;
    float v = O[idx];
    __nv_bfloat16 h = __float2bfloat16(v);
    hi[idx] = h;
    lo[idx] = __float2bfloat16(v - __bfloat162float(h));
}

extern "C" void kernel_launch(void* const* d_in, const int* in_sizes, int n_in,
                              void* d_out, int out_size) {
    const float* x      = (const float*)d_in[0];
    const float* gamma  = (const float*)d_in[1];
    const float* beta   = (const float*)d_in[2];
    const float* w_qkv  = (const float*)d_in[3];
    const float* res_k  = (const float*)d_in[4];
    const float* w_out  = (const float*)d_in[5];
    const float* b_out  = (const float*)d_in[6];
    float* out = (float*)d_out;

    __nv_bfloat16 *nh, *nl, *wqh, *wql, *woh, *wol, *Oh, *Ol, *Xh, *Xl;
    __nv_bfloat16 *Znh[2], *Znl[2], *Zth[2], *Ztl[2], *XZh, *XZl, *WtAh, *WtAl, *WtBh, *WtBl;
    __nv_bfloat16 *qbh, *qbl, *kbh, *kbl, *vth, *vtl, *qlh, *qll, *klh, *kll, *yth, *ytl;
    float *q, *k, *v, *ql, *kl, *X, *Zf, *A3V, *Y, *O, *Opart, *dpart;
    unsigned* mb;
    cudaGetSymbolAddress((void**)&nh, g_nh);
    cudaGetSymbolAddress((void**)&nl, g_nl);
    cudaGetSymbolAddress((void**)&wqh, g_wqh);
    cudaGetSymbolAddress((void**)&wql, g_wql);
    cudaGetSymbolAddress((void**)&woh, g_woh);
    cudaGetSymbolAddress((void**)&wol, g_wol);
    cudaGetSymbolAddress((void**)&Oh, g_Oh);
    cudaGetSymbolAddress((void**)&Ol, g_Ol);
    cudaGetSymbolAddress((void**)&Xh, g_Xh);
    cudaGetSymbolAddress((void**)&Xl, g_Xl);
    {
        __nv_bfloat16* p;
        cudaGetSymbolAddress((void**)&p, g_Znh); Znh[0] = p; Znh[1] = p + (size_t)BH*MLM*MLM;
        cudaGetSymbolAddress((void**)&p, g_Znl); Znl[0] = p; Znl[1] = p + (size_t)BH*MLM*MLM;
        cudaGetSymbolAddress((void**)&p, g_Zth); Zth[0] = p; Zth[1] = p + (size_t)BH*MLM*MLM;
        cudaGetSymbolAddress((void**)&p, g_Ztl); Ztl[0] = p; Ztl[1] = p + (size_t)BH*MLM*MLM;
    }
    cudaGetSymbolAddress((void**)&XZh, g_XZh);
    cudaGetSymbolAddress((void**)&XZl, g_XZl);
    cudaGetSymbolAddress((void**)&WtAh, g_WtAh);
    cudaGetSymbolAddress((void**)&WtAl, g_WtAl);
    cudaGetSymbolAddress((void**)&WtBh, g_WtBh);
    cudaGetSymbolAddress((void**)&WtBl, g_WtBl);
    cudaGetSymbolAddress((void**)&q,  g_q);
    cudaGetSymbolAddress((void**)&k,  g_k);
    cudaGetSymbolAddress((void**)&v,  g_v);
    cudaGetSymbolAddress((void**)&qbh, g_qbh);
    cudaGetSymbolAddress((void**)&qbl, g_qbl);
    cudaGetSymbolAddress((void**)&kbh, g_kbh);
    cudaGetSymbolAddress((void**)&kbl, g_kbl);
    cudaGetSymbolAddress((void**)&vth, g_vth);
    cudaGetSymbolAddress((void**)&vtl, g_vtl);
    cudaGetSymbolAddress((void**)&ql, g_ql);
    cudaGetSymbolAddress((void**)&kl, g_kl);
    cudaGetSymbolAddress((void**)&qlh, g_qlh);
    cudaGetSymbolAddress((void**)&qll, g_qll);
    cudaGetSymbolAddress((void**)&klh, g_klh);
    cudaGetSymbolAddress((void**)&kll, g_kll);
    cudaGetSymbolAddress((void**)&yth, g_yth);
    cudaGetSymbolAddress((void**)&ytl, g_ytl);
    cudaGetSymbolAddress((void**)&X,  g_X);
    cudaGetSymbolAddress((void**)&Zf, g_Zf);
    cudaGetSymbolAddress((void**)&Opart, g_Opart);
    cudaGetSymbolAddress((void**)&dpart, g_dpart);
    cudaGetSymbolAddress((void**)&A3V, g_A3V);
    cudaGetSymbolAddress((void**)&Y,  g_Y);
    cudaGetSymbolAddress((void**)&O,  g_O);
    cudaGetSymbolAddress((void**)&mb, g_maxbits);

    cudaFuncSetAttribute(attn2_kernel, cudaFuncAttributeMaxDynamicSharedMemorySize, ATTN2_SMEM);
    cudaFuncSetAttribute(tc_gemm, cudaFuncAttributeMaxDynamicSharedMemorySize, TCG_SMEM);
    cudaFuncSetAttribute(attn3v_mma, cudaFuncAttributeMaxDynamicSharedMemorySize, A3_SMEM);
    cudaFuncSetAttribute(attn1_mma, cudaFuncAttributeMaxDynamicSharedMemorySize, A1_SMEM);

    const size_t sM = (size_t)MLM * MLM;

    ln_kernel<<<B_ * NTOK, 256>>>(x, gamma, beta, nh, nl);
    tsplit_kernel<<<(D_ * 3 * D_ + 255) / 256, 256>>>(w_qkv, wqh, wql, D_, 3 * D_);
    tsplit_kernel<<<(D_ * D_ + 255) / 256, 256>>>(w_out, woh, wol, D_, D_);

    tc_gemm<<<dim3(12, 256, 1), 256, TCG_SMEM>>>(nh, nl, wqh, wql, D_, 0, 0, 0, 2,
        q, k, v, nullptr, nullptr, nullptr,
        nullptr, nullptr, nullptr, nullptr, nullptr, 1.f, 0.f, 1.f);

    bsplit_kernel<<<16384, 256>>>(q, qbh, qbl);
    bsplit_kernel<<<16384, 256>>>(k, kbh, kbl);
    vtrans_kernel<<<dim3(NTOK / 64, BH), 256>>>(v, vth, vtl);

    landmark_kernel<<<dim3(BH, MLM), 64>>>(q, k, ql, kl);
    bsplit_kernel<<<512, 256>>>(ql, qlh, qll);
    bsplit_kernel<<<512, 256>>>(kl, klh, kll);

    attn2_kernel<<<dim3(BH, 8), 256, ATTN2_SMEM>>>(ql, kl, X, Xh, Xl);
    initmax_kernel<<<1, 1>>>(mb);
    rowcol_kernel<<<BH, 256>>>(X, mb);
    zinit_kernel<<<8192, 256>>>(X, mb, Znh[0], Znl[0], Zth[0], Ztl[0]);

    int cur = 0;
    for (int it = 0; it < 6; it++) {
        int nxt = cur ^ 1;
        int np = (it < 4) ? 1 : 2;
        tc_gemm<<<dim3(2, 2, BH), 256, TCG_SMEM>>>(Xh, Xl, Zth[cur], Ztl[cur], MLM, sM, sM, 2, np,
            nullptr, nullptr, nullptr, nullptr, nullptr, nullptr,
            XZh, XZl, WtAh, WtAl, nullptr, 1.f, 7.f, 1.f);
        tc_gemm<<<dim3(2, 2, BH), 256, TCG_SMEM>>>(XZh, XZl, WtAh, WtAl, MLM, sM, sM, 2, np,
            nullptr, nullptr, nullptr, nullptr, nullptr, nullptr,
            nullptr, nullptr, WtBh, WtBl, nullptr, 1.f, 15.f, 1.f);
        tc_gemm<<<dim3(2, 2, BH), 256, TCG_SMEM>>>(XZh, XZl, WtBh, WtBl, MLM, sM, sM, 2, np,
            nullptr, nullptr, nullptr, nullptr, nullptr, nullptr,
            nullptr, nullptr, WtAh, WtAl, nullptr, 1.f, 13.f, 1.f);
        tc_gemm<<<dim3(2, 2, BH), 256, TCG_SMEM>>>(Znh[cur], Znl[cur], WtAh, WtAl, MLM, sM, sM, 2, np,
            nullptr, nullptr, nullptr, nullptr, nullptr, nullptr,
            Znh[nxt], Znl[nxt], Zth[nxt], Ztl[nxt], (it == 5) ? Zf : nullptr, 0.25f, 0.f, -0.25f);
        cur = nxt;
    }

    attn3v_mma<<<dim3(NCHK, BH), 256, A3_SMEM>>>(qlh, qll, kbh, kbl, vth, vtl, Opart, dpart);
    a3v_reduce<<<2048, 256>>>(Opart, dpart, A3V);

    sgemm_kernel<<<dim3(1, 2, BH), 256>>>(Zf, A3V, Y, MLM, DH_, MLM,
        sM, (size_t)MLM * DH_, (size_t)MLM * DH_);
    ytrans_kernel<<<BH, 256>>>(Y, yth, ytl);

    conv_kernel<<<dim3(64, H_, B_), 256>>>(v, res_k, O);
    attn1_mma<<<dim3(NTOK / 128, BH), 256, A1_SMEM>>>(qbh, qbl, klh, kll, yth, ytl, O);

    osplit_kernel<<<(int)(((size_t)B_*NTOK*D_) / 256), 256>>>(O, Oh, Ol);
    tc_gemm<<<dim3(4, 256, 1), 256, TCG_SMEM>>>(Oh, Ol, woh, wol, D_, 0, 0, 1, 2,
        nullptr, nullptr, nullptr, out, b_out, x,
        nullptr, nullptr, nullptr, nullptr, nullptr, 1.f, 0.f, 1.f);
}

// round 9
// speedup vs baseline: 5.7853x; 1.2188x over previous
#include <cuda_runtime.h>
#include <cuda_bf16.h>
#include <math.h>
#include <stdint.h>

#define B_    4
#define NTOK  8192
#define D_    512
#define H_    8
#define DH_   64
#define MLM   256
#define LSEG  32
#define BH    (B_*H_)
#define KER_  33
#define NCHK  8

__device__ __forceinline__ uint32_t smem_to_u32(const void* p) {
    uint32_t a;
    asm("{ .reg .u64 t; cvta.to.shared.u64 t, %1; cvt.u32.u64 %0, t; }" : "=r"(a) : "l"(p));
    return a;
}
__device__ __forceinline__ void mma_bf16(float (&d)[4], const uint32_t (&a)[4], const uint32_t (&b)[2]) {
    asm volatile("mma.sync.aligned.m16n8k16.row.col.f32.bf16.bf16.f32 "
        "{%0,%1,%2,%3}, {%4,%5,%6,%7}, {%8,%9}, {%0,%1,%2,%3};"
        : "+f"(d[0]), "+f"(d[1]), "+f"(d[2]), "+f"(d[3])
        : "r"(a[0]), "r"(a[1]), "r"(a[2]), "r"(a[3]), "r"(b[0]), "r"(b[1]));
}
__device__ __forceinline__ void mma_bf16p(float (&d)[4], const uint32_t (&a)[4], uint32_t b0, uint32_t b1) {
    asm volatile("mma.sync.aligned.m16n8k16.row.col.f32.bf16.bf16.f32 "
        "{%0,%1,%2,%3}, {%4,%5,%6,%7}, {%8,%9}, {%0,%1,%2,%3};"
        : "+f"(d[0]), "+f"(d[1]), "+f"(d[2]), "+f"(d[3])
        : "r"(a[0]), "r"(a[1]), "r"(a[2]), "r"(a[3]), "r"(b0), "r"(b1));
}
__device__ __forceinline__ void ldsm4(uint32_t (&r)[4], uint32_t a) {
    asm volatile("ldmatrix.sync.aligned.m8n8.x4.shared.b16 {%0,%1,%2,%3}, [%4];"
        : "=r"(r[0]), "=r"(r[1]), "=r"(r[2]), "=r"(r[3]) : "r"(a));
}
__device__ __forceinline__ void ldsm2(uint32_t (&r)[2], uint32_t a) {
    asm volatile("ldmatrix.sync.aligned.m8n8.x2.shared.b16 {%0,%1}, [%2];"
        : "=r"(r[0]), "=r"(r[1]) : "r"(a));
}
__device__ __forceinline__ float fexp(float s) {
    float t = s * 1.44269504088896341f;
    float i = rintf(t);
    float f = t - i;
    float p = 1.54035303933816e-4f;
    p = p * f + 1.33335581464284e-3f;
    p = p * f + 9.61812910762848e-3f;
    p = p * f + 5.55041086648216e-2f;
    p = p * f + 2.40226506959101e-1f;
    p = p * f + 6.93147180559945e-1f;
    p = p * f + 1.0f;
    return p * __int_as_float(((int)i + 127) << 23);
}

// scratch
__device__ __nv_bfloat16 g_nh[(size_t)B_*NTOK*D_];
__device__ __nv_bfloat16 g_nl[(size_t)B_*NTOK*D_];
__device__ __nv_bfloat16 g_wqh[(size_t)3*D_*D_];
__device__ __nv_bfloat16 g_wql[(size_t)3*D_*D_];
__device__ __nv_bfloat16 g_woh[(size_t)D_*D_];
__device__ __nv_bfloat16 g_wol[(size_t)D_*D_];
__device__ __nv_bfloat16 g_Oh[(size_t)B_*NTOK*D_];
__device__ __nv_bfloat16 g_Ol[(size_t)B_*NTOK*D_];
__device__ float g_q [(size_t)BH*NTOK*DH_];
__device__ float g_k [(size_t)BH*NTOK*DH_];
__device__ float g_v [(size_t)BH*NTOK*DH_];
__device__ __nv_bfloat16 g_qbh[(size_t)BH*NTOK*DH_];
__device__ __nv_bfloat16 g_qbl[(size_t)BH*NTOK*DH_];
__device__ __nv_bfloat16 g_kbh[(size_t)BH*NTOK*DH_];
__device__ __nv_bfloat16 g_kbl[(size_t)BH*NTOK*DH_];
__device__ __nv_bfloat16 g_vth[(size_t)BH*NTOK*DH_];
__device__ __nv_bfloat16 g_vtl[(size_t)BH*NTOK*DH_];
__device__ float g_ql[(size_t)BH*MLM*DH_];
__device__ float g_kl[(size_t)BH*MLM*DH_];
__device__ __nv_bfloat16 g_qlh[(size_t)BH*MLM*DH_];
__device__ __nv_bfloat16 g_qll[(size_t)BH*MLM*DH_];
__device__ __nv_bfloat16 g_klh[(size_t)BH*MLM*DH_];
__device__ __nv_bfloat16 g_kll[(size_t)BH*MLM*DH_];
__device__ __nv_bfloat16 g_yth[(size_t)BH*MLM*DH_];
__device__ __nv_bfloat16 g_ytl[(size_t)BH*MLM*DH_];
__device__ float g_X [(size_t)BH*MLM*MLM];
__device__ __nv_bfloat16 g_Xh[(size_t)BH*MLM*MLM];
__device__ __nv_bfloat16 g_Xl[(size_t)BH*MLM*MLM];
__device__ __nv_bfloat16 g_Znh[2][(size_t)BH*MLM*MLM];
__device__ __nv_bfloat16 g_Znl[2][(size_t)BH*MLM*MLM];
__device__ __nv_bfloat16 g_Zth[2][(size_t)BH*MLM*MLM];
__device__ __nv_bfloat16 g_Ztl[2][(size_t)BH*MLM*MLM];
__device__ __nv_bfloat16 g_XZh[(size_t)BH*MLM*MLM];
__device__ __nv_bfloat16 g_XZl[(size_t)BH*MLM*MLM];
__device__ __nv_bfloat16 g_WtAh[(size_t)BH*MLM*MLM];
__device__ __nv_bfloat16 g_WtAl[(size_t)BH*MLM*MLM];
__device__ __nv_bfloat16 g_WtBh[(size_t)BH*MLM*MLM];
__device__ __nv_bfloat16 g_WtBl[(size_t)BH*MLM*MLM];
__device__ float g_Zf[(size_t)BH*MLM*MLM];
__device__ float g_Opart[(size_t)NCHK*BH*MLM*DH_];
__device__ float g_dpart[(size_t)NCHK*BH*MLM];
__device__ float g_A3V[(size_t)BH*MLM*DH_];
__device__ float g_Y  [(size_t)BH*MLM*DH_];
__device__ float g_O  [(size_t)B_*NTOK*D_];
__device__ unsigned g_maxbits[2];

__global__ void ln_kernel(const float* __restrict__ x, const float* __restrict__ gamma,
                          const float* __restrict__ beta,
                          __nv_bfloat16* __restrict__ ohi, __nv_bfloat16* __restrict__ olo) {
    int row = blockIdx.x, tid = threadIdx.x;
    const float* xr = x + (size_t)row * D_;
    float v0 = xr[tid], v1 = xr[tid + 256];
    float s = v0 + v1, s2 = v0*v0 + v1*v1;
    #pragma unroll
    for (int o = 16; o > 0; o >>= 1) {
        s  += __shfl_xor_sync(0xffffffffu, s,  o);
        s2 += __shfl_xor_sync(0xffffffffu, s2, o);
    }
    __shared__ float sh[16];
    int w = tid >> 5;
    if ((tid & 31) == 0) { sh[w] = s; sh[w + 8] = s2; }
    __syncthreads();
    if (tid == 0) {
        float a = 0.f, b2 = 0.f;
        #pragma unroll
        for (int i = 0; i < 8; i++) { a += sh[i]; b2 += sh[i + 8]; }
        sh[0] = a; sh[8] = b2;
    }
    __syncthreads();
    float mu  = sh[0] * (1.f / D_);
    float var = sh[8] * (1.f / D_) - mu * mu;
    float inv = rsqrtf(var + 1e-5f);
    size_t base = (size_t)row * D_;
    #pragma unroll
    for (int half = 0; half < 2; half++) {
        int c = tid + half * 256;
        float v = (half == 0 ? v0 : v1);
        float nv = (v - mu) * inv * gamma[c] + beta[c];
        __nv_bfloat16 hi = __float2bfloat16(nv);
        ohi[base + c] = hi;
        olo[base + c] = __float2bfloat16(nv - __bfloat162float(hi));
    }
}

__global__ void tsplit_kernel(const float* __restrict__ W, __nv_bfloat16* __restrict__ Thi,
                              __nv_bfloat16* __restrict__ Tlo, int K, int N) {
    int idx = blockIdx.x * 256 + threadIdx.x;
    if (idx >= K * N) return;
    int k = idx / N, n = idx % N;
    float v = W[idx];
    __nv_bfloat16 hi = __float2bfloat16(v);
    Thi[(size_t)n * K + k] = hi;
    Tlo[(size_t)n * K + k] = __float2bfloat16(v - __bfloat162float(hi));
}
__global__ void bsplit_kernel(const float* __restrict__ s, __nv_bfloat16* __restrict__ h,
                              __nv_bfloat16* __restrict__ l) {
    size_t i = ((size_t)blockIdx.x * 256 + threadIdx.x) * 4;
    float4 v = *(const float4*)(s + i);
    __nv_bfloat16 hh[4], ll[4];
    float vv[4] = {v.x, v.y, v.z, v.w};
    #pragma unroll
    for (int t = 0; t < 4; t++) {
        hh[t] = __float2bfloat16(vv[t]);
        ll[t] = __float2bfloat16(vv[t] - __bfloat162float(hh[t]));
    }
    *(uint2*)(h + i) = *(uint2*)hh;
    *(uint2*)(l + i) = *(uint2*)ll;
}
__global__ void vtrans_kernel(const float* __restrict__ v, __nv_bfloat16* __restrict__ vth,
                              __nv_bfloat16* __restrict__ vtl) {
    __shared__ float ts[64][68];
    int bh = blockIdx.y, k0 = blockIdx.x * 64;
    int tid = threadIdx.x;
    const float* vb = v + ((size_t)bh * NTOK + k0) * DH_;
    #pragma unroll
    for (int i = 0; i < 4; i++) {
        int lin = tid + i * 256;
        int r = lin >> 4, c4 = lin & 15;
        *(float4*)&ts[r][c4 * 4] = *(const float4*)(vb + r * 64 + c4 * 4);
    }
    __syncthreads();
    #pragma unroll
    for (int i = 0; i < 16; i++) {
        int lin = tid + i * 256;
        int dh = lin >> 6, ky = lin & 63;
        float val = ts[ky][dh];
        __nv_bfloat16 h = __float2bfloat16(val);
        size_t o = ((size_t)bh * 64 + dh) * NTOK + k0 + ky;
        vth[o] = h;
        vtl[o] = __float2bfloat16(val - __bfloat162float(h));
    }
}
__global__ void ytrans_kernel(const float* __restrict__ Y, __nv_bfloat16* __restrict__ yth,
                              __nv_bfloat16* __restrict__ ytl) {
    int bh = blockIdx.x, tid = threadIdx.x;
    #pragma unroll
    for (int i = 0; i < 64; i++) {
        int lin = tid + i * 256;
        int dh = lin >> 8, lm = lin & 255;
        float val = Y[(size_t)bh * 16384 + lm * 64 + dh];
        __nv_bfloat16 h = __float2bfloat16(val);
        size_t o = (size_t)bh * 16384 + dh * 256 + lm;
        yth[o] = h;
        ytl[o] = __float2bfloat16(val - __bfloat162float(h));
    }
}

// bf16-split MMA GEMM, double-buffered, NPASS compile-time.
#define TCG_SMEM (2 * 4 * 5120 * 2)
template<int NPASS>
__global__ void __launch_bounds__(256) tc_gemm(
        const __nv_bfloat16* __restrict__ Ahi, const __nv_bfloat16* __restrict__ Alo,
        const __nv_bfloat16* __restrict__ Bhi, const __nv_bfloat16* __restrict__ Blo,
        int K, size_t strA, size_t strB, int mode,
        float* __restrict__ qp, float* __restrict__ kp, float* __restrict__ vp,
        float* __restrict__ Cout, const float* __restrict__ bias, const float* __restrict__ addx,
        __nv_bfloat16* __restrict__ Nhi, __nv_bfloat16* __restrict__ Nlo,
        __nv_bfloat16* __restrict__ Thi, __nv_bfloat16* __restrict__ Tlo,
        float* __restrict__ Cf32, float alpha, float diagc, float beta)
{
    extern __shared__ __align__(16) char smem[];
    __nv_bfloat16* tiles = reinterpret_cast<__nv_bfloat16*>(smem);
    uint32_t sbase = smem_to_u32(smem);
    int tid = threadIdx.x;
    int wid = tid >> 5, lane = tid & 31;
    int wm = (wid & 3) * 32, wn = (wid >> 2) * 64;
    int bz = blockIdx.z;
    int m0 = blockIdx.y * 128, n0 = blockIdx.x * 128;
    size_t oz = (size_t)bz * 65536;
    Ahi += (size_t)bz * strA; Alo += (size_t)bz * strA;
    Bhi += (size_t)bz * strB; Blo += (size_t)bz * strB;
    const __nv_bfloat16* srcs[4] = {Ahi, Alo, Bhi, Blo};
    const int row0s[4] = {m0, m0, n0, n0};
    const int NB = (NPASS == 1) ? 2 : 4;

    float acc[2][8][4];
    #pragma unroll
    for (int a = 0; a < 2; a++)
        #pragma unroll
        for (int b = 0; b < 8; b++)
            #pragma unroll
            for (int c = 0; c < 4; c++) acc[a][b][c] = 0.f;

    int r_ld = tid >> 2, c_ld = tid & 3;
    uint4 pf[4][2];
    int nch = K >> 5;

    #pragma unroll
    for (int bs = 0; bs < NB; bs++) {
        int bsel = (NPASS == 1) ? bs * 2 : bs;
        #pragma unroll
        for (int i = 0; i < 2; i++)
            pf[bs][i] = *reinterpret_cast<const uint4*>(srcs[bsel] + (size_t)(row0s[bsel] + r_ld + i * 64) * K + c_ld * 8);
    }
    #pragma unroll
    for (int bs = 0; bs < NB; bs++) {
        int bsel = (NPASS == 1) ? bs * 2 : bs;
        #pragma unroll
        for (int i = 0; i < 2; i++)
            *reinterpret_cast<uint4*>(tiles + bsel * 5120 + (r_ld + i * 64) * 40 + c_ld * 8) = pf[bs][i];
    }
    __syncthreads();

    for (int ch = 0; ch < nch; ch++) {
        int s = ch & 1;
        uint32_t stg_off = (uint32_t)s * 4 * 5120;
        if (ch + 1 < nch) {
            int k0 = (ch + 1) << 5;
            #pragma unroll
            for (int bs = 0; bs < NB; bs++) {
                int bsel = (NPASS == 1) ? bs * 2 : bs;
                #pragma unroll
                for (int i = 0; i < 2; i++)
                    pf[bs][i] = *reinterpret_cast<const uint4*>(srcs[bsel] + (size_t)(row0s[bsel] + r_ld + i * 64) * K + k0 + c_ld * 8);
            }
        }
        #pragma unroll
        for (int ks = 0; ks < 32; ks += 16) {
            uint32_t Ah[2][4], Al[2][4];
            #pragma unroll
            for (int mf = 0; mf < 2; mf++) {
                int row = wm + mf * 16 + (lane & 15);
                int col = ks + ((lane >> 4) << 3);
                ldsm4(Ah[mf], sbase + (uint32_t)(stg_off + row * 40 + col) * 2);
                if (NPASS > 1) ldsm4(Al[mf], sbase + (uint32_t)(stg_off + 5120 + row * 40 + col) * 2);
            }
            #pragma unroll
            for (int nf = 0; nf < 8; nf++) {
                int rowb = wn + nf * 8 + (lane & 7);
                int colb = ks + ((lane >> 3) & 1) * 8;
                uint32_t Bh2[2], Bl2[2];
                ldsm2(Bh2, sbase + (uint32_t)(stg_off + 2 * 5120 + rowb * 40 + colb) * 2);
                if (NPASS > 1) ldsm2(Bl2, sbase + (uint32_t)(stg_off + 3 * 5120 + rowb * 40 + colb) * 2);
                #pragma unroll
                for (int mf = 0; mf < 2; mf++) {
                    mma_bf16(acc[mf][nf], Ah[mf], Bh2);
                    if (NPASS > 1) {
                        mma_bf16(acc[mf][nf], Ah[mf], Bl2);
                        mma_bf16(acc[mf][nf], Al[mf], Bh2);
                    }
                }
            }
        }
        if (ch + 1 < nch) {
            uint32_t nxt_off = (uint32_t)((ch + 1) & 1) * 4 * 5120;
            #pragma unroll
            for (int bs = 0; bs < NB; bs++) {
                int bsel = (NPASS == 1) ? bs * 2 : bs;
                #pragma unroll
                for (int i = 0; i < 2; i++)
                    *reinterpret_cast<uint4*>(tiles + nxt_off + bsel * 5120 + (r_ld + i * 64) * 40 + c_ld * 8) = pf[bs][i];
            }
        }
        __syncthreads();
    }

    float* stg = reinterpret_cast<float*>(smem);
    {
        int r = lane >> 2, c = (lane & 3) * 2;
        #pragma unroll
        for (int mf = 0; mf < 2; mf++)
            #pragma unroll
            for (int nf = 0; nf < 8; nf++) {
                int rr = wm + mf * 16 + r, cc = wn + nf * 8 + c;
                *reinterpret_cast<float2*>(&stg[rr * 132 + cc]) = make_float2(acc[mf][nf][0], acc[mf][nf][1]);
                *reinterpret_cast<float2*>(&stg[(rr + 8) * 132 + cc]) = make_float2(acc[mf][nf][2], acc[mf][nf][3]);
            }
    }
    __syncthreads();

    if (mode == 0) {
        #pragma unroll 4
        for (int i = 0; i < 16; i++) {
            int lin = tid + (i << 8);
            int token = lin >> 5, c4 = lin & 31;
            int gn = n0 + (c4 << 2);
            float4 v = *reinterpret_cast<float4*>(&stg[token * 132 + (c4 << 2)]);
            int gmm = m0 + token;
            int b_ = gmm >> 13, n_ = gmm & 8191;
            int sec = gn >> 9, cc = gn & 511, h_ = cc >> 6, dh = cc & 63;
            size_t idx = ((((size_t)b_ * H_ + h_) * NTOK) + n_) * DH_ + dh;
            if (sec == 2) {
                *reinterpret_cast<float4*>(&vp[idx]) = v;
            } else {
                if (sec == 0) { v.x *= 0.125f; v.y *= 0.125f; v.z *= 0.125f; v.w *= 0.125f; }
                float* fp = (sec == 0) ? qp : kp;
                __nv_bfloat16* hp = (sec == 0) ? Nhi : Thi;
                __nv_bfloat16* lp = (sec == 0) ? Nlo : Tlo;
                *reinterpret_cast<float4*>(&fp[idx]) = v;
                float vv[4] = {v.x, v.y, v.z, v.w};
                __nv_bfloat16 hb[4], lb[4];
                #pragma unroll
                for (int t2 = 0; t2 < 4; t2++) {
                    hb[t2] = __float2bfloat16(vv[t2]);
                    lb[t2] = __float2bfloat16(vv[t2] - __bfloat162float(hb[t2]));
                }
                *reinterpret_cast<uint2*>(&hp[idx]) = *reinterpret_cast<uint2*>(hb);
                *reinterpret_cast<uint2*>(&lp[idx]) = *reinterpret_cast<uint2*>(lb);
            }
        }
    } else if (mode == 1) {
        #pragma unroll 4
        for (int i = 0; i < 16; i++) {
            int lin = tid + (i << 8);
            int token = lin >> 5, c4 = lin & 31;
            int gn = n0 + (c4 << 2);
            int gmm = m0 + token;
            float4 v = *reinterpret_cast<float4*>(&stg[token * 132 + (c4 << 2)]);
            float4 bb = *reinterpret_cast<const float4*>(&bias[gn]);
            float4 xx = *reinterpret_cast<const float4*>(&addx[(size_t)gmm * 512 + gn]);
            v.x += bb.x + xx.x; v.y += bb.y + xx.y; v.z += bb.z + xx.z; v.w += bb.w + xx.w;
            *reinterpret_cast<float4*>(&Cout[(size_t)gmm * 512 + gn]) = v;
        }
    } else {
        if (Thi) {
            #pragma unroll 4
            for (int i = 0; i < 64; i++) {
                int idx = tid + (i << 8);
                int gn_l = idx >> 7, gm_l = idx & 127;
                int gmm = m0 + gm_l, gn = n0 + gn_l;
                float v = stg[gm_l * 132 + gn_l];
                float t = (gmm == gn ? diagc : 0.f) - beta * v;
                __nv_bfloat16 h = __float2bfloat16(t);
                Thi[oz + (size_t)gn * 256 + gmm] = h;
                Tlo[oz + (size_t)gn * 256 + gmm] = __float2bfloat16(t - __bfloat162float(h));
            }
        }
        if (Nhi) {
            #pragma unroll 4
            for (int i = 0; i < 16; i++) {
                int lin = tid + (i << 8);
                int token = lin >> 5, c4 = lin & 31;
                int gn = n0 + (c4 << 2);
                int gmm = m0 + token;
                float4 v = *reinterpret_cast<float4*>(&stg[token * 132 + (c4 << 2)]);
                float vv[4] = {v.x * alpha, v.y * alpha, v.z * alpha, v.w * alpha};
                __nv_bfloat16 h[4], l2[4];
                #pragma unroll
                for (int t2 = 0; t2 < 4; t2++) {
                    h[t2] = __float2bfloat16(vv[t2]);
                    l2[t2] = __float2bfloat16(vv[t2] - __bfloat162float(h[t2]));
                }
                *reinterpret_cast<uint2*>(&Nhi[oz + (size_t)gmm * 256 + gn]) = *reinterpret_cast<uint2*>(h);
                *reinterpret_cast<uint2*>(&Nlo[oz + (size_t)gmm * 256 + gn]) = *reinterpret_cast<uint2*>(l2);
            }
        }
        if (Cf32) {
            #pragma unroll 4
            for (int i = 0; i < 16; i++) {
                int lin = tid + (i << 8);
                int token = lin >> 5, c4 = lin & 31;
                int gn = n0 + (c4 << 2);
                int gmm = m0 + token;
                float4 v = *reinterpret_cast<float4*>(&stg[token * 132 + (c4 << 2)]);
                v.x *= alpha; v.y *= alpha; v.z *= alpha; v.w *= alpha;
                *reinterpret_cast<float4*>(&Cf32[oz + (size_t)gmm * 256 + gn]) = v;
            }
        }
    }
}

// SIMT SGEMM for Y = Zf @ A3V
__global__ void __launch_bounds__(256) sgemm_kernel(
        const float* __restrict__ A, const float* __restrict__ B, float* __restrict__ C,
        int M, int N, int K, size_t sA, size_t sB, size_t sC)
{
    int bz = blockIdx.z;
    A += (size_t)bz * sA; B += (size_t)bz * sB; C += (size_t)bz * sC;
    int m0 = blockIdx.y * 128, n0 = blockIdx.x * 128;
    __shared__ float As[8][128];
    __shared__ float Bs[8][128];
    int tid = threadIdx.x;
    int tx = tid & 15, ty = tid >> 4;
    float acc[8][8];
    #pragma unroll
    for (int i = 0; i < 8; i++)
        #pragma unroll
        for (int j = 0; j < 8; j++) acc[i][j] = 0.f;
    for (int k0 = 0; k0 < K; k0 += 8) {
        #pragma unroll
        for (int i = 0; i < 4; i++) {
            int lin = tid + i * 256;
            int kk = lin & 7, mm = lin >> 3;
            int gmm = m0 + mm, gk = k0 + kk;
            As[kk][mm] = (gmm < M && gk < K) ? A[(size_t)gmm * K + gk] : 0.f;
        }
        #pragma unroll
        for (int i = 0; i < 4; i++) {
            int lin = tid + i * 256;
            int nn = lin & 127, kk = lin >> 7;
            int gn = n0 + nn, gk = k0 + kk;
            Bs[kk][nn] = (gn < N && gk < K) ? B[(size_t)gk * N + gn] : 0.f;
        }
        __syncthreads();
        #pragma unroll
        for (int kk = 0; kk < 8; kk++) {
            float a[8], b[8];
            *(float4*)&a[0] = *(const float4*)&As[kk][ty * 8];
            *(float4*)&a[4] = *(const float4*)&As[kk][ty * 8 + 4];
            *(float4*)&b[0] = *(const float4*)&Bs[kk][tx * 8];
            *(float4*)&b[4] = *(const float4*)&Bs[kk][tx * 8 + 4];
            #pragma unroll
            for (int i = 0; i < 8; i++)
                #pragma unroll
                for (int j = 0; j < 8; j++) acc[i][j] += a[i] * b[j];
        }
        __syncthreads();
    }
    #pragma unroll
    for (int i = 0; i < 8; i++) {
        int gmm = m0 + ty * 8 + i;
        if (gmm >= M) continue;
        #pragma unroll
        for (int j = 0; j < 8; j++) {
            int gn = n0 + tx * 8 + j;
            if (gn >= N) continue;
            C[(size_t)gmm * N + gn] = acc[i][j];
        }
    }
}

__global__ void landmark_kernel(const float* __restrict__ q, const float* __restrict__ k,
                                float* __restrict__ ql, float* __restrict__ kl) {
    int bh = blockIdx.x, m = blockIdx.y;
    int dh = threadIdx.x;
    size_t base = ((size_t)bh * NTOK + (size_t)m * LSEG) * DH_ + dh;
    float aq = 0.f, ak = 0.f;
    #pragma unroll
    for (int i = 0; i < LSEG; i++) {
        aq += q[base + (size_t)i * DH_];
        ak += k[base + (size_t)i * DH_];
    }
    size_t o = ((size_t)bh * MLM + m) * DH_ + dh;
    ql[o] = aq * (1.f / LSEG);
    kl[o] = ak * (1.f / LSEG);
}

#define ATTN2_SMEM ((256 * 68 + 32 * 64 + 8) * 4)
__global__ void attn2_kernel(const float* __restrict__ ql, const float* __restrict__ kl,
                             float* __restrict__ X,
                             __nv_bfloat16* __restrict__ Xh, __nv_bfloat16* __restrict__ Xl) {
    extern __shared__ __align__(16) float sh2[];
    float* kls  = sh2;
    float* qs   = sh2 + 256 * 68;
    float* wsum = qs + 32 * 64;
    int bh = blockIdx.x, mt = blockIdx.y;
    int tid = threadIdx.x;
    #pragma unroll
    for (int i = 0; i < 16; i++) {
        int lin = tid + i * 256;
        int r = lin >> 4, c = lin & 15;
        *(float4*)&kls[r * 68 + c * 4] = *(const float4*)&kl[((size_t)bh * MLM + r) * DH_ + c * 4];
    }
    #pragma unroll
    for (int i = 0; i < 2; i++) {
        int lin = tid + i * 256;
        int r = lin >> 4, c = lin & 15;
        *(float4*)&qs[r * 64 + c * 4] = *(const float4*)&ql[((size_t)bh * MLM + mt * 32 + r) * DH_ + c * 4];
    }
    __syncthreads();
    int j = tid, wid = tid >> 5, lane = tid & 31;
    const float* kr = &kls[j * 68];
    for (int ml = 0; ml < 32; ml++) {
        const float* qr = &qs[ml * 64];
        float a0 = 0.f, a1 = 0.f, a2 = 0.f, a3 = 0.f;
        #pragma unroll
        for (int d4 = 0; d4 < 16; d4++) {
            float4 kv = *(const float4*)&kr[d4 * 4];
            float4 qv = *(const float4*)&qr[d4 * 4];
            a0 += qv.x * kv.x; a1 += qv.y * kv.y; a2 += qv.z * kv.z; a3 += qv.w * kv.w;
        }
        float e = fexp(a0 + a1 + a2 + a3);
        float t = e;
        #pragma unroll
        for (int o = 16; o > 0; o >>= 1) t += __shfl_xor_sync(0xffffffffu, t, o);
        if (lane == 0) wsum[wid] = t;
        __syncthreads();
        float S = 0.f;
        #pragma unroll
        for (int w = 0; w < 8; w++) S += wsum[w];
        float val = e * (1.f / S);
        size_t o = ((size_t)bh * MLM + mt * 32 + ml) * MLM + j;
        X[o] = val;
        __nv_bfloat16 h = __float2bfloat16(val);
        Xh[o] = h;
        Xl[o] = __float2bfloat16(val - __bfloat162float(h));
        __syncthreads();
    }
}

__global__ void initmax_kernel(unsigned* mb) { mb[0] = 0u; mb[1] = 0u; }
__global__ void rowcol_kernel(const float* __restrict__ X, unsigned* mb) {
    int bh = blockIdx.x, i = threadIdx.x;
    const float* Xm = X + (size_t)bh * MLM * MLM;
    float rs = 0.f, cs = 0.f;
    for (int j = 0; j < MLM; j++) {
        rs += fabsf(Xm[(size_t)i * MLM + j]);
        cs += fabsf(Xm[(size_t)j * MLM + i]);
    }
    #pragma unroll
    for (int o = 16; o > 0; o >>= 1) {
        rs = fmaxf(rs, __shfl_xor_sync(0xffffffffu, rs, o));
        cs = fmaxf(cs, __shfl_xor_sync(0xffffffffu, cs, o));
    }
    __shared__ float shr[8], shc[8];
    int w = i >> 5;
    if ((i & 31) == 0) { shr[w] = rs; shc[w] = cs; }
    __syncthreads();
    if (i == 0) {
        float mr = shr[0], mc = shc[0];
        #pragma unroll
        for (int k2 = 1; k2 < 8; k2++) { mr = fmaxf(mr, shr[k2]); mc = fmaxf(mc, shc[k2]); }
        atomicMax(&mb[0], __float_as_uint(mr));
        atomicMax(&mb[1], __float_as_uint(mc));
    }
}
__global__ void zinit_kernel(const float* __restrict__ X, const unsigned* __restrict__ mb,
                             __nv_bfloat16* __restrict__ Znh, __nv_bfloat16* __restrict__ Znl,
                             __nv_bfloat16* __restrict__ Zth, __nv_bfloat16* __restrict__ Ztl) {
    float inv = 1.f / (__uint_as_float(mb[0]) * __uint_as_float(mb[1]));
    size_t idx = (size_t)blockIdx.x * 256 + threadIdx.x;
    int bh = (int)(idx >> 16);
    int r = (int)((idx >> 8) & 255);
    int c = (int)(idx & 255);
    float tv = X[idx] * inv;
    __nv_bfloat16 th = __float2bfloat16(tv);
    Zth[idx] = th; Ztl[idx] = __float2bfloat16(tv - __bfloat162float(th));
    float nv = X[((size_t)bh << 16) + ((size_t)c << 8) + r] * inv;
    __nv_bfloat16 nh = __float2bfloat16(nv);
    Znh[idx] = nh; Znl[idx] = __float2bfloat16(nv - __bfloat162float(nh));
}

// attn3@v via MMA
#define A3_SMEM 93184
__global__ void __launch_bounds__(256, 1) attn3v_mma(
        const __nv_bfloat16* __restrict__ qlh_, const __nv_bfloat16* __restrict__ qll_,
        const __nv_bfloat16* __restrict__ kh_, const __nv_bfloat16* __restrict__ klo_,
        const __nv_bfloat16* __restrict__ vth_, const __nv_bfloat16* __restrict__ vtl_,
        float* __restrict__ Opart, float* __restrict__ denpart)
{
    extern __shared__ __align__(16) __nv_bfloat16 sm3[];
    uint32_t sb = smem_to_u32(sm3);
    int tid = threadIdx.x, wid = tid >> 5, lane = tid & 31;
    int chunk = blockIdx.x, bh = blockIdx.y;
    int key0 = chunk * (NTOK / NCHK);
    {
        size_t qb = (size_t)bh * MLM * DH_;
        #pragma unroll
        for (int i = 0; i < 8; i++) {
            int lin = tid + i * 256;
            int r = lin >> 3, c = lin & 7;
            *(uint4*)(sm3 + r * 72 + c * 8) = *(const uint4*)(qlh_ + qb + r * 64 + c * 8);
            *(uint4*)(sm3 + 18432 + r * 72 + c * 8) = *(const uint4*)(qll_ + qb + r * 64 + c * 8);
        }
    }
    __syncthreads();
    uint32_t Ah[2][4][4], Al[2][4][4];
    #pragma unroll
    for (int mf = 0; mf < 2; mf++) {
        int row = wid * 32 + mf * 16 + (lane & 15);
        #pragma unroll
        for (int ks = 0; ks < 4; ks++) {
            int col = ks * 16 + ((lane >> 4) << 3);
            ldsm4(Ah[mf][ks], sb + (uint32_t)(row * 72 + col) * 2);
            ldsm4(Al[mf][ks], sb + (uint32_t)(18432 + row * 72 + col) * 2);
        }
    }
    float Oacc[2][8][4];
    #pragma unroll
    for (int a = 0; a < 2; a++)
        #pragma unroll
        for (int b = 0; b < 8; b++)
            #pragma unroll
            for (int c = 0; c < 4; c++) Oacc[a][b][c] = 0.f;
    float den[2][2] = {{0.f, 0.f}, {0.f, 0.f}};

    for (int t32 = 0; t32 < (NTOK / NCHK) / 32; t32++) {
        int kt0 = key0 + t32 * 32;
        __syncthreads();
        {
            int r = tid >> 3, c = tid & 7;
            *(uint4*)(sm3 + 36864 + r * 72 + c * 8) = *(const uint4*)(kh_ + ((size_t)bh * NTOK + kt0 + r) * 64 + c * 8);
            *(uint4*)(sm3 + 39168 + r * 72 + c * 8) = *(const uint4*)(klo_ + ((size_t)bh * NTOK + kt0 + r) * 64 + c * 8);
            int r2 = tid >> 2, c2 = tid & 3;
            *(uint4*)(sm3 + 41472 + r2 * 40 + c2 * 8) = *(const uint4*)(vth_ + ((size_t)bh * 64 + r2) * NTOK + kt0 + c2 * 8);
            *(uint4*)(sm3 + 44032 + r2 * 40 + c2 * 8) = *(const uint4*)(vtl_ + ((size_t)bh * 64 + r2) * NTOK + kt0 + c2 * 8);
        }
        __syncthreads();
        float S[2][4][4];
        #pragma unroll
        for (int a = 0; a < 2; a++)
            #pragma unroll
            for (int b = 0; b < 4; b++)
                #pragma unroll
                for (int c = 0; c < 4; c++) S[a][b][c] = 0.f;
        #pragma unroll
        for (int ks = 0; ks < 4; ks++) {
            #pragma unroll
            for (int np = 0; np < 2; np++) {
                int row = np * 16 + ((lane >> 4) & 1) * 8 + (lane & 7);
                int col = ks * 16 + ((lane >> 3) & 1) * 8;
                uint32_t bh4[4], bl4[4];
                ldsm4(bh4, sb + (uint32_t)(36864 + row * 72 + col) * 2);
                ldsm4(bl4, sb + (uint32_t)(39168 + row * 72 + col) * 2);
                #pragma unroll
                for (int mf = 0; mf < 2; mf++) {
                    mma_bf16p(S[mf][2*np],   Ah[mf][ks], bh4[0], bh4[1]);
                    mma_bf16p(S[mf][2*np],   Ah[mf][ks], bl4[0], bl4[1]);
                    mma_bf16p(S[mf][2*np],   Al[mf][ks], bh4[0], bh4[1]);
                    mma_bf16p(S[mf][2*np+1], Ah[mf][ks], bh4[2], bh4[3]);
                    mma_bf16p(S[mf][2*np+1], Ah[mf][ks], bl4[2], bl4[3]);
                    mma_bf16p(S[mf][2*np+1], Al[mf][ks], bh4[2], bh4[3]);
                }
            }
        }
        #pragma unroll
        for (int kt = 0; kt < 2; kt++) {
            uint32_t pah[2][4], pal[2][4];
            #pragma unroll
            for (int mf = 0; mf < 2; mf++) {
                float e[8];
                #pragma unroll
                for (int j = 0; j < 4; j++) { e[j] = fexp(S[mf][2*kt][j]); e[4+j] = fexp(S[mf][2*kt+1][j]); }
                den[mf][0] += e[0] + e[1] + e[4] + e[5];
                den[mf][1] += e[2] + e[3] + e[6] + e[7];
                #pragma unroll
                for (int j = 0; j < 4; j++) {
                    __nv_bfloat162 h2 = __floats2bfloat162_rn(e[2*j], e[2*j+1]);
                    pah[mf][j] = *(uint32_t*)&h2;
                    float r0 = e[2*j]   - __bfloat162float(__low2bfloat16(h2));
                    float r1 = e[2*j+1] - __bfloat162float(__high2bfloat16(h2));
                    __nv_bfloat162 l2 = __floats2bfloat162_rn(r0, r1);
                    pal[mf][j] = *(uint32_t*)&l2;
                }
            }
            #pragma unroll
            for (int np = 0; np < 4; np++) {
                int row = np * 16 + ((lane >> 4) & 1) * 8 + (lane & 7);
                int col = kt * 16 + ((lane >> 3) & 1) * 8;
                uint32_t vh4[4], vl4[4];
                ldsm4(vh4, sb + (uint32_t)(41472 + row * 40 + col) * 2);
                ldsm4(vl4, sb + (uint32_t)(44032 + row * 40 + col) * 2);
                #pragma unroll
                for (int mf = 0; mf < 2; mf++) {
                    mma_bf16p(Oacc[mf][2*np],   pah[mf], vh4[0], vh4[1]);
                    mma_bf16p(Oacc[mf][2*np],   pah[mf], vl4[0], vl4[1]);
                    mma_bf16p(Oacc[mf][2*np],   pal[mf], vh4[0], vh4[1]);
                    mma_bf16p(Oacc[mf][2*np+1], pah[mf], vh4[2], vh4[3]);
                    mma_bf16p(Oacc[mf][2*np+1], pah[mf], vl4[2], vl4[3]);
                    mma_bf16p(Oacc[mf][2*np+1], pal[mf], vh4[2], vh4[3]);
                }
            }
        }
    }
    #pragma unroll
    for (int mf = 0; mf < 2; mf++)
        #pragma unroll
        for (int j = 0; j < 2; j++) {
            den[mf][j] += __shfl_xor_sync(0xffffffffu, den[mf][j], 1);
            den[mf][j] += __shfl_xor_sync(0xffffffffu, den[mf][j], 2);
        }
    int g = lane >> 2, t = lane & 3;
    size_t ob = ((size_t)chunk * BH + bh) * MLM * 64;
    #pragma unroll
    for (int mf = 0; mf < 2; mf++) {
        int lm0 = wid * 32 + mf * 16 + g;
        #pragma unroll
        for (int nf = 0; nf < 8; nf++) {
            int c = nf * 8 + t * 2;
            *(float2*)&Opart[ob + (size_t)lm0 * 64 + c] = make_float2(Oacc[mf][nf][0], Oacc[mf][nf][1]);
            *(float2*)&Opart[ob + (size_t)(lm0 + 8) * 64 + c] = make_float2(Oacc[mf][nf][2], Oacc[mf][nf][3]);
        }
        if (t == 0) {
            denpart[((size_t)chunk * BH + bh) * MLM + lm0] = den[mf][0];
            denpart[((size_t)chunk * BH + bh) * MLM + lm0 + 8] = den[mf][1];
        }
    }
}

__global__ void a3v_reduce(const float* __restrict__ Opart, const float* __restrict__ denpart,
                           float* __restrict__ A3V) {
    int idx = blockIdx.x * 256 + threadIdx.x;
    int bh = idx >> 14, lm = (idx >> 6) & 255;
    float s = 0.f, d = 0.f;
    #pragma unroll
    for (int c = 0; c < NCHK; c++) {
        s += Opart[((size_t)c * BH + bh) * 16384 + (idx & 16383)];
        d += denpart[((size_t)c * BH + bh) * 256 + lm];
    }
    A3V[idx] = s / d;
}

__global__ void conv_kernel(const float* __restrict__ v, const float* __restrict__ ker,
                            float* __restrict__ O) {
    int nt = blockIdx.x, h = blockIdx.y, b = blockIdx.z;
    int n0 = nt * 128;
    __shared__ float vsh[160][64];
    __shared__ float kw[KER_];
    int tid = threadIdx.x;
    if (tid < KER_) kw[tid] = ker[h * KER_ + tid];
    const float* vb = v + ((size_t)b * H_ + h) * NTOK * DH_;
    #pragma unroll
    for (int i = 0; i < 10; i++) {
        int f4 = tid + i * 256;
        int row2 = f4 >> 4, c4 = f4 & 15;
        int n = n0 - 16 + row2;
        float4 val = make_float4(0.f, 0.f, 0.f, 0.f);
        if (n >= 0 && n < NTOK) val = ((const float4*)(vb + (size_t)n * DH_))[c4];
        ((float4*)vsh)[f4] = val;
    }
    __syncthreads();
    int dh = tid & 63, g = tid >> 6;
    for (int ii = 0; ii < 32; ii++) {
        int nn = g * 32 + ii;
        float o = 0.f;
        #pragma unroll
        for (int t = 0; t < KER_; t++) o += kw[t] * vsh[nn + t][dh];
        O[((size_t)b * NTOK + (n0 + nn)) * D_ + h * DH_ + dh] = o;
    }
}

// attn1 via MMA: O += softmax(q@kl^T)@Y
#define A1_SMEM 178176
__global__ void __launch_bounds__(256, 1) attn1_mma(
        const __nv_bfloat16* __restrict__ qh_, const __nv_bfloat16* __restrict__ qlo_,
        const __nv_bfloat16* __restrict__ klh_, const __nv_bfloat16* __restrict__ kll_,
        const __nv_bfloat16* __restrict__ yth_, const __nv_bfloat16* __restrict__ ytl_,
        float* __restrict__ O)
{
    extern __shared__ __align__(16) __nv_bfloat16 sm1[];
    uint32_t sb = smem_to_u32(sm1);
    int tid = threadIdx.x, wid = tid >> 5, lane = tid & 31;
    int bh = blockIdx.y;
    int tile0 = blockIdx.x * 128;
    {
        size_t qb = ((size_t)bh * NTOK + tile0) * DH_;
        #pragma unroll
        for (int i = 0; i < 4; i++) {
            int lin = tid + i * 256;
            int r = lin >> 3, c = lin & 7;
            *(uint4*)(sm1 + r * 72 + c * 8) = *(const uint4*)(qh_ + qb + r * 64 + c * 8);
            *(uint4*)(sm1 + 9216 + r * 72 + c * 8) = *(const uint4*)(qlo_ + qb + r * 64 + c * 8);
        }
        size_t kb = (size_t)bh * MLM * DH_;
        #pragma unroll
        for (int i = 0; i < 8; i++) {
            int lin = tid + i * 256;
            int r = lin >> 3, c = lin & 7;
            *(uint4*)(sm1 + 18432 + r * 72 + c * 8) = *(const uint4*)(klh_ + kb + r * 64 + c * 8);
            *(uint4*)(sm1 + 36864 + r * 72 + c * 8) = *(const uint4*)(kll_ + kb + r * 64 + c * 8);
        }
        size_t yb = (size_t)bh * 64 * MLM;
        #pragma unroll
        for (int i = 0; i < 8; i++) {
            int lin = tid + i * 256;
            int r = lin >> 5, c = lin & 31;
            *(uint4*)(sm1 + 55296 + r * 264 + c * 8) = *(const uint4*)(yth_ + yb + r * 256 + c * 8);
            *(uint4*)(sm1 + 72192 + r * 264 + c * 8) = *(const uint4*)(ytl_ + yb + r * 256 + c * 8);
        }
    }
    __syncthreads();
    uint32_t Ah[4][4], Al[4][4];
    {
        int row = wid * 16 + (lane & 15);
        #pragma unroll
        for (int ks = 0; ks < 4; ks++) {
            int col = ks * 16 + ((lane >> 4) << 3);
            ldsm4(Ah[ks], sb + (uint32_t)(row * 72 + col) * 2);
            ldsm4(Al[ks], sb + (uint32_t)(9216 + row * 72 + col) * 2);
        }
    }
    float Oacc[8][4];
    #pragma unroll
    for (int b = 0; b < 8; b++)
        #pragma unroll
        for (int c = 0; c < 4; c++) Oacc[b][c] = 0.f;
    float dlo = 0.f, dhi = 0.f;

    #pragma unroll
    for (int half = 0; half < 2; half++) {
        int lmb = half * 128;
        float S[16][4];
        #pragma unroll
        for (int b = 0; b < 16; b++)
            #pragma unroll
            for (int c = 0; c < 4; c++) S[b][c] = 0.f;
        #pragma unroll
        for (int ks = 0; ks < 4; ks++) {
            #pragma unroll
            for (int np = 0; np < 8; np++) {
                int row = lmb + np * 16 + ((lane >> 4) & 1) * 8 + (lane & 7);
                int col = ks * 16 + ((lane >> 3) & 1) * 8;
                uint32_t bh4[4], bl4[4];
                ldsm4(bh4, sb + (uint32_t)(18432 + row * 72 + col) * 2);
                ldsm4(bl4, sb + (uint32_t)(36864 + row * 72 + col) * 2);
                mma_bf16p(S[2*np],   Ah[ks], bh4[0], bh4[1]);
                mma_bf16p(S[2*np],   Ah[ks], bl4[0], bl4[1]);
                mma_bf16p(S[2*np],   Al[ks], bh4[0], bh4[1]);
                mma_bf16p(S[2*np+1], Ah[ks], bh4[2], bh4[3]);
                mma_bf16p(S[2*np+1], Ah[ks], bl4[2], bl4[3]);
                mma_bf16p(S[2*np+1], Al[ks], bh4[2], bh4[3]);
            }
        }
        #pragma unroll
        for (int kt = 0; kt < 8; kt++) {
            float e[8];
            #pragma unroll
            for (int j = 0; j < 4; j++) { e[j] = fexp(S[2*kt][j]); e[4+j] = fexp(S[2*kt+1][j]); }
            dlo += e[0] + e[1] + e[4] + e[5];
            dhi += e[2] + e[3] + e[6] + e[7];
            uint32_t pah[4], pal[4];
            #pragma unroll
            for (int j = 0; j < 4; j++) {
                __nv_bfloat162 h2 = __floats2bfloat162_rn(e[2*j], e[2*j+1]);
                pah[j] = *(uint32_t*)&h2;
                float r0 = e[2*j]   - __bfloat162float(__low2bfloat16(h2));
                float r1 = e[2*j+1] - __bfloat162float(__high2bfloat16(h2));
                __nv_bfloat162 l2 = __floats2bfloat162_rn(r0, r1);
                pal[j] = *(uint32_t*)&l2;
            }
            #pragma unroll
            for (int np = 0; np < 4; np++) {
                int row = np * 16 + ((lane >> 4) & 1) * 8 + (lane & 7);
                int col = lmb + kt * 16 + ((lane >> 3) & 1) * 8;
                uint32_t yh4[4], yl4[4];
                ldsm4(yh4, sb + (uint32_t)(55296 + row * 264 + col) * 2);
                ldsm4(yl4, sb + (uint32_t)(72192 + row * 264 + col) * 2);
                mma_bf16p(Oacc[2*np],   pah, yh4[0], yh4[1]);
                mma_bf16p(Oacc[2*np],   pah, yl4[0], yl4[1]);
                mma_bf16p(Oacc[2*np],   pal, yh4[0], yh4[1]);
                mma_bf16p(Oacc[2*np+1], pah, yh4[2], yh4[3]);
                mma_bf16p(Oacc[2*np+1], pah, yl4[2], yl4[3]);
                mma_bf16p(Oacc[2*np+1], pal, yh4[2], yh4[3]);
            }
        }
    }
    dlo += __shfl_xor_sync(0xffffffffu, dlo, 1);
    dlo += __shfl_xor_sync(0xffffffffu, dlo, 2);
    dhi += __shfl_xor_sync(0xffffffffu, dhi, 1);
    dhi += __shfl_xor_sync(0xffffffffu, dhi, 2);
    float ilo = 1.f / dlo, ihi = 1.f / dhi;
    int g = lane >> 2, t = lane & 3;
    int tok0 = tile0 + wid * 16 + g;
    int b = bh >> 3, h = bh & 7;
    size_t ob = ((size_t)b * NTOK + tok0) * D_ + h * DH_;
    #pragma unroll
    for (int nf = 0; nf < 8; nf++) {
        int c = nf * 8 + t * 2;
        float2* p0 = (float2*)&O[ob + c];
        float2 v0 = *p0;
        v0.x += Oacc[nf][0] * ilo; v0.y += Oacc[nf][1] * ilo;
        *p0 = v0;
        float2* p1 = (float2*)&O[ob + (size_t)8 * D_ + c];
        float2 v1 = *p1;
        v1.x += Oacc[nf][2] * ihi; v1.y += Oacc[nf][3] * ihi;
        *p1 = v1;
    }
}

__global__ void osplit_kernel(const float* __restrict__ O, __nv_bfloat16* __restrict__ hi,
                              __nv_bfloat16* __restrict__ lo) {
    size_t idx = (size_t)blockIdx.x * 256 + threadIdx.x;
    float v = O[idx];
    __nv_bfloat16 h = __float2bfloat16(v);
    hi[idx] = h;
    lo[idx] = __float2bfloat16(v - __bfloat162float(h));
}

extern "C" void kernel_launch(void* const* d_in, const int* in_sizes, int n_in,
                              void* d_out, int out_size) {
    const float* x      = (const float*)d_in[0];
    const float* gamma  = (const float*)d_in[1];
    const float* beta   = (const float*)d_in[2];
    const float* w_qkv  = (const float*)d_in[3];
    const float* res_k  = (const float*)d_in[4];
    const float* w_out  = (const float*)d_in[5];
    const float* b_out  = (const float*)d_in[6];
    float* out = (float*)d_out;

    __nv_bfloat16 *nh, *nl, *wqh, *wql, *woh, *wol, *Oh, *Ol, *Xh, *Xl;
    __nv_bfloat16 *Znh[2], *Znl[2], *Zth[2], *Ztl[2], *XZh, *XZl, *WtAh, *WtAl, *WtBh, *WtBl;
    __nv_bfloat16 *qbh, *qbl, *kbh, *kbl, *vth, *vtl, *qlh, *qll, *klh, *kll, *yth, *ytl;
    float *q, *k, *v, *ql, *kl, *X, *Zf, *A3V, *Y, *O, *Opart, *dpart;
    unsigned* mb;
    cudaGetSymbolAddress((void**)&nh, g_nh);
    cudaGetSymbolAddress((void**)&nl, g_nl);
    cudaGetSymbolAddress((void**)&wqh, g_wqh);
    cudaGetSymbolAddress((void**)&wql, g_wql);
    cudaGetSymbolAddress((void**)&woh, g_woh);
    cudaGetSymbolAddress((void**)&wol, g_wol);
    cudaGetSymbolAddress((void**)&Oh, g_Oh);
    cudaGetSymbolAddress((void**)&Ol, g_Ol);
    cudaGetSymbolAddress((void**)&Xh, g_Xh);
    cudaGetSymbolAddress((void**)&Xl, g_Xl);
    {
        __nv_bfloat16* p;
        cudaGetSymbolAddress((void**)&p, g_Znh); Znh[0] = p; Znh[1] = p + (size_t)BH*MLM*MLM;
        cudaGetSymbolAddress((void**)&p, g_Znl); Znl[0] = p; Znl[1] = p + (size_t)BH*MLM*MLM;
        cudaGetSymbolAddress((void**)&p, g_Zth); Zth[0] = p; Zth[1] = p + (size_t)BH*MLM*MLM;
        cudaGetSymbolAddress((void**)&p, g_Ztl); Ztl[0] = p; Ztl[1] = p + (size_t)BH*MLM*MLM;
    }
    cudaGetSymbolAddress((void**)&XZh, g_XZh);
    cudaGetSymbolAddress((void**)&XZl, g_XZl);
    cudaGetSymbolAddress((void**)&WtAh, g_WtAh);
    cudaGetSymbolAddress((void**)&WtAl, g_WtAl);
    cudaGetSymbolAddress((void**)&WtBh, g_WtBh);
    cudaGetSymbolAddress((void**)&WtBl, g_WtBl);
    cudaGetSymbolAddress((void**)&q,  g_q);
    cudaGetSymbolAddress((void**)&k,  g_k);
    cudaGetSymbolAddress((void**)&v,  g_v);
    cudaGetSymbolAddress((void**)&qbh, g_qbh);
    cudaGetSymbolAddress((void**)&qbl, g_qbl);
    cudaGetSymbolAddress((void**)&kbh, g_kbh);
    cudaGetSymbolAddress((void**)&kbl, g_kbl);
    cudaGetSymbolAddress((void**)&vth, g_vth);
    cudaGetSymbolAddress((void**)&vtl, g_vtl);
    cudaGetSymbolAddress((void**)&ql, g_ql);
    cudaGetSymbolAddress((void**)&kl, g_kl);
    cudaGetSymbolAddress((void**)&qlh, g_qlh);
    cudaGetSymbolAddress((void**)&qll, g_qll);
    cudaGetSymbolAddress((void**)&klh, g_klh);
    cudaGetSymbolAddress((void**)&kll, g_kll);
    cudaGetSymbolAddress((void**)&yth, g_yth);
    cudaGetSymbolAddress((void**)&ytl, g_ytl);
    cudaGetSymbolAddress((void**)&X,  g_X);
    cudaGetSymbolAddress((void**)&Zf, g_Zf);
    cudaGetSymbolAddress((void**)&Opart, g_Opart);
    cudaGetSymbolAddress((void**)&dpart, g_dpart);
    cudaGetSymbolAddress((void**)&A3V, g_A3V);
    cudaGetSymbolAddress((void**)&Y,  g_Y);
    cudaGetSymbolAddress((void**)&O,  g_O);
    cudaGetSymbolAddress((void**)&mb, g_maxbits);

    cudaFuncSetAttribute(attn2_kernel, cudaFuncAttributeMaxDynamicSharedMemorySize, ATTN2_SMEM);
    cudaFuncSetAttribute(tc_gemm<1>, cudaFuncAttributeMaxDynamicSharedMemorySize, TCG_SMEM);
    cudaFuncSetAttribute(tc_gemm<2>, cudaFuncAttributeMaxDynamicSharedMemorySize, TCG_SMEM);
    cudaFuncSetAttribute(attn3v_mma, cudaFuncAttributeMaxDynamicSharedMemorySize, A3_SMEM);
    cudaFuncSetAttribute(attn1_mma, cudaFuncAttributeMaxDynamicSharedMemorySize, A1_SMEM);

    const size_t sM = (size_t)MLM * MLM;

    ln_kernel<<<B_ * NTOK, 256>>>(x, gamma, beta, nh, nl);
    tsplit_kernel<<<(D_ * 3 * D_ + 255) / 256, 256>>>(w_qkv, wqh, wql, D_, 3 * D_);
    tsplit_kernel<<<(D_ * D_ + 255) / 256, 256>>>(w_out, woh, wol, D_, D_);

    // QKV, mode 0, fused q/k splits
    tc_gemm<2><<<dim3(12, 256, 1), 256, TCG_SMEM>>>(nh, nl, wqh, wql, D_, 0, 0, 0,
        q, k, v, nullptr, nullptr, nullptr,
        qbh, qbl, kbh, kbl, nullptr, 1.f, 0.f, 1.f);

    vtrans_kernel<<<dim3(NTOK / 64, BH), 256>>>(v, vth, vtl);

    landmark_kernel<<<dim3(BH, MLM), 64>>>(q, k, ql, kl);
    bsplit_kernel<<<512, 256>>>(ql, qlh, qll);
    bsplit_kernel<<<512, 256>>>(kl, klh, kll);

    attn2_kernel<<<dim3(BH, 8), 256, ATTN2_SMEM>>>(ql, kl, X, Xh, Xl);
    initmax_kernel<<<1, 1>>>(mb);
    rowcol_kernel<<<BH, 256>>>(X, mb);
    zinit_kernel<<<8192, 256>>>(X, mb, Znh[0], Znl[0], Zth[0], Ztl[0]);

    int cur = 0;
    for (int it = 0; it < 6; it++) {
        int nxt = cur ^ 1;
        if (it < 4) {
            tc_gemm<1><<<dim3(2, 2, BH), 256, TCG_SMEM>>>(Xh, Xl, Zth[cur], Ztl[cur], MLM, sM, sM, 2,
                nullptr, nullptr, nullptr, nullptr, nullptr, nullptr,
                XZh, XZl, WtAh, WtAl, nullptr, 1.f, 7.f, 1.f);
            tc_gemm<1><<<dim3(2, 2, BH), 256, TCG_SMEM>>>(XZh, XZl, WtAh, WtAl, MLM, sM, sM, 2,
                nullptr, nullptr, nullptr, nullptr, nullptr, nullptr,
                nullptr, nullptr, WtBh, WtBl, nullptr, 1.f, 15.f, 1.f);
            tc_gemm<1><<<dim3(2, 2, BH), 256, TCG_SMEM>>>(XZh, XZl, WtBh, WtBl, MLM, sM, sM, 2,
                nullptr, nullptr, nullptr, nullptr, nullptr, nullptr,
                nullptr, nullptr, WtAh, WtAl, nullptr, 1.f, 13.f, 1.f);
            tc_gemm<1><<<dim3(2, 2, BH), 256, TCG_SMEM>>>(Znh[cur], Znl[cur], WtAh, WtAl, MLM, sM, sM, 2,
                nullptr, nullptr, nullptr, nullptr, nullptr, nullptr,
                Znh[nxt], Znl[nxt], Zth[nxt], Ztl[nxt], nullptr, 0.25f, 0.f, -0.25f);
        } else {
            tc_gemm<2><<<dim3(2, 2, BH), 256, TCG_SMEM>>>(Xh, Xl, Zth[cur], Ztl[cur], MLM, sM, sM, 2,
                nullptr, nullptr, nullptr, nullptr, nullptr, nullptr,
                XZh, XZl, WtAh, WtAl, nullptr, 1.f, 7.f, 1.f);
            tc_gemm<2><<<dim3(2, 2, BH), 256, TCG_SMEM>>>(XZh, XZl, WtAh, WtAl, MLM, sM, sM, 2,
                nullptr, nullptr, nullptr, nullptr, nullptr, nullptr,
                nullptr, nullptr, WtBh, WtBl, nullptr, 1.f, 15.f, 1.f);
            tc_gemm<2><<<dim3(2, 2, BH), 256, TCG_SMEM>>>(XZh, XZl, WtBh, WtBl, MLM, sM, sM, 2,
                nullptr, nullptr, nullptr, nullptr, nullptr, nullptr,
                nullptr, nullptr, WtAh, WtAl, nullptr, 1.f, 13.f, 1.f);
            tc_gemm<2><<<dim3(2, 2, BH), 256, TCG_SMEM>>>(Znh[cur], Znl[cur], WtAh, WtAl, MLM, sM, sM, 2,
                nullptr, nullptr, nullptr, nullptr, nullptr, nullptr,
                Znh[nxt], Znl[nxt], Zth[nxt], Ztl[nxt], (it == 5) ? Zf : nullptr, 0.25f, 0.f, -0.25f);
        }
        cur = nxt;
    }

    attn3v_mma<<<dim3(NCHK, BH), 256, A3_SMEM>>>(qlh, qll, kbh, kbl, vth, vtl, Opart, dpart);
    a3v_reduce<<<2048, 256>>>(Opart, dpart, A3V);

    sgemm_kernel<<<dim3(1, 2, BH), 256>>>(Zf, A3V, Y, MLM, DH_, MLM,
        sM, (size_t)MLM * DH_, (size_t)MLM * DH_);
    ytrans_kernel<<<BH, 256>>>(Y, yth, ytl);

    conv_kernel<<<dim3(64, H_, B_), 256>>>(v, res_k, O);
    attn1_mma<<<dim3(NTOK / 128, BH), 256, A1_SMEM>>>(qbh, qbl, klh, kll, yth, ytl, O);

    osplit_kernel<<<(int)(((size_t)B_*NTOK*D_) / 256), 256>>>(O, Oh, Ol);
    // out-proj: mode 1 (K, strA=0, strB=0, mode=1)
    tc_gemm<2><<<dim3(4, 256, 1), 256, TCG_SMEM>>>(Oh, Ol, woh, wol, D_, 0, 0, 1,
        nullptr, nullptr, nullptr, out, b_out, x,
        nullptr, nullptr, nullptr, nullptr, nullptr, 1.f, 0.f, 1.f);
}

// round 10
// speedup vs baseline: 6.1206x; 1.0580x over previous
#include <cuda_runtime.h>
#include <cuda_bf16.h>
#include <math.h>
#include <stdint.h>

#define B_    4
#define NTOK  8192
#define D_    512
#define H_    8
#define DH_   64
#define MLM   256
#define LSEG  32
#define BH    (B_*H_)
#define KER_  33
#define NCHK  8

__device__ __forceinline__ uint32_t smem_to_u32(const void* p) {
    uint32_t a;
    asm("{ .reg .u64 t; cvta.to.shared.u64 t, %1; cvt.u32.u64 %0, t; }" : "=r"(a) : "l"(p));
    return a;
}
__device__ __forceinline__ void cp_async16(uint32_t saddr, const void* gptr) {
    asm volatile("cp.async.cg.shared.global [%0], [%1], 16;" :: "r"(saddr), "l"(gptr));
}
#define CP_COMMIT() asm volatile("cp.async.commit_group;" ::: "memory")
#define CP_WAIT0()  asm volatile("cp.async.wait_group 0;" ::: "memory")
__device__ __forceinline__ void mma_bf16p(float (&d)[4], const uint32_t (&a)[4], uint32_t b0, uint32_t b1) {
    asm volatile("mma.sync.aligned.m16n8k16.row.col.f32.bf16.bf16.f32 "
        "{%0,%1,%2,%3}, {%4,%5,%6,%7}, {%8,%9}, {%0,%1,%2,%3};"
        : "+f"(d[0]), "+f"(d[1]), "+f"(d[2]), "+f"(d[3])
        : "r"(a[0]), "r"(a[1]), "r"(a[2]), "r"(a[3]), "r"(b0), "r"(b1));
}
__device__ __forceinline__ void ldsm4(uint32_t (&r)[4], uint32_t a) {
    asm volatile("ldmatrix.sync.aligned.m8n8.x4.shared.b16 {%0,%1,%2,%3}, [%4];"
        : "=r"(r[0]), "=r"(r[1]), "=r"(r[2]), "=r"(r[3]) : "r"(a));
}
__device__ __forceinline__ float fexp(float s) {
    float t = s * 1.44269504088896341f;
    float i = rintf(t);
    float f = t - i;
    float p = 1.54035303933816e-4f;
    p = p * f + 1.33335581464284e-3f;
    p = p * f + 9.61812910762848e-3f;
    p = p * f + 5.55041086648216e-2f;
    p = p * f + 2.40226506959101e-1f;
    p = p * f + 6.93147180559945e-1f;
    p = p * f + 1.0f;
    return p * __int_as_float(((int)i + 127) << 23);
}

// scratch
__device__ __nv_bfloat16 g_nh[(size_t)B_*NTOK*D_];
__device__ __nv_bfloat16 g_nl[(size_t)B_*NTOK*D_];
__device__ __nv_bfloat16 g_wqh[(size_t)3*D_*D_];
__device__ __nv_bfloat16 g_wql[(size_t)3*D_*D_];
__device__ __nv_bfloat16 g_woh[(size_t)D_*D_];
__device__ __nv_bfloat16 g_wol[(size_t)D_*D_];
__device__ __nv_bfloat16 g_Oh[(size_t)B_*NTOK*D_];
__device__ __nv_bfloat16 g_Ol[(size_t)B_*NTOK*D_];
__device__ float g_q [(size_t)BH*NTOK*DH_];
__device__ float g_k [(size_t)BH*NTOK*DH_];
__device__ float g_v [(size_t)BH*NTOK*DH_];
__device__ __nv_bfloat16 g_qbh[(size_t)BH*NTOK*DH_];
__device__ __nv_bfloat16 g_qbl[(size_t)BH*NTOK*DH_];
__device__ __nv_bfloat16 g_kbh[(size_t)BH*NTOK*DH_];
__device__ __nv_bfloat16 g_kbl[(size_t)BH*NTOK*DH_];
__device__ __nv_bfloat16 g_vth[(size_t)BH*NTOK*DH_];
__device__ __nv_bfloat16 g_vtl[(size_t)BH*NTOK*DH_];
__device__ float g_ql[(size_t)BH*MLM*DH_];
__device__ float g_kl[(size_t)BH*MLM*DH_];
__device__ __nv_bfloat16 g_qlh[(size_t)BH*MLM*DH_];
__device__ __nv_bfloat16 g_qll[(size_t)BH*MLM*DH_];
__device__ __nv_bfloat16 g_klh[(size_t)BH*MLM*DH_];
__device__ __nv_bfloat16 g_kll[(size_t)BH*MLM*DH_];
__device__ __nv_bfloat16 g_yth[(size_t)BH*MLM*DH_];
__device__ __nv_bfloat16 g_ytl[(size_t)BH*MLM*DH_];
__device__ float g_X [(size_t)BH*MLM*MLM];
__device__ __nv_bfloat16 g_Xh[(size_t)BH*MLM*MLM];
__device__ __nv_bfloat16 g_Xl[(size_t)BH*MLM*MLM];
__device__ __nv_bfloat16 g_Znh[2][(size_t)BH*MLM*MLM];
__device__ __nv_bfloat16 g_Znl[2][(size_t)BH*MLM*MLM];
__device__ __nv_bfloat16 g_Zth[2][(size_t)BH*MLM*MLM];
__device__ __nv_bfloat16 g_Ztl[2][(size_t)BH*MLM*MLM];
__device__ __nv_bfloat16 g_XZh[(size_t)BH*MLM*MLM];
__device__ __nv_bfloat16 g_XZl[(size_t)BH*MLM*MLM];
__device__ __nv_bfloat16 g_WtAh[(size_t)BH*MLM*MLM];
__device__ __nv_bfloat16 g_WtAl[(size_t)BH*MLM*MLM];
__device__ __nv_bfloat16 g_WtBh[(size_t)BH*MLM*MLM];
__device__ __nv_bfloat16 g_WtBl[(size_t)BH*MLM*MLM];
__device__ float g_Zf[(size_t)BH*MLM*MLM];
__device__ float g_Opart[(size_t)NCHK*BH*MLM*DH_];
__device__ float g_dpart[(size_t)NCHK*BH*MLM];
__device__ float g_A3V[(size_t)BH*MLM*DH_];
__device__ float g_Y  [(size_t)BH*MLM*DH_];
__device__ float g_O  [(size_t)B_*NTOK*D_];
__device__ unsigned g_maxbits[2];

__global__ void ln_kernel(const float* __restrict__ x, const float* __restrict__ gamma,
                          const float* __restrict__ beta,
                          __nv_bfloat16* __restrict__ ohi, __nv_bfloat16* __restrict__ olo) {
    int row = blockIdx.x, tid = threadIdx.x;
    const float* xr = x + (size_t)row * D_;
    float v0 = xr[tid], v1 = xr[tid + 256];
    float s = v0 + v1, s2 = v0*v0 + v1*v1;
    #pragma unroll
    for (int o = 16; o > 0; o >>= 1) {
        s  += __shfl_xor_sync(0xffffffffu, s,  o);
        s2 += __shfl_xor_sync(0xffffffffu, s2, o);
    }
    __shared__ float sh[16];
    int w = tid >> 5;
    if ((tid & 31) == 0) { sh[w] = s; sh[w + 8] = s2; }
    __syncthreads();
    if (tid == 0) {
        float a = 0.f, b2 = 0.f;
        #pragma unroll
        for (int i = 0; i < 8; i++) { a += sh[i]; b2 += sh[i + 8]; }
        sh[0] = a; sh[8] = b2;
    }
    __syncthreads();
    float mu  = sh[0] * (1.f / D_);
    float var = sh[8] * (1.f / D_) - mu * mu;
    float inv = rsqrtf(var + 1e-5f);
    size_t base = (size_t)row * D_;
    #pragma unroll
    for (int half = 0; half < 2; half++) {
        int c = tid + half * 256;
        float v = (half == 0 ? v0 : v1);
        float nv = (v - mu) * inv * gamma[c] + beta[c];
        __nv_bfloat16 hi = __float2bfloat16(nv);
        ohi[base + c] = hi;
        olo[base + c] = __float2bfloat16(nv - __bfloat162float(hi));
    }
}

__global__ void tsplit_kernel(const float* __restrict__ W, __nv_bfloat16* __restrict__ Thi,
                              __nv_bfloat16* __restrict__ Tlo, int K, int N) {
    int idx = blockIdx.x * 256 + threadIdx.x;
    if (idx >= K * N) return;
    int k = idx / N, n = idx % N;
    float v = W[idx];
    __nv_bfloat16 hi = __float2bfloat16(v);
    Thi[(size_t)n * K + k] = hi;
    Tlo[(size_t)n * K + k] = __float2bfloat16(v - __bfloat162float(hi));
}
__global__ void bsplit_kernel(const float* __restrict__ s, __nv_bfloat16* __restrict__ h,
                              __nv_bfloat16* __restrict__ l) {
    size_t i = ((size_t)blockIdx.x * 256 + threadIdx.x) * 4;
    float4 v = *(const float4*)(s + i);
    __nv_bfloat16 hh[4], ll[4];
    float vv[4] = {v.x, v.y, v.z, v.w};
    #pragma unroll
    for (int t = 0; t < 4; t++) {
        hh[t] = __float2bfloat16(vv[t]);
        ll[t] = __float2bfloat16(vv[t] - __bfloat162float(hh[t]));
    }
    *(uint2*)(h + i) = *(uint2*)hh;
    *(uint2*)(l + i) = *(uint2*)ll;
}
__global__ void vtrans_kernel(const float* __restrict__ v, __nv_bfloat16* __restrict__ vth,
                              __nv_bfloat16* __restrict__ vtl) {
    __shared__ float ts[64][68];
    int bh = blockIdx.y, k0 = blockIdx.x * 64;
    int tid = threadIdx.x;
    const float* vb = v + ((size_t)bh * NTOK + k0) * DH_;
    #pragma unroll
    for (int i = 0; i < 4; i++) {
        int lin = tid + i * 256;
        int r = lin >> 4, c4 = lin & 15;
        *(float4*)&ts[r][c4 * 4] = *(const float4*)(vb + r * 64 + c4 * 4);
    }
    __syncthreads();
    #pragma unroll
    for (int i = 0; i < 16; i++) {
        int lin = tid + i * 256;
        int dh = lin >> 6, ky = lin & 63;
        float val = ts[ky][dh];
        __nv_bfloat16 h = __float2bfloat16(val);
        size_t o = ((size_t)bh * 64 + dh) * NTOK + k0 + ky;
        vth[o] = h;
        vtl[o] = __float2bfloat16(val - __bfloat162float(h));
    }
}
__global__ void ytrans_kernel(const float* __restrict__ Y, __nv_bfloat16* __restrict__ yth,
                              __nv_bfloat16* __restrict__ ytl) {
    int bh = blockIdx.x, tid = threadIdx.x;
    #pragma unroll
    for (int i = 0; i < 64; i++) {
        int lin = tid + i * 256;
        int dh = lin >> 8, lm = lin & 255;
        float val = Y[(size_t)bh * 16384 + lm * 64 + dh];
        __nv_bfloat16 h = __float2bfloat16(val);
        size_t o = (size_t)bh * 16384 + dh * 256 + lm;
        yth[o] = h;
        ytl[o] = __float2bfloat16(val - __bfloat162float(h));
    }
}

// bf16-split MMA GEMM, cp.async double-buffered, NPASS compile-time, 2 CTAs/SM.
#define TCG_SMEM (2 * 4 * 5120 * 2)
template<int NPASS>
__global__ void __launch_bounds__(256, 2) tc_gemm(
        const __nv_bfloat16* __restrict__ Ahi, const __nv_bfloat16* __restrict__ Alo,
        const __nv_bfloat16* __restrict__ Bhi, const __nv_bfloat16* __restrict__ Blo,
        int K, size_t strA, size_t strB, int mode,
        float* __restrict__ qp, float* __restrict__ kp, float* __restrict__ vp,
        float* __restrict__ Cout, const float* __restrict__ bias, const float* __restrict__ addx,
        __nv_bfloat16* __restrict__ Nhi, __nv_bfloat16* __restrict__ Nlo,
        __nv_bfloat16* __restrict__ Thi, __nv_bfloat16* __restrict__ Tlo,
        float* __restrict__ Cf32, float alpha, float diagc, float beta)
{
    extern __shared__ __align__(16) char smem[];
    uint32_t sbase = smem_to_u32(smem);
    int tid = threadIdx.x;
    int wid = tid >> 5, lane = tid & 31;
    int wm = (wid & 3) * 32, wn = (wid >> 2) * 64;
    int bz = blockIdx.z;
    int m0 = blockIdx.y * 128, n0 = blockIdx.x * 128;
    size_t oz = (size_t)bz * 65536;
    Ahi += (size_t)bz * strA; Alo += (size_t)bz * strA;
    Bhi += (size_t)bz * strB; Blo += (size_t)bz * strB;
    const __nv_bfloat16* srcs[4] = {Ahi, Alo, Bhi, Blo};
    const int row0s[4] = {m0, m0, n0, n0};
    const int NB = (NPASS == 1) ? 2 : 4;

    float acc[2][8][4];
    #pragma unroll
    for (int a = 0; a < 2; a++)
        #pragma unroll
        for (int b = 0; b < 8; b++)
            #pragma unroll
            for (int c = 0; c < 4; c++) acc[a][b][c] = 0.f;

    int r_ld = tid >> 2, c_ld = tid & 3;
    int nch = K >> 5;

    // issue chunk 0
    #pragma unroll
    for (int bs = 0; bs < NB; bs++) {
        int bsel = (NPASS == 1) ? bs * 2 : bs;
        #pragma unroll
        for (int i = 0; i < 2; i++)
            cp_async16(sbase + (uint32_t)(bsel * 5120 + (r_ld + i * 64) * 40 + c_ld * 8) * 2,
                       srcs[bsel] + (size_t)(row0s[bsel] + r_ld + i * 64) * K + c_ld * 8);
    }
    CP_COMMIT();

    for (int ch = 0; ch < nch; ch++) {
        CP_WAIT0();
        __syncthreads();
        if (ch + 1 < nch) {
            int k0 = (ch + 1) << 5;
            uint32_t nxt_off = (uint32_t)((ch + 1) & 1) * 4 * 5120;
            #pragma unroll
            for (int bs = 0; bs < NB; bs++) {
                int bsel = (NPASS == 1) ? bs * 2 : bs;
                #pragma unroll
                for (int i = 0; i < 2; i++)
                    cp_async16(sbase + (uint32_t)(nxt_off + bsel * 5120 + (r_ld + i * 64) * 40 + c_ld * 8) * 2,
                               srcs[bsel] + (size_t)(row0s[bsel] + r_ld + i * 64) * K + k0 + c_ld * 8);
            }
            CP_COMMIT();
        }
        uint32_t stg_off = (uint32_t)(ch & 1) * 4 * 5120;
        #pragma unroll
        for (int ks = 0; ks < 32; ks += 16) {
            uint32_t Ah[2][4], Al[2][4];
            #pragma unroll
            for (int mf = 0; mf < 2; mf++) {
                int row = wm + mf * 16 + (lane & 15);
                int col = ks + ((lane >> 4) << 3);
                ldsm4(Ah[mf], sbase + (uint32_t)(stg_off + row * 40 + col) * 2);
                if (NPASS > 1) ldsm4(Al[mf], sbase + (uint32_t)(stg_off + 5120 + row * 40 + col) * 2);
            }
            #pragma unroll
            for (int p = 0; p < 4; p++) {
                int rowb = wn + (2 * p + (lane >> 4)) * 8 + (lane & 7);
                int colb = ks + ((lane >> 3) & 1) * 8;
                uint32_t Bh4[4], Bl4[4];
                ldsm4(Bh4, sbase + (uint32_t)(stg_off + 2 * 5120 + rowb * 40 + colb) * 2);
                if (NPASS > 1) ldsm4(Bl4, sbase + (uint32_t)(stg_off + 3 * 5120 + rowb * 40 + colb) * 2);
                #pragma unroll
                for (int mf = 0; mf < 2; mf++) {
                    mma_bf16p(acc[mf][2*p],   Ah[mf], Bh4[0], Bh4[1]);
                    mma_bf16p(acc[mf][2*p+1], Ah[mf], Bh4[2], Bh4[3]);
                    if (NPASS > 1) {
                        mma_bf16p(acc[mf][2*p],   Ah[mf], Bl4[0], Bl4[1]);
                        mma_bf16p(acc[mf][2*p+1], Ah[mf], Bl4[2], Bl4[3]);
                        mma_bf16p(acc[mf][2*p],   Al[mf], Bh4[0], Bh4[1]);
                        mma_bf16p(acc[mf][2*p+1], Al[mf], Bh4[2], Bh4[3]);
                    }
                }
            }
        }
    }
    __syncthreads();

    float* stg = reinterpret_cast<float*>(smem);
    {
        int r = lane >> 2, c = (lane & 3) * 2;
        #pragma unroll
        for (int mf = 0; mf < 2; mf++)
            #pragma unroll
            for (int nf = 0; nf < 8; nf++) {
                int rr = wm + mf * 16 + r, cc = wn + nf * 8 + c;
                *reinterpret_cast<float2*>(&stg[rr * 132 + cc]) = make_float2(acc[mf][nf][0], acc[mf][nf][1]);
                *reinterpret_cast<float2*>(&stg[(rr + 8) * 132 + cc]) = make_float2(acc[mf][nf][2], acc[mf][nf][3]);
            }
    }
    __syncthreads();

    if (mode == 0) {
        #pragma unroll 4
        for (int i = 0; i < 16; i++) {
            int lin = tid + (i << 8);
            int token = lin >> 5, c4 = lin & 31;
            int gn = n0 + (c4 << 2);
            float4 v = *reinterpret_cast<float4*>(&stg[token * 132 + (c4 << 2)]);
            int gmm = m0 + token;
            int b_ = gmm >> 13, n_ = gmm & 8191;
            int sec = gn >> 9, cc = gn & 511, h_ = cc >> 6, dh = cc & 63;
            size_t idx = ((((size_t)b_ * H_ + h_) * NTOK) + n_) * DH_ + dh;
            if (sec == 2) {
                *reinterpret_cast<float4*>(&vp[idx]) = v;
            } else {
                if (sec == 0) { v.x *= 0.125f; v.y *= 0.125f; v.z *= 0.125f; v.w *= 0.125f; }
                float* fp = (sec == 0) ? qp : kp;
                __nv_bfloat16* hp = (sec == 0) ? Nhi : Thi;
                __nv_bfloat16* lp = (sec == 0) ? Nlo : Tlo;
                *reinterpret_cast<float4*>(&fp[idx]) = v;
                float vv[4] = {v.x, v.y, v.z, v.w};
                __nv_bfloat16 hb[4], lb[4];
                #pragma unroll
                for (int t2 = 0; t2 < 4; t2++) {
                    hb[t2] = __float2bfloat16(vv[t2]);
                    lb[t2] = __float2bfloat16(vv[t2] - __bfloat162float(hb[t2]));
                }
                *reinterpret_cast<uint2*>(&hp[idx]) = *reinterpret_cast<uint2*>(hb);
                *reinterpret_cast<uint2*>(&lp[idx]) = *reinterpret_cast<uint2*>(lb);
            }
        }
    } else if (mode == 1) {
        #pragma unroll 4
        for (int i = 0; i < 16; i++) {
            int lin = tid + (i << 8);
            int token = lin >> 5, c4 = lin & 31;
            int gn = n0 + (c4 << 2);
            int gmm = m0 + token;
            float4 v = *reinterpret_cast<float4*>(&stg[token * 132 + (c4 << 2)]);
            float4 bb = *reinterpret_cast<const float4*>(&bias[gn]);
            float4 xx = *reinterpret_cast<const float4*>(&addx[(size_t)gmm * 512 + gn]);
            v.x += bb.x + xx.x; v.y += bb.y + xx.y; v.z += bb.z + xx.z; v.w += bb.w + xx.w;
            *reinterpret_cast<float4*>(&Cout[(size_t)gmm * 512 + gn]) = v;
        }
    } else {
        if (Thi) {
            #pragma unroll 4
            for (int i = 0; i < 64; i++) {
                int idx = tid + (i << 8);
                int gn_l = idx >> 7, gm_l = idx & 127;
                int gmm = m0 + gm_l, gn = n0 + gn_l;
                float v = stg[gm_l * 132 + gn_l];
                float t = (gmm == gn ? diagc : 0.f) - beta * v;
                __nv_bfloat16 h = __float2bfloat16(t);
                Thi[oz + (size_t)gn * 256 + gmm] = h;
                Tlo[oz + (size_t)gn * 256 + gmm] = __float2bfloat16(t - __bfloat162float(h));
            }
        }
        if (Nhi) {
            #pragma unroll 4
            for (int i = 0; i < 16; i++) {
                int lin = tid + (i << 8);
                int token = lin >> 5, c4 = lin & 31;
                int gn = n0 + (c4 << 2);
                int gmm = m0 + token;
                float4 v = *reinterpret_cast<float4*>(&stg[token * 132 + (c4 << 2)]);
                float vv[4] = {v.x * alpha, v.y * alpha, v.z * alpha, v.w * alpha};
                __nv_bfloat16 h[4], l2[4];
                #pragma unroll
                for (int t2 = 0; t2 < 4; t2++) {
                    h[t2] = __float2bfloat16(vv[t2]);
                    l2[t2] = __float2bfloat16(vv[t2] - __bfloat162float(h[t2]));
                }
                *reinterpret_cast<uint2*>(&Nhi[oz + (size_t)gmm * 256 + gn]) = *reinterpret_cast<uint2*>(h);
                *reinterpret_cast<uint2*>(&Nlo[oz + (size_t)gmm * 256 + gn]) = *reinterpret_cast<uint2*>(l2);
            }
        }
        if (Cf32) {
            #pragma unroll 4
            for (int i = 0; i < 16; i++) {
                int lin = tid + (i << 8);
                int token = lin >> 5, c4 = lin & 31;
                int gn = n0 + (c4 << 2);
                int gmm = m0 + token;
                float4 v = *reinterpret_cast<float4*>(&stg[token * 132 + (c4 << 2)]);
                v.x *= alpha; v.y *= alpha; v.z *= alpha; v.w *= alpha;
                *reinterpret_cast<float4*>(&Cf32[oz + (size_t)gmm * 256 + gn]) = v;
            }
        }
    }
}

// SIMT SGEMM for Y = Zf @ A3V
__global__ void __launch_bounds__(256) sgemm_kernel(
        const float* __restrict__ A, const float* __restrict__ B, float* __restrict__ C,
        int M, int N, int K, size_t sA, size_t sB, size_t sC)
{
    int bz = blockIdx.z;
    A += (size_t)bz * sA; B += (size_t)bz * sB; C += (size_t)bz * sC;
    int m0 = blockIdx.y * 128, n0 = blockIdx.x * 128;
    __shared__ float As[8][128];
    __shared__ float Bs[8][128];
    int tid = threadIdx.x;
    int tx = tid & 15, ty = tid >> 4;
    float acc[8][8];
    #pragma unroll
    for (int i = 0; i < 8; i++)
        #pragma unroll
        for (int j = 0; j < 8; j++) acc[i][j] = 0.f;
    for (int k0 = 0; k0 < K; k0 += 8) {
        #pragma unroll
        for (int i = 0; i < 4; i++) {
            int lin = tid + i * 256;
            int kk = lin & 7, mm = lin >> 3;
            int gmm = m0 + mm, gk = k0 + kk;
            As[kk][mm] = (gmm < M && gk < K) ? A[(size_t)gmm * K + gk] : 0.f;
        }
        #pragma unroll
        for (int i = 0; i < 4; i++) {
            int lin = tid + i * 256;
            int nn = lin & 127, kk = lin >> 7;
            int gn = n0 + nn, gk = k0 + kk;
            Bs[kk][nn] = (gn < N && gk < K) ? B[(size_t)gk * N + gn] : 0.f;
        }
        __syncthreads();
        #pragma unroll
        for (int kk = 0; kk < 8; kk++) {
            float a[8], b[8];
            *(float4*)&a[0] = *(const float4*)&As[kk][ty * 8];
            *(float4*)&a[4] = *(const float4*)&As[kk][ty * 8 + 4];
            *(float4*)&b[0] = *(const float4*)&Bs[kk][tx * 8];
            *(float4*)&b[4] = *(const float4*)&Bs[kk][tx * 8 + 4];
            #pragma unroll
            for (int i = 0; i < 8; i++)
                #pragma unroll
                for (int j = 0; j < 8; j++) acc[i][j] += a[i] * b[j];
        }
        __syncthreads();
    }
    #pragma unroll
    for (int i = 0; i < 8; i++) {
        int gmm = m0 + ty * 8 + i;
        if (gmm >= M) continue;
        #pragma unroll
        for (int j = 0; j < 8; j++) {
            int gn = n0 + tx * 8 + j;
            if (gn >= N) continue;
            C[(size_t)gmm * N + gn] = acc[i][j];
        }
    }
}

__global__ void landmark_kernel(const float* __restrict__ q, const float* __restrict__ k,
                                float* __restrict__ ql, float* __restrict__ kl) {
    int bh = blockIdx.x, m = blockIdx.y;
    int dh = threadIdx.x;
    size_t base = ((size_t)bh * NTOK + (size_t)m * LSEG) * DH_ + dh;
    float aq = 0.f, ak = 0.f;
    #pragma unroll
    for (int i = 0; i < LSEG; i++) {
        aq += q[base + (size_t)i * DH_];
        ak += k[base + (size_t)i * DH_];
    }
    size_t o = ((size_t)bh * MLM + m) * DH_ + dh;
    ql[o] = aq * (1.f / LSEG);
    kl[o] = ak * (1.f / LSEG);
}

#define ATTN2_SMEM ((256 * 68 + 32 * 64 + 8) * 4)
__global__ void attn2_kernel(const float* __restrict__ ql, const float* __restrict__ kl,
                             float* __restrict__ X,
                             __nv_bfloat16* __restrict__ Xh, __nv_bfloat16* __restrict__ Xl) {
    extern __shared__ __align__(16) float sh2[];
    float* kls  = sh2;
    float* qs   = sh2 + 256 * 68;
    float* wsum = qs + 32 * 64;
    int bh = blockIdx.x, mt = blockIdx.y;
    int tid = threadIdx.x;
    #pragma unroll
    for (int i = 0; i < 16; i++) {
        int lin = tid + i * 256;
        int r = lin >> 4, c = lin & 15;
        *(float4*)&kls[r * 68 + c * 4] = *(const float4*)&kl[((size_t)bh * MLM + r) * DH_ + c * 4];
    }
    #pragma unroll
    for (int i = 0; i < 2; i++) {
        int lin = tid + i * 256;
        int r = lin >> 4, c = lin & 15;
        *(float4*)&qs[r * 64 + c * 4] = *(const float4*)&ql[((size_t)bh * MLM + mt * 32 + r) * DH_ + c * 4];
    }
    __syncthreads();
    int j = tid, wid = tid >> 5, lane = tid & 31;
    const float* kr = &kls[j * 68];
    for (int ml = 0; ml < 32; ml++) {
        const float* qr = &qs[ml * 64];
        float a0 = 0.f, a1 = 0.f, a2 = 0.f, a3 = 0.f;
        #pragma unroll
        for (int d4 = 0; d4 < 16; d4++) {
            float4 kv = *(const float4*)&kr[d4 * 4];
            float4 qv = *(const float4*)&qr[d4 * 4];
            a0 += qv.x * kv.x; a1 += qv.y * kv.y; a2 += qv.z * kv.z; a3 += qv.w * kv.w;
        }
        float e = fexp(a0 + a1 + a2 + a3);
        float t = e;
        #pragma unroll
        for (int o = 16; o > 0; o >>= 1) t += __shfl_xor_sync(0xffffffffu, t, o);
        if (lane == 0) wsum[wid] = t;
        __syncthreads();
        float S = 0.f;
        #pragma unroll
        for (int w = 0; w < 8; w++) S += wsum[w];
        float val = e * (1.f / S);
        size_t o = ((size_t)bh * MLM + mt * 32 + ml) * MLM + j;
        X[o] = val;
        __nv_bfloat16 h = __float2bfloat16(val);
        Xh[o] = h;
        Xl[o] = __float2bfloat16(val - __bfloat162float(h));
        __syncthreads();
    }
}

__global__ void initmax_kernel(unsigned* mb) { mb[0] = 0u; mb[1] = 0u; }
__global__ void rowcol_kernel(const float* __restrict__ X, unsigned* mb) {
    int bh = blockIdx.x, i = threadIdx.x;
    const float* Xm = X + (size_t)bh * MLM * MLM;
    float rs = 0.f, cs = 0.f;
    for (int j = 0; j < MLM; j++) {
        rs += fabsf(Xm[(size_t)i * MLM + j]);
        cs += fabsf(Xm[(size_t)j * MLM + i]);
    }
    #pragma unroll
    for (int o = 16; o > 0; o >>= 1) {
        rs = fmaxf(rs, __shfl_xor_sync(0xffffffffu, rs, o));
        cs = fmaxf(cs, __shfl_xor_sync(0xffffffffu, cs, o));
    }
    __shared__ float shr[8], shc[8];
    int w = i >> 5;
    if ((i & 31) == 0) { shr[w] = rs; shc[w] = cs; }
    __syncthreads();
    if (i == 0) {
        float mr = shr[0], mc = shc[0];
        #pragma unroll
        for (int k2 = 1; k2 < 8; k2++) { mr = fmaxf(mr, shr[k2]); mc = fmaxf(mc, shc[k2]); }
        atomicMax(&mb[0], __float_as_uint(mr));
        atomicMax(&mb[1], __float_as_uint(mc));
    }
}
__global__ void zinit_kernel(const float* __restrict__ X, const unsigned* __restrict__ mb,
                             __nv_bfloat16* __restrict__ Znh, __nv_bfloat16* __restrict__ Znl,
                             __nv_bfloat16* __restrict__ Zth, __nv_bfloat16* __restrict__ Ztl) {
    float inv = 1.f / (__uint_as_float(mb[0]) * __uint_as_float(mb[1]));
    size_t idx = (size_t)blockIdx.x * 256 + threadIdx.x;
    int bh = (int)(idx >> 16);
    int r = (int)((idx >> 8) & 255);
    int c = (int)(idx & 255);
    float tv = X[idx] * inv;
    __nv_bfloat16 th = __float2bfloat16(tv);
    Zth[idx] = th; Ztl[idx] = __float2bfloat16(tv - __bfloat162float(th));
    float nv = X[((size_t)bh << 16) + ((size_t)c << 8) + r] * inv;
    __nv_bfloat16 nh = __float2bfloat16(nv);
    Znh[idx] = nh; Znl[idx] = __float2bfloat16(nv - __bfloat162float(nh));
}

// attn3@v via MMA
#define A3_SMEM 93184
__global__ void __launch_bounds__(256, 1) attn3v_mma(
        const __nv_bfloat16* __restrict__ qlh_, const __nv_bfloat16* __restrict__ qll_,
        const __nv_bfloat16* __restrict__ kh_, const __nv_bfloat16* __restrict__ klo_,
        const __nv_bfloat16* __restrict__ vth_, const __nv_bfloat16* __restrict__ vtl_,
        float* __restrict__ Opart, float* __restrict__ denpart)
{
    extern __shared__ __align__(16) __nv_bfloat16 sm3[];
    uint32_t sb = smem_to_u32(sm3);
    int tid = threadIdx.x, wid = tid >> 5, lane = tid & 31;
    int chunk = blockIdx.x, bh = blockIdx.y;
    int key0 = chunk * (NTOK / NCHK);
    {
        size_t qb = (size_t)bh * MLM * DH_;
        #pragma unroll
        for (int i = 0; i < 8; i++) {
            int lin = tid + i * 256;
            int r = lin >> 3, c = lin & 7;
            *(uint4*)(sm3 + r * 72 + c * 8) = *(const uint4*)(qlh_ + qb + r * 64 + c * 8);
            *(uint4*)(sm3 + 18432 + r * 72 + c * 8) = *(const uint4*)(qll_ + qb + r * 64 + c * 8);
        }
    }
    __syncthreads();
    uint32_t Ah[2][4][4], Al[2][4][4];
    #pragma unroll
    for (int mf = 0; mf < 2; mf++) {
        int row = wid * 32 + mf * 16 + (lane & 15);
        #pragma unroll
        for (int ks = 0; ks < 4; ks++) {
            int col = ks * 16 + ((lane >> 4) << 3);
            ldsm4(Ah[mf][ks], sb + (uint32_t)(row * 72 + col) * 2);
            ldsm4(Al[mf][ks], sb + (uint32_t)(18432 + row * 72 + col) * 2);
        }
    }
    float Oacc[2][8][4];
    #pragma unroll
    for (int a = 0; a < 2; a++)
        #pragma unroll
        for (int b = 0; b < 8; b++)
            #pragma unroll
            for (int c = 0; c < 4; c++) Oacc[a][b][c] = 0.f;
    float den[2][2] = {{0.f, 0.f}, {0.f, 0.f}};

    for (int t32 = 0; t32 < (NTOK / NCHK) / 32; t32++) {
        int kt0 = key0 + t32 * 32;
        __syncthreads();
        {
            int r = tid >> 3, c = tid & 7;
            *(uint4*)(sm3 + 36864 + r * 72 + c * 8) = *(const uint4*)(kh_ + ((size_t)bh * NTOK + kt0 + r) * 64 + c * 8);
            *(uint4*)(sm3 + 39168 + r * 72 + c * 8) = *(const uint4*)(klo_ + ((size_t)bh * NTOK + kt0 + r) * 64 + c * 8);
            int r2 = tid >> 2, c2 = tid & 3;
            *(uint4*)(sm3 + 41472 + r2 * 40 + c2 * 8) = *(const uint4*)(vth_ + ((size_t)bh * 64 + r2) * NTOK + kt0 + c2 * 8);
            *(uint4*)(sm3 + 44032 + r2 * 40 + c2 * 8) = *(const uint4*)(vtl_ + ((size_t)bh * 64 + r2) * NTOK + kt0 + c2 * 8);
        }
        __syncthreads();
        float S[2][4][4];
        #pragma unroll
        for (int a = 0; a < 2; a++)
            #pragma unroll
            for (int b = 0; b < 4; b++)
                #pragma unroll
                for (int c = 0; c < 4; c++) S[a][b][c] = 0.f;
        #pragma unroll
        for (int ks = 0; ks < 4; ks++) {
            #pragma unroll
            for (int np = 0; np < 2; np++) {
                int row = np * 16 + ((lane >> 4) & 1) * 8 + (lane & 7);
                int col = ks * 16 + ((lane >> 3) & 1) * 8;
                uint32_t bh4[4], bl4[4];
                ldsm4(bh4, sb + (uint32_t)(36864 + row * 72 + col) * 2);
                ldsm4(bl4, sb + (uint32_t)(39168 + row * 72 + col) * 2);
                #pragma unroll
                for (int mf = 0; mf < 2; mf++) {
                    mma_bf16p(S[mf][2*np],   Ah[mf][ks], bh4[0], bh4[1]);
                    mma_bf16p(S[mf][2*np],   Ah[mf][ks], bl4[0], bl4[1]);
                    mma_bf16p(S[mf][2*np],   Al[mf][ks], bh4[0], bh4[1]);
                    mma_bf16p(S[mf][2*np+1], Ah[mf][ks], bh4[2], bh4[3]);
                    mma_bf16p(S[mf][2*np+1], Ah[mf][ks], bl4[2], bl4[3]);
                    mma_bf16p(S[mf][2*np+1], Al[mf][ks], bh4[2], bh4[3]);
                }
            }
        }
        #pragma unroll
        for (int kt = 0; kt < 2; kt++) {
            uint32_t pah[2][4], pal[2][4];
            #pragma unroll
            for (int mf = 0; mf < 2; mf++) {
                float e[8];
                #pragma unroll
                for (int j = 0; j < 4; j++) { e[j] = fexp(S[mf][2*kt][j]); e[4+j] = fexp(S[mf][2*kt+1][j]); }
                den[mf][0] += e[0] + e[1] + e[4] + e[5];
                den[mf][1] += e[2] + e[3] + e[6] + e[7];
                #pragma unroll
                for (int j = 0; j < 4; j++) {
                    __nv_bfloat162 h2 = __floats2bfloat162_rn(e[2*j], e[2*j+1]);
                    pah[mf][j] = *(uint32_t*)&h2;
                    float r0 = e[2*j]   - __bfloat162float(__low2bfloat16(h2));
                    float r1 = e[2*j+1] - __bfloat162float(__high2bfloat16(h2));
                    __nv_bfloat162 l2 = __floats2bfloat162_rn(r0, r1);
                    pal[mf][j] = *(uint32_t*)&l2;
                }
            }
            #pragma unroll
            for (int np = 0; np < 4; np++) {
                int row = np * 16 + ((lane >> 4) & 1) * 8 + (lane & 7);
                int col = kt * 16 + ((lane >> 3) & 1) * 8;
                uint32_t vh4[4], vl4[4];
                ldsm4(vh4, sb + (uint32_t)(41472 + row * 40 + col) * 2);
                ldsm4(vl4, sb + (uint32_t)(44032 + row * 40 + col) * 2);
                #pragma unroll
                for (int mf = 0; mf < 2; mf++) {
                    mma_bf16p(Oacc[mf][2*np],   pah[mf], vh4[0], vh4[1]);
                    mma_bf16p(Oacc[mf][2*np],   pah[mf], vl4[0], vl4[1]);
                    mma_bf16p(Oacc[mf][2*np],   pal[mf], vh4[0], vh4[1]);
                    mma_bf16p(Oacc[mf][2*np+1], pah[mf], vh4[2], vh4[3]);
                    mma_bf16p(Oacc[mf][2*np+1], pah[mf], vl4[2], vl4[3]);
                    mma_bf16p(Oacc[mf][2*np+1], pal[mf], vh4[2], vh4[3]);
                }
            }
        }
    }
    #pragma unroll
    for (int mf = 0; mf < 2; mf++)
        #pragma unroll
        for (int j = 0; j < 2; j++) {
            den[mf][j] += __shfl_xor_sync(0xffffffffu, den[mf][j], 1);
            den[mf][j] += __shfl_xor_sync(0xffffffffu, den[mf][j], 2);
        }
    int g = lane >> 2, t = lane & 3;
    size_t ob = ((size_t)chunk * BH + bh) * MLM * 64;
    #pragma unroll
    for (int mf = 0; mf < 2; mf++) {
        int lm0 = wid * 32 + mf * 16 + g;
        #pragma unroll
        for (int nf = 0; nf < 8; nf++) {
            int c = nf * 8 + t * 2;
            *(float2*)&Opart[ob + (size_t)lm0 * 64 + c] = make_float2(Oacc[mf][nf][0], Oacc[mf][nf][1]);
            *(float2*)&Opart[ob + (size_t)(lm0 + 8) * 64 + c] = make_float2(Oacc[mf][nf][2], Oacc[mf][nf][3]);
        }
        if (t == 0) {
            denpart[((size_t)chunk * BH + bh) * MLM + lm0] = den[mf][0];
            denpart[((size_t)chunk * BH + bh) * MLM + lm0 + 8] = den[mf][1];
        }
    }
}

__global__ void a3v_reduce(const float* __restrict__ Opart, const float* __restrict__ denpart,
                           float* __restrict__ A3V) {
    int idx = blockIdx.x * 256 + threadIdx.x;
    int bh = idx >> 14, lm = (idx >> 6) & 255;
    float s = 0.f, d = 0.f;
    #pragma unroll
    for (int c = 0; c < NCHK; c++) {
        s += Opart[((size_t)c * BH + bh) * 16384 + (idx & 16383)];
        d += denpart[((size_t)c * BH + bh) * 256 + lm];
    }
    A3V[idx] = s / d;
}

__global__ void conv_kernel(const float* __restrict__ v, const float* __restrict__ ker,
                            float* __restrict__ O) {
    int nt = blockIdx.x, h = blockIdx.y, b = blockIdx.z;
    int n0 = nt * 128;
    __shared__ float vsh[160][64];
    __shared__ float kw[KER_];
    int tid = threadIdx.x;
    if (tid < KER_) kw[tid] = ker[h * KER_ + tid];
    const float* vb = v + ((size_t)b * H_ + h) * NTOK * DH_;
    #pragma unroll
    for (int i = 0; i < 10; i++) {
        int f4 = tid + i * 256;
        int row2 = f4 >> 4, c4 = f4 & 15;
        int n = n0 - 16 + row2;
        float4 val = make_float4(0.f, 0.f, 0.f, 0.f);
        if (n >= 0 && n < NTOK) val = ((const float4*)(vb + (size_t)n * DH_))[c4];
        ((float4*)vsh)[f4] = val;
    }
    __syncthreads();
    int dh = tid & 63, g = tid >> 6;
    for (int ii = 0; ii < 32; ii++) {
        int nn = g * 32 + ii;
        float o = 0.f;
        #pragma unroll
        for (int t = 0; t < KER_; t++) o += kw[t] * vsh[nn + t][dh];
        O[((size_t)b * NTOK + (n0 + nn)) * D_ + h * DH_ + dh] = o;
    }
}

// attn1 via MMA: O += softmax(q@kl^T)@Y
#define A1_SMEM 178176
__global__ void __launch_bounds__(256, 1) attn1_mma(
        const __nv_bfloat16* __restrict__ qh_, const __nv_bfloat16* __restrict__ qlo_,
        const __nv_bfloat16* __restrict__ klh_, const __nv_bfloat16* __restrict__ kll_,
        const __nv_bfloat16* __restrict__ yth_, const __nv_bfloat16* __restrict__ ytl_,
        float* __restrict__ O)
{
    extern __shared__ __align__(16) __nv_bfloat16 sm1[];
    uint32_t sb = smem_to_u32(sm1);
    int tid = threadIdx.x, wid = tid >> 5, lane = tid & 31;
    int bh = blockIdx.y;
    int tile0 = blockIdx.x * 128;
    {
        size_t qb = ((size_t)bh * NTOK + tile0) * DH_;
        #pragma unroll
        for (int i = 0; i < 4; i++) {
            int lin = tid + i * 256;
            int r = lin >> 3, c = lin & 7;
            *(uint4*)(sm1 + r * 72 + c * 8) = *(const uint4*)(qh_ + qb + r * 64 + c * 8);
            *(uint4*)(sm1 + 9216 + r * 72 + c * 8) = *(const uint4*)(qlo_ + qb + r * 64 + c * 8);
        }
        size_t kb = (size_t)bh * MLM * DH_;
        #pragma unroll
        for (int i = 0; i < 8; i++) {
            int lin = tid + i * 256;
            int r = lin >> 3, c = lin & 7;
            *(uint4*)(sm1 + 18432 + r * 72 + c * 8) = *(const uint4*)(klh_ + kb + r * 64 + c * 8);
            *(uint4*)(sm1 + 36864 + r * 72 + c * 8) = *(const uint4*)(kll_ + kb + r * 64 + c * 8);
        }
        size_t yb = (size_t)bh * 64 * MLM;
        #pragma unroll
        for (int i = 0; i < 8; i++) {
            int lin = tid + i * 256;
            int r = lin >> 5, c = lin & 31;
            *(uint4*)(sm1 + 55296 + r * 264 + c * 8) = *(const uint4*)(yth_ + yb + r * 256 + c * 8);
            *(uint4*)(sm1 + 72192 + r * 264 + c * 8) = *(const uint4*)(ytl_ + yb + r * 256 + c * 8);
        }
    }
    __syncthreads();
    uint32_t Ah[4][4], Al[4][4];
    {
        int row = wid * 16 + (lane & 15);
        #pragma unroll
        for (int ks = 0; ks < 4; ks++) {
            int col = ks * 16 + ((lane >> 4) << 3);
            ldsm4(Ah[ks], sb + (uint32_t)(row * 72 + col) * 2);
            ldsm4(Al[ks], sb + (uint32_t)(9216 + row * 72 + col) * 2);
        }
    }
    float Oacc[8][4];
    #pragma unroll
    for (int b = 0; b < 8; b++)
        #pragma unroll
        for (int c = 0; c < 4; c++) Oacc[b][c] = 0.f;
    float dlo = 0.f, dhi = 0.f;

    #pragma unroll
    for (int half = 0; half < 2; half++) {
        int lmb = half * 128;
        float S[16][4];
        #pragma unroll
        for (int b = 0; b < 16; b++)
            #pragma unroll
            for (int c = 0; c < 4; c++) S[b][c] = 0.f;
        #pragma unroll
        for (int ks = 0; ks < 4; ks++) {
            #pragma unroll
            for (int np = 0; np < 8; np++) {
                int row = lmb + np * 16 + ((lane >> 4) & 1) * 8 + (lane & 7);
                int col = ks * 16 + ((lane >> 3) & 1) * 8;
                uint32_t bh4[4], bl4[4];
                ldsm4(bh4, sb + (uint32_t)(18432 + row * 72 + col) * 2);
                ldsm4(bl4, sb + (uint32_t)(36864 + row * 72 + col) * 2);
                mma_bf16p(S[2*np],   Ah[ks], bh4[0], bh4[1]);
                mma_bf16p(S[2*np],   Ah[ks], bl4[0], bl4[1]);
                mma_bf16p(S[2*np],   Al[ks], bh4[0], bh4[1]);
                mma_bf16p(S[2*np+1], Ah[ks], bh4[2], bh4[3]);
                mma_bf16p(S[2*np+1], Ah[ks], bl4[2], bl4[3]);
                mma_bf16p(S[2*np+1], Al[ks], bh4[2], bh4[3]);
            }
        }
        #pragma unroll
        for (int kt = 0; kt < 8; kt++) {
            float e[8];
            #pragma unroll
            for (int j = 0; j < 4; j++) { e[j] = fexp(S[2*kt][j]); e[4+j] = fexp(S[2*kt+1][j]); }
            dlo += e[0] + e[1] + e[4] + e[5];
            dhi += e[2] + e[3] + e[6] + e[7];
            uint32_t pah[4], pal[4];
            #pragma unroll
            for (int j = 0; j < 4; j++) {
                __nv_bfloat162 h2 = __floats2bfloat162_rn(e[2*j], e[2*j+1]);
                pah[j] = *(uint32_t*)&h2;
                float r0 = e[2*j]   - __bfloat162float(__low2bfloat16(h2));
                float r1 = e[2*j+1] - __bfloat162float(__high2bfloat16(h2));
                __nv_bfloat162 l2 = __floats2bfloat162_rn(r0, r1);
                pal[j] = *(uint32_t*)&l2;
            }
            #pragma unroll
            for (int np = 0; np < 4; np++) {
                int row = np * 16 + ((lane >> 4) & 1) * 8 + (lane & 7);
                int col = lmb + kt * 16 + ((lane >> 3) & 1) * 8;
                uint32_t yh4[4], yl4[4];
                ldsm4(yh4, sb + (uint32_t)(55296 + row * 264 + col) * 2);
                ldsm4(yl4, sb + (uint32_t)(72192 + row * 264 + col) * 2);
                mma_bf16p(Oacc[2*np],   pah, yh4[0], yh4[1]);
                mma_bf16p(Oacc[2*np],   pah, yl4[0], yl4[1]);
                mma_bf16p(Oacc[2*np],   pal, yh4[0], yh4[1]);
                mma_bf16p(Oacc[2*np+1], pah, yh4[2], yh4[3]);
                mma_bf16p(Oacc[2*np+1], pah, yl4[2], yl4[3]);
                mma_bf16p(Oacc[2*np+1], pal, yh4[2], yh4[3]);
            }
        }
    }
    dlo += __shfl_xor_sync(0xffffffffu, dlo, 1);
    dlo += __shfl_xor_sync(0xffffffffu, dlo, 2);
    dhi += __shfl_xor_sync(0xffffffffu, dhi, 1);
    dhi += __shfl_xor_sync(0xffffffffu, dhi, 2);
    float ilo = 1.f / dlo, ihi = 1.f / dhi;
    int g = lane >> 2, t = lane & 3;
    int tok0 = tile0 + wid * 16 + g;
    int b = bh >> 3, h = bh & 7;
    size_t ob = ((size_t)b * NTOK + tok0) * D_ + h * DH_;
    #pragma unroll
    for (int nf = 0; nf < 8; nf++) {
        int c = nf * 8 + t * 2;
        float2* p0 = (float2*)&O[ob + c];
        float2 v0 = *p0;
        v0.x += Oacc[nf][0] * ilo; v0.y += Oacc[nf][1] * ilo;
        *p0 = v0;
        float2* p1 = (float2*)&O[ob + (size_t)8 * D_ + c];
        float2 v1 = *p1;
        v1.x += Oacc[nf][2] * ihi; v1.y += Oacc[nf][3] * ihi;
        *p1 = v1;
    }
}

__global__ void osplit_kernel(const float* __restrict__ O, __nv_bfloat16* __restrict__ hi,
                              __nv_bfloat16* __restrict__ lo) {
    size_t idx = (size_t)blockIdx.x * 256 + threadIdx.x;
    float v = O[idx];
    __nv_bfloat16 h = __float2bfloat16(v);
    hi[idx] = h;
    lo[idx] = __float2bfloat16(v - __bfloat162float(h));
}

extern "C" void kernel_launch(void* const* d_in, const int* in_sizes, int n_in,
                              void* d_out, int out_size) {
    const float* x      = (const float*)d_in[0];
    const float* gamma  = (const float*)d_in[1];
    const float* beta   = (const float*)d_in[2];
    const float* w_qkv  = (const float*)d_in[3];
    const float* res_k  = (const float*)d_in[4];
    const float* w_out  = (const float*)d_in[5];
    const float* b_out  = (const float*)d_in[6];
    float* out = (float*)d_out;

    __nv_bfloat16 *nh, *nl, *wqh, *wql, *woh, *wol, *Oh, *Ol, *Xh, *Xl;
    __nv_bfloat16 *Znh[2], *Znl[2], *Zth[2], *Ztl[2], *XZh, *XZl, *WtAh, *WtAl, *WtBh, *WtBl;
    __nv_bfloat16 *qbh, *qbl, *kbh, *kbl, *vth, *vtl, *qlh, *qll, *klh, *kll, *yth, *ytl;
    float *q, *k, *v, *ql, *kl, *X, *Zf, *A3V, *Y, *O, *Opart, *dpart;
    unsigned* mb;
    cudaGetSymbolAddress((void**)&nh, g_nh);
    cudaGetSymbolAddress((void**)&nl, g_nl);
    cudaGetSymbolAddress((void**)&wqh, g_wqh);
    cudaGetSymbolAddress((void**)&wql, g_wql);
    cudaGetSymbolAddress((void**)&woh, g_woh);
    cudaGetSymbolAddress((void**)&wol, g_wol);
    cudaGetSymbolAddress((void**)&Oh, g_Oh);
    cudaGetSymbolAddress((void**)&Ol, g_Ol);
    cudaGetSymbolAddress((void**)&Xh, g_Xh);
    cudaGetSymbolAddress((void**)&Xl, g_Xl);
    {
        __nv_bfloat16* p;
        cudaGetSymbolAddress((void**)&p, g_Znh); Znh[0] = p; Znh[1] = p + (size_t)BH*MLM*MLM;
        cudaGetSymbolAddress((void**)&p, g_Znl); Znl[0] = p; Znl[1] = p + (size_t)BH*MLM*MLM;
        cudaGetSymbolAddress((void**)&p, g_Zth); Zth[0] = p; Zth[1] = p + (size_t)BH*MLM*MLM;
        cudaGetSymbolAddress((void**)&p, g_Ztl); Ztl[0] = p; Ztl[1] = p + (size_t)BH*MLM*MLM;
    }
    cudaGetSymbolAddress((void**)&XZh, g_XZh);
    cudaGetSymbolAddress((void**)&XZl, g_XZl);
    cudaGetSymbolAddress((void**)&WtAh, g_WtAh);
    cudaGetSymbolAddress((void**)&WtAl, g_WtAl);
    cudaGetSymbolAddress((void**)&WtBh, g_WtBh);
    cudaGetSymbolAddress((void**)&WtBl, g_WtBl);
    cudaGetSymbolAddress((void**)&q,  g_q);
    cudaGetSymbolAddress((void**)&k,  g_k);
    cudaGetSymbolAddress((void**)&v,  g_v);
    cudaGetSymbolAddress((void**)&qbh, g_qbh);
    cudaGetSymbolAddress((void**)&qbl, g_qbl);
    cudaGetSymbolAddress((void**)&kbh, g_kbh);
    cudaGetSymbolAddress((void**)&kbl, g_kbl);
    cudaGetSymbolAddress((void**)&vth, g_vth);
    cudaGetSymbolAddress((void**)&vtl, g_vtl);
    cudaGetSymbolAddress((void**)&ql, g_ql);
    cudaGetSymbolAddress((void**)&kl, g_kl);
    cudaGetSymbolAddress((void**)&qlh, g_qlh);
    cudaGetSymbolAddress((void**)&qll, g_qll);
    cudaGetSymbolAddress((void**)&klh, g_klh);
    cudaGetSymbolAddress((void**)&kll, g_kll);
    cudaGetSymbolAddress((void**)&yth, g_yth);
    cudaGetSymbolAddress((void**)&ytl, g_ytl);
    cudaGetSymbolAddress((void**)&X,  g_X);
    cudaGetSymbolAddress((void**)&Zf, g_Zf);
    cudaGetSymbolAddress((void**)&Opart, g_Opart);
    cudaGetSymbolAddress((void**)&dpart, g_dpart);
    cudaGetSymbolAddress((void**)&A3V, g_A3V);
    cudaGetSymbolAddress((void**)&Y,  g_Y);
    cudaGetSymbolAddress((void**)&O,  g_O);
    cudaGetSymbolAddress((void**)&mb, g_maxbits);

    cudaFuncSetAttribute(attn2_kernel, cudaFuncAttributeMaxDynamicSharedMemorySize, ATTN2_SMEM);
    cudaFuncSetAttribute(tc_gemm<1>, cudaFuncAttributeMaxDynamicSharedMemorySize, TCG_SMEM);
    cudaFuncSetAttribute(tc_gemm<2>, cudaFuncAttributeMaxDynamicSharedMemorySize, TCG_SMEM);
    cudaFuncSetAttribute(attn3v_mma, cudaFuncAttributeMaxDynamicSharedMemorySize, A3_SMEM);
    cudaFuncSetAttribute(attn1_mma, cudaFuncAttributeMaxDynamicSharedMemorySize, A1_SMEM);

    const size_t sM = (size_t)MLM * MLM;

    ln_kernel<<<B_ * NTOK, 256>>>(x, gamma, beta, nh, nl);
    tsplit_kernel<<<(D_ * 3 * D_ + 255) / 256, 256>>>(w_qkv, wqh, wql, D_, 3 * D_);
    tsplit_kernel<<<(D_ * D_ + 255) / 256, 256>>>(w_out, woh, wol, D_, D_);

    tc_gemm<2><<<dim3(12, 256, 1), 256, TCG_SMEM>>>(nh, nl, wqh, wql, D_, 0, 0, 0,
        q, k, v, nullptr, nullptr, nullptr,
        qbh, qbl, kbh, kbl, nullptr, 1.f, 0.f, 1.f);

    vtrans_kernel<<<dim3(NTOK / 64, BH), 256>>>(v, vth, vtl);

    landmark_kernel<<<dim3(BH, MLM), 64>>>(q, k, ql, kl);
    bsplit_kernel<<<512, 256>>>(ql, qlh, qll);
    bsplit_kernel<<<512, 256>>>(kl, klh, kll);

    attn2_kernel<<<dim3(BH, 8), 256, ATTN2_SMEM>>>(ql, kl, X, Xh, Xl);
    initmax_kernel<<<1, 1>>>(mb);
    rowcol_kernel<<<BH, 256>>>(X, mb);
    zinit_kernel<<<8192, 256>>>(X, mb, Znh[0], Znl[0], Zth[0], Ztl[0]);

    int cur = 0;
    for (int it = 0; it < 6; it++) {
        int nxt = cur ^ 1;
        if (it < 4) {
            tc_gemm<1><<<dim3(2, 2, BH), 256, TCG_SMEM>>>(Xh, Xl, Zth[cur], Ztl[cur], MLM, sM, sM, 2,
                nullptr, nullptr, nullptr, nullptr, nullptr, nullptr,
                XZh, XZl, WtAh, WtAl, nullptr, 1.f, 7.f, 1.f);
            tc_gemm<1><<<dim3(2, 2, BH), 256, TCG_SMEM>>>(XZh, XZl, WtAh, WtAl, MLM, sM, sM, 2,
                nullptr, nullptr, nullptr, nullptr, nullptr, nullptr,
                nullptr, nullptr, WtBh, WtBl, nullptr, 1.f, 15.f, 1.f);
            tc_gemm<1><<<dim3(2, 2, BH), 256, TCG_SMEM>>>(XZh, XZl, WtBh, WtBl, MLM, sM, sM, 2,
                nullptr, nullptr, nullptr, nullptr, nullptr, nullptr,
                nullptr, nullptr, WtAh, WtAl, nullptr, 1.f, 13.f, 1.f);
            tc_gemm<1><<<dim3(2, 2, BH), 256, TCG_SMEM>>>(Znh[cur], Znl[cur], WtAh, WtAl, MLM, sM, sM, 2,
                nullptr, nullptr, nullptr, nullptr, nullptr, nullptr,
                Znh[nxt], Znl[nxt], Zth[nxt], Ztl[nxt], nullptr, 0.25f, 0.f, -0.25f);
        } else {
            tc_gemm<2><<<dim3(2, 2, BH), 256, TCG_SMEM>>>(Xh, Xl, Zth[cur], Ztl[cur], MLM, sM, sM, 2,
                nullptr, nullptr, nullptr, nullptr, nullptr, nullptr,
                XZh, XZl, WtAh, WtAl, nullptr, 1.f, 7.f, 1.f);
            tc_gemm<2><<<dim3(2, 2, BH), 256, TCG_SMEM>>>(XZh, XZl, WtAh, WtAl, MLM, sM, sM, 2,
                nullptr, nullptr, nullptr, nullptr, nullptr, nullptr,
                nullptr, nullptr, WtBh, WtBl, nullptr, 1.f, 15.f, 1.f);
            tc_gemm<2><<<dim3(2, 2, BH), 256, TCG_SMEM>>>(XZh, XZl, WtBh, WtBl, MLM, sM, sM, 2,
                nullptr, nullptr, nullptr, nullptr, nullptr, nullptr,
                nullptr, nullptr, WtAh, WtAl, nullptr, 1.f, 13.f, 1.f);
            tc_gemm<2><<<dim3(2, 2, BH), 256, TCG_SMEM>>>(Znh[cur], Znl[cur], WtAh, WtAl, MLM, sM, sM, 2,
                nullptr, nullptr, nullptr, nullptr, nullptr, nullptr,
                Znh[nxt], Znl[nxt], Zth[nxt], Ztl[nxt], (it == 5) ? Zf : nullptr, 0.25f, 0.f, -0.25f);
        }
        cur = nxt;
    }

    attn3v_mma<<<dim3(NCHK, BH), 256, A3_SMEM>>>(qlh, qll, kbh, kbl, vth, vtl, Opart, dpart);
    a3v_reduce<<<2048, 256>>>(Opart, dpart, A3V);

    sgemm_kernel<<<dim3(1, 2, BH), 256>>>(Zf, A3V, Y, MLM, DH_, MLM,
        sM, (size_t)MLM * DH_, (size_t)MLM * DH_);
    ytrans_kernel<<<BH, 256>>>(Y, yth, ytl);

    conv_kernel<<<dim3(64, H_, B_), 256>>>(v, res_k, O);
    attn1_mma<<<dim3(NTOK / 128, BH), 256, A1_SMEM>>>(qbh, qbl, klh, kll, yth, ytl, O);

    osplit_kernel<<<(int)(((size_t)B_*NTOK*D_) / 256), 256>>>(O, Oh, Ol);
    tc_gemm<2><<<dim3(4, 256, 1), 256, TCG_SMEM>>>(Oh, Ol, woh, wol, D_, 0, 0, 1,
        nullptr, nullptr, nullptr, out, b_out, x,
        nullptr, nullptr, nullptr, nullptr, nullptr, 1.f, 0.f, 1.f);
}

// round 11
// speedup vs baseline: 6.1376x; 1.0028x over previous
#include <cuda_runtime.h>
#include <cuda_bf16.h>
#include <math.h>
#include <stdint.h>

#define B_    4
#define NTOK  8192
#define D_    512
#define H_    8
#define DH_   64
#define MLM   256
#define LSEG  32
#define BH    (B_*H_)
#define KER_  33
#define NCHK  8
#define A1_TPB 4

__device__ __forceinline__ uint32_t smem_to_u32(const void* p) {
    uint32_t a;
    asm("{ .reg .u64 t; cvta.to.shared.u64 t, %1; cvt.u32.u64 %0, t; }" : "=r"(a) : "l"(p));
    return a;
}
__device__ __forceinline__ void cp_async16(uint32_t saddr, const void* gptr) {
    asm volatile("cp.async.cg.shared.global [%0], [%1], 16;" :: "r"(saddr), "l"(gptr));
}
#define CP_COMMIT() asm volatile("cp.async.commit_group;" ::: "memory")
#define CP_WAIT0()  asm volatile("cp.async.wait_group 0;" ::: "memory")
__device__ __forceinline__ void mma_bf16p(float (&d)[4], const uint32_t (&a)[4], uint32_t b0, uint32_t b1) {
    asm volatile("mma.sync.aligned.m16n8k16.row.col.f32.bf16.bf16.f32 "
        "{%0,%1,%2,%3}, {%4,%5,%6,%7}, {%8,%9}, {%0,%1,%2,%3};"
        : "+f"(d[0]), "+f"(d[1]), "+f"(d[2]), "+f"(d[3])
        : "r"(a[0]), "r"(a[1]), "r"(a[2]), "r"(a[3]), "r"(b0), "r"(b1));
}
__device__ __forceinline__ void ldsm4(uint32_t (&r)[4], uint32_t a) {
    asm volatile("ldmatrix.sync.aligned.m8n8.x4.shared.b16 {%0,%1,%2,%3}, [%4];"
        : "=r"(r[0]), "=r"(r[1]), "=r"(r[2]), "=r"(r[3]) : "r"(a));
}
__device__ __forceinline__ float fexp(float s) {
    float t = s * 1.44269504088896341f;
    float i = rintf(t);
    float f = t - i;
    float p = 1.54035303933816e-4f;
    p = p * f + 1.33335581464284e-3f;
    p = p * f + 9.61812910762848e-3f;
    p = p * f + 5.55041086648216e-2f;
    p = p * f + 2.40226506959101e-1f;
    p = p * f + 6.93147180559945e-1f;
    p = p * f + 1.0f;
    return p * __int_as_float(((int)i + 127) << 23);
}

// scratch
__device__ __nv_bfloat16 g_nh[(size_t)B_*NTOK*D_];
__device__ __nv_bfloat16 g_nl[(size_t)B_*NTOK*D_];
__device__ __nv_bfloat16 g_wqh[(size_t)3*D_*D_];
__device__ __nv_bfloat16 g_wql[(size_t)3*D_*D_];
__device__ __nv_bfloat16 g_woh[(size_t)D_*D_];
__device__ __nv_bfloat16 g_wol[(size_t)D_*D_];
__device__ __nv_bfloat16 g_Oh[(size_t)B_*NTOK*D_];
__device__ __nv_bfloat16 g_Ol[(size_t)B_*NTOK*D_];
__device__ float g_q [(size_t)BH*NTOK*DH_];
__device__ float g_k [(size_t)BH*NTOK*DH_];
__device__ float g_v [(size_t)BH*NTOK*DH_];
__device__ __nv_bfloat16 g_qbh[(size_t)BH*NTOK*DH_];
__device__ __nv_bfloat16 g_qbl[(size_t)BH*NTOK*DH_];
__device__ __nv_bfloat16 g_kbh[(size_t)BH*NTOK*DH_];
__device__ __nv_bfloat16 g_kbl[(size_t)BH*NTOK*DH_];
__device__ __nv_bfloat16 g_vth[(size_t)BH*NTOK*DH_];
__device__ __nv_bfloat16 g_vtl[(size_t)BH*NTOK*DH_];
__device__ float g_ql[(size_t)BH*MLM*DH_];
__device__ float g_kl[(size_t)BH*MLM*DH_];
__device__ __nv_bfloat16 g_qlh[(size_t)BH*MLM*DH_];
__device__ __nv_bfloat16 g_qll[(size_t)BH*MLM*DH_];
__device__ __nv_bfloat16 g_klh[(size_t)BH*MLM*DH_];
__device__ __nv_bfloat16 g_kll[(size_t)BH*MLM*DH_];
__device__ __nv_bfloat16 g_yth[(size_t)BH*MLM*DH_];
__device__ __nv_bfloat16 g_ytl[(size_t)BH*MLM*DH_];
__device__ float g_X [(size_t)BH*MLM*MLM];
__device__ __nv_bfloat16 g_Xh[(size_t)BH*MLM*MLM];
__device__ __nv_bfloat16 g_Xl[(size_t)BH*MLM*MLM];
__device__ __nv_bfloat16 g_Znh[2][(size_t)BH*MLM*MLM];
__device__ __nv_bfloat16 g_Znl[2][(size_t)BH*MLM*MLM];
__device__ __nv_bfloat16 g_Zth[2][(size_t)BH*MLM*MLM];
__device__ __nv_bfloat16 g_Ztl[2][(size_t)BH*MLM*MLM];
__device__ __nv_bfloat16 g_XZh[(size_t)BH*MLM*MLM];
__device__ __nv_bfloat16 g_XZl[(size_t)BH*MLM*MLM];
__device__ __nv_bfloat16 g_WtAh[(size_t)BH*MLM*MLM];
__device__ __nv_bfloat16 g_WtAl[(size_t)BH*MLM*MLM];
__device__ __nv_bfloat16 g_WtBh[(size_t)BH*MLM*MLM];
__device__ __nv_bfloat16 g_WtBl[(size_t)BH*MLM*MLM];
__device__ float g_Zf[(size_t)BH*MLM*MLM];
__device__ float g_Opart[(size_t)NCHK*BH*MLM*DH_];
__device__ float g_dpart[(size_t)NCHK*BH*MLM];
__device__ float g_A3V[(size_t)BH*MLM*DH_];
__device__ float g_Y  [(size_t)BH*MLM*DH_];
__device__ float g_O  [(size_t)B_*NTOK*D_];
__device__ unsigned g_maxbits[2];

__global__ void ln_kernel(const float* __restrict__ x, const float* __restrict__ gamma,
                          const float* __restrict__ beta,
                          __nv_bfloat16* __restrict__ ohi, __nv_bfloat16* __restrict__ olo) {
    int row = blockIdx.x, tid = threadIdx.x;
    const float* xr = x + (size_t)row * D_;
    float v0 = xr[tid], v1 = xr[tid + 256];
    float s = v0 + v1, s2 = v0*v0 + v1*v1;
    #pragma unroll
    for (int o = 16; o > 0; o >>= 1) {
        s  += __shfl_xor_sync(0xffffffffu, s,  o);
        s2 += __shfl_xor_sync(0xffffffffu, s2, o);
    }
    __shared__ float sh[16];
    int w = tid >> 5;
    if ((tid & 31) == 0) { sh[w] = s; sh[w + 8] = s2; }
    __syncthreads();
    if (tid == 0) {
        float a = 0.f, b2 = 0.f;
        #pragma unroll
        for (int i = 0; i < 8; i++) { a += sh[i]; b2 += sh[i + 8]; }
        sh[0] = a; sh[8] = b2;
    }
    __syncthreads();
    float mu  = sh[0] * (1.f / D_);
    float var = sh[8] * (1.f / D_) - mu * mu;
    float inv = rsqrtf(var + 1e-5f);
    size_t base = (size_t)row * D_;
    #pragma unroll
    for (int half = 0; half < 2; half++) {
        int c = tid + half * 256;
        float v = (half == 0 ? v0 : v1);
        float nv = (v - mu) * inv * gamma[c] + beta[c];
        __nv_bfloat16 hi = __float2bfloat16(nv);
        ohi[base + c] = hi;
        olo[base + c] = __float2bfloat16(nv - __bfloat162float(hi));
    }
}

__global__ void tsplit_kernel(const float* __restrict__ W, __nv_bfloat16* __restrict__ Thi,
                              __nv_bfloat16* __restrict__ Tlo, int K, int N) {
    int idx = blockIdx.x * 256 + threadIdx.x;
    if (idx >= K * N) return;
    int k = idx / N, n = idx % N;
    float v = W[idx];
    __nv_bfloat16 hi = __float2bfloat16(v);
    Thi[(size_t)n * K + k] = hi;
    Tlo[(size_t)n * K + k] = __float2bfloat16(v - __bfloat162float(hi));
}
__global__ void vtrans_kernel(const float* __restrict__ v, __nv_bfloat16* __restrict__ vth,
                              __nv_bfloat16* __restrict__ vtl) {
    __shared__ float ts[64][68];
    int bh = blockIdx.y, k0 = blockIdx.x * 64;
    int tid = threadIdx.x;
    const float* vb = v + ((size_t)bh * NTOK + k0) * DH_;
    #pragma unroll
    for (int i = 0; i < 4; i++) {
        int lin = tid + i * 256;
        int r = lin >> 4, c4 = lin & 15;
        *(float4*)&ts[r][c4 * 4] = *(const float4*)(vb + r * 64 + c4 * 4);
    }
    __syncthreads();
    #pragma unroll
    for (int i = 0; i < 16; i++) {
        int lin = tid + i * 256;
        int dh = lin >> 6, ky = lin & 63;
        float val = ts[ky][dh];
        __nv_bfloat16 h = __float2bfloat16(val);
        size_t o = ((size_t)bh * 64 + dh) * NTOK + k0 + ky;
        vth[o] = h;
        vtl[o] = __float2bfloat16(val - __bfloat162float(h));
    }
}
__global__ void ytrans_kernel(const float* __restrict__ Y, __nv_bfloat16* __restrict__ yth,
                              __nv_bfloat16* __restrict__ ytl) {
    int bh = blockIdx.x, tid = threadIdx.x;
    #pragma unroll
    for (int i = 0; i < 64; i++) {
        int lin = tid + i * 256;
        int dh = lin >> 8, lm = lin & 255;
        float val = Y[(size_t)bh * 16384 + lm * 64 + dh];
        __nv_bfloat16 h = __float2bfloat16(val);
        size_t o = (size_t)bh * 16384 + dh * 256 + lm;
        yth[o] = h;
        ytl[o] = __float2bfloat16(val - __bfloat162float(h));
    }
}

// bf16-split MMA GEMM, cp.async double-buffered, NPASS compile-time, 2 CTAs/SM.
#define TCG_SMEM (2 * 4 * 5120 * 2)
template<int NPASS>
__global__ void __launch_bounds__(256, 2) tc_gemm(
        const __nv_bfloat16* __restrict__ Ahi, const __nv_bfloat16* __restrict__ Alo,
        const __nv_bfloat16* __restrict__ Bhi, const __nv_bfloat16* __restrict__ Blo,
        int K, size_t strA, size_t strB, int mode,
        float* __restrict__ qp, float* __restrict__ kp, float* __restrict__ vp,
        float* __restrict__ Cout, const float* __restrict__ bias, const float* __restrict__ addx,
        __nv_bfloat16* __restrict__ Nhi, __nv_bfloat16* __restrict__ Nlo,
        __nv_bfloat16* __restrict__ Thi, __nv_bfloat16* __restrict__ Tlo,
        float* __restrict__ Cf32, float alpha, float diagc, float beta)
{
    extern __shared__ __align__(16) char smem[];
    uint32_t sbase = smem_to_u32(smem);
    int tid = threadIdx.x;
    int wid = tid >> 5, lane = tid & 31;
    int wm = (wid & 3) * 32, wn = (wid >> 2) * 64;
    int bz = blockIdx.z;
    int m0 = blockIdx.y * 128, n0 = blockIdx.x * 128;
    size_t oz = (size_t)bz * 65536;
    Ahi += (size_t)bz * strA; Alo += (size_t)bz * strA;
    Bhi += (size_t)bz * strB; Blo += (size_t)bz * strB;
    const __nv_bfloat16* srcs[4] = {Ahi, Alo, Bhi, Blo};
    const int row0s[4] = {m0, m0, n0, n0};
    const int NB = (NPASS == 1) ? 2 : 4;

    float acc[2][8][4];
    #pragma unroll
    for (int a = 0; a < 2; a++)
        #pragma unroll
        for (int b = 0; b < 8; b++)
            #pragma unroll
            for (int c = 0; c < 4; c++) acc[a][b][c] = 0.f;

    int r_ld = tid >> 2, c_ld = tid & 3;
    int nch = K >> 5;

    #pragma unroll
    for (int bs = 0; bs < NB; bs++) {
        int bsel = (NPASS == 1) ? bs * 2 : bs;
        #pragma unroll
        for (int i = 0; i < 2; i++)
            cp_async16(sbase + (uint32_t)(bsel * 5120 + (r_ld + i * 64) * 40 + c_ld * 8) * 2,
                       srcs[bsel] + (size_t)(row0s[bsel] + r_ld + i * 64) * K + c_ld * 8);
    }
    CP_COMMIT();

    for (int ch = 0; ch < nch; ch++) {
        CP_WAIT0();
        __syncthreads();
        if (ch + 1 < nch) {
            int k0 = (ch + 1) << 5;
            uint32_t nxt_off = (uint32_t)((ch + 1) & 1) * 4 * 5120;
            #pragma unroll
            for (int bs = 0; bs < NB; bs++) {
                int bsel = (NPASS == 1) ? bs * 2 : bs;
                #pragma unroll
                for (int i = 0; i < 2; i++)
                    cp_async16(sbase + (uint32_t)(nxt_off + bsel * 5120 + (r_ld + i * 64) * 40 + c_ld * 8) * 2,
                               srcs[bsel] + (size_t)(row0s[bsel] + r_ld + i * 64) * K + k0 + c_ld * 8);
            }
            CP_COMMIT();
        }
        uint32_t stg_off = (uint32_t)(ch & 1) * 4 * 5120;
        #pragma unroll
        for (int ks = 0; ks < 32; ks += 16) {
            uint32_t Ah[2][4], Al[2][4];
            #pragma unroll
            for (int mf = 0; mf < 2; mf++) {
                int row = wm + mf * 16 + (lane & 15);
                int col = ks + ((lane >> 4) << 3);
                ldsm4(Ah[mf], sbase + (uint32_t)(stg_off + row * 40 + col) * 2);
                if (NPASS > 1) ldsm4(Al[mf], sbase + (uint32_t)(stg_off + 5120 + row * 40 + col) * 2);
            }
            #pragma unroll
            for (int p = 0; p < 4; p++) {
                int rowb = wn + (2 * p + (lane >> 4)) * 8 + (lane & 7);
                int colb = ks + ((lane >> 3) & 1) * 8;
                uint32_t Bh4[4], Bl4[4];
                ldsm4(Bh4, sbase + (uint32_t)(stg_off + 2 * 5120 + rowb * 40 + colb) * 2);
                if (NPASS > 1) ldsm4(Bl4, sbase + (uint32_t)(stg_off + 3 * 5120 + rowb * 40 + colb) * 2);
                #pragma unroll
                for (int mf = 0; mf < 2; mf++) {
                    mma_bf16p(acc[mf][2*p],   Ah[mf], Bh4[0], Bh4[1]);
                    mma_bf16p(acc[mf][2*p+1], Ah[mf], Bh4[2], Bh4[3]);
                    if (NPASS > 1) {
                        mma_bf16p(acc[mf][2*p],   Ah[mf], Bl4[0], Bl4[1]);
                        mma_bf16p(acc[mf][2*p+1], Ah[mf], Bl4[2], Bl4[3]);
                        mma_bf16p(acc[mf][2*p],   Al[mf], Bh4[0], Bh4[1]);
                        mma_bf16p(acc[mf][2*p+1], Al[mf], Bh4[2], Bh4[3]);
                    }
                }
            }
        }
    }
    __syncthreads();

    float* stg = reinterpret_cast<float*>(smem);
    {
        int r = lane >> 2, c = (lane & 3) * 2;
        #pragma unroll
        for (int mf = 0; mf < 2; mf++)
            #pragma unroll
            for (int nf = 0; nf < 8; nf++) {
                int rr = wm + mf * 16 + r, cc = wn + nf * 8 + c;
                *reinterpret_cast<float2*>(&stg[rr * 132 + cc]) = make_float2(acc[mf][nf][0], acc[mf][nf][1]);
                *reinterpret_cast<float2*>(&stg[(rr + 8) * 132 + cc]) = make_float2(acc[mf][nf][2], acc[mf][nf][3]);
            }
    }
    __syncthreads();

    if (mode == 0) {
        #pragma unroll 4
        for (int i = 0; i < 16; i++) {
            int lin = tid + (i << 8);
            int token = lin >> 5, c4 = lin & 31;
            int gn = n0 + (c4 << 2);
            float4 v = *reinterpret_cast<float4*>(&stg[token * 132 + (c4 << 2)]);
            int gmm = m0 + token;
            int b_ = gmm >> 13, n_ = gmm & 8191;
            int sec = gn >> 9, cc = gn & 511, h_ = cc >> 6, dh = cc & 63;
            size_t idx = ((((size_t)b_ * H_ + h_) * NTOK) + n_) * DH_ + dh;
            if (sec == 2) {
                *reinterpret_cast<float4*>(&vp[idx]) = v;
            } else {
                if (sec == 0) { v.x *= 0.125f; v.y *= 0.125f; v.z *= 0.125f; v.w *= 0.125f; }
                float* fp = (sec == 0) ? qp : kp;
                __nv_bfloat16* hp = (sec == 0) ? Nhi : Thi;
                __nv_bfloat16* lp = (sec == 0) ? Nlo : Tlo;
                *reinterpret_cast<float4*>(&fp[idx]) = v;
                float vv[4] = {v.x, v.y, v.z, v.w};
                __nv_bfloat16 hb[4], lb[4];
                #pragma unroll
                for (int t2 = 0; t2 < 4; t2++) {
                    hb[t2] = __float2bfloat16(vv[t2]);
                    lb[t2] = __float2bfloat16(vv[t2] - __bfloat162float(hb[t2]));
                }
                *reinterpret_cast<uint2*>(&hp[idx]) = *reinterpret_cast<uint2*>(hb);
                *reinterpret_cast<uint2*>(&lp[idx]) = *reinterpret_cast<uint2*>(lb);
            }
        }
    } else if (mode == 1) {
        #pragma unroll 4
        for (int i = 0; i < 16; i++) {
            int lin = tid + (i << 8);
            int token = lin >> 5, c4 = lin & 31;
            int gn = n0 + (c4 << 2);
            int gmm = m0 + token;
            float4 v = *reinterpret_cast<float4*>(&stg[token * 132 + (c4 << 2)]);
            float4 bb = *reinterpret_cast<const float4*>(&bias[gn]);
            float4 xx = *reinterpret_cast<const float4*>(&addx[(size_t)gmm * 512 + gn]);
            v.x += bb.x + xx.x; v.y += bb.y + xx.y; v.z += bb.z + xx.z; v.w += bb.w + xx.w;
            *reinterpret_cast<float4*>(&Cout[(size_t)gmm * 512 + gn]) = v;
        }
    } else {
        if (Thi) {
            #pragma unroll 4
            for (int i = 0; i < 64; i++) {
                int idx = tid + (i << 8);
                int gn_l = idx >> 7, gm_l = idx & 127;
                int gmm = m0 + gm_l, gn = n0 + gn_l;
                float v = stg[gm_l * 132 + gn_l];
                float t = (gmm == gn ? diagc : 0.f) - beta * v;
                __nv_bfloat16 h = __float2bfloat16(t);
                Thi[oz + (size_t)gn * 256 + gmm] = h;
                Tlo[oz + (size_t)gn * 256 + gmm] = __float2bfloat16(t - __bfloat162float(h));
            }
        }
        if (Nhi) {
            #pragma unroll 4
            for (int i = 0; i < 16; i++) {
                int lin = tid + (i << 8);
                int token = lin >> 5, c4 = lin & 31;
                int gn = n0 + (c4 << 2);
                int gmm = m0 + token;
                float4 v = *reinterpret_cast<float4*>(&stg[token * 132 + (c4 << 2)]);
                float vv[4] = {v.x * alpha, v.y * alpha, v.z * alpha, v.w * alpha};
                __nv_bfloat16 h[4], l2[4];
                #pragma unroll
                for (int t2 = 0; t2 < 4; t2++) {
                    h[t2] = __float2bfloat16(vv[t2]);
                    l2[t2] = __float2bfloat16(vv[t2] - __bfloat162float(h[t2]));
                }
                *reinterpret_cast<uint2*>(&Nhi[oz + (size_t)gmm * 256 + gn]) = *reinterpret_cast<uint2*>(h);
                *reinterpret_cast<uint2*>(&Nlo[oz + (size_t)gmm * 256 + gn]) = *reinterpret_cast<uint2*>(l2);
            }
        }
        if (Cf32) {
            #pragma unroll 4
            for (int i = 0; i < 16; i++) {
                int lin = tid + (i << 8);
                int token = lin >> 5, c4 = lin & 31;
                int gn = n0 + (c4 << 2);
                int gmm = m0 + token;
                float4 v = *reinterpret_cast<float4*>(&stg[token * 132 + (c4 << 2)]);
                v.x *= alpha; v.y *= alpha; v.z *= alpha; v.w *= alpha;
                *reinterpret_cast<float4*>(&Cf32[oz + (size_t)gmm * 256 + gn]) = v;
            }
        }
    }
}

// SIMT SGEMM for Y = Zf @ A3V
__global__ void __launch_bounds__(256) sgemm_kernel(
        const float* __restrict__ A, const float* __restrict__ B, float* __restrict__ C,
        int M, int N, int K, size_t sA, size_t sB, size_t sC)
{
    int bz = blockIdx.z;
    A += (size_t)bz * sA; B += (size_t)bz * sB; C += (size_t)bz * sC;
    int m0 = blockIdx.y * 128, n0 = blockIdx.x * 128;
    __shared__ float As[8][128];
    __shared__ float Bs[8][128];
    int tid = threadIdx.x;
    int tx = tid & 15, ty = tid >> 4;
    float acc[8][8];
    #pragma unroll
    for (int i = 0; i < 8; i++)
        #pragma unroll
        for (int j = 0; j < 8; j++) acc[i][j] = 0.f;
    for (int k0 = 0; k0 < K; k0 += 8) {
        #pragma unroll
        for (int i = 0; i < 4; i++) {
            int lin = tid + i * 256;
            int kk = lin & 7, mm = lin >> 3;
            int gmm = m0 + mm, gk = k0 + kk;
            As[kk][mm] = (gmm < M && gk < K) ? A[(size_t)gmm * K + gk] : 0.f;
        }
        #pragma unroll
        for (int i = 0; i < 4; i++) {
            int lin = tid + i * 256;
            int nn = lin & 127, kk = lin >> 7;
            int gn = n0 + nn, gk = k0 + kk;
            Bs[kk][nn] = (gn < N && gk < K) ? B[(size_t)gk * N + gn] : 0.f;
        }
        __syncthreads();
        #pragma unroll
        for (int kk = 0; kk < 8; kk++) {
            float a[8], b[8];
            *(float4*)&a[0] = *(const float4*)&As[kk][ty * 8];
            *(float4*)&a[4] = *(const float4*)&As[kk][ty * 8 + 4];
            *(float4*)&b[0] = *(const float4*)&Bs[kk][tx * 8];
            *(float4*)&b[4] = *(const float4*)&Bs[kk][tx * 8 + 4];
            #pragma unroll
            for (int i = 0; i < 8; i++)
                #pragma unroll
                for (int j = 0; j < 8; j++) acc[i][j] += a[i] * b[j];
        }
        __syncthreads();
    }
    #pragma unroll
    for (int i = 0; i < 8; i++) {
        int gmm = m0 + ty * 8 + i;
        if (gmm >= M) continue;
        #pragma unroll
        for (int j = 0; j < 8; j++) {
            int gn = n0 + tx * 8 + j;
            if (gn >= N) continue;
            C[(size_t)gmm * N + gn] = acc[i][j];
        }
    }
}

// landmark means + fused bf16 splits
__global__ void landmark_kernel(const float* __restrict__ q, const float* __restrict__ k,
                                float* __restrict__ ql, float* __restrict__ kl,
                                __nv_bfloat16* __restrict__ qlh, __nv_bfloat16* __restrict__ qll,
                                __nv_bfloat16* __restrict__ klh, __nv_bfloat16* __restrict__ kll) {
    int bh = blockIdx.x, m = blockIdx.y;
    int dh = threadIdx.x;
    size_t base = ((size_t)bh * NTOK + (size_t)m * LSEG) * DH_ + dh;
    float aq = 0.f, ak = 0.f;
    #pragma unroll
    for (int i = 0; i < LSEG; i++) {
        aq += q[base + (size_t)i * DH_];
        ak += k[base + (size_t)i * DH_];
    }
    size_t o = ((size_t)bh * MLM + m) * DH_ + dh;
    float qv = aq * (1.f / LSEG), kv = ak * (1.f / LSEG);
    ql[o] = qv; kl[o] = kv;
    __nv_bfloat16 qh = __float2bfloat16(qv);
    qlh[o] = qh; qll[o] = __float2bfloat16(qv - __bfloat162float(qh));
    __nv_bfloat16 kh = __float2bfloat16(kv);
    klh[o] = kh; kll[o] = __float2bfloat16(kv - __bfloat162float(kh));
}

#define ATTN2_SMEM ((256 * 68 + 32 * 64 + 8) * 4)
__global__ void attn2_kernel(const float* __restrict__ ql, const float* __restrict__ kl,
                             float* __restrict__ X,
                             __nv_bfloat16* __restrict__ Xh, __nv_bfloat16* __restrict__ Xl) {
    extern __shared__ __align__(16) float sh2[];
    float* kls  = sh2;
    float* qs   = sh2 + 256 * 68;
    float* wsum = qs + 32 * 64;
    int bh = blockIdx.x, mt = blockIdx.y;
    int tid = threadIdx.x;
    #pragma unroll
    for (int i = 0; i < 16; i++) {
        int lin = tid + i * 256;
        int r = lin >> 4, c = lin & 15;
        *(float4*)&kls[r * 68 + c * 4] = *(const float4*)&kl[((size_t)bh * MLM + r) * DH_ + c * 4];
    }
    #pragma unroll
    for (int i = 0; i < 2; i++) {
        int lin = tid + i * 256;
        int r = lin >> 4, c = lin & 15;
        *(float4*)&qs[r * 64 + c * 4] = *(const float4*)&ql[((size_t)bh * MLM + mt * 32 + r) * DH_ + c * 4];
    }
    __syncthreads();
    int j = tid, wid = tid >> 5, lane = tid & 31;
    const float* kr = &kls[j * 68];
    for (int ml = 0; ml < 32; ml++) {
        const float* qr = &qs[ml * 64];
        float a0 = 0.f, a1 = 0.f, a2 = 0.f, a3 = 0.f;
        #pragma unroll
        for (int d4 = 0; d4 < 16; d4++) {
            float4 kv = *(const float4*)&kr[d4 * 4];
            float4 qv = *(const float4*)&qr[d4 * 4];
            a0 += qv.x * kv.x; a1 += qv.y * kv.y; a2 += qv.z * kv.z; a3 += qv.w * kv.w;
        }
        float e = fexp(a0 + a1 + a2 + a3);
        float t = e;
        #pragma unroll
        for (int o = 16; o > 0; o >>= 1) t += __shfl_xor_sync(0xffffffffu, t, o);
        if (lane == 0) wsum[wid] = t;
        __syncthreads();
        float S = 0.f;
        #pragma unroll
        for (int w = 0; w < 8; w++) S += wsum[w];
        float val = e * (1.f / S);
        size_t o = ((size_t)bh * MLM + mt * 32 + ml) * MLM + j;
        X[o] = val;
        __nv_bfloat16 h = __float2bfloat16(val);
        Xh[o] = h;
        Xl[o] = __float2bfloat16(val - __bfloat162float(h));
        __syncthreads();
    }
}

__global__ void initmax_kernel(unsigned* mb) { mb[0] = 0u; mb[1] = 0u; }
__global__ void rowcol_kernel(const float* __restrict__ X, unsigned* mb) {
    int bh = blockIdx.x, i = threadIdx.x;
    const float* Xm = X + (size_t)bh * MLM * MLM;
    float rs = 0.f, cs = 0.f;
    for (int j = 0; j < MLM; j++) {
        rs += fabsf(Xm[(size_t)i * MLM + j]);
        cs += fabsf(Xm[(size_t)j * MLM + i]);
    }
    #pragma unroll
    for (int o = 16; o > 0; o >>= 1) {
        rs = fmaxf(rs, __shfl_xor_sync(0xffffffffu, rs, o));
        cs = fmaxf(cs, __shfl_xor_sync(0xffffffffu, cs, o));
    }
    __shared__ float shr[8], shc[8];
    int w = i >> 5;
    if ((i & 31) == 0) { shr[w] = rs; shc[w] = cs; }
    __syncthreads();
    if (i == 0) {
        float mr = shr[0], mc = shc[0];
        #pragma unroll
        for (int k2 = 1; k2 < 8; k2++) { mr = fmaxf(mr, shr[k2]); mc = fmaxf(mc, shc[k2]); }
        atomicMax(&mb[0], __float_as_uint(mr));
        atomicMax(&mb[1], __float_as_uint(mc));
    }
}
__global__ void zinit_kernel(const float* __restrict__ X, const unsigned* __restrict__ mb,
                             __nv_bfloat16* __restrict__ Znh, __nv_bfloat16* __restrict__ Znl,
                             __nv_bfloat16* __restrict__ Zth, __nv_bfloat16* __restrict__ Ztl) {
    float inv = 1.f / (__uint_as_float(mb[0]) * __uint_as_float(mb[1]));
    size_t idx = (size_t)blockIdx.x * 256 + threadIdx.x;
    int bh = (int)(idx >> 16);
    int r = (int)((idx >> 8) & 255);
    int c = (int)(idx & 255);
    float tv = X[idx] * inv;
    __nv_bfloat16 th = __float2bfloat16(tv);
    Zth[idx] = th; Ztl[idx] = __float2bfloat16(tv - __bfloat162float(th));
    float nv = X[((size_t)bh << 16) + ((size_t)c << 8) + r] * inv;
    __nv_bfloat16 nh = __float2bfloat16(nv);
    Znh[idx] = nh; Znl[idx] = __float2bfloat16(nv - __bfloat162float(nh));
}

// attn3@v via MMA
#define A3_SMEM 93184
__global__ void __launch_bounds__(256, 1) attn3v_mma(
        const __nv_bfloat16* __restrict__ qlh_, const __nv_bfloat16* __restrict__ qll_,
        const __nv_bfloat16* __restrict__ kh_, const __nv_bfloat16* __restrict__ klo_,
        const __nv_bfloat16* __restrict__ vth_, const __nv_bfloat16* __restrict__ vtl_,
        float* __restrict__ Opart, float* __restrict__ denpart)
{
    extern __shared__ __align__(16) __nv_bfloat16 sm3[];
    uint32_t sb = smem_to_u32(sm3);
    int tid = threadIdx.x, wid = tid >> 5, lane = tid & 31;
    int chunk = blockIdx.x, bh = blockIdx.y;
    int key0 = chunk * (NTOK / NCHK);
    {
        size_t qb = (size_t)bh * MLM * DH_;
        #pragma unroll
        for (int i = 0; i < 8; i++) {
            int lin = tid + i * 256;
            int r = lin >> 3, c = lin & 7;
            *(uint4*)(sm3 + r * 72 + c * 8) = *(const uint4*)(qlh_ + qb + r * 64 + c * 8);
            *(uint4*)(sm3 + 18432 + r * 72 + c * 8) = *(const uint4*)(qll_ + qb + r * 64 + c * 8);
        }
    }
    __syncthreads();
    uint32_t Ah[2][4][4], Al[2][4][4];
    #pragma unroll
    for (int mf = 0; mf < 2; mf++) {
        int row = wid * 32 + mf * 16 + (lane & 15);
        #pragma unroll
        for (int ks = 0; ks < 4; ks++) {
            int col = ks * 16 + ((lane >> 4) << 3);
            ldsm4(Ah[mf][ks], sb + (uint32_t)(row * 72 + col) * 2);
            ldsm4(Al[mf][ks], sb + (uint32_t)(18432 + row * 72 + col) * 2);
        }
    }
    float Oacc[2][8][4];
    #pragma unroll
    for (int a = 0; a < 2; a++)
        #pragma unroll
        for (int b = 0; b < 8; b++)
            #pragma unroll
            for (int c = 0; c < 4; c++) Oacc[a][b][c] = 0.f;
    float den[2][2] = {{0.f, 0.f}, {0.f, 0.f}};

    for (int t32 = 0; t32 < (NTOK / NCHK) / 32; t32++) {
        int kt0 = key0 + t32 * 32;
        __syncthreads();
        {
            int r = tid >> 3, c = tid & 7;
            *(uint4*)(sm3 + 36864 + r * 72 + c * 8) = *(const uint4*)(kh_ + ((size_t)bh * NTOK + kt0 + r) * 64 + c * 8);
            *(uint4*)(sm3 + 39168 + r * 72 + c * 8) = *(const uint4*)(klo_ + ((size_t)bh * NTOK + kt0 + r) * 64 + c * 8);
            int r2 = tid >> 2, c2 = tid & 3;
            *(uint4*)(sm3 + 41472 + r2 * 40 + c2 * 8) = *(const uint4*)(vth_ + ((size_t)bh * 64 + r2) * NTOK + kt0 + c2 * 8);
            *(uint4*)(sm3 + 44032 + r2 * 40 + c2 * 8) = *(const uint4*)(vtl_ + ((size_t)bh * 64 + r2) * NTOK + kt0 + c2 * 8);
        }
        __syncthreads();
        float S[2][4][4];
        #pragma unroll
        for (int a = 0; a < 2; a++)
            #pragma unroll
            for (int b = 0; b < 4; b++)
                #pragma unroll
                for (int c = 0; c < 4; c++) S[a][b][c] = 0.f;
        #pragma unroll
        for (int ks = 0; ks < 4; ks++) {
            #pragma unroll
            for (int np = 0; np < 2; np++) {
                int row = np * 16 + ((lane >> 4) & 1) * 8 + (lane & 7);
                int col = ks * 16 + ((lane >> 3) & 1) * 8;
                uint32_t bh4[4], bl4[4];
                ldsm4(bh4, sb + (uint32_t)(36864 + row * 72 + col) * 2);
                ldsm4(bl4, sb + (uint32_t)(39168 + row * 72 + col) * 2);
                #pragma unroll
                for (int mf = 0; mf < 2; mf++) {
                    mma_bf16p(S[mf][2*np],   Ah[mf][ks], bh4[0], bh4[1]);
                    mma_bf16p(S[mf][2*np],   Ah[mf][ks], bl4[0], bl4[1]);
                    mma_bf16p(S[mf][2*np],   Al[mf][ks], bh4[0], bh4[1]);
                    mma_bf16p(S[mf][2*np+1], Ah[mf][ks], bh4[2], bh4[3]);
                    mma_bf16p(S[mf][2*np+1], Ah[mf][ks], bl4[2], bl4[3]);
                    mma_bf16p(S[mf][2*np+1], Al[mf][ks], bh4[2], bh4[3]);
                }
            }
        }
        #pragma unroll
        for (int kt = 0; kt < 2; kt++) {
            uint32_t pah[2][4], pal[2][4];
            #pragma unroll
            for (int mf = 0; mf < 2; mf++) {
                float e[8];
                #pragma unroll
                for (int j = 0; j < 4; j++) { e[j] = fexp(S[mf][2*kt][j]); e[4+j] = fexp(S[mf][2*kt+1][j]); }
                den[mf][0] += e[0] + e[1] + e[4] + e[5];
                den[mf][1] += e[2] + e[3] + e[6] + e[7];
                #pragma unroll
                for (int j = 0; j < 4; j++) {
                    __nv_bfloat162 h2 = __floats2bfloat162_rn(e[2*j], e[2*j+1]);
                    pah[mf][j] = *(uint32_t*)&h2;
                    float r0 = e[2*j]   - __bfloat162float(__low2bfloat16(h2));
                    float r1 = e[2*j+1] - __bfloat162float(__high2bfloat16(h2));
                    __nv_bfloat162 l2 = __floats2bfloat162_rn(r0, r1);
                    pal[mf][j] = *(uint32_t*)&l2;
                }
            }
            #pragma unroll
            for (int np = 0; np < 4; np++) {
                int row = np * 16 + ((lane >> 4) & 1) * 8 + (lane & 7);
                int col = kt * 16 + ((lane >> 3) & 1) * 8;
                uint32_t vh4[4], vl4[4];
                ldsm4(vh4, sb + (uint32_t)(41472 + row * 40 + col) * 2);
                ldsm4(vl4, sb + (uint32_t)(44032 + row * 40 + col) * 2);
                #pragma unroll
                for (int mf = 0; mf < 2; mf++) {
                    mma_bf16p(Oacc[mf][2*np],   pah[mf], vh4[0], vh4[1]);
                    mma_bf16p(Oacc[mf][2*np],   pah[mf], vl4[0], vl4[1]);
                    mma_bf16p(Oacc[mf][2*np],   pal[mf], vh4[0], vh4[1]);
                    mma_bf16p(Oacc[mf][2*np+1], pah[mf], vh4[2], vh4[3]);
                    mma_bf16p(Oacc[mf][2*np+1], pah[mf], vl4[2], vl4[3]);
                    mma_bf16p(Oacc[mf][2*np+1], pal[mf], vh4[2], vh4[3]);
                }
            }
        }
    }
    #pragma unroll
    for (int mf = 0; mf < 2; mf++)
        #pragma unroll
        for (int j = 0; j < 2; j++) {
            den[mf][j] += __shfl_xor_sync(0xffffffffu, den[mf][j], 1);
            den[mf][j] += __shfl_xor_sync(0xffffffffu, den[mf][j], 2);
        }
    int g = lane >> 2, t = lane & 3;
    size_t ob = ((size_t)chunk * BH + bh) * MLM * 64;
    #pragma unroll
    for (int mf = 0; mf < 2; mf++) {
        int lm0 = wid * 32 + mf * 16 + g;
        #pragma unroll
        for (int nf = 0; nf < 8; nf++) {
            int c = nf * 8 + t * 2;
            *(float2*)&Opart[ob + (size_t)lm0 * 64 + c] = make_float2(Oacc[mf][nf][0], Oacc[mf][nf][1]);
            *(float2*)&Opart[ob + (size_t)(lm0 + 8) * 64 + c] = make_float2(Oacc[mf][nf][2], Oacc[mf][nf][3]);
        }
        if (t == 0) {
            denpart[((size_t)chunk * BH + bh) * MLM + lm0] = den[mf][0];
            denpart[((size_t)chunk * BH + bh) * MLM + lm0 + 8] = den[mf][1];
        }
    }
}

__global__ void a3v_reduce(const float* __restrict__ Opart, const float* __restrict__ denpart,
                           float* __restrict__ A3V) {
    int idx = blockIdx.x * 256 + threadIdx.x;
    int bh = idx >> 14, lm = (idx >> 6) & 255;
    float s = 0.f, d = 0.f;
    #pragma unroll
    for (int c = 0; c < NCHK; c++) {
        s += Opart[((size_t)c * BH + bh) * 16384 + (idx & 16383)];
        d += denpart[((size_t)c * BH + bh) * 256 + lm];
    }
    A3V[idx] = s / d;
}

__global__ void conv_kernel(const float* __restrict__ v, const float* __restrict__ ker,
                            float* __restrict__ O) {
    int nt = blockIdx.x, h = blockIdx.y, b = blockIdx.z;
    int n0 = nt * 128;
    __shared__ float vsh[160][64];
    __shared__ float kw[KER_];
    int tid = threadIdx.x;
    if (tid < KER_) kw[tid] = ker[h * KER_ + tid];
    const float* vb = v + ((size_t)b * H_ + h) * NTOK * DH_;
    #pragma unroll
    for (int i = 0; i < 10; i++) {
        int f4 = tid + i * 256;
        int row2 = f4 >> 4, c4 = f4 & 15;
        int n = n0 - 16 + row2;
        float4 val = make_float4(0.f, 0.f, 0.f, 0.f);
        if (n >= 0 && n < NTOK) val = ((const float4*)(vb + (size_t)n * DH_))[c4];
        ((float4*)vsh)[f4] = val;
    }
    __syncthreads();
    int dh = tid & 63, g = tid >> 6;
    for (int ii = 0; ii < 32; ii++) {
        int nn = g * 32 + ii;
        float o = 0.f;
        #pragma unroll
        for (int t = 0; t < KER_; t++) o += kw[t] * vsh[nn + t][dh];
        O[((size_t)b * NTOK + (n0 + nn)) * D_ + h * DH_ + dh] = o;
    }
}

// attn1 via MMA, A1_TPB token tiles per block (kl/Y loaded once)
#define A1_SMEM 178176
__global__ void __launch_bounds__(256, 1) attn1_mma(
        const __nv_bfloat16* __restrict__ qh_, const __nv_bfloat16* __restrict__ qlo_,
        const __nv_bfloat16* __restrict__ klh_, const __nv_bfloat16* __restrict__ kll_,
        const __nv_bfloat16* __restrict__ yth_, const __nv_bfloat16* __restrict__ ytl_,
        float* __restrict__ O)
{
    extern __shared__ __align__(16) __nv_bfloat16 sm1[];
    uint32_t sb = smem_to_u32(sm1);
    int tid = threadIdx.x, wid = tid >> 5, lane = tid & 31;
    int bh = blockIdx.y;
    {
        size_t kb = (size_t)bh * MLM * DH_;
        #pragma unroll
        for (int i = 0; i < 8; i++) {
            int lin = tid + i * 256;
            int r = lin >> 3, c = lin & 7;
            *(uint4*)(sm1 + 18432 + r * 72 + c * 8) = *(const uint4*)(klh_ + kb + r * 64 + c * 8);
            *(uint4*)(sm1 + 36864 + r * 72 + c * 8) = *(const uint4*)(kll_ + kb + r * 64 + c * 8);
        }
        size_t yb = (size_t)bh * 64 * MLM;
        #pragma unroll
        for (int i = 0; i < 8; i++) {
            int lin = tid + i * 256;
            int r = lin >> 5, c = lin & 31;
            *(uint4*)(sm1 + 55296 + r * 264 + c * 8) = *(const uint4*)(yth_ + yb + r * 256 + c * 8);
            *(uint4*)(sm1 + 72192 + r * 264 + c * 8) = *(const uint4*)(ytl_ + yb + r * 256 + c * 8);
        }
    }
    int b = bh >> 3, h = bh & 7;

    for (int tt = 0; tt < A1_TPB; tt++) {
        int tile0 = (blockIdx.x * A1_TPB + tt) * 128;
        __syncthreads();   // q buffers free (prev tile readers done) / kl-Y visible on first pass
        {
            size_t qb = ((size_t)bh * NTOK + tile0) * DH_;
            #pragma unroll
            for (int i = 0; i < 4; i++) {
                int lin = tid + i * 256;
                int r = lin >> 3, c = lin & 7;
                *(uint4*)(sm1 + r * 72 + c * 8) = *(const uint4*)(qh_ + qb + r * 64 + c * 8);
                *(uint4*)(sm1 + 9216 + r * 72 + c * 8) = *(const uint4*)(qlo_ + qb + r * 64 + c * 8);
            }
        }
        __syncthreads();
        uint32_t Ah[4][4], Al[4][4];
        {
            int row = wid * 16 + (lane & 15);
            #pragma unroll
            for (int ks = 0; ks < 4; ks++) {
                int col = ks * 16 + ((lane >> 4) << 3);
                ldsm4(Ah[ks], sb + (uint32_t)(row * 72 + col) * 2);
                ldsm4(Al[ks], sb + (uint32_t)(9216 + row * 72 + col) * 2);
            }
        }
        float Oacc[8][4];
        #pragma unroll
        for (int bb = 0; bb < 8; bb++)
            #pragma unroll
            for (int c = 0; c < 4; c++) Oacc[bb][c] = 0.f;
        float dlo = 0.f, dhi = 0.f;

        #pragma unroll
        for (int half = 0; half < 2; half++) {
            int lmb = half * 128;
            float S[16][4];
            #pragma unroll
            for (int bb = 0; bb < 16; bb++)
                #pragma unroll
                for (int c = 0; c < 4; c++) S[bb][c] = 0.f;
            #pragma unroll
            for (int ks = 0; ks < 4; ks++) {
                #pragma unroll
                for (int np = 0; np < 8; np++) {
                    int row = lmb + np * 16 + ((lane >> 4) & 1) * 8 + (lane & 7);
                    int col = ks * 16 + ((lane >> 3) & 1) * 8;
                    uint32_t bh4[4], bl4[4];
                    ldsm4(bh4, sb + (uint32_t)(18432 + row * 72 + col) * 2);
                    ldsm4(bl4, sb + (uint32_t)(36864 + row * 72 + col) * 2);
                    mma_bf16p(S[2*np],   Ah[ks], bh4[0], bh4[1]);
                    mma_bf16p(S[2*np],   Ah[ks], bl4[0], bl4[1]);
                    mma_bf16p(S[2*np],   Al[ks], bh4[0], bh4[1]);
                    mma_bf16p(S[2*np+1], Ah[ks], bh4[2], bh4[3]);
                    mma_bf16p(S[2*np+1], Ah[ks], bl4[2], bl4[3]);
                    mma_bf16p(S[2*np+1], Al[ks], bh4[2], bh4[3]);
                }
            }
            #pragma unroll
            for (int kt = 0; kt < 8; kt++) {
                float e[8];
                #pragma unroll
                for (int j = 0; j < 4; j++) { e[j] = fexp(S[2*kt][j]); e[4+j] = fexp(S[2*kt+1][j]); }
                dlo += e[0] + e[1] + e[4] + e[5];
                dhi += e[2] + e[3] + e[6] + e[7];
                uint32_t pah[4], pal[4];
                #pragma unroll
                for (int j = 0; j < 4; j++) {
                    __nv_bfloat162 h2 = __floats2bfloat162_rn(e[2*j], e[2*j+1]);
                    pah[j] = *(uint32_t*)&h2;
                    float r0 = e[2*j]   - __bfloat162float(__low2bfloat16(h2));
                    float r1 = e[2*j+1] - __bfloat162float(__high2bfloat16(h2));
                    __nv_bfloat162 l2 = __floats2bfloat162_rn(r0, r1);
                    pal[j] = *(uint32_t*)&l2;
                }
                #pragma unroll
                for (int np = 0; np < 4; np++) {
                    int row = np * 16 + ((lane >> 4) & 1) * 8 + (lane & 7);
                    int col = lmb + kt * 16 + ((lane >> 3) & 1) * 8;
                    uint32_t yh4[4], yl4[4];
                    ldsm4(yh4, sb + (uint32_t)(55296 + row * 264 + col) * 2);
                    ldsm4(yl4, sb + (uint32_t)(72192 + row * 264 + col) * 2);
                    mma_bf16p(Oacc[2*np],   pah, yh4[0], yh4[1]);
                    mma_bf16p(Oacc[2*np],   pah, yl4[0], yl4[1]);
                    mma_bf16p(Oacc[2*np],   pal, yh4[0], yh4[1]);
                    mma_bf16p(Oacc[2*np+1], pah, yh4[2], yh4[3]);
                    mma_bf16p(Oacc[2*np+1], pah, yl4[2], yl4[3]);
                    mma_bf16p(Oacc[2*np+1], pal, yh4[2], yh4[3]);
                }
            }
        }
        dlo += __shfl_xor_sync(0xffffffffu, dlo, 1);
        dlo += __shfl_xor_sync(0xffffffffu, dlo, 2);
        dhi += __shfl_xor_sync(0xffffffffu, dhi, 1);
        dhi += __shfl_xor_sync(0xffffffffu, dhi, 2);
        float ilo = 1.f / dlo, ihi = 1.f / dhi;
        int g = lane >> 2, t = lane & 3;
        int tok0 = tile0 + wid * 16 + g;
        size_t ob = ((size_t)b * NTOK + tok0) * D_ + h * DH_;
        #pragma unroll
        for (int nf = 0; nf < 8; nf++) {
            int c = nf * 8 + t * 2;
            float2* p0 = (float2*)&O[ob + c];
            float2 v0 = *p0;
            v0.x += Oacc[nf][0] * ilo; v0.y += Oacc[nf][1] * ilo;
            *p0 = v0;
            float2* p1 = (float2*)&O[ob + (size_t)8 * D_ + c];
            float2 v1 = *p1;
            v1.x += Oacc[nf][2] * ihi; v1.y += Oacc[nf][3] * ihi;
            *p1 = v1;
        }
    }
}

__global__ void osplit_kernel(const float* __restrict__ O, __nv_bfloat16* __restrict__ hi,
                              __nv_bfloat16* __restrict__ lo) {
    size_t idx = (size_t)blockIdx.x * 256 + threadIdx.x;
    float v = O[idx];
    __nv_bfloat16 h = __float2bfloat16(v);
    hi[idx] = h;
    lo[idx] = __float2bfloat16(v - __bfloat162float(h));
}

extern "C" void kernel_launch(void* const* d_in, const int* in_sizes, int n_in,
                              void* d_out, int out_size) {
    const float* x      = (const float*)d_in[0];
    const float* gamma  = (const float*)d_in[1];
    const float* beta   = (const float*)d_in[2];
    const float* w_qkv  = (const float*)d_in[3];
    const float* res_k  = (const float*)d_in[4];
    const float* w_out  = (const float*)d_in[5];
    const float* b_out  = (const float*)d_in[6];
    float* out = (float*)d_out;

    __nv_bfloat16 *nh, *nl, *wqh, *wql, *woh, *wol, *Oh, *Ol, *Xh, *Xl;
    __nv_bfloat16 *Znh[2], *Znl[2], *Zth[2], *Ztl[2], *XZh, *XZl, *WtAh, *WtAl, *WtBh, *WtBl;
    __nv_bfloat16 *qbh, *qbl, *kbh, *kbl, *vth, *vtl, *qlh, *qll, *klh, *kll, *yth, *ytl;
    float *q, *k, *v, *ql, *kl, *X, *Zf, *A3V, *Y, *O, *Opart, *dpart;
    unsigned* mb;
    cudaGetSymbolAddress((void**)&nh, g_nh);
    cudaGetSymbolAddress((void**)&nl, g_nl);
    cudaGetSymbolAddress((void**)&wqh, g_wqh);
    cudaGetSymbolAddress((void**)&wql, g_wql);
    cudaGetSymbolAddress((void**)&woh, g_woh);
    cudaGetSymbolAddress((void**)&wol, g_wol);
    cudaGetSymbolAddress((void**)&Oh, g_Oh);
    cudaGetSymbolAddress((void**)&Ol, g_Ol);
    cudaGetSymbolAddress((void**)&Xh, g_Xh);
    cudaGetSymbolAddress((void**)&Xl, g_Xl);
    {
        __nv_bfloat16* p;
        cudaGetSymbolAddress((void**)&p, g_Znh); Znh[0] = p; Znh[1] = p + (size_t)BH*MLM*MLM;
        cudaGetSymbolAddress((void**)&p, g_Znl); Znl[0] = p; Znl[1] = p + (size_t)BH*MLM*MLM;
        cudaGetSymbolAddress((void**)&p, g_Zth); Zth[0] = p; Zth[1] = p + (size_t)BH*MLM*MLM;
        cudaGetSymbolAddress((void**)&p, g_Ztl); Ztl[0] = p; Ztl[1] = p + (size_t)BH*MLM*MLM;
    }
    cudaGetSymbolAddress((void**)&XZh, g_XZh);
    cudaGetSymbolAddress((void**)&XZl, g_XZl);
    cudaGetSymbolAddress((void**)&WtAh, g_WtAh);
    cudaGetSymbolAddress((void**)&WtAl, g_WtAl);
    cudaGetSymbolAddress((void**)&WtBh, g_WtBh);
    cudaGetSymbolAddress((void**)&WtBl, g_WtBl);
    cudaGetSymbolAddress((void**)&q,  g_q);
    cudaGetSymbolAddress((void**)&k,  g_k);
    cudaGetSymbolAddress((void**)&v,  g_v);
    cudaGetSymbolAddress((void**)&qbh, g_qbh);
    cudaGetSymbolAddress((void**)&qbl, g_qbl);
    cudaGetSymbolAddress((void**)&kbh, g_kbh);
    cudaGetSymbolAddress((void**)&kbl, g_kbl);
    cudaGetSymbolAddress((void**)&vth, g_vth);
    cudaGetSymbolAddress((void**)&vtl, g_vtl);
    cudaGetSymbolAddress((void**)&ql, g_ql);
    cudaGetSymbolAddress((void**)&kl, g_kl);
    cudaGetSymbolAddress((void**)&qlh, g_qlh);
    cudaGetSymbolAddress((void**)&qll, g_qll);
    cudaGetSymbolAddress((void**)&klh, g_klh);
    cudaGetSymbolAddress((void**)&kll, g_kll);
    cudaGetSymbolAddress((void**)&yth, g_yth);
    cudaGetSymbolAddress((void**)&ytl, g_ytl);
    cudaGetSymbolAddress((void**)&X,  g_X);
    cudaGetSymbolAddress((void**)&Zf, g_Zf);
    cudaGetSymbolAddress((void**)&Opart, g_Opart);
    cudaGetSymbolAddress((void**)&dpart, g_dpart);
    cudaGetSymbolAddress((void**)&A3V, g_A3V);
    cudaGetSymbolAddress((void**)&Y,  g_Y);
    cudaGetSymbolAddress((void**)&O,  g_O);
    cudaGetSymbolAddress((void**)&mb, g_maxbits);

    cudaFuncSetAttribute(attn2_kernel, cudaFuncAttributeMaxDynamicSharedMemorySize, ATTN2_SMEM);
    cudaFuncSetAttribute(tc_gemm<1>, cudaFuncAttributeMaxDynamicSharedMemorySize, TCG_SMEM);
    cudaFuncSetAttribute(tc_gemm<2>, cudaFuncAttributeMaxDynamicSharedMemorySize, TCG_SMEM);
    cudaFuncSetAttribute(attn3v_mma, cudaFuncAttributeMaxDynamicSharedMemorySize, A3_SMEM);
    cudaFuncSetAttribute(attn1_mma, cudaFuncAttributeMaxDynamicSharedMemorySize, A1_SMEM);

    const size_t sM = (size_t)MLM * MLM;

    ln_kernel<<<B_ * NTOK, 256>>>(x, gamma, beta, nh, nl);
    tsplit_kernel<<<(D_ * 3 * D_ + 255) / 256, 256>>>(w_qkv, wqh, wql, D_, 3 * D_);
    tsplit_kernel<<<(D_ * D_ + 255) / 256, 256>>>(w_out, woh, wol, D_, D_);

    tc_gemm<2><<<dim3(12, 256, 1), 256, TCG_SMEM>>>(nh, nl, wqh, wql, D_, 0, 0, 0,
        q, k, v, nullptr, nullptr, nullptr,
        qbh, qbl, kbh, kbl, nullptr, 1.f, 0.f, 1.f);

    vtrans_kernel<<<dim3(NTOK / 64, BH), 256>>>(v, vth, vtl);
    landmark_kernel<<<dim3(BH, MLM), 64>>>(q, k, ql, kl, qlh, qll, klh, kll);

    attn2_kernel<<<dim3(BH, 8), 256, ATTN2_SMEM>>>(ql, kl, X, Xh, Xl);
    initmax_kernel<<<1, 1>>>(mb);
    rowcol_kernel<<<BH, 256>>>(X, mb);
    zinit_kernel<<<8192, 256>>>(X, mb, Znh[0], Znl[0], Zth[0], Ztl[0]);

    int cur = 0;
    for (int it = 0; it < 6; it++) {
        int nxt = cur ^ 1;
        if (it < 5) {
            tc_gemm<1><<<dim3(2, 2, BH), 256, TCG_SMEM>>>(Xh, Xl, Zth[cur], Ztl[cur], MLM, sM, sM, 2,
                nullptr, nullptr, nullptr, nullptr, nullptr, nullptr,
                XZh, XZl, WtAh, WtAl, nullptr, 1.f, 7.f, 1.f);
            tc_gemm<1><<<dim3(2, 2, BH), 256, TCG_SMEM>>>(XZh, XZl, WtAh, WtAl, MLM, sM, sM, 2,
                nullptr, nullptr, nullptr, nullptr, nullptr, nullptr,
                nullptr, nullptr, WtBh, WtBl, nullptr, 1.f, 15.f, 1.f);
            tc_gemm<1><<<dim3(2, 2, BH), 256, TCG_SMEM>>>(XZh, XZl, WtBh, WtBl, MLM, sM, sM, 2,
                nullptr, nullptr, nullptr, nullptr, nullptr, nullptr,
                nullptr, nullptr, WtAh, WtAl, nullptr, 1.f, 13.f, 1.f);
            tc_gemm<1><<<dim3(2, 2, BH), 256, TCG_SMEM>>>(Znh[cur], Znl[cur], WtAh, WtAl, MLM, sM, sM, 2,
                nullptr, nullptr, nullptr, nullptr, nullptr, nullptr,
                Znh[nxt], Znl[nxt], Zth[nxt], Ztl[nxt], nullptr, 0.25f, 0.f, -0.25f);
        } else {
            tc_gemm<2><<<dim3(2, 2, BH), 256, TCG_SMEM>>>(Xh, Xl, Zth[cur], Ztl[cur], MLM, sM, sM, 2,
                nullptr, nullptr, nullptr, nullptr, nullptr, nullptr,
                XZh, XZl, WtAh, WtAl, nullptr, 1.f, 7.f, 1.f);
            tc_gemm<2><<<dim3(2, 2, BH), 256, TCG_SMEM>>>(XZh, XZl, WtAh, WtAl, MLM, sM, sM, 2,
                nullptr, nullptr, nullptr, nullptr, nullptr, nullptr,
                nullptr, nullptr, WtBh, WtBl, nullptr, 1.f, 15.f, 1.f);
            tc_gemm<2><<<dim3(2, 2, BH), 256, TCG_SMEM>>>(XZh, XZl, WtBh, WtBl, MLM, sM, sM, 2,
                nullptr, nullptr, nullptr, nullptr, nullptr, nullptr,
                nullptr, nullptr, WtAh, WtAl, nullptr, 1.f, 13.f, 1.f);
            tc_gemm<2><<<dim3(2, 2, BH), 256, TCG_SMEM>>>(Znh[cur], Znl[cur], WtAh, WtAl, MLM, sM, sM, 2,
                nullptr, nullptr, nullptr, nullptr, nullptr, nullptr,
                Znh[nxt], Znl[nxt], Zth[nxt], Ztl[nxt], Zf, 0.25f, 0.f, -0.25f);
        }
        cur = nxt;
    }

    attn3v_mma<<<dim3(NCHK, BH), 256, A3_SMEM>>>(qlh, qll, kbh, kbl, vth, vtl, Opart, dpart);
    a3v_reduce<<<2048, 256>>>(Opart, dpart, A3V);

    sgemm_kernel<<<dim3(1, 2, BH), 256>>>(Zf, A3V, Y, MLM, DH_, MLM,
        sM, (size_t)MLM * DH_, (size_t)MLM * DH_);
    ytrans_kernel<<<BH, 256>>>(Y, yth, ytl);

    conv_kernel<<<dim3(64, H_, B_), 256>>>(v, res_k, O);
    attn1_mma<<<dim3(NTOK / 128 / A1_TPB, BH), 256, A1_SMEM>>>(qbh, qbl, klh, kll, yth, ytl, O);

    osplit_kernel<<<(int)(((size_t)B_*NTOK*D_) / 256), 256>>>(O, Oh, Ol);
    tc_gemm<2><<<dim3(4, 256, 1), 256, TCG_SMEM>>>(Oh, Ol, woh, wol, D_, 0, 0, 1,
        nullptr, nullptr, nullptr, out, b_out, x,
        nullptr, nullptr, nullptr, nullptr, nullptr, 1.f, 0.f, 1.f);
}

// round 13
// speedup vs baseline: 6.2482x; 1.0180x over previous
#include <cuda_runtime.h>
#include <cuda_bf16.h>
#include <math.h>
#include <stdint.h>

#define B_    4
#define NTOK  8192
#define D_    512
#define H_    8
#define DH_   64
#define MLM   256
#define LSEG  32
#define BH    (B_*H_)
#define KER_  33
#define NCHK  8
#define A1_TPB 4

__device__ __forceinline__ uint32_t smem_to_u32(const void* p) {
    uint32_t a;
    asm("{ .reg .u64 t; cvta.to.shared.u64 t, %1; cvt.u32.u64 %0, t; }" : "=r"(a) : "l"(p));
    return a;
}
__device__ __forceinline__ void cp_async16(uint32_t saddr, const void* gptr) {
    asm volatile("cp.async.cg.shared.global [%0], [%1], 16;" :: "r"(saddr), "l"(gptr));
}
#define CP_COMMIT() asm volatile("cp.async.commit_group;" ::: "memory")
#define CP_WAIT0()  asm volatile("cp.async.wait_group 0;" ::: "memory")
__device__ __forceinline__ void mma_bf16p(float (&d)[4], const uint32_t (&a)[4], uint32_t b0, uint32_t b1) {
    asm volatile("mma.sync.aligned.m16n8k16.row.col.f32.bf16.bf16.f32 "
        "{%0,%1,%2,%3}, {%4,%5,%6,%7}, {%8,%9}, {%0,%1,%2,%3};"
        : "+f"(d[0]), "+f"(d[1]), "+f"(d[2]), "+f"(d[3])
        : "r"(a[0]), "r"(a[1]), "r"(a[2]), "r"(a[3]), "r"(b0), "r"(b1));
}
__device__ __forceinline__ void ldsm4(uint32_t (&r)[4], uint32_t a) {
    asm volatile("ldmatrix.sync.aligned.m8n8.x4.shared.b16 {%0,%1,%2,%3}, [%4];"
        : "=r"(r[0]), "=r"(r[1]), "=r"(r[2]), "=r"(r[3]) : "r"(a));
}
__device__ __forceinline__ float fexp(float s) {
    float t = s * 1.44269504088896341f;
    float i = rintf(t);
    float f = t - i;
    float p = 1.54035303933816e-4f;
    p = p * f + 1.33335581464284e-3f;
    p = p * f + 9.61812910762848e-3f;
    p = p * f + 5.55041086648216e-2f;
    p = p * f + 2.40226506959101e-1f;
    p = p * f + 6.93147180559945e-1f;
    p = p * f + 1.0f;
    return p * __int_as_float(((int)i + 127) << 23);
}

// scratch
__device__ __nv_bfloat16 g_nh[(size_t)B_*NTOK*D_];
__device__ __nv_bfloat16 g_nl[(size_t)B_*NTOK*D_];
__device__ __nv_bfloat16 g_wqh[(size_t)3*D_*D_];
__device__ __nv_bfloat16 g_wql[(size_t)3*D_*D_];
__device__ __nv_bfloat16 g_woh[(size_t)D_*D_];
__device__ __nv_bfloat16 g_wol[(size_t)D_*D_];
__device__ __nv_bfloat16 g_Oh[(size_t)B_*NTOK*D_];
__device__ __nv_bfloat16 g_Ol[(size_t)B_*NTOK*D_];
__device__ float g_q [(size_t)BH*NTOK*DH_];
__device__ float g_k [(size_t)BH*NTOK*DH_];
__device__ float g_v [(size_t)BH*NTOK*DH_];
__device__ __nv_bfloat16 g_qbh[(size_t)BH*NTOK*DH_];
__device__ __nv_bfloat16 g_qbl[(size_t)BH*NTOK*DH_];
__device__ __nv_bfloat16 g_kbh[(size_t)BH*NTOK*DH_];
__device__ __nv_bfloat16 g_kbl[(size_t)BH*NTOK*DH_];
__device__ __nv_bfloat16 g_vth[(size_t)BH*NTOK*DH_];
__device__ __nv_bfloat16 g_vtl[(size_t)BH*NTOK*DH_];
__device__ float g_ql[(size_t)BH*MLM*DH_];
__device__ float g_kl[(size_t)BH*MLM*DH_];
__device__ __nv_bfloat16 g_qlh[(size_t)BH*MLM*DH_];
__device__ __nv_bfloat16 g_qll[(size_t)BH*MLM*DH_];
__device__ __nv_bfloat16 g_klh[(size_t)BH*MLM*DH_];
__device__ __nv_bfloat16 g_kll[(size_t)BH*MLM*DH_];
__device__ __nv_bfloat16 g_yth[(size_t)BH*MLM*DH_];
__device__ __nv_bfloat16 g_ytl[(size_t)BH*MLM*DH_];
__device__ float g_X [(size_t)BH*MLM*MLM];
__device__ __nv_bfloat16 g_Xh[(size_t)BH*MLM*MLM];
__device__ __nv_bfloat16 g_Xl[(size_t)BH*MLM*MLM];
__device__ __nv_bfloat16 g_Znh[2][(size_t)BH*MLM*MLM];
__device__ __nv_bfloat16 g_Znl[2][(size_t)BH*MLM*MLM];
__device__ __nv_bfloat16 g_Zth[2][(size_t)BH*MLM*MLM];
__device__ __nv_bfloat16 g_Ztl[2][(size_t)BH*MLM*MLM];
__device__ __nv_bfloat16 g_XZh[(size_t)BH*MLM*MLM];
__device__ __nv_bfloat16 g_XZl[(size_t)BH*MLM*MLM];
__device__ __nv_bfloat16 g_WtAh[(size_t)BH*MLM*MLM];
__device__ __nv_bfloat16 g_WtAl[(size_t)BH*MLM*MLM];
__device__ __nv_bfloat16 g_WtBh[(size_t)BH*MLM*MLM];
__device__ __nv_bfloat16 g_WtBl[(size_t)BH*MLM*MLM];
__device__ float g_Zf[(size_t)BH*MLM*MLM];
__device__ float g_Opart[(size_t)NCHK*BH*MLM*DH_];
__device__ float g_dpart[(size_t)NCHK*BH*MLM];
__device__ float g_A3V[(size_t)BH*MLM*DH_];
__device__ float g_Y  [(size_t)BH*MLM*DH_];
__device__ float g_O  [(size_t)B_*NTOK*D_];
__device__ unsigned g_maxbits[2];
__device__ unsigned g_bar_count;
__device__ unsigned g_bar_gen;

__global__ void ln_kernel(const float* __restrict__ x, const float* __restrict__ gamma,
                          const float* __restrict__ beta,
                          __nv_bfloat16* __restrict__ ohi, __nv_bfloat16* __restrict__ olo) {
    int row = blockIdx.x, tid = threadIdx.x;
    const float* xr = x + (size_t)row * D_;
    float v0 = xr[tid], v1 = xr[tid + 256];
    float s = v0 + v1, s2 = v0*v0 + v1*v1;
    #pragma unroll
    for (int o = 16; o > 0; o >>= 1) {
        s  += __shfl_xor_sync(0xffffffffu, s,  o);
        s2 += __shfl_xor_sync(0xffffffffu, s2, o);
    }
    __shared__ float sh[16];
    int w = tid >> 5;
    if ((tid & 31) == 0) { sh[w] = s; sh[w + 8] = s2; }
    __syncthreads();
    if (tid == 0) {
        float a = 0.f, b2 = 0.f;
        #pragma unroll
        for (int i = 0; i < 8; i++) { a += sh[i]; b2 += sh[i + 8]; }
        sh[0] = a; sh[8] = b2;
    }
    __syncthreads();
    float mu  = sh[0] * (1.f / D_);
    float var = sh[8] * (1.f / D_) - mu * mu;
    float inv = rsqrtf(var + 1e-5f);
    size_t base = (size_t)row * D_;
    #pragma unroll
    for (int half = 0; half < 2; half++) {
        int c = tid + half * 256;
        float v = (half == 0 ? v0 : v1);
        float nv = (v - mu) * inv * gamma[c] + beta[c];
        __nv_bfloat16 hi = __float2bfloat16(nv);
        ohi[base + c] = hi;
        olo[base + c] = __float2bfloat16(nv - __bfloat162float(hi));
    }
}

__global__ void tsplit_kernel(const float* __restrict__ W, __nv_bfloat16* __restrict__ Thi,
                              __nv_bfloat16* __restrict__ Tlo, int K, int N) {
    int idx = blockIdx.x * 256 + threadIdx.x;
    if (idx >= K * N) return;
    int k = idx / N, n = idx % N;
    float v = W[idx];
    __nv_bfloat16 hi = __float2bfloat16(v);
    Thi[(size_t)n * K + k] = hi;
    Tlo[(size_t)n * K + k] = __float2bfloat16(v - __bfloat162float(hi));
}
__global__ void vtrans_kernel(const float* __restrict__ v, __nv_bfloat16* __restrict__ vth,
                              __nv_bfloat16* __restrict__ vtl) {
    __shared__ float ts[64][68];
    int bh = blockIdx.y, k0 = blockIdx.x * 64;
    int tid = threadIdx.x;
    const float* vb = v + ((size_t)bh * NTOK + k0) * DH_;
    #pragma unroll
    for (int i = 0; i < 4; i++) {
        int lin = tid + i * 256;
        int r = lin >> 4, c4 = lin & 15;
        *(float4*)&ts[r][c4 * 4] = *(const float4*)(vb + r * 64 + c4 * 4);
    }
    __syncthreads();
    #pragma unroll
    for (int i = 0; i < 16; i++) {
        int lin = tid + i * 256;
        int dh = lin >> 6, ky = lin & 63;
        float val = ts[ky][dh];
        __nv_bfloat16 h = __float2bfloat16(val);
        size_t o = ((size_t)bh * 64 + dh) * NTOK + k0 + ky;
        vth[o] = h;
        vtl[o] = __float2bfloat16(val - __bfloat162float(h));
    }
}
__global__ void ytrans_kernel(const float* __restrict__ Y, __nv_bfloat16* __restrict__ yth,
                              __nv_bfloat16* __restrict__ ytl) {
    int bh = blockIdx.x, tid = threadIdx.x;
    #pragma unroll
    for (int i = 0; i < 64; i++) {
        int lin = tid + i * 256;
        int dh = lin >> 8, lm = lin & 255;
        float val = Y[(size_t)bh * 16384 + lm * 64 + dh];
        __nv_bfloat16 h = __float2bfloat16(val);
        size_t o = (size_t)bh * 16384 + dh * 256 + lm;
        yth[o] = h;
        ytl[o] = __float2bfloat16(val - __bfloat162float(h));
    }
}

// ---- shared GEMM tile mainloop ----
template<int NPASS>
__device__ __forceinline__ void gemm_tile_main(
        uint32_t sbase, int tid, int wid, int lane, int wm, int wn,
        const __nv_bfloat16* Ahi, const __nv_bfloat16* Alo,
        const __nv_bfloat16* Bhi, const __nv_bfloat16* Blo,
        int kdim, int m0, int n0, float (&acc)[2][8][4])
{
    const __nv_bfloat16* srcs[4] = {Ahi, Alo, Bhi, Blo};
    const int row0s[4] = {m0, m0, n0, n0};
    const int NB = (NPASS == 1) ? 2 : 4;
    int r_ld = tid >> 2, c_ld = tid & 3;
    int nch = kdim >> 5;
    #pragma unroll
    for (int bs = 0; bs < NB; bs++) {
        int bsel = (NPASS == 1) ? bs * 2 : bs;
        #pragma unroll
        for (int i = 0; i < 2; i++)
            cp_async16(sbase + (uint32_t)(bsel * 5120 + (r_ld + i * 64) * 40 + c_ld * 8) * 2,
                       srcs[bsel] + (size_t)(row0s[bsel] + r_ld + i * 64) * kdim + c_ld * 8);
    }
    CP_COMMIT();
    for (int ch = 0; ch < nch; ch++) {
        CP_WAIT0();
        __syncthreads();
        if (ch + 1 < nch) {
            int k0 = (ch + 1) << 5;
            uint32_t nxt_off = (uint32_t)((ch + 1) & 1) * 4 * 5120;
            #pragma unroll
            for (int bs = 0; bs < NB; bs++) {
                int bsel = (NPASS == 1) ? bs * 2 : bs;
                #pragma unroll
                for (int i = 0; i < 2; i++)
                    cp_async16(sbase + (uint32_t)(nxt_off + bsel * 5120 + (r_ld + i * 64) * 40 + c_ld * 8) * 2,
                               srcs[bsel] + (size_t)(row0s[bsel] + r_ld + i * 64) * kdim + k0 + c_ld * 8);
            }
            CP_COMMIT();
        }
        uint32_t stg_off = (uint32_t)(ch & 1) * 4 * 5120;
        #pragma unroll
        for (int ks = 0; ks < 32; ks += 16) {
            uint32_t Ah[2][4], Al[2][4];
            #pragma unroll
            for (int mf = 0; mf < 2; mf++) {
                int row = wm + mf * 16 + (lane & 15);
                int col = ks + ((lane >> 4) << 3);
                ldsm4(Ah[mf], sbase + (uint32_t)(stg_off + row * 40 + col) * 2);
                if (NPASS > 1) ldsm4(Al[mf], sbase + (uint32_t)(stg_off + 5120 + row * 40 + col) * 2);
            }
            #pragma unroll
            for (int p = 0; p < 4; p++) {
                int rowb = wn + (2 * p + (lane >> 4)) * 8 + (lane & 7);
                int colb = ks + ((lane >> 3) & 1) * 8;
                uint32_t Bh4[4], Bl4[4];
                ldsm4(Bh4, sbase + (uint32_t)(stg_off + 2 * 5120 + rowb * 40 + colb) * 2);
                if (NPASS > 1) ldsm4(Bl4, sbase + (uint32_t)(stg_off + 3 * 5120 + rowb * 40 + colb) * 2);
                #pragma unroll
                for (int mf = 0; mf < 2; mf++) {
                    mma_bf16p(acc[mf][2*p],   Ah[mf], Bh4[0], Bh4[1]);
                    mma_bf16p(acc[mf][2*p+1], Ah[mf], Bh4[2], Bh4[3]);
                    if (NPASS > 1) {
                        mma_bf16p(acc[mf][2*p],   Ah[mf], Bl4[0], Bl4[1]);
                        mma_bf16p(acc[mf][2*p+1], Ah[mf], Bl4[2], Bl4[3]);
                        mma_bf16p(acc[mf][2*p],   Al[mf], Bh4[0], Bh4[1]);
                        mma_bf16p(acc[mf][2*p+1], Al[mf], Bh4[2], Bh4[3]);
                    }
                }
            }
        }
    }
    __syncthreads();
}

__device__ __forceinline__ void stage_acc(char* smem, int tid, int wid, int lane, int wm, int wn,
                                          float (&acc)[2][8][4]) {
    float* stg = reinterpret_cast<float*>(smem);
    int r = lane >> 2, c = (lane & 3) * 2;
    #pragma unroll
    for (int mf = 0; mf < 2; mf++)
        #pragma unroll
        for (int nf = 0; nf < 8; nf++) {
            int rr = wm + mf * 16 + r, cc = wn + nf * 8 + c;
            *reinterpret_cast<float2*>(&stg[rr * 132 + cc]) = make_float2(acc[mf][nf][0], acc[mf][nf][1]);
            *reinterpret_cast<float2*>(&stg[(rr + 8) * 132 + cc]) = make_float2(acc[mf][nf][2], acc[mf][nf][3]);
        }
    __syncthreads();
}

// ---- standalone GEMM kernel (modes 0/1) ----
#define TCG_SMEM (2 * 4 * 5120 * 2)
template<int NPASS>
__global__ void __launch_bounds__(256, 2) tc_gemm(
        const __nv_bfloat16* __restrict__ Ahi, const __nv_bfloat16* __restrict__ Alo,
        const __nv_bfloat16* __restrict__ Bhi, const __nv_bfloat16* __restrict__ Blo,
        int K, int mode,
        float* __restrict__ qp, float* __restrict__ kp, float* __restrict__ vp,
        float* __restrict__ Cout, const float* __restrict__ bias, const float* __restrict__ addx,
        __nv_bfloat16* __restrict__ Nhi, __nv_bfloat16* __restrict__ Nlo,
        __nv_bfloat16* __restrict__ Thi, __nv_bfloat16* __restrict__ Tlo)
{
    extern __shared__ __align__(16) char smem[];
    uint32_t sbase = smem_to_u32(smem);
    int tid = threadIdx.x;
    int wid = tid >> 5, lane = tid & 31;
    int wm = (wid & 3) * 32, wn = (wid >> 2) * 64;
    int m0 = blockIdx.y * 128, n0 = blockIdx.x * 128;

    float acc[2][8][4];
    #pragma unroll
    for (int a = 0; a < 2; a++)
        #pragma unroll
        for (int b = 0; b < 8; b++)
            #pragma unroll
            for (int c = 0; c < 4; c++) acc[a][b][c] = 0.f;

    gemm_tile_main<NPASS>(sbase, tid, wid, lane, wm, wn, Ahi, Alo, Bhi, Blo, K, m0, n0, acc);
    stage_acc(smem, tid, wid, lane, wm, wn, acc);
    float* stg = reinterpret_cast<float*>(smem);

    if (mode == 0) {
        #pragma unroll 4
        for (int i = 0; i < 16; i++) {
            int lin = tid + (i << 8);
            int token = lin >> 5, c4 = lin & 31;
            int gn = n0 + (c4 << 2);
            float4 v = *reinterpret_cast<float4*>(&stg[token * 132 + (c4 << 2)]);
            int gmm = m0 + token;
            int b_ = gmm >> 13, n_ = gmm & 8191;
            int sec = gn >> 9, cc = gn & 511, h_ = cc >> 6, dh = cc & 63;
            size_t idx = ((((size_t)b_ * H_ + h_) * NTOK) + n_) * DH_ + dh;
            if (sec == 2) {
                *reinterpret_cast<float4*>(&vp[idx]) = v;
            } else {
                if (sec == 0) { v.x *= 0.125f; v.y *= 0.125f; v.z *= 0.125f; v.w *= 0.125f; }
                float* fp = (sec == 0) ? qp : kp;
                __nv_bfloat16* hp = (sec == 0) ? Nhi : Thi;
                __nv_bfloat16* lp = (sec == 0) ? Nlo : Tlo;
                *reinterpret_cast<float4*>(&fp[idx]) = v;
                float vv[4] = {v.x, v.y, v.z, v.w};
                __nv_bfloat16 hb[4], lb[4];
                #pragma unroll
                for (int t2 = 0; t2 < 4; t2++) {
                    hb[t2] = __float2bfloat16(vv[t2]);
                    lb[t2] = __float2bfloat16(vv[t2] - __bfloat162float(hb[t2]));
                }
                *reinterpret_cast<uint2*>(&hp[idx]) = *reinterpret_cast<uint2*>(hb);
                *reinterpret_cast<uint2*>(&lp[idx]) = *reinterpret_cast<uint2*>(lb);
            }
        }
    } else {
        #pragma unroll 4
        for (int i = 0; i < 16; i++) {
            int lin = tid + (i << 8);
            int token = lin >> 5, c4 = lin & 31;
            int gn = n0 + (c4 << 2);
            int gmm = m0 + token;
            float4 v = *reinterpret_cast<float4*>(&stg[token * 132 + (c4 << 2)]);
            float4 bb = *reinterpret_cast<const float4*>(&bias[gn]);
            float4 xx = *reinterpret_cast<const float4*>(&addx[(size_t)gmm * 512 + gn]);
            v.x += bb.x + xx.x; v.y += bb.y + xx.y; v.z += bb.z + xx.z; v.w += bb.w + xx.w;
            *reinterpret_cast<float4*>(&Cout[(size_t)gmm * 512 + gn]) = v;
        }
    }
}

// ---- persistent pinv ----
__device__ __forceinline__ void grid_barrier() {
    __syncthreads();
    if (threadIdx.x == 0) {
        __threadfence();
        unsigned gen = atomicAdd(&g_bar_gen, 0u);
        unsigned ticket = atomicAdd(&g_bar_count, 1u);
        if (ticket == 127u) {
            g_bar_count = 0u;
            __threadfence();
            atomicAdd(&g_bar_gen, 1u);
        } else {
            while (atomicAdd(&g_bar_gen, 0u) == gen) { }
        }
    }
    __syncthreads();
}

template<int NPASS>
__device__ __forceinline__ void pinv_stage(char* smem, uint32_t sbase,
        const __nv_bfloat16* Ahi, const __nv_bfloat16* Alo,
        const __nv_bfloat16* Bhi, const __nv_bfloat16* Blo,
        __nv_bfloat16* Nhi, __nv_bfloat16* Nlo,
        __nv_bfloat16* Thi, __nv_bfloat16* Tlo,
        float* Cf32, float alpha, float diagc, float beta,
        size_t oz, int m0, int n0)
{
    int tid = threadIdx.x;
    int wid = tid >> 5, lane = tid & 31;
    int wm = (wid & 3) * 32, wn = (wid >> 2) * 64;
    float acc[2][8][4];
    #pragma unroll
    for (int a = 0; a < 2; a++)
        #pragma unroll
        for (int b = 0; b < 8; b++)
            #pragma unroll
            for (int c = 0; c < 4; c++) acc[a][b][c] = 0.f;
    gemm_tile_main<NPASS>(sbase, tid, wid, lane, wm, wn,
        Ahi + oz, Alo + oz, Bhi + oz, Blo + oz, MLM, m0, n0, acc);
    stage_acc(smem, tid, wid, lane, wm, wn, acc);
    float* stg = reinterpret_cast<float*>(smem);
    if (Thi) {
        #pragma unroll 4
        for (int i = 0; i < 64; i++) {
            int idx = tid + (i << 8);
            int gn_l = idx >> 7, gm_l = idx & 127;
            int gmm = m0 + gm_l, gn = n0 + gn_l;
            float v = stg[gm_l * 132 + gn_l];
            float t = (gmm == gn ? diagc : 0.f) - beta * v;
            __nv_bfloat16 h = __float2bfloat16(t);
            Thi[oz + (size_t)gn * 256 + gmm] = h;
            Tlo[oz + (size_t)gn * 256 + gmm] = __float2bfloat16(t - __bfloat162float(h));
        }
    }
    if (Nhi) {
        #pragma unroll 4
        for (int i = 0; i < 16; i++) {
            int lin = tid + (i << 8);
            int token = lin >> 5, c4 = lin & 31;
            int gn = n0 + (c4 << 2);
            int gmm = m0 + token;
            float4 v = *reinterpret_cast<float4*>(&stg[token * 132 + (c4 << 2)]);
            float vv[4] = {v.x * alpha, v.y * alpha, v.z * alpha, v.w * alpha};
            __nv_bfloat16 h[4], l2[4];
            #pragma unroll
            for (int t2 = 0; t2 < 4; t2++) {
                h[t2] = __float2bfloat16(vv[t2]);
                l2[t2] = __float2bfloat16(vv[t2] - __bfloat162float(h[t2]));
            }
            *reinterpret_cast<uint2*>(&Nhi[oz + (size_t)gmm * 256 + gn]) = *reinterpret_cast<uint2*>(h);
            *reinterpret_cast<uint2*>(&Nlo[oz + (size_t)gmm * 256 + gn]) = *reinterpret_cast<uint2*>(l2);
        }
    }
    if (Cf32) {
        #pragma unroll 4
        for (int i = 0; i < 16; i++) {
            int lin = tid + (i << 8);
            int token = lin >> 5, c4 = lin & 31;
            int gn = n0 + (c4 << 2);
            int gmm = m0 + token;
            float4 v = *reinterpret_cast<float4*>(&stg[token * 132 + (c4 << 2)]);
            v.x *= alpha; v.y *= alpha; v.z *= alpha; v.w *= alpha;
            *reinterpret_cast<float4*>(&Cf32[oz + (size_t)gmm * 256 + gn]) = v;
        }
    }
    __syncthreads();
}

__global__ void __launch_bounds__(256, 2) pinv_persistent(
        const __nv_bfloat16* __restrict__ Xh, const __nv_bfloat16* __restrict__ Xl,
        __nv_bfloat16* __restrict__ Znh0, __nv_bfloat16* __restrict__ Znl0,
        __nv_bfloat16* __restrict__ Zth0, __nv_bfloat16* __restrict__ Ztl0,
        __nv_bfloat16* __restrict__ XZh, __nv_bfloat16* __restrict__ XZl,
        __nv_bfloat16* __restrict__ WtAh, __nv_bfloat16* __restrict__ WtAl,
        __nv_bfloat16* __restrict__ WtBh, __nv_bfloat16* __restrict__ WtBl,
        float* __restrict__ Zf)
{
    extern __shared__ __align__(16) char smem[];
    uint32_t sbase = smem_to_u32(smem);
    int b = blockIdx.x;
    size_t oz = (size_t)(b >> 2) * 65536;
    int m0 = ((b >> 1) & 1) * 128, n0 = (b & 1) * 128;
    const size_t SB = (size_t)BH * 65536;

    int cur = 0;
    for (int it = 0; it < 6; it++) {
        __nv_bfloat16* Znc = Znh0 + cur * SB; __nv_bfloat16* Znlc = Znl0 + cur * SB;
        __nv_bfloat16* Ztc = Zth0 + cur * SB; __nv_bfloat16* Ztlc = Ztl0 + cur * SB;
        int nxt = cur ^ 1;
        __nv_bfloat16* Znn = Znh0 + nxt * SB; __nv_bfloat16* Znln = Znl0 + nxt * SB;
        __nv_bfloat16* Ztn = Zth0 + nxt * SB; __nv_bfloat16* Ztln = Ztl0 + nxt * SB;
        if (it < 5) {
            pinv_stage<1>(smem, sbase, Xh, Xl, Ztc, Ztlc, XZh, XZl, WtAh, WtAl, nullptr, 1.f, 7.f, 1.f, oz, m0, n0);
            grid_barrier();
            pinv_stage<1>(smem, sbase, XZh, XZl, WtAh, WtAl, nullptr, nullptr, WtBh, WtBl, nullptr, 1.f, 15.f, 1.f, oz, m0, n0);
            grid_barrier();
            pinv_stage<1>(smem, sbase, XZh, XZl, WtBh, WtBl, nullptr, nullptr, WtAh, WtAl, nullptr, 1.f, 13.f, 1.f, oz, m0, n0);
            grid_barrier();
            pinv_stage<1>(smem, sbase, Znc, Znlc, WtAh, WtAl, Znn, Znln, Ztn, Ztln, nullptr, 0.25f, 0.f, -0.25f, oz, m0, n0);
            grid_barrier();
        } else {
            pinv_stage<2>(smem, sbase, Xh, Xl, Ztc, Ztlc, XZh, XZl, WtAh, WtAl, nullptr, 1.f, 7.f, 1.f, oz, m0, n0);
            grid_barrier();
            pinv_stage<2>(smem, sbase, XZh, XZl, WtAh, WtAl, nullptr, nullptr, WtBh, WtBl, nullptr, 1.f, 15.f, 1.f, oz, m0, n0);
            grid_barrier();
            pinv_stage<2>(smem, sbase, XZh, XZl, WtBh, WtBl, nullptr, nullptr, WtAh, WtAl, nullptr, 1.f, 13.f, 1.f, oz, m0, n0);
            grid_barrier();
            pinv_stage<2>(smem, sbase, Znc, Znlc, WtAh, WtAl, nullptr, nullptr, nullptr, nullptr, Zf, 0.25f, 0.f, -0.25f, oz, m0, n0);
        }
        cur = nxt;
    }
}

// SIMT SGEMM for Y = Zf @ A3V
__global__ void __launch_bounds__(256) sgemm_kernel(
        const float* __restrict__ A, const float* __restrict__ B, float* __restrict__ C,
        int M, int N, int K, size_t sA, size_t sB, size_t sC)
{
    int bz = blockIdx.z;
    A += (size_t)bz * sA; B += (size_t)bz * sB; C += (size_t)bz * sC;
    int m0 = blockIdx.y * 128, n0 = blockIdx.x * 128;
    __shared__ float As[8][128];
    __shared__ float Bs[8][128];
    int tid = threadIdx.x;
    int tx = tid & 15, ty = tid >> 4;
    float acc[8][8];
    #pragma unroll
    for (int i = 0; i < 8; i++)
        #pragma unroll
        for (int j = 0; j < 8; j++) acc[i][j] = 0.f;
    for (int k0 = 0; k0 < K; k0 += 8) {
        #pragma unroll
        for (int i = 0; i < 4; i++) {
            int lin = tid + i * 256;
            int kk = lin & 7, mm = lin >> 3;
            int gmm = m0 + mm, gk = k0 + kk;
            As[kk][mm] = (gmm < M && gk < K) ? A[(size_t)gmm * K + gk] : 0.f;
        }
        #pragma unroll
        for (int i = 0; i < 4; i++) {
            int lin = tid + i * 256;
            int nn = lin & 127, kk = lin >> 7;
            int gn = n0 + nn, gk = k0 + kk;
            Bs[kk][nn] = (gn < N && gk < K) ? B[(size_t)gk * N + gn] : 0.f;
        }
        __syncthreads();
        #pragma unroll
        for (int kk = 0; kk < 8; kk++) {
            float a[8], b[8];
            *(float4*)&a[0] = *(const float4*)&As[kk][ty * 8];
            *(float4*)&a[4] = *(const float4*)&As[kk][ty * 8 + 4];
            *(float4*)&b[0] = *(const float4*)&Bs[kk][tx * 8];
            *(float4*)&b[4] = *(const float4*)&Bs[kk][tx * 8 + 4];
            #pragma unroll
            for (int i = 0; i < 8; i++)
                #pragma unroll
                for (int j = 0; j < 8; j++) acc[i][j] += a[i] * b[j];
        }
        __syncthreads();
    }
    #pragma unroll
    for (int i = 0; i < 8; i++) {
        int gmm = m0 + ty * 8 + i;
        if (gmm >= M) continue;
        #pragma unroll
        for (int j = 0; j < 8; j++) {
            int gn = n0 + tx * 8 + j;
            if (gn >= N) continue;
            C[(size_t)gmm * N + gn] = acc[i][j];
        }
    }
}

__global__ void landmark_kernel(const float* __restrict__ q, const float* __restrict__ k,
                                float* __restrict__ ql, float* __restrict__ kl,
                                __nv_bfloat16* __restrict__ qlh, __nv_bfloat16* __restrict__ qll,
                                __nv_bfloat16* __restrict__ klh, __nv_bfloat16* __restrict__ kll) {
    int bh = blockIdx.x, m = blockIdx.y;
    int dh = threadIdx.x;
    size_t base = ((size_t)bh * NTOK + (size_t)m * LSEG) * DH_ + dh;
    float aq = 0.f, ak = 0.f;
    #pragma unroll
    for (int i = 0; i < LSEG; i++) {
        aq += q[base + (size_t)i * DH_];
        ak += k[base + (size_t)i * DH_];
    }
    size_t o = ((size_t)bh * MLM + m) * DH_ + dh;
    float qv = aq * (1.f / LSEG), kv = ak * (1.f / LSEG);
    ql[o] = qv; kl[o] = kv;
    __nv_bfloat16 qh = __float2bfloat16(qv);
    qlh[o] = qh; qll[o] = __float2bfloat16(qv - __bfloat162float(qh));
    __nv_bfloat16 kh = __float2bfloat16(kv);
    klh[o] = kh; kll[o] = __float2bfloat16(kv - __bfloat162float(kh));
}

#define ATTN2_SMEM ((256 * 68 + 32 * 64 + 8) * 4)
__global__ void attn2_kernel(const float* __restrict__ ql, const float* __restrict__ kl,
                             float* __restrict__ X,
                             __nv_bfloat16* __restrict__ Xh, __nv_bfloat16* __restrict__ Xl) {
    extern __shared__ __align__(16) float sh2[];
    float* kls  = sh2;
    float* qs   = sh2 + 256 * 68;
    float* wsum = qs + 32 * 64;
    int bh = blockIdx.x, mt = blockIdx.y;
    int tid = threadIdx.x;
    #pragma unroll
    for (int i = 0; i < 16; i++) {
        int lin = tid + i * 256;
        int r = lin >> 4, c = lin & 15;
        *(float4*)&kls[r * 68 + c * 4] = *(const float4*)&kl[((size_t)bh * MLM + r) * DH_ + c * 4];
    }
    #pragma unroll
    for (int i = 0; i < 2; i++) {
        int lin = tid + i * 256;
        int r = lin >> 4, c = lin & 15;
        *(float4*)&qs[r * 64 + c * 4] = *(const float4*)&ql[((size_t)bh * MLM + mt * 32 + r) * DH_ + c * 4];
    }
    __syncthreads();
    int j = tid, wid = tid >> 5, lane = tid & 31;
    const float* kr = &kls[j * 68];
    for (int ml = 0; ml < 32; ml++) {
        const float* qr = &qs[ml * 64];
        float a0 = 0.f, a1 = 0.f, a2 = 0.f, a3 = 0.f;
        #pragma unroll
        for (int d4 = 0; d4 < 16; d4++) {
            float4 kv = *(const float4*)&kr[d4 * 4];
            float4 qv = *(const float4*)&qr[d4 * 4];
            a0 += qv.x * kv.x; a1 += qv.y * kv.y; a2 += qv.z * kv.z; a3 += qv.w * kv.w;
        }
        float e = fexp(a0 + a1 + a2 + a3);
        float t = e;
        #pragma unroll
        for (int o = 16; o > 0; o >>= 1) t += __shfl_xor_sync(0xffffffffu, t, o);
        if (lane == 0) wsum[wid] = t;
        __syncthreads();
        float S = 0.f;
        #pragma unroll
        for (int w = 0; w < 8; w++) S += wsum[w];
        float val = e * (1.f / S);
        size_t o = ((size_t)bh * MLM + mt * 32 + ml) * MLM + j;
        X[o] = val;
        __nv_bfloat16 h = __float2bfloat16(val);
        Xh[o] = h;
        Xl[o] = __float2bfloat16(val - __bfloat162float(h));
        __syncthreads();
    }
}

__global__ void initmax_kernel(unsigned* mb) { mb[0] = 0u; mb[1] = 0u; g_bar_count = 0u; g_bar_gen = 0u; }
__global__ void rowcol_kernel(const float* __restrict__ X, unsigned* mb) {
    int bh = blockIdx.x, i = threadIdx.x;
    const float* Xm = X + (size_t)bh * MLM * MLM;
    float rs = 0.f, cs = 0.f;
    for (int j = 0; j < MLM; j++) {
        rs += fabsf(Xm[(size_t)i * MLM + j]);
        cs += fabsf(Xm[(size_t)j * MLM + i]);
    }
    #pragma unroll
    for (int o = 16; o > 0; o >>= 1) {
        rs = fmaxf(rs, __shfl_xor_sync(0xffffffffu, rs, o));
        cs = fmaxf(cs, __shfl_xor_sync(0xffffffffu, cs, o));
    }
    __shared__ float shr[8], shc[8];
    int w = i >> 5;
    if ((i & 31) == 0) { shr[w] = rs; shc[w] = cs; }
    __syncthreads();
    if (i == 0) {
        float mr = shr[0], mc = shc[0];
        #pragma unroll
        for (int k2 = 1; k2 < 8; k2++) { mr = fmaxf(mr, shr[k2]); mc = fmaxf(mc, shc[k2]); }
        atomicMax(&mb[0], __float_as_uint(mr));
        atomicMax(&mb[1], __float_as_uint(mc));
    }
}
__global__ void zinit_kernel(const float* __restrict__ X, const unsigned* __restrict__ mb,
                             __nv_bfloat16* __restrict__ Znh, __nv_bfloat16* __restrict__ Znl,
                             __nv_bfloat16* __restrict__ Zth, __nv_bfloat16* __restrict__ Ztl) {
    float inv = 1.f / (__uint_as_float(mb[0]) * __uint_as_float(mb[1]));
    size_t idx = (size_t)blockIdx.x * 256 + threadIdx.x;
    int bh = (int)(idx >> 16);
    int r = (int)((idx >> 8) & 255);
    int c = (int)(idx & 255);
    float tv = X[idx] * inv;
    __nv_bfloat16 th = __float2bfloat16(tv);
    Zth[idx] = th; Ztl[idx] = __float2bfloat16(tv - __bfloat162float(th));
    float nv = X[((size_t)bh << 16) + ((size_t)c << 8) + r] * inv;
    __nv_bfloat16 nh = __float2bfloat16(nv);
    Znh[idx] = nh; Znl[idx] = __float2bfloat16(nv - __bfloat162float(nh));
}

// attn3@v via MMA
#define A3_SMEM 93184
__global__ void __launch_bounds__(256, 1) attn3v_mma(
        const __nv_bfloat16* __restrict__ qlh_, const __nv_bfloat16* __restrict__ qll_,
        const __nv_bfloat16* __restrict__ kh_, const __nv_bfloat16* __restrict__ klo_,
        const __nv_bfloat16* __restrict__ vth_, const __nv_bfloat16* __restrict__ vtl_,
        float* __restrict__ Opart, float* __restrict__ denpart)
{
    extern __shared__ __align__(16) __nv_bfloat16 sm3[];
    uint32_t sb = smem_to_u32(sm3);
    int tid = threadIdx.x, wid = tid >> 5, lane = tid & 31;
    int chunk = blockIdx.x, bh = blockIdx.y;
    int key0 = chunk * (NTOK / NCHK);
    {
        size_t qb = (size_t)bh * MLM * DH_;
        #pragma unroll
        for (int i = 0; i < 8; i++) {
            int lin = tid + i * 256;
            int r = lin >> 3, c = lin & 7;
            *(uint4*)(sm3 + r * 72 + c * 8) = *(const uint4*)(qlh_ + qb + r * 64 + c * 8);
            *(uint4*)(sm3 + 18432 + r * 72 + c * 8) = *(const uint4*)(qll_ + qb + r * 64 + c * 8);
        }
    }
    __syncthreads();
    uint32_t Ah[2][4][4], Al[2][4][4];
    #pragma unroll
    for (int mf = 0; mf < 2; mf++) {
        int row = wid * 32 + mf * 16 + (lane & 15);
        #pragma unroll
        for (int ks = 0; ks < 4; ks++) {
            int col = ks * 16 + ((lane >> 4) << 3);
            ldsm4(Ah[mf][ks], sb + (uint32_t)(row * 72 + col) * 2);
            ldsm4(Al[mf][ks], sb + (uint32_t)(18432 + row * 72 + col) * 2);
        }
    }
    float Oacc[2][8][4];
    #pragma unroll
    for (int a = 0; a < 2; a++)
        #pragma unroll
        for (int b = 0; b < 8; b++)
            #pragma unroll
            for (int c = 0; c < 4; c++) Oacc[a][b][c] = 0.f;
    float den[2][2] = {{0.f, 0.f}, {0.f, 0.f}};

    for (int t32 = 0; t32 < (NTOK / NCHK) / 32; t32++) {
        int kt0 = key0 + t32 * 32;
        __syncthreads();
        {
            int r = tid >> 3, c = tid & 7;
            *(uint4*)(sm3 + 36864 + r * 72 + c * 8) = *(const uint4*)(kh_ + ((size_t)bh * NTOK + kt0 + r) * 64 + c * 8);
            *(uint4*)(sm3 + 39168 + r * 72 + c * 8) = *(const uint4*)(klo_ + ((size_t)bh * NTOK + kt0 + r) * 64 + c * 8);
            int r2 = tid >> 2, c2 = tid & 3;
            *(uint4*)(sm3 + 41472 + r2 * 40 + c2 * 8) = *(const uint4*)(vth_ + ((size_t)bh * 64 + r2) * NTOK + kt0 + c2 * 8);
            *(uint4*)(sm3 + 44032 + r2 * 40 + c2 * 8) = *(const uint4*)(vtl_ + ((size_t)bh * 64 + r2) * NTOK + kt0 + c2 * 8);
        }
        __syncthreads();
        float S[2][4][4];
        #pragma unroll
        for (int a = 0; a < 2; a++)
            #pragma unroll
            for (int b = 0; b < 4; b++)
                #pragma unroll
                for (int c = 0; c < 4; c++) S[a][b][c] = 0.f;
        #pragma unroll
        for (int ks = 0; ks < 4; ks++) {
            #pragma unroll
            for (int np = 0; np < 2; np++) {
                int row = np * 16 + ((lane >> 4) & 1) * 8 + (lane & 7);
                int col = ks * 16 + ((lane >> 3) & 1) * 8;
                uint32_t bh4[4], bl4[4];
                ldsm4(bh4, sb + (uint32_t)(36864 + row * 72 + col) * 2);
                ldsm4(bl4, sb + (uint32_t)(39168 + row * 72 + col) * 2);
                #pragma unroll
                for (int mf = 0; mf < 2; mf++) {
                    mma_bf16p(S[mf][2*np],   Ah[mf][ks], bh4[0], bh4[1]);
                    mma_bf16p(S[mf][2*np],   Ah[mf][ks], bl4[0], bl4[1]);
                    mma_bf16p(S[mf][2*np],   Al[mf][ks], bh4[0], bh4[1]);
                    mma_bf16p(S[mf][2*np+1], Ah[mf][ks], bh4[2], bh4[3]);
                    mma_bf16p(S[mf][2*np+1], Ah[mf][ks], bl4[2], bl4[3]);
                    mma_bf16p(S[mf][2*np+1], Al[mf][ks], bh4[2], bh4[3]);
                }
            }
        }
        #pragma unroll
        for (int kt = 0; kt < 2; kt++) {
            uint32_t pah[2][4], pal[2][4];
            #pragma unroll
            for (int mf = 0; mf < 2; mf++) {
                float e[8];
                #pragma unroll
                for (int j = 0; j < 4; j++) { e[j] = fexp(S[mf][2*kt][j]); e[4+j] = fexp(S[mf][2*kt+1][j]); }
                den[mf][0] += e[0] + e[1] + e[4] + e[5];
                den[mf][1] += e[2] + e[3] + e[6] + e[7];
                #pragma unroll
                for (int j = 0; j < 4; j++) {
                    __nv_bfloat162 h2 = __floats2bfloat162_rn(e[2*j], e[2*j+1]);
                    pah[mf][j] = *(uint32_t*)&h2;
                    float r0 = e[2*j]   - __bfloat162float(__low2bfloat16(h2));
                    float r1 = e[2*j+1] - __bfloat162float(__high2bfloat16(h2));
                    __nv_bfloat162 l2 = __floats2bfloat162_rn(r0, r1);
                    pal[mf][j] = *(uint32_t*)&l2;
                }
            }
            #pragma unroll
            for (int np = 0; np < 4; np++) {
                int row = np * 16 + ((lane >> 4) & 1) * 8 + (lane & 7);
                int col = kt * 16 + ((lane >> 3) & 1) * 8;
                uint32_t vh4[4], vl4[4];
                ldsm4(vh4, sb + (uint32_t)(41472 + row * 40 + col) * 2);
                ldsm4(vl4, sb + (uint32_t)(44032 + row * 40 + col) * 2);
                #pragma unroll
                for (int mf = 0; mf < 2; mf++) {
                    mma_bf16p(Oacc[mf][2*np],   pah[mf], vh4[0], vh4[1]);
                    mma_bf16p(Oacc[mf][2*np],   pah[mf], vl4[0], vl4[1]);
                    mma_bf16p(Oacc[mf][2*np],   pal[mf], vh4[0], vh4[1]);
                    mma_bf16p(Oacc[mf][2*np+1], pah[mf], vh4[2], vh4[3]);
                    mma_bf16p(Oacc[mf][2*np+1], pah[mf], vl4[2], vl4[3]);
                    mma_bf16p(Oacc[mf][2*np+1], pal[mf], vh4[2], vh4[3]);
                }
            }
        }
    }
    #pragma unroll
    for (int mf = 0; mf < 2; mf++)
        #pragma unroll
        for (int j = 0; j < 2; j++) {
            den[mf][j] += __shfl_xor_sync(0xffffffffu, den[mf][j], 1);
            den[mf][j] += __shfl_xor_sync(0xffffffffu, den[mf][j], 2);
        }
    int g = lane >> 2, t = lane & 3;
    size_t ob = ((size_t)chunk * BH + bh) * MLM * 64;
    #pragma unroll
    for (int mf = 0; mf < 2; mf++) {
        int lm0 = wid * 32 + mf * 16 + g;
        #pragma unroll
        for (int nf = 0; nf < 8; nf++) {
            int c = nf * 8 + t * 2;
            *(float2*)&Opart[ob + (size_t)lm0 * 64 + c] = make_float2(Oacc[mf][nf][0], Oacc[mf][nf][1]);
            *(float2*)&Opart[ob + (size_t)(lm0 + 8) * 64 + c] = make_float2(Oacc[mf][nf][2], Oacc[mf][nf][3]);
        }
        if (t == 0) {
            denpart[((size_t)chunk * BH + bh) * MLM + lm0] = den[mf][0];
            denpart[((size_t)chunk * BH + bh) * MLM + lm0 + 8] = den[mf][1];
        }
    }
}

__global__ void a3v_reduce(const float* __restrict__ Opart, const float* __restrict__ denpart,
                           float* __restrict__ A3V) {
    int idx = blockIdx.x * 256 + threadIdx.x;
    int bh = idx >> 14, lm = (idx >> 6) & 255;
    float s = 0.f, d = 0.f;
    #pragma unroll
    for (int c = 0; c < NCHK; c++) {
        s += Opart[((size_t)c * BH + bh) * 16384 + (idx & 16383)];
        d += denpart[((size_t)c * BH + bh) * 256 + lm];
    }
    A3V[idx] = s / d;
}

__global__ void conv_kernel(const float* __restrict__ v, const float* __restrict__ ker,
                            float* __restrict__ O) {
    int nt = blockIdx.x, h = blockIdx.y, b = blockIdx.z;
    int n0 = nt * 128;
    __shared__ float vsh[160][64];
    __shared__ float kw[KER_];
    int tid = threadIdx.x;
    if (tid < KER_) kw[tid] = ker[h * KER_ + tid];
    const float* vb = v + ((size_t)b * H_ + h) * NTOK * DH_;
    #pragma unroll
    for (int i = 0; i < 10; i++) {
        int f4 = tid + i * 256;
        int row2 = f4 >> 4, c4 = f4 & 15;
        int n = n0 - 16 + row2;
        float4 val = make_float4(0.f, 0.f, 0.f, 0.f);
        if (n >= 0 && n < NTOK) val = ((const float4*)(vb + (size_t)n * DH_))[c4];
        ((float4*)vsh)[f4] = val;
    }
    __syncthreads();
    int dh = tid & 63, g = tid >> 6;
    for (int ii = 0; ii < 32; ii++) {
        int nn = g * 32 + ii;
        float o = 0.f;
        #pragma unroll
        for (int t = 0; t < KER_; t++) o += kw[t] * vsh[nn + t][dh];
        O[((size_t)b * NTOK + (n0 + nn)) * D_ + h * DH_ + dh] = o;
    }
}

// attn1 via MMA, A1_TPB token tiles per block
#define A1_SMEM 178176
__global__ void __launch_bounds__(256, 1) attn1_mma(
        const __nv_bfloat16* __restrict__ qh_, const __nv_bfloat16* __restrict__ qlo_,
        const __nv_bfloat16* __restrict__ klh_, const __nv_bfloat16* __restrict__ kll_,
        const __nv_bfloat16* __restrict__ yth_, const __nv_bfloat16* __restrict__ ytl_,
        float* __restrict__ O)
{
    extern __shared__ __align__(16) __nv_bfloat16 sm1[];
    uint32_t sb = smem_to_u32(sm1);
    int tid = threadIdx.x, wid = tid >> 5, lane = tid & 31;
    int bh = blockIdx.y;
    {
        size_t kb = (size_t)bh * MLM * DH_;
        #pragma unroll
        for (int i = 0; i < 8; i++) {
            int lin = tid + i * 256;
            int r = lin >> 3, c = lin & 7;
            *(uint4*)(sm1 + 18432 + r * 72 + c * 8) = *(const uint4*)(klh_ + kb + r * 64 + c * 8);
            *(uint4*)(sm1 + 36864 + r * 72 + c * 8) = *(const uint4*)(kll_ + kb + r * 64 + c * 8);
        }
        size_t yb = (size_t)bh * 64 * MLM;
        #pragma unroll
        for (int i = 0; i < 8; i++) {
            int lin = tid + i * 256;
            int r = lin >> 5, c = lin & 31;
            *(uint4*)(sm1 + 55296 + r * 264 + c * 8) = *(const uint4*)(yth_ + yb + r * 256 + c * 8);
            *(uint4*)(sm1 + 72192 + r * 264 + c * 8) = *(const uint4*)(ytl_ + yb + r * 256 + c * 8);
        }
    }
    int b = bh >> 3, h = bh & 7;

    for (int tt = 0; tt < A1_TPB; tt++) {
        int tile0 = (blockIdx.x * A1_TPB + tt) * 128;
        __syncthreads();
        {
            size_t qb = ((size_t)bh * NTOK + tile0) * DH_;
            #pragma unroll
            for (int i = 0; i < 4; i++) {
                int lin = tid + i * 256;
                int r = lin >> 3, c = lin & 7;
                *(uint4*)(sm1 + r * 72 + c * 8) = *(const uint4*)(qh_ + qb + r * 64 + c * 8);
                *(uint4*)(sm1 + 9216 + r * 72 + c * 8) = *(const uint4*)(qlo_ + qb + r * 64 + c * 8);
            }
        }
        __syncthreads();
        uint32_t Ah[4][4], Al[4][4];
        {
            int row = wid * 16 + (lane & 15);
            #pragma unroll
            for (int ks = 0; ks < 4; ks++) {
                int col = ks * 16 + ((lane >> 4) << 3);
                ldsm4(Ah[ks], sb + (uint32_t)(row * 72 + col) * 2);
                ldsm4(Al[ks], sb + (uint32_t)(9216 + row * 72 + col) * 2);
            }
        }
        float Oacc[8][4];
        #pragma unroll
        for (int bb = 0; bb < 8; bb++)
            #pragma unroll
            for (int c = 0; c < 4; c++) Oacc[bb][c] = 0.f;
        float dlo = 0.f, dhi = 0.f;

        #pragma unroll
        for (int half = 0; half < 2; half++) {
            int lmb = half * 128;
            float S[16][4];
            #pragma unroll
            for (int bb = 0; bb < 16; bb++)
                #pragma unroll
                for (int c = 0; c < 4; c++) S[bb][c] = 0.f;
            #pragma unroll
            for (int ks = 0; ks < 4; ks++) {
                #pragma unroll
                for (int np = 0; np < 8; np++) {
                    int row = lmb + np * 16 + ((lane >> 4) & 1) * 8 + (lane & 7);
                    int col = ks * 16 + ((lane >> 3) & 1) * 8;
                    uint32_t bh4[4], bl4[4];
                    ldsm4(bh4, sb + (uint32_t)(18432 + row * 72 + col) * 2);
                    ldsm4(bl4, sb + (uint32_t)(36864 + row * 72 + col) * 2);
                    mma_bf16p(S[2*np],   Ah[ks], bh4[0], bh4[1]);
                    mma_bf16p(S[2*np],   Ah[ks], bl4[0], bl4[1]);
                    mma_bf16p(S[2*np],   Al[ks], bh4[0], bh4[1]);
                    mma_bf16p(S[2*np+1], Ah[ks], bh4[2], bh4[3]);
                    mma_bf16p(S[2*np+1], Ah[ks], bl4[2], bl4[3]);
                    mma_bf16p(S[2*np+1], Al[ks], bh4[2], bh4[3]);
                }
            }
            #pragma unroll
            for (int kt = 0; kt < 8; kt++) {
                float e[8];
                #pragma unroll
                for (int j = 0; j < 4; j++) { e[j] = fexp(S[2*kt][j]); e[4+j] = fexp(S[2*kt+1][j]); }
                dlo += e[0] + e[1] + e[4] + e[5];
                dhi += e[2] + e[3] + e[6] + e[7];
                uint32_t pah[4], pal[4];
                #pragma unroll
                for (int j = 0; j < 4; j++) {
                    __nv_bfloat162 h2 = __floats2bfloat162_rn(e[2*j], e[2*j+1]);
                    pah[j] = *(uint32_t*)&h2;
                    float r0 = e[2*j]   - __bfloat162float(__low2bfloat16(h2));
                    float r1 = e[2*j+1] - __bfloat162float(__high2bfloat16(h2));
                    __nv_bfloat162 l2 = __floats2bfloat162_rn(r0, r1);
                    pal[j] = *(uint32_t*)&l2;
                }
                #pragma unroll
                for (int np = 0; np < 4; np++) {
                    int row = np * 16 + ((lane >> 4) & 1) * 8 + (lane & 7);
                    int col = lmb + kt * 16 + ((lane >> 3) & 1) * 8;
                    uint32_t yh4[4], yl4[4];
                    ldsm4(yh4, sb + (uint32_t)(55296 + row * 264 + col) * 2);
                    ldsm4(yl4, sb + (uint32_t)(72192 + row * 264 + col) * 2);
                    mma_bf16p(Oacc[2*np],   pah, yh4[0], yh4[1]);
                    mma_bf16p(Oacc[2*np],   pah, yl4[0], yl4[1]);
                    mma_bf16p(Oacc[2*np],   pal, yh4[0], yh4[1]);
                    mma_bf16p(Oacc[2*np+1], pah, yh4[2], yh4[3]);
                    mma_bf16p(Oacc[2*np+1], pah, yl4[2], yl4[3]);
                    mma_bf16p(Oacc[2*np+1], pal, yh4[2], yh4[3]);
                }
            }
        }
        dlo += __shfl_xor_sync(0xffffffffu, dlo, 1);
        dlo += __shfl_xor_sync(0xffffffffu, dlo, 2);
        dhi += __shfl_xor_sync(0xffffffffu, dhi, 1);
        dhi += __shfl_xor_sync(0xffffffffu, dhi, 2);
        float ilo = 1.f / dlo, ihi = 1.f / dhi;
        int g = lane >> 2, t = lane & 3;
        int tok0 = tile0 + wid * 16 + g;
        size_t ob = ((size_t)b * NTOK + tok0) * D_ + h * DH_;
        #pragma unroll
        for (int nf = 0; nf < 8; nf++) {
            int c = nf * 8 + t * 2;
            float2* p0 = (float2*)&O[ob + c];
            float2 v0 = *p0;
            v0.x += Oacc[nf][0] * ilo; v0.y += Oacc[nf][1] * ilo;
            *p0 = v0;
            float2* p1 = (float2*)&O[ob + (size_t)8 * D_ + c];
            float2 v1 = *p1;
            v1.x += Oacc[nf][2] * ihi; v1.y += Oacc[nf][3] * ihi;
            *p1 = v1;
        }
    }
}

__global__ void osplit_kernel(const float* __restrict__ O, __nv_bfloat16* __restrict__ hi,
                              __nv_bfloat16* __restrict__ lo) {
    size_t idx = (size_t)blockIdx.x * 256 + threadIdx.x;
    float v = O[idx];
    __nv_bfloat16 h = __float2bfloat16(v);
    hi[idx] = h;
    lo[idx] = __float2bfloat16(v - __bfloat162float(h));
}

extern "C" void kernel_launch(void* const* d_in, const int* in_sizes, int n_in,
                              void* d_out, int out_size) {
    const float* x      = (const float*)d_in[0];
    const float* gamma  = (const float*)d_in[1];
    const float* beta   = (const float*)d_in[2];
    const float* w_qkv  = (const float*)d_in[3];
    const float* res_k  = (const float*)d_in[4];
    const float* w_out  = (const float*)d_in[5];
    const float* b_out  = (const float*)d_in[6];
    float* out = (float*)d_out;

    __nv_bfloat16 *nh, *nl, *wqh, *wql, *woh, *wol, *Oh, *Ol, *Xh, *Xl;
    __nv_bfloat16 *Znh, *Znl, *Zth, *Ztl, *XZh, *XZl, *WtAh, *WtAl, *WtBh, *WtBl;
    __nv_bfloat16 *qbh, *qbl, *kbh, *kbl, *vth, *vtl, *qlh, *qll, *klh, *kll, *yth, *ytl;
    float *q, *k, *v, *ql, *kl, *X, *Zf, *A3V, *Y, *O, *Opart, *dpart;
    unsigned* mb;
    cudaGetSymbolAddress((void**)&nh, g_nh);
    cudaGetSymbolAddress((void**)&nl, g_nl);
    cudaGetSymbolAddress((void**)&wqh, g_wqh);
    cudaGetSymbolAddress((void**)&wql, g_wql);
    cudaGetSymbolAddress((void**)&woh, g_woh);
    cudaGetSymbolAddress((void**)&wol, g_wol);
    cudaGetSymbolAddress((void**)&Oh, g_Oh);
    cudaGetSymbolAddress((void**)&Ol, g_Ol);
    cudaGetSymbolAddress((void**)&Xh, g_Xh);
    cudaGetSymbolAddress((void**)&Xl, g_Xl);
    cudaGetSymbolAddress((void**)&Znh, g_Znh);
    cudaGetSymbolAddress((void**)&Znl, g_Znl);
    cudaGetSymbolAddress((void**)&Zth, g_Zth);
    cudaGetSymbolAddress((void**)&Ztl, g_Ztl);
    cudaGetSymbolAddress((void**)&XZh, g_XZh);
    cudaGetSymbolAddress((void**)&XZl, g_XZl);
    cudaGetSymbolAddress((void**)&WtAh, g_WtAh);
    cudaGetSymbolAddress((void**)&WtAl, g_WtAl);
    cudaGetSymbolAddress((void**)&WtBh, g_WtBh);
    cudaGetSymbolAddress((void**)&WtBl, g_WtBl);
    cudaGetSymbolAddress((void**)&q,  g_q);
    cudaGetSymbolAddress((void**)&k,  g_k);
    cudaGetSymbolAddress((void**)&v,  g_v);
    cudaGetSymbolAddress((void**)&qbh, g_qbh);
    cudaGetSymbolAddress((void**)&qbl, g_qbl);
    cudaGetSymbolAddress((void**)&kbh, g_kbh);
    cudaGetSymbolAddress((void**)&kbl, g_kbl);
    cudaGetSymbolAddress((void**)&vth, g_vth);
    cudaGetSymbolAddress((void**)&vtl, g_vtl);
    cudaGetSymbolAddress((void**)&ql, g_ql);
    cudaGetSymbolAddress((void**)&kl, g_kl);
    cudaGetSymbolAddress((void**)&qlh, g_qlh);
    cudaGetSymbolAddress((void**)&qll, g_qll);
    cudaGetSymbolAddress((void**)&klh, g_klh);
    cudaGetSymbolAddress((void**)&kll, g_kll);
    cudaGetSymbolAddress((void**)&yth, g_yth);
    cudaGetSymbolAddress((void**)&ytl, g_ytl);
    cudaGetSymbolAddress((void**)&X,  g_X);
    cudaGetSymbolAddress((void**)&Zf, g_Zf);
    cudaGetSymbolAddress((void**)&Opart, g_Opart);
    cudaGetSymbolAddress((void**)&dpart, g_dpart);
    cudaGetSymbolAddress((void**)&A3V, g_A3V);
    cudaGetSymbolAddress((void**)&Y,  g_Y);
    cudaGetSymbolAddress((void**)&O,  g_O);
    cudaGetSymbolAddress((void**)&mb, g_maxbits);

    cudaFuncSetAttribute(attn2_kernel, cudaFuncAttributeMaxDynamicSharedMemorySize, ATTN2_SMEM);
    cudaFuncSetAttribute(tc_gemm<2>, cudaFuncAttributeMaxDynamicSharedMemorySize, TCG_SMEM);
    cudaFuncSetAttribute(pinv_persistent, cudaFuncAttributeMaxDynamicSharedMemorySize, TCG_SMEM);
    cudaFuncSetAttribute(attn3v_mma, cudaFuncAttributeMaxDynamicSharedMemorySize, A3_SMEM);
    cudaFuncSetAttribute(attn1_mma, cudaFuncAttributeMaxDynamicSharedMemorySize, A1_SMEM);

    ln_kernel<<<B_ * NTOK, 256>>>(x, gamma, beta, nh, nl);
    tsplit_kernel<<<(D_ * 3 * D_ + 255) / 256, 256>>>(w_qkv, wqh, wql, D_, 3 * D_);
    tsplit_kernel<<<(D_ * D_ + 255) / 256, 256>>>(w_out, woh, wol, D_, D_);

    tc_gemm<2><<<dim3(12, 256, 1), 256, TCG_SMEM>>>(nh, nl, wqh, wql, D_, 0,
        q, k, v, nullptr, nullptr, nullptr, qbh, qbl, kbh, kbl);

    vtrans_kernel<<<dim3(NTOK / 64, BH), 256>>>(v, vth, vtl);
    landmark_kernel<<<dim3(BH, MLM), 64>>>(q, k, ql, kl, qlh, qll, klh, kll);

    attn2_kernel<<<dim3(BH, 8), 256, ATTN2_SMEM>>>(ql, kl, X, Xh, Xl);
    initmax_kernel<<<1, 1>>>(mb);
    rowcol_kernel<<<BH, 256>>>(X, mb);
    zinit_kernel<<<8192, 256>>>(X, mb, Znh, Znl, Zth, Ztl);

    pinv_persistent<<<128, 256, TCG_SMEM>>>(Xh, Xl, Znh, Znl, Zth, Ztl,
        XZh, XZl, WtAh, WtAl, WtBh, WtBl, Zf);

    attn3v_mma<<<dim3(NCHK, BH), 256, A3_SMEM>>>(qlh, qll, kbh, kbl, vth, vtl, Opart, dpart);
    a3v_reduce<<<2048, 256>>>(Opart, dpart, A3V);

    sgemm_kernel<<<dim3(1, 2, BH), 256>>>(Zf, A3V, Y, MLM, DH_, MLM,
        (size_t)MLM * MLM, (size_t)MLM * DH_, (size_t)MLM * DH_);
    ytrans_kernel<<<BH, 256>>>(Y, yth, ytl);

    conv_kernel<<<dim3(64, H_, B_), 256>>>(v, res_k, O);
    attn1_mma<<<dim3(NTOK / 128 / A1_TPB, BH), 256, A1_SMEM>>>(qbh, qbl, klh, kll, yth, ytl, O);

    osplit_kernel<<<(int)(((size_t)B_*NTOK*D_) / 256), 256>>>(O, Oh, Ol);
    tc_gemm<2><<<dim3(4, 256, 1), 256, TCG_SMEM>>>(Oh, Ol, woh, wol, D_, 1,
        nullptr, nullptr, nullptr, out, b_out, x, nullptr, nullptr, nullptr, nullptr);
}

// round 14
// speedup vs baseline: 6.2721x; 1.0038x over previous
#include <cuda_runtime.h>
#include <cuda_bf16.h>
#include <math.h>
#include <stdint.h>

#define B_    4
#define NTOK  8192
#define D_    512
#define H_    8
#define DH_   64
#define MLM   256
#define LSEG  32
#define BH    (B_*H_)
#define KER_  33
#define NCHK  8
#define A1_TPB 4

__device__ __forceinline__ uint32_t smem_to_u32(const void* p) {
    uint32_t a;
    asm("{ .reg .u64 t; cvta.to.shared.u64 t, %1; cvt.u32.u64 %0, t; }" : "=r"(a) : "l"(p));
    return a;
}
__device__ __forceinline__ void cp_async16(uint32_t saddr, const void* gptr) {
    asm volatile("cp.async.cg.shared.global [%0], [%1], 16;" :: "r"(saddr), "l"(gptr));
}
#define CP_COMMIT() asm volatile("cp.async.commit_group;" ::: "memory")
#define CP_WAIT0()  asm volatile("cp.async.wait_group 0;" ::: "memory")
__device__ __forceinline__ void mma_bf16p(float (&d)[4], const uint32_t (&a)[4], uint32_t b0, uint32_t b1) {
    asm volatile("mma.sync.aligned.m16n8k16.row.col.f32.bf16.bf16.f32 "
        "{%0,%1,%2,%3}, {%4,%5,%6,%7}, {%8,%9}, {%0,%1,%2,%3};"
        : "+f"(d[0]), "+f"(d[1]), "+f"(d[2]), "+f"(d[3])
        : "r"(a[0]), "r"(a[1]), "r"(a[2]), "r"(a[3]), "r"(b0), "r"(b1));
}
__device__ __forceinline__ void ldsm4(uint32_t (&r)[4], uint32_t a) {
    asm volatile("ldmatrix.sync.aligned.m8n8.x4.shared.b16 {%0,%1,%2,%3}, [%4];"
        : "=r"(r[0]), "=r"(r[1]), "=r"(r[2]), "=r"(r[3]) : "r"(a));
}
__device__ __forceinline__ float fexp(float s) {
    float t = s * 1.44269504088896341f;
    float i = rintf(t);
    float f = t - i;
    float p = 1.54035303933816e-4f;
    p = p * f + 1.33335581464284e-3f;
    p = p * f + 9.61812910762848e-3f;
    p = p * f + 5.55041086648216e-2f;
    p = p * f + 2.40226506959101e-1f;
    p = p * f + 6.93147180559945e-1f;
    p = p * f + 1.0f;
    return p * __int_as_float(((int)i + 127) << 23);
}

// scratch
__device__ __nv_bfloat16 g_nh[(size_t)B_*NTOK*D_];
__device__ __nv_bfloat16 g_nl[(size_t)B_*NTOK*D_];
__device__ __nv_bfloat16 g_wqh[(size_t)3*D_*D_];
__device__ __nv_bfloat16 g_wql[(size_t)3*D_*D_];
__device__ __nv_bfloat16 g_woh[(size_t)D_*D_];
__device__ __nv_bfloat16 g_wol[(size_t)D_*D_];
__device__ __nv_bfloat16 g_Oh[(size_t)B_*NTOK*D_];
__device__ __nv_bfloat16 g_Ol[(size_t)B_*NTOK*D_];
__device__ float g_q [(size_t)BH*NTOK*DH_];
__device__ float g_k [(size_t)BH*NTOK*DH_];
__device__ float g_v [(size_t)BH*NTOK*DH_];
__device__ __nv_bfloat16 g_qbh[(size_t)BH*NTOK*DH_];
__device__ __nv_bfloat16 g_qbl[(size_t)BH*NTOK*DH_];
__device__ __nv_bfloat16 g_kbh[(size_t)BH*NTOK*DH_];
__device__ __nv_bfloat16 g_kbl[(size_t)BH*NTOK*DH_];
__device__ __nv_bfloat16 g_vth[(size_t)BH*NTOK*DH_];
__device__ __nv_bfloat16 g_vtl[(size_t)BH*NTOK*DH_];
__device__ float g_ql[(size_t)BH*MLM*DH_];
__device__ float g_kl[(size_t)BH*MLM*DH_];
__device__ __nv_bfloat16 g_qlh[(size_t)BH*MLM*DH_];
__device__ __nv_bfloat16 g_qll[(size_t)BH*MLM*DH_];
__device__ __nv_bfloat16 g_klh[(size_t)BH*MLM*DH_];
__device__ __nv_bfloat16 g_kll[(size_t)BH*MLM*DH_];
__device__ __nv_bfloat16 g_yth[(size_t)BH*MLM*DH_];
__device__ __nv_bfloat16 g_ytl[(size_t)BH*MLM*DH_];
__device__ float g_X [(size_t)BH*MLM*MLM];
__device__ __nv_bfloat16 g_Xh[(size_t)BH*MLM*MLM];
__device__ __nv_bfloat16 g_Xl[(size_t)BH*MLM*MLM];
__device__ __nv_bfloat16 g_Znh[2][(size_t)BH*MLM*MLM];
__device__ __nv_bfloat16 g_Znl[2][(size_t)BH*MLM*MLM];
__device__ __nv_bfloat16 g_Zth[2][(size_t)BH*MLM*MLM];
__device__ __nv_bfloat16 g_Ztl[2][(size_t)BH*MLM*MLM];
__device__ __nv_bfloat16 g_XZh[(size_t)BH*MLM*MLM];
__device__ __nv_bfloat16 g_XZl[(size_t)BH*MLM*MLM];
__device__ __nv_bfloat16 g_WtAh[(size_t)BH*MLM*MLM];
__device__ __nv_bfloat16 g_WtAl[(size_t)BH*MLM*MLM];
__device__ __nv_bfloat16 g_WtBh[(size_t)BH*MLM*MLM];
__device__ __nv_bfloat16 g_WtBl[(size_t)BH*MLM*MLM];
__device__ float g_Zf[(size_t)BH*MLM*MLM];
__device__ float g_Opart[(size_t)NCHK*BH*MLM*DH_];
__device__ float g_dpart[(size_t)NCHK*BH*MLM];
__device__ float g_A3V[(size_t)BH*MLM*DH_];
__device__ float g_Y  [(size_t)BH*MLM*DH_];
__device__ unsigned g_maxbits[2];
__device__ unsigned g_bar_count;
__device__ unsigned g_bar_gen;

__global__ void ln_kernel(const float* __restrict__ x, const float* __restrict__ gamma,
                          const float* __restrict__ beta,
                          __nv_bfloat16* __restrict__ ohi, __nv_bfloat16* __restrict__ olo) {
    int row = blockIdx.x, tid = threadIdx.x;
    const float* xr = x + (size_t)row * D_;
    float v0 = xr[tid], v1 = xr[tid + 256];
    float s = v0 + v1, s2 = v0*v0 + v1*v1;
    #pragma unroll
    for (int o = 16; o > 0; o >>= 1) {
        s  += __shfl_xor_sync(0xffffffffu, s,  o);
        s2 += __shfl_xor_sync(0xffffffffu, s2, o);
    }
    __shared__ float sh[16];
    int w = tid >> 5;
    if ((tid & 31) == 0) { sh[w] = s; sh[w + 8] = s2; }
    __syncthreads();
    if (tid == 0) {
        float a = 0.f, b2 = 0.f;
        #pragma unroll
        for (int i = 0; i < 8; i++) { a += sh[i]; b2 += sh[i + 8]; }
        sh[0] = a; sh[8] = b2;
    }
    __syncthreads();
    float mu  = sh[0] * (1.f / D_);
    float var = sh[8] * (1.f / D_) - mu * mu;
    float inv = rsqrtf(var + 1e-5f);
    size_t base = (size_t)row * D_;
    #pragma unroll
    for (int half = 0; half < 2; half++) {
        int c = tid + half * 256;
        float v = (half == 0 ? v0 : v1);
        float nv = (v - mu) * inv * gamma[c] + beta[c];
        __nv_bfloat16 hi = __float2bfloat16(nv);
        ohi[base + c] = hi;
        olo[base + c] = __float2bfloat16(nv - __bfloat162float(hi));
    }
}

__global__ void tsplit_kernel(const float* __restrict__ W, __nv_bfloat16* __restrict__ Thi,
                              __nv_bfloat16* __restrict__ Tlo, int K, int N) {
    int idx = blockIdx.x * 256 + threadIdx.x;
    if (idx >= K * N) return;
    int k = idx / N, n = idx % N;
    float v = W[idx];
    __nv_bfloat16 hi = __float2bfloat16(v);
    Thi[(size_t)n * K + k] = hi;
    Tlo[(size_t)n * K + k] = __float2bfloat16(v - __bfloat162float(hi));
}
__global__ void vtrans_kernel(const float* __restrict__ v, __nv_bfloat16* __restrict__ vth,
                              __nv_bfloat16* __restrict__ vtl) {
    __shared__ float ts[64][68];
    int bh = blockIdx.y, k0 = blockIdx.x * 64;
    int tid = threadIdx.x;
    const float* vb = v + ((size_t)bh * NTOK + k0) * DH_;
    #pragma unroll
    for (int i = 0; i < 4; i++) {
        int lin = tid + i * 256;
        int r = lin >> 4, c4 = lin & 15;
        *(float4*)&ts[r][c4 * 4] = *(const float4*)(vb + r * 64 + c4 * 4);
    }
    __syncthreads();
    #pragma unroll
    for (int i = 0; i < 16; i++) {
        int lin = tid + i * 256;
        int dh = lin >> 6, ky = lin & 63;
        float val = ts[ky][dh];
        __nv_bfloat16 h = __float2bfloat16(val);
        size_t o = ((size_t)bh * 64 + dh) * NTOK + k0 + ky;
        vth[o] = h;
        vtl[o] = __float2bfloat16(val - __bfloat162float(h));
    }
}
__global__ void ytrans_kernel(const float* __restrict__ Y, __nv_bfloat16* __restrict__ yth,
                              __nv_bfloat16* __restrict__ ytl) {
    int bh = blockIdx.x, tid = threadIdx.x;
    #pragma unroll
    for (int i = 0; i < 64; i++) {
        int lin = tid + i * 256;
        int dh = lin >> 8, lm = lin & 255;
        float val = Y[(size_t)bh * 16384 + lm * 64 + dh];
        __nv_bfloat16 h = __float2bfloat16(val);
        size_t o = (size_t)bh * 16384 + dh * 256 + lm;
        yth[o] = h;
        ytl[o] = __float2bfloat16(val - __bfloat162float(h));
    }
}

// ---- shared GEMM tile mainloop ----
template<int NPASS>
__device__ __forceinline__ void gemm_tile_main(
        uint32_t sbase, int tid, int wid, int lane, int wm, int wn,
        const __nv_bfloat16* Ahi, const __nv_bfloat16* Alo,
        const __nv_bfloat16* Bhi, const __nv_bfloat16* Blo,
        int kdim, int m0, int n0, float (&acc)[2][8][4])
{
    const __nv_bfloat16* srcs[4] = {Ahi, Alo, Bhi, Blo};
    const int row0s[4] = {m0, m0, n0, n0};
    const int NB = (NPASS == 1) ? 2 : 4;
    int r_ld = tid >> 2, c_ld = tid & 3;
    int nch = kdim >> 5;
    #pragma unroll
    for (int bs = 0; bs < NB; bs++) {
        int bsel = (NPASS == 1) ? bs * 2 : bs;
        #pragma unroll
        for (int i = 0; i < 2; i++)
            cp_async16(sbase + (uint32_t)(bsel * 5120 + (r_ld + i * 64) * 40 + c_ld * 8) * 2,
                       srcs[bsel] + (size_t)(row0s[bsel] + r_ld + i * 64) * kdim + c_ld * 8);
    }
    CP_COMMIT();
    for (int ch = 0; ch < nch; ch++) {
        CP_WAIT0();
        __syncthreads();
        if (ch + 1 < nch) {
            int k0 = (ch + 1) << 5;
            uint32_t nxt_off = (uint32_t)((ch + 1) & 1) * 4 * 5120;
            #pragma unroll
            for (int bs = 0; bs < NB; bs++) {
                int bsel = (NPASS == 1) ? bs * 2 : bs;
                #pragma unroll
                for (int i = 0; i < 2; i++)
                    cp_async16(sbase + (uint32_t)(nxt_off + bsel * 5120 + (r_ld + i * 64) * 40 + c_ld * 8) * 2,
                               srcs[bsel] + (size_t)(row0s[bsel] + r_ld + i * 64) * kdim + k0 + c_ld * 8);
            }
            CP_COMMIT();
        }
        uint32_t stg_off = (uint32_t)(ch & 1) * 4 * 5120;
        #pragma unroll
        for (int ks = 0; ks < 32; ks += 16) {
            uint32_t Ah[2][4], Al[2][4];
            #pragma unroll
            for (int mf = 0; mf < 2; mf++) {
                int row = wm + mf * 16 + (lane & 15);
                int col = ks + ((lane >> 4) << 3);
                ldsm4(Ah[mf], sbase + (uint32_t)(stg_off + row * 40 + col) * 2);
                if (NPASS > 1) ldsm4(Al[mf], sbase + (uint32_t)(stg_off + 5120 + row * 40 + col) * 2);
            }
            #pragma unroll
            for (int p = 0; p < 4; p++) {
                int rowb = wn + (2 * p + (lane >> 4)) * 8 + (lane & 7);
                int colb = ks + ((lane >> 3) & 1) * 8;
                uint32_t Bh4[4], Bl4[4];
                ldsm4(Bh4, sbase + (uint32_t)(stg_off + 2 * 5120 + rowb * 40 + colb) * 2);
                if (NPASS > 1) ldsm4(Bl4, sbase + (uint32_t)(stg_off + 3 * 5120 + rowb * 40 + colb) * 2);
                #pragma unroll
                for (int mf = 0; mf < 2; mf++) {
                    mma_bf16p(acc[mf][2*p],   Ah[mf], Bh4[0], Bh4[1]);
                    mma_bf16p(acc[mf][2*p+1], Ah[mf], Bh4[2], Bh4[3]);
                    if (NPASS > 1) {
                        mma_bf16p(acc[mf][2*p],   Ah[mf], Bl4[0], Bl4[1]);
                        mma_bf16p(acc[mf][2*p+1], Ah[mf], Bl4[2], Bl4[3]);
                        mma_bf16p(acc[mf][2*p],   Al[mf], Bh4[0], Bh4[1]);
                        mma_bf16p(acc[mf][2*p+1], Al[mf], Bh4[2], Bh4[3]);
                    }
                }
            }
        }
    }
    __syncthreads();
}

__device__ __forceinline__ void stage_acc(char* smem, int tid, int wid, int lane, int wm, int wn,
                                          float (&acc)[2][8][4]) {
    float* stg = reinterpret_cast<float*>(smem);
    int r = lane >> 2, c = (lane & 3) * 2;
    #pragma unroll
    for (int mf = 0; mf < 2; mf++)
        #pragma unroll
        for (int nf = 0; nf < 8; nf++) {
            int rr = wm + mf * 16 + r, cc = wn + nf * 8 + c;
            *reinterpret_cast<float2*>(&stg[rr * 132 + cc]) = make_float2(acc[mf][nf][0], acc[mf][nf][1]);
            *reinterpret_cast<float2*>(&stg[(rr + 8) * 132 + cc]) = make_float2(acc[mf][nf][2], acc[mf][nf][3]);
        }
    __syncthreads();
}

// ---- standalone GEMM kernel (modes 0/1) ----
#define TCG_SMEM (2 * 4 * 5120 * 2)
template<int NPASS>
__global__ void __launch_bounds__(256, 2) tc_gemm(
        const __nv_bfloat16* __restrict__ Ahi, const __nv_bfloat16* __restrict__ Alo,
        const __nv_bfloat16* __restrict__ Bhi, const __nv_bfloat16* __restrict__ Blo,
        int K, int mode,
        float* __restrict__ qp, float* __restrict__ kp, float* __restrict__ vp,
        float* __restrict__ Cout, const float* __restrict__ bias, const float* __restrict__ addx,
        __nv_bfloat16* __restrict__ Nhi, __nv_bfloat16* __restrict__ Nlo,
        __nv_bfloat16* __restrict__ Thi, __nv_bfloat16* __restrict__ Tlo)
{
    extern __shared__ __align__(16) char smem[];
    uint32_t sbase = smem_to_u32(smem);
    int tid = threadIdx.x;
    int wid = tid >> 5, lane = tid & 31;
    int wm = (wid & 3) * 32, wn = (wid >> 2) * 64;
    int m0 = blockIdx.y * 128, n0 = blockIdx.x * 128;

    float acc[2][8][4];
    #pragma unroll
    for (int a = 0; a < 2; a++)
        #pragma unroll
        for (int b = 0; b < 8; b++)
            #pragma unroll
            for (int c = 0; c < 4; c++) acc[a][b][c] = 0.f;

    gemm_tile_main<NPASS>(sbase, tid, wid, lane, wm, wn, Ahi, Alo, Bhi, Blo, K, m0, n0, acc);
    stage_acc(smem, tid, wid, lane, wm, wn, acc);
    float* stg = reinterpret_cast<float*>(smem);

    if (mode == 0) {
        #pragma unroll 4
        for (int i = 0; i < 16; i++) {
            int lin = tid + (i << 8);
            int token = lin >> 5, c4 = lin & 31;
            int gn = n0 + (c4 << 2);
            float4 v = *reinterpret_cast<float4*>(&stg[token * 132 + (c4 << 2)]);
            int gmm = m0 + token;
            int b_ = gmm >> 13, n_ = gmm & 8191;
            int sec = gn >> 9, cc = gn & 511, h_ = cc >> 6, dh = cc & 63;
            size_t idx = ((((size_t)b_ * H_ + h_) * NTOK) + n_) * DH_ + dh;
            if (sec == 2) {
                *reinterpret_cast<float4*>(&vp[idx]) = v;
            } else {
                if (sec == 0) { v.x *= 0.125f; v.y *= 0.125f; v.z *= 0.125f; v.w *= 0.125f; }
                float* fp = (sec == 0) ? qp : kp;
                __nv_bfloat16* hp = (sec == 0) ? Nhi : Thi;
                __nv_bfloat16* lp = (sec == 0) ? Nlo : Tlo;
                *reinterpret_cast<float4*>(&fp[idx]) = v;
                float vv[4] = {v.x, v.y, v.z, v.w};
                __nv_bfloat16 hb[4], lb[4];
                #pragma unroll
                for (int t2 = 0; t2 < 4; t2++) {
                    hb[t2] = __float2bfloat16(vv[t2]);
                    lb[t2] = __float2bfloat16(vv[t2] - __bfloat162float(hb[t2]));
                }
                *reinterpret_cast<uint2*>(&hp[idx]) = *reinterpret_cast<uint2*>(hb);
                *reinterpret_cast<uint2*>(&lp[idx]) = *reinterpret_cast<uint2*>(lb);
            }
        }
    } else {
        #pragma unroll 4
        for (int i = 0; i < 16; i++) {
            int lin = tid + (i << 8);
            int token = lin >> 5, c4 = lin & 31;
            int gn = n0 + (c4 << 2);
            int gmm = m0 + token;
            float4 v = *reinterpret_cast<float4*>(&stg[token * 132 + (c4 << 2)]);
            float4 bb = *reinterpret_cast<const float4*>(&bias[gn]);
            float4 xx = *reinterpret_cast<const float4*>(&addx[(size_t)gmm * 512 + gn]);
            v.x += bb.x + xx.x; v.y += bb.y + xx.y; v.z += bb.z + xx.z; v.w += bb.w + xx.w;
            *reinterpret_cast<float4*>(&Cout[(size_t)gmm * 512 + gn]) = v;
        }
    }
}

// ---- persistent pinv ----
__device__ __forceinline__ void grid_barrier() {
    __syncthreads();
    if (threadIdx.x == 0) {
        __threadfence();
        unsigned gen = atomicAdd(&g_bar_gen, 0u);
        unsigned ticket = atomicAdd(&g_bar_count, 1u);
        if (ticket == 127u) {
            g_bar_count = 0u;
            __threadfence();
            atomicAdd(&g_bar_gen, 1u);
        } else {
            while (atomicAdd(&g_bar_gen, 0u) == gen) { }
        }
    }
    __syncthreads();
}

template<int NPASS>
__device__ __forceinline__ void pinv_stage(char* smem, uint32_t sbase,
        const __nv_bfloat16* Ahi, const __nv_bfloat16* Alo,
        const __nv_bfloat16* Bhi, const __nv_bfloat16* Blo,
        __nv_bfloat16* Nhi, __nv_bfloat16* Nlo,
        __nv_bfloat16* Thi, __nv_bfloat16* Tlo,
        float* Cf32, float alpha, float diagc, float beta,
        size_t oz, int m0, int n0)
{
    int tid = threadIdx.x;
    int wid = tid >> 5, lane = tid & 31;
    int wm = (wid & 3) * 32, wn = (wid >> 2) * 64;
    float acc[2][8][4];
    #pragma unroll
    for (int a = 0; a < 2; a++)
        #pragma unroll
        for (int b = 0; b < 8; b++)
            #pragma unroll
            for (int c = 0; c < 4; c++) acc[a][b][c] = 0.f;
    gemm_tile_main<NPASS>(sbase, tid, wid, lane, wm, wn,
        Ahi + oz, Alo + oz, Bhi + oz, Blo + oz, MLM, m0, n0, acc);
    stage_acc(smem, tid, wid, lane, wm, wn, acc);
    float* stg = reinterpret_cast<float*>(smem);
    if (Thi) {
        #pragma unroll 4
        for (int i = 0; i < 64; i++) {
            int idx = tid + (i << 8);
            int gn_l = idx >> 7, gm_l = idx & 127;
            int gmm = m0 + gm_l, gn = n0 + gn_l;
            float v = stg[gm_l * 132 + gn_l];
            float t = (gmm == gn ? diagc : 0.f) - beta * v;
            __nv_bfloat16 h = __float2bfloat16(t);
            Thi[oz + (size_t)gn * 256 + gmm] = h;
            Tlo[oz + (size_t)gn * 256 + gmm] = __float2bfloat16(t - __bfloat162float(h));
        }
    }
    if (Nhi) {
        #pragma unroll 4
        for (int i = 0; i < 16; i++) {
            int lin = tid + (i << 8);
            int token = lin >> 5, c4 = lin & 31;
            int gn = n0 + (c4 << 2);
            int gmm = m0 + token;
            float4 v = *reinterpret_cast<float4*>(&stg[token * 132 + (c4 << 2)]);
            float vv[4] = {v.x * alpha, v.y * alpha, v.z * alpha, v.w * alpha};
            __nv_bfloat16 h[4], l2[4];
            #pragma unroll
            for (int t2 = 0; t2 < 4; t2++) {
                h[t2] = __float2bfloat16(vv[t2]);
                l2[t2] = __float2bfloat16(vv[t2] - __bfloat162float(h[t2]));
            }
            *reinterpret_cast<uint2*>(&Nhi[oz + (size_t)gmm * 256 + gn]) = *reinterpret_cast<uint2*>(h);
            *reinterpret_cast<uint2*>(&Nlo[oz + (size_t)gmm * 256 + gn]) = *reinterpret_cast<uint2*>(l2);
        }
    }
    if (Cf32) {
        #pragma unroll 4
        for (int i = 0; i < 16; i++) {
            int lin = tid + (i << 8);
            int token = lin >> 5, c4 = lin & 31;
            int gn = n0 + (c4 << 2);
            int gmm = m0 + token;
            float4 v = *reinterpret_cast<float4*>(&stg[token * 132 + (c4 << 2)]);
            v.x *= alpha; v.y *= alpha; v.z *= alpha; v.w *= alpha;
            *reinterpret_cast<float4*>(&Cf32[oz + (size_t)gmm * 256 + gn]) = v;
        }
    }
    __syncthreads();
}

__global__ void __launch_bounds__(256, 2) pinv_persistent(
        const __nv_bfloat16* __restrict__ Xh, const __nv_bfloat16* __restrict__ Xl,
        __nv_bfloat16* __restrict__ Znh0, __nv_bfloat16* __restrict__ Znl0,
        __nv_bfloat16* __restrict__ Zth0, __nv_bfloat16* __restrict__ Ztl0,
        __nv_bfloat16* __restrict__ XZh, __nv_bfloat16* __restrict__ XZl,
        __nv_bfloat16* __restrict__ WtAh, __nv_bfloat16* __restrict__ WtAl,
        __nv_bfloat16* __restrict__ WtBh, __nv_bfloat16* __restrict__ WtBl,
        float* __restrict__ Zf)
{
    extern __shared__ __align__(16) char smem[];
    uint32_t sbase = smem_to_u32(smem);
    int b = blockIdx.x;
    size_t oz = (size_t)(b >> 2) * 65536;
    int m0 = ((b >> 1) & 1) * 128, n0 = (b & 1) * 128;
    const size_t SB = (size_t)BH * 65536;

    int cur = 0;
    for (int it = 0; it < 6; it++) {
        __nv_bfloat16* Znc = Znh0 + cur * SB; __nv_bfloat16* Znlc = Znl0 + cur * SB;
        __nv_bfloat16* Ztc = Zth0 + cur * SB; __nv_bfloat16* Ztlc = Ztl0 + cur * SB;
        int nxt = cur ^ 1;
        __nv_bfloat16* Znn = Znh0 + nxt * SB; __nv_bfloat16* Znln = Znl0 + nxt * SB;
        __nv_bfloat16* Ztn = Zth0 + nxt * SB; __nv_bfloat16* Ztln = Ztl0 + nxt * SB;
        if (it < 5) {
            pinv_stage<1>(smem, sbase, Xh, Xl, Ztc, Ztlc, XZh, XZl, WtAh, WtAl, nullptr, 1.f, 7.f, 1.f, oz, m0, n0);
            grid_barrier();
            pinv_stage<1>(smem, sbase, XZh, XZl, WtAh, WtAl, nullptr, nullptr, WtBh, WtBl, nullptr, 1.f, 15.f, 1.f, oz, m0, n0);
            grid_barrier();
            pinv_stage<1>(smem, sbase, XZh, XZl, WtBh, WtBl, nullptr, nullptr, WtAh, WtAl, nullptr, 1.f, 13.f, 1.f, oz, m0, n0);
            grid_barrier();
            pinv_stage<1>(smem, sbase, Znc, Znlc, WtAh, WtAl, Znn, Znln, Ztn, Ztln, nullptr, 0.25f, 0.f, -0.25f, oz, m0, n0);
            grid_barrier();
        } else {
            pinv_stage<2>(smem, sbase, Xh, Xl, Ztc, Ztlc, XZh, XZl, WtAh, WtAl, nullptr, 1.f, 7.f, 1.f, oz, m0, n0);
            grid_barrier();
            pinv_stage<2>(smem, sbase, XZh, XZl, WtAh, WtAl, nullptr, nullptr, WtBh, WtBl, nullptr, 1.f, 15.f, 1.f, oz, m0, n0);
            grid_barrier();
            pinv_stage<2>(smem, sbase, XZh, XZl, WtBh, WtBl, nullptr, nullptr, WtAh, WtAl, nullptr, 1.f, 13.f, 1.f, oz, m0, n0);
            grid_barrier();
            pinv_stage<2>(smem, sbase, Znc, Znlc, WtAh, WtAl, nullptr, nullptr, nullptr, nullptr, Zf, 0.25f, 0.f, -0.25f, oz, m0, n0);
        }
        cur = nxt;
    }
}

// SIMT SGEMM for Y = Zf @ A3V
__global__ void __launch_bounds__(256) sgemm_kernel(
        const float* __restrict__ A, const float* __restrict__ B, float* __restrict__ C,
        int M, int N, int K, size_t sA, size_t sB, size_t sC)
{
    int bz = blockIdx.z;
    A += (size_t)bz * sA; B += (size_t)bz * sB; C += (size_t)bz * sC;
    int m0 = blockIdx.y * 128, n0 = blockIdx.x * 128;
    __shared__ float As[8][128];
    __shared__ float Bs[8][128];
    int tid = threadIdx.x;
    int tx = tid & 15, ty = tid >> 4;
    float acc[8][8];
    #pragma unroll
    for (int i = 0; i < 8; i++)
        #pragma unroll
        for (int j = 0; j < 8; j++) acc[i][j] = 0.f;
    for (int k0 = 0; k0 < K; k0 += 8) {
        #pragma unroll
        for (int i = 0; i < 4; i++) {
            int lin = tid + i * 256;
            int kk = lin & 7, mm = lin >> 3;
            int gmm = m0 + mm, gk = k0 + kk;
            As[kk][mm] = (gmm < M && gk < K) ? A[(size_t)gmm * K + gk] : 0.f;
        }
        #pragma unroll
        for (int i = 0; i < 4; i++) {
            int lin = tid + i * 256;
            int nn = lin & 127, kk = lin >> 7;
            int gn = n0 + nn, gk = k0 + kk;
            Bs[kk][nn] = (gn < N && gk < K) ? B[(size_t)gk * N + gn] : 0.f;
        }
        __syncthreads();
        #pragma unroll
        for (int kk = 0; kk < 8; kk++) {
            float a[8], b[8];
            *(float4*)&a[0] = *(const float4*)&As[kk][ty * 8];
            *(float4*)&a[4] = *(const float4*)&As[kk][ty * 8 + 4];
            *(float4*)&b[0] = *(const float4*)&Bs[kk][tx * 8];
            *(float4*)&b[4] = *(const float4*)&Bs[kk][tx * 8 + 4];
            #pragma unroll
            for (int i = 0; i < 8; i++)
                #pragma unroll
                for (int j = 0; j < 8; j++) acc[i][j] += a[i] * b[j];
        }
        __syncthreads();
    }
    #pragma unroll
    for (int i = 0; i < 8; i++) {
        int gmm = m0 + ty * 8 + i;
        if (gmm >= M) continue;
        #pragma unroll
        for (int j = 0; j < 8; j++) {
            int gn = n0 + tx * 8 + j;
            if (gn >= N) continue;
            C[(size_t)gmm * N + gn] = acc[i][j];
        }
    }
}

__global__ void landmark_kernel(const float* __restrict__ q, const float* __restrict__ k,
                                float* __restrict__ ql, float* __restrict__ kl,
                                __nv_bfloat16* __restrict__ qlh, __nv_bfloat16* __restrict__ qll,
                                __nv_bfloat16* __restrict__ klh, __nv_bfloat16* __restrict__ kll) {
    int bh = blockIdx.x, m = blockIdx.y;
    int dh = threadIdx.x;
    size_t base = ((size_t)bh * NTOK + (size_t)m * LSEG) * DH_ + dh;
    float aq = 0.f, ak = 0.f;
    #pragma unroll
    for (int i = 0; i < LSEG; i++) {
        aq += q[base + (size_t)i * DH_];
        ak += k[base + (size_t)i * DH_];
    }
    size_t o = ((size_t)bh * MLM + m) * DH_ + dh;
    float qv = aq * (1.f / LSEG), kv = ak * (1.f / LSEG);
    ql[o] = qv; kl[o] = kv;
    __nv_bfloat16 qh = __float2bfloat16(qv);
    qlh[o] = qh; qll[o] = __float2bfloat16(qv - __bfloat162float(qh));
    __nv_bfloat16 kh = __float2bfloat16(kv);
    klh[o] = kh; kll[o] = __float2bfloat16(kv - __bfloat162float(kh));
}

#define ATTN2_SMEM ((256 * 68 + 32 * 64 + 8) * 4)
__global__ void attn2_kernel(const float* __restrict__ ql, const float* __restrict__ kl,
                             float* __restrict__ X,
                             __nv_bfloat16* __restrict__ Xh, __nv_bfloat16* __restrict__ Xl) {
    extern __shared__ __align__(16) float sh2[];
    float* kls  = sh2;
    float* qs   = sh2 + 256 * 68;
    float* wsum = qs + 32 * 64;
    int bh = blockIdx.x, mt = blockIdx.y;
    int tid = threadIdx.x;
    #pragma unroll
    for (int i = 0; i < 16; i++) {
        int lin = tid + i * 256;
        int r = lin >> 4, c = lin & 15;
        *(float4*)&kls[r * 68 + c * 4] = *(const float4*)&kl[((size_t)bh * MLM + r) * DH_ + c * 4];
    }
    #pragma unroll
    for (int i = 0; i < 2; i++) {
        int lin = tid + i * 256;
        int r = lin >> 4, c = lin & 15;
        *(float4*)&qs[r * 64 + c * 4] = *(const float4*)&ql[((size_t)bh * MLM + mt * 32 + r) * DH_ + c * 4];
    }
    __syncthreads();
    int j = tid, wid = tid >> 5, lane = tid & 31;
    const float* kr = &kls[j * 68];
    for (int ml = 0; ml < 32; ml++) {
        const float* qr = &qs[ml * 64];
        float a0 = 0.f, a1 = 0.f, a2 = 0.f, a3 = 0.f;
        #pragma unroll
        for (int d4 = 0; d4 < 16; d4++) {
            float4 kv = *(const float4*)&kr[d4 * 4];
            float4 qv = *(const float4*)&qr[d4 * 4];
            a0 += qv.x * kv.x; a1 += qv.y * kv.y; a2 += qv.z * kv.z; a3 += qv.w * kv.w;
        }
        float e = fexp(a0 + a1 + a2 + a3);
        float t = e;
        #pragma unroll
        for (int o = 16; o > 0; o >>= 1) t += __shfl_xor_sync(0xffffffffu, t, o);
        if (lane == 0) wsum[wid] = t;
        __syncthreads();
        float S = 0.f;
        #pragma unroll
        for (int w = 0; w < 8; w++) S += wsum[w];
        float val = e * (1.f / S);
        size_t o = ((size_t)bh * MLM + mt * 32 + ml) * MLM + j;
        X[o] = val;
        __nv_bfloat16 h = __float2bfloat16(val);
        Xh[o] = h;
        Xl[o] = __float2bfloat16(val - __bfloat162float(h));
        __syncthreads();
    }
}

__global__ void initmax_kernel(unsigned* mb) { mb[0] = 0u; mb[1] = 0u; g_bar_count = 0u; g_bar_gen = 0u; }
__global__ void rowcol_kernel(const float* __restrict__ X, unsigned* mb) {
    int bh = blockIdx.x, i = threadIdx.x;
    const float* Xm = X + (size_t)bh * MLM * MLM;
    float rs = 0.f, cs = 0.f;
    for (int j = 0; j < MLM; j++) {
        rs += fabsf(Xm[(size_t)i * MLM + j]);
        cs += fabsf(Xm[(size_t)j * MLM + i]);
    }
    #pragma unroll
    for (int o = 16; o > 0; o >>= 1) {
        rs = fmaxf(rs, __shfl_xor_sync(0xffffffffu, rs, o));
        cs = fmaxf(cs, __shfl_xor_sync(0xffffffffu, cs, o));
    }
    __shared__ float shr[8], shc[8];
    int w = i >> 5;
    if ((i & 31) == 0) { shr[w] = rs; shc[w] = cs; }
    __syncthreads();
    if (i == 0) {
        float mr = shr[0], mc = shc[0];
        #pragma unroll
        for (int k2 = 1; k2 < 8; k2++) { mr = fmaxf(mr, shr[k2]); mc = fmaxf(mc, shc[k2]); }
        atomicMax(&mb[0], __float_as_uint(mr));
        atomicMax(&mb[1], __float_as_uint(mc));
    }
}
__global__ void zinit_kernel(const float* __restrict__ X, const unsigned* __restrict__ mb,
                             __nv_bfloat16* __restrict__ Znh, __nv_bfloat16* __restrict__ Znl,
                             __nv_bfloat16* __restrict__ Zth, __nv_bfloat16* __restrict__ Ztl) {
    float inv = 1.f / (__uint_as_float(mb[0]) * __uint_as_float(mb[1]));
    size_t idx = (size_t)blockIdx.x * 256 + threadIdx.x;
    int bh = (int)(idx >> 16);
    int r = (int)((idx >> 8) & 255);
    int c = (int)(idx & 255);
    float tv = X[idx] * inv;
    __nv_bfloat16 th = __float2bfloat16(tv);
    Zth[idx] = th; Ztl[idx] = __float2bfloat16(tv - __bfloat162float(th));
    float nv = X[((size_t)bh << 16) + ((size_t)c << 8) + r] * inv;
    __nv_bfloat16 nh = __float2bfloat16(nv);
    Znh[idx] = nh; Znl[idx] = __float2bfloat16(nv - __bfloat162float(nh));
}

// attn3@v via MMA
#define A3_SMEM 93184
__global__ void __launch_bounds__(256, 1) attn3v_mma(
        const __nv_bfloat16* __restrict__ qlh_, const __nv_bfloat16* __restrict__ qll_,
        const __nv_bfloat16* __restrict__ kh_, const __nv_bfloat16* __restrict__ klo_,
        const __nv_bfloat16* __restrict__ vth_, const __nv_bfloat16* __restrict__ vtl_,
        float* __restrict__ Opart, float* __restrict__ denpart)
{
    extern __shared__ __align__(16) __nv_bfloat16 sm3[];
    uint32_t sb = smem_to_u32(sm3);
    int tid = threadIdx.x, wid = tid >> 5, lane = tid & 31;
    int chunk = blockIdx.x, bh = blockIdx.y;
    int key0 = chunk * (NTOK / NCHK);
    {
        size_t qb = (size_t)bh * MLM * DH_;
        #pragma unroll
        for (int i = 0; i < 8; i++) {
            int lin = tid + i * 256;
            int r = lin >> 3, c = lin & 7;
            *(uint4*)(sm3 + r * 72 + c * 8) = *(const uint4*)(qlh_ + qb + r * 64 + c * 8);
            *(uint4*)(sm3 + 18432 + r * 72 + c * 8) = *(const uint4*)(qll_ + qb + r * 64 + c * 8);
        }
    }
    __syncthreads();
    uint32_t Ah[2][4][4], Al[2][4][4];
    #pragma unroll
    for (int mf = 0; mf < 2; mf++) {
        int row = wid * 32 + mf * 16 + (lane & 15);
        #pragma unroll
        for (int ks = 0; ks < 4; ks++) {
            int col = ks * 16 + ((lane >> 4) << 3);
            ldsm4(Ah[mf][ks], sb + (uint32_t)(row * 72 + col) * 2);
            ldsm4(Al[mf][ks], sb + (uint32_t)(18432 + row * 72 + col) * 2);
        }
    }
    float Oacc[2][8][4];
    #pragma unroll
    for (int a = 0; a < 2; a++)
        #pragma unroll
        for (int b = 0; b < 8; b++)
            #pragma unroll
            for (int c = 0; c < 4; c++) Oacc[a][b][c] = 0.f;
    float den[2][2] = {{0.f, 0.f}, {0.f, 0.f}};

    for (int t32 = 0; t32 < (NTOK / NCHK) / 32; t32++) {
        int kt0 = key0 + t32 * 32;
        __syncthreads();
        {
            int r = tid >> 3, c = tid & 7;
            *(uint4*)(sm3 + 36864 + r * 72 + c * 8) = *(const uint4*)(kh_ + ((size_t)bh * NTOK + kt0 + r) * 64 + c * 8);
            *(uint4*)(sm3 + 39168 + r * 72 + c * 8) = *(const uint4*)(klo_ + ((size_t)bh * NTOK + kt0 + r) * 64 + c * 8);
            int r2 = tid >> 2, c2 = tid & 3;
            *(uint4*)(sm3 + 41472 + r2 * 40 + c2 * 8) = *(const uint4*)(vth_ + ((size_t)bh * 64 + r2) * NTOK + kt0 + c2 * 8);
            *(uint4*)(sm3 + 44032 + r2 * 40 + c2 * 8) = *(const uint4*)(vtl_ + ((size_t)bh * 64 + r2) * NTOK + kt0 + c2 * 8);
        }
        __syncthreads();
        float S[2][4][4];
        #pragma unroll
        for (int a = 0; a < 2; a++)
            #pragma unroll
            for (int b = 0; b < 4; b++)
                #pragma unroll
                for (int c = 0; c < 4; c++) S[a][b][c] = 0.f;
        #pragma unroll
        for (int ks = 0; ks < 4; ks++) {
            #pragma unroll
            for (int np = 0; np < 2; np++) {
                int row = np * 16 + ((lane >> 4) & 1) * 8 + (lane & 7);
                int col = ks * 16 + ((lane >> 3) & 1) * 8;
                uint32_t bh4[4], bl4[4];
                ldsm4(bh4, sb + (uint32_t)(36864 + row * 72 + col) * 2);
                ldsm4(bl4, sb + (uint32_t)(39168 + row * 72 + col) * 2);
                #pragma unroll
                for (int mf = 0; mf < 2; mf++) {
                    mma_bf16p(S[mf][2*np],   Ah[mf][ks], bh4[0], bh4[1]);
                    mma_bf16p(S[mf][2*np],   Ah[mf][ks], bl4[0], bl4[1]);
                    mma_bf16p(S[mf][2*np],   Al[mf][ks], bh4[0], bh4[1]);
                    mma_bf16p(S[mf][2*np+1], Ah[mf][ks], bh4[2], bh4[3]);
                    mma_bf16p(S[mf][2*np+1], Ah[mf][ks], bl4[2], bl4[3]);
                    mma_bf16p(S[mf][2*np+1], Al[mf][ks], bh4[2], bh4[3]);
                }
            }
        }
        #pragma unroll
        for (int kt = 0; kt < 2; kt++) {
            uint32_t pah[2][4], pal[2][4];
            #pragma unroll
            for (int mf = 0; mf < 2; mf++) {
                float e[8];
                #pragma unroll
                for (int j = 0; j < 4; j++) { e[j] = fexp(S[mf][2*kt][j]); e[4+j] = fexp(S[mf][2*kt+1][j]); }
                den[mf][0] += e[0] + e[1] + e[4] + e[5];
                den[mf][1] += e[2] + e[3] + e[6] + e[7];
                #pragma unroll
                for (int j = 0; j < 4; j++) {
                    __nv_bfloat162 h2 = __floats2bfloat162_rn(e[2*j], e[2*j+1]);
                    pah[mf][j] = *(uint32_t*)&h2;
                    float r0 = e[2*j]   - __bfloat162float(__low2bfloat16(h2));
                    float r1 = e[2*j+1] - __bfloat162float(__high2bfloat16(h2));
                    __nv_bfloat162 l2 = __floats2bfloat162_rn(r0, r1);
                    pal[mf][j] = *(uint32_t*)&l2;
                }
            }
            #pragma unroll
            for (int np = 0; np < 4; np++) {
                int row = np * 16 + ((lane >> 4) & 1) * 8 + (lane & 7);
                int col = kt * 16 + ((lane >> 3) & 1) * 8;
                uint32_t vh4[4], vl4[4];
                ldsm4(vh4, sb + (uint32_t)(41472 + row * 40 + col) * 2);
                ldsm4(vl4, sb + (uint32_t)(44032 + row * 40 + col) * 2);
                #pragma unroll
                for (int mf = 0; mf < 2; mf++) {
                    mma_bf16p(Oacc[mf][2*np],   pah[mf], vh4[0], vh4[1]);
                    mma_bf16p(Oacc[mf][2*np],   pah[mf], vl4[0], vl4[1]);
                    mma_bf16p(Oacc[mf][2*np],   pal[mf], vh4[0], vh4[1]);
                    mma_bf16p(Oacc[mf][2*np+1], pah[mf], vh4[2], vh4[3]);
                    mma_bf16p(Oacc[mf][2*np+1], pah[mf], vl4[2], vl4[3]);
                    mma_bf16p(Oacc[mf][2*np+1], pal[mf], vh4[2], vh4[3]);
                }
            }
        }
    }
    #pragma unroll
    for (int mf = 0; mf < 2; mf++)
        #pragma unroll
        for (int j = 0; j < 2; j++) {
            den[mf][j] += __shfl_xor_sync(0xffffffffu, den[mf][j], 1);
            den[mf][j] += __shfl_xor_sync(0xffffffffu, den[mf][j], 2);
        }
    int g = lane >> 2, t = lane & 3;
    size_t ob = ((size_t)chunk * BH + bh) * MLM * 64;
    #pragma unroll
    for (int mf = 0; mf < 2; mf++) {
        int lm0 = wid * 32 + mf * 16 + g;
        #pragma unroll
        for (int nf = 0; nf < 8; nf++) {
            int c = nf * 8 + t * 2;
            *(float2*)&Opart[ob + (size_t)lm0 * 64 + c] = make_float2(Oacc[mf][nf][0], Oacc[mf][nf][1]);
            *(float2*)&Opart[ob + (size_t)(lm0 + 8) * 64 + c] = make_float2(Oacc[mf][nf][2], Oacc[mf][nf][3]);
        }
        if (t == 0) {
            denpart[((size_t)chunk * BH + bh) * MLM + lm0] = den[mf][0];
            denpart[((size_t)chunk * BH + bh) * MLM + lm0 + 8] = den[mf][1];
        }
    }
}

__global__ void a3v_reduce(const float* __restrict__ Opart, const float* __restrict__ denpart,
                           float* __restrict__ A3V) {
    int idx = blockIdx.x * 256 + threadIdx.x;
    int bh = idx >> 14, lm = (idx >> 6) & 255;
    float s = 0.f, d = 0.f;
    #pragma unroll
    for (int c = 0; c < NCHK; c++) {
        s += Opart[((size_t)c * BH + bh) * 16384 + (idx & 16383)];
        d += denpart[((size_t)c * BH + bh) * 256 + lm];
    }
    A3V[idx] = s / d;
}

// attn1 + conv + osplit fused. smem: q/kl/Y bf16 regions (89088 elem = 178176B),
// then vconv float [160][68] (43520B), then kw (33 floats).
#define A1V_OFF  89088
#define A1KW_OFF (178176 + 43520)
#define A1_SMEM  (178176 + 43520 + 256)
__global__ void __launch_bounds__(256, 1) attn1_mma(
        const __nv_bfloat16* __restrict__ qh_, const __nv_bfloat16* __restrict__ qlo_,
        const __nv_bfloat16* __restrict__ klh_, const __nv_bfloat16* __restrict__ kll_,
        const __nv_bfloat16* __restrict__ yth_, const __nv_bfloat16* __restrict__ ytl_,
        const float* __restrict__ v_, const float* __restrict__ ker,
        __nv_bfloat16* __restrict__ Ohi, __nv_bfloat16* __restrict__ Olo)
{
    extern __shared__ __align__(16) __nv_bfloat16 sm1[];
    uint32_t sb = smem_to_u32(sm1);
    float* vs = reinterpret_cast<float*>(sm1 + A1V_OFF);          // [160][68]
    float* kw = reinterpret_cast<float*>((char*)sm1 + A1KW_OFF);  // [33]
    int tid = threadIdx.x, wid = tid >> 5, lane = tid & 31;
    int bh = blockIdx.y;
    int b = bh >> 3, h = bh & 7;
    {
        size_t kb = (size_t)bh * MLM * DH_;
        #pragma unroll
        for (int i = 0; i < 8; i++) {
            int lin = tid + i * 256;
            int r = lin >> 3, c = lin & 7;
            *(uint4*)(sm1 + 18432 + r * 72 + c * 8) = *(const uint4*)(klh_ + kb + r * 64 + c * 8);
            *(uint4*)(sm1 + 36864 + r * 72 + c * 8) = *(const uint4*)(kll_ + kb + r * 64 + c * 8);
        }
        size_t yb = (size_t)bh * 64 * MLM;
        #pragma unroll
        for (int i = 0; i < 8; i++) {
            int lin = tid + i * 256;
            int r = lin >> 5, c = lin & 31;
            *(uint4*)(sm1 + 55296 + r * 264 + c * 8) = *(const uint4*)(yth_ + yb + r * 256 + c * 8);
            *(uint4*)(sm1 + 72192 + r * 264 + c * 8) = *(const uint4*)(ytl_ + yb + r * 256 + c * 8);
        }
        if (tid < KER_) kw[tid] = ker[h * KER_ + tid];
    }
    const float* vb = v_ + ((size_t)b * H_ + h) * NTOK * DH_;

    for (int tt = 0; tt < A1_TPB; tt++) {
        int tile0 = (blockIdx.x * A1_TPB + tt) * 128;
        __syncthreads();
        {
            size_t qb = ((size_t)bh * NTOK + tile0) * DH_;
            #pragma unroll
            for (int i = 0; i < 4; i++) {
                int lin = tid + i * 256;
                int r = lin >> 3, c = lin & 7;
                *(uint4*)(sm1 + r * 72 + c * 8) = *(const uint4*)(qh_ + qb + r * 64 + c * 8);
                *(uint4*)(sm1 + 9216 + r * 72 + c * 8) = *(const uint4*)(qlo_ + qb + r * 64 + c * 8);
            }
            // v halo: rows tile0-16 .. tile0+143
            #pragma unroll
            for (int i = 0; i < 10; i++) {
                int f4 = tid + i * 256;
                int row = f4 >> 4, c4 = f4 & 15;
                int n = tile0 - 16 + row;
                float4 val = make_float4(0.f, 0.f, 0.f, 0.f);
                if (n >= 0 && n < NTOK) val = ((const float4*)(vb + (size_t)n * DH_))[c4];
                *(float4*)&vs[row * 68 + c4 * 4] = val;
            }
        }
        __syncthreads();
        uint32_t Ah[4][4], Al[4][4];
        {
            int row = wid * 16 + (lane & 15);
            #pragma unroll
            for (int ks = 0; ks < 4; ks++) {
                int col = ks * 16 + ((lane >> 4) << 3);
                ldsm4(Ah[ks], sb + (uint32_t)(row * 72 + col) * 2);
                ldsm4(Al[ks], sb + (uint32_t)(9216 + row * 72 + col) * 2);
            }
        }
        float Oacc[8][4];
        #pragma unroll
        for (int bb = 0; bb < 8; bb++)
            #pragma unroll
            for (int c = 0; c < 4; c++) Oacc[bb][c] = 0.f;
        float dlo = 0.f, dhi = 0.f;

        #pragma unroll
        for (int half = 0; half < 2; half++) {
            int lmb = half * 128;
            float S[16][4];
            #pragma unroll
            for (int bb = 0; bb < 16; bb++)
                #pragma unroll
                for (int c = 0; c < 4; c++) S[bb][c] = 0.f;
            #pragma unroll
            for (int ks = 0; ks < 4; ks++) {
                #pragma unroll
                for (int np = 0; np < 8; np++) {
                    int row = lmb + np * 16 + ((lane >> 4) & 1) * 8 + (lane & 7);
                    int col = ks * 16 + ((lane >> 3) & 1) * 8;
                    uint32_t bh4[4], bl4[4];
                    ldsm4(bh4, sb + (uint32_t)(18432 + row * 72 + col) * 2);
                    ldsm4(bl4, sb + (uint32_t)(36864 + row * 72 + col) * 2);
                    mma_bf16p(S[2*np],   Ah[ks], bh4[0], bh4[1]);
                    mma_bf16p(S[2*np],   Ah[ks], bl4[0], bl4[1]);
                    mma_bf16p(S[2*np],   Al[ks], bh4[0], bh4[1]);
                    mma_bf16p(S[2*np+1], Ah[ks], bh4[2], bh4[3]);
                    mma_bf16p(S[2*np+1], Ah[ks], bl4[2], bl4[3]);
                    mma_bf16p(S[2*np+1], Al[ks], bh4[2], bh4[3]);
                }
            }
            #pragma unroll
            for (int kt = 0; kt < 8; kt++) {
                float e[8];
                #pragma unroll
                for (int j = 0; j < 4; j++) { e[j] = fexp(S[2*kt][j]); e[4+j] = fexp(S[2*kt+1][j]); }
                dlo += e[0] + e[1] + e[4] + e[5];
                dhi += e[2] + e[3] + e[6] + e[7];
                uint32_t pah[4], pal[4];
                #pragma unroll
                for (int j = 0; j < 4; j++) {
                    __nv_bfloat162 h2 = __floats2bfloat162_rn(e[2*j], e[2*j+1]);
                    pah[j] = *(uint32_t*)&h2;
                    float r0 = e[2*j]   - __bfloat162float(__low2bfloat16(h2));
                    float r1 = e[2*j+1] - __bfloat162float(__high2bfloat16(h2));
                    __nv_bfloat162 l2 = __floats2bfloat162_rn(r0, r1);
                    pal[j] = *(uint32_t*)&l2;
                }
                #pragma unroll
                for (int np = 0; np < 4; np++) {
                    int row = np * 16 + ((lane >> 4) & 1) * 8 + (lane & 7);
                    int col = lmb + kt * 16 + ((lane >> 3) & 1) * 8;
                    uint32_t yh4[4], yl4[4];
                    ldsm4(yh4, sb + (uint32_t)(55296 + row * 264 + col) * 2);
                    ldsm4(yl4, sb + (uint32_t)(72192 + row * 264 + col) * 2);
                    mma_bf16p(Oacc[2*np],   pah, yh4[0], yh4[1]);
                    mma_bf16p(Oacc[2*np],   pah, yl4[0], yl4[1]);
                    mma_bf16p(Oacc[2*np],   pal, yh4[0], yh4[1]);
                    mma_bf16p(Oacc[2*np+1], pah, yh4[2], yh4[3]);
                    mma_bf16p(Oacc[2*np+1], pah, yl4[2], yl4[3]);
                    mma_bf16p(Oacc[2*np+1], pal, yh4[2], yh4[3]);
                }
            }
        }
        dlo += __shfl_xor_sync(0xffffffffu, dlo, 1);
        dlo += __shfl_xor_sync(0xffffffffu, dlo, 2);
        dhi += __shfl_xor_sync(0xffffffffu, dhi, 1);
        dhi += __shfl_xor_sync(0xffffffffu, dhi, 2);
        float ilo = 1.f / dlo, ihi = 1.f / dhi;
        int g = lane >> 2, t = lane & 3;
        int tok0 = tile0 + wid * 16 + g;
        int r0 = wid * 16 + g;              // local row in tile
        size_t ob = ((size_t)b * NTOK + tok0) * D_ + h * DH_;
        #pragma unroll
        for (int nf = 0; nf < 8; nf++) {
            int c = nf * 8 + t * 2;
            // conv for (r0, c), (r0, c+1), (r0+8, c), (r0+8, c+1)
            float cv00 = 0.f, cv01 = 0.f, cv10 = 0.f, cv11 = 0.f;
            #pragma unroll
            for (int tap = 0; tap < KER_; tap++) {
                float w = kw[tap];
                cv00 += w * vs[(r0 + tap) * 68 + c];
                cv01 += w * vs[(r0 + tap) * 68 + c + 1];
                cv10 += w * vs[(r0 + 8 + tap) * 68 + c];
                cv11 += w * vs[(r0 + 8 + tap) * 68 + c + 1];
            }
            float o00 = Oacc[nf][0] * ilo + cv00;
            float o01 = Oacc[nf][1] * ilo + cv01;
            float o10 = Oacc[nf][2] * ihi + cv10;
            float o11 = Oacc[nf][3] * ihi + cv11;
            __nv_bfloat162 h0 = __floats2bfloat162_rn(o00, o01);
            __nv_bfloat162 l0 = __floats2bfloat162_rn(o00 - __bfloat162float(__low2bfloat16(h0)),
                                                      o01 - __bfloat162float(__high2bfloat16(h0)));
            *(uint32_t*)&Ohi[ob + c] = *(uint32_t*)&h0;
            *(uint32_t*)&Olo[ob + c] = *(uint32_t*)&l0;
            __nv_bfloat162 h1 = __floats2bfloat162_rn(o10, o11);
            __nv_bfloat162 l1 = __floats2bfloat162_rn(o10 - __bfloat162float(__low2bfloat16(h1)),
                                                      o11 - __bfloat162float(__high2bfloat16(h1)));
            *(uint32_t*)&Ohi[ob + (size_t)8 * D_ + c] = *(uint32_t*)&h1;
            *(uint32_t*)&Olo[ob + (size_t)8 * D_ + c] = *(uint32_t*)&l1;
        }
    }
}

extern "C" void kernel_launch(void* const* d_in, const int* in_sizes, int n_in,
                              void* d_out, int out_size) {
    const float* x      = (const float*)d_in[0];
    const float* gamma  = (const float*)d_in[1];
    const float* beta   = (const float*)d_in[2];
    const float* w_qkv  = (const float*)d_in[3];
    const float* res_k  = (const float*)d_in[4];
    const float* w_out  = (const float*)d_in[5];
    const float* b_out  = (const float*)d_in[6];
    float* out = (float*)d_out;

    __nv_bfloat16 *nh, *nl, *wqh, *wql, *woh, *wol, *Oh, *Ol, *Xh, *Xl;
    __nv_bfloat16 *Znh, *Znl, *Zth, *Ztl, *XZh, *XZl, *WtAh, *WtAl, *WtBh, *WtBl;
    __nv_bfloat16 *qbh, *qbl, *kbh, *kbl, *vth, *vtl, *qlh, *qll, *klh, *kll, *yth, *ytl;
    float *q, *k, *v, *ql, *kl, *X, *Zf, *A3V, *Y, *Opart, *dpart;
    unsigned* mb;
    cudaGetSymbolAddress((void**)&nh, g_nh);
    cudaGetSymbolAddress((void**)&nl, g_nl);
    cudaGetSymbolAddress((void**)&wqh, g_wqh);
    cudaGetSymbolAddress((void**)&wql, g_wql);
    cudaGetSymbolAddress((void**)&woh, g_woh);
    cudaGetSymbolAddress((void**)&wol, g_wol);
    cudaGetSymbolAddress((void**)&Oh, g_Oh);
    cudaGetSymbolAddress((void**)&Ol, g_Ol);
    cudaGetSymbolAddress((void**)&Xh, g_Xh);
    cudaGetSymbolAddress((void**)&Xl, g_Xl);
    cudaGetSymbolAddress((void**)&Znh, g_Znh);
    cudaGetSymbolAddress((void**)&Znl, g_Znl);
    cudaGetSymbolAddress((void**)&Zth, g_Zth);
    cudaGetSymbolAddress((void**)&Ztl, g_Ztl);
    cudaGetSymbolAddress((void**)&XZh, g_XZh);
    cudaGetSymbolAddress((void**)&XZl, g_XZl);
    cudaGetSymbolAddress((void**)&WtAh, g_WtAh);
    cudaGetSymbolAddress((void**)&WtAl, g_WtAl);
    cudaGetSymbolAddress((void**)&WtBh, g_WtBh);
    cudaGetSymbolAddress((void**)&WtBl, g_WtBl);
    cudaGetSymbolAddress((void**)&q,  g_q);
    cudaGetSymbolAddress((void**)&k,  g_k);
    cudaGetSymbolAddress((void**)&v,  g_v);
    cudaGetSymbolAddress((void**)&qbh, g_qbh);
    cudaGetSymbolAddress((void**)&qbl, g_qbl);
    cudaGetSymbolAddress((void**)&kbh, g_kbh);
    cudaGetSymbolAddress((void**)&kbl, g_kbl);
    cudaGetSymbolAddress((void**)&vth, g_vth);
    cudaGetSymbolAddress((void**)&vtl, g_vtl);
    cudaGetSymbolAddress((void**)&ql, g_ql);
    cudaGetSymbolAddress((void**)&kl, g_kl);
    cudaGetSymbolAddress((void**)&qlh, g_qlh);
    cudaGetSymbolAddress((void**)&qll, g_qll);
    cudaGetSymbolAddress((void**)&klh, g_klh);
    cudaGetSymbolAddress((void**)&kll, g_kll);
    cudaGetSymbolAddress((void**)&yth, g_yth);
    cudaGetSymbolAddress((void**)&ytl, g_ytl);
    cudaGetSymbolAddress((void**)&X,  g_X);
    cudaGetSymbolAddress((void**)&Zf, g_Zf);
    cudaGetSymbolAddress((void**)&Opart, g_Opart);
    cudaGetSymbolAddress((void**)&dpart, g_dpart);
    cudaGetSymbolAddress((void**)&A3V, g_A3V);
    cudaGetSymbolAddress((void**)&Y,  g_Y);
    cudaGetSymbolAddress((void**)&mb, g_maxbits);

    cudaFuncSetAttribute(attn2_kernel, cudaFuncAttributeMaxDynamicSharedMemorySize, ATTN2_SMEM);
    cudaFuncSetAttribute(tc_gemm<2>, cudaFuncAttributeMaxDynamicSharedMemorySize, TCG_SMEM);
    cudaFuncSetAttribute(pinv_persistent, cudaFuncAttributeMaxDynamicSharedMemorySize, TCG_SMEM);
    cudaFuncSetAttribute(attn3v_mma, cudaFuncAttributeMaxDynamicSharedMemorySize, A3_SMEM);
    cudaFuncSetAttribute(attn1_mma, cudaFuncAttributeMaxDynamicSharedMemorySize, A1_SMEM);

    ln_kernel<<<B_ * NTOK, 256>>>(x, gamma, beta, nh, nl);
    tsplit_kernel<<<(D_ * 3 * D_ + 255) / 256, 256>>>(w_qkv, wqh, wql, D_, 3 * D_);
    tsplit_kernel<<<(D_ * D_ + 255) / 256, 256>>>(w_out, woh, wol, D_, D_);

    tc_gemm<2><<<dim3(12, 256, 1), 256, TCG_SMEM>>>(nh, nl, wqh, wql, D_, 0,
        q, k, v, nullptr, nullptr, nullptr, qbh, qbl, kbh, kbl);

    vtrans_kernel<<<dim3(NTOK / 64, BH), 256>>>(v, vth, vtl);
    landmark_kernel<<<dim3(BH, MLM), 64>>>(q, k, ql, kl, qlh, qll, klh, kll);

    attn2_kernel<<<dim3(BH, 8), 256, ATTN2_SMEM>>>(ql, kl, X, Xh, Xl);
    initmax_kernel<<<1, 1>>>(mb);
    rowcol_kernel<<<BH, 256>>>(X, mb);
    zinit_kernel<<<8192, 256>>>(X, mb, Znh, Znl, Zth, Ztl);

    pinv_persistent<<<128, 256, TCG_SMEM>>>(Xh, Xl, Znh, Znl, Zth, Ztl,
        XZh, XZl, WtAh, WtAl, WtBh, WtBl, Zf);

    attn3v_mma<<<dim3(NCHK, BH), 256, A3_SMEM>>>(qlh, qll, kbh, kbl, vth, vtl, Opart, dpart);
    a3v_reduce<<<2048, 256>>>(Opart, dpart, A3V);

    sgemm_kernel<<<dim3(1, 2, BH), 256>>>(Zf, A3V, Y, MLM, DH_, MLM,
        (size_t)MLM * MLM, (size_t)MLM * DH_, (size_t)MLM * DH_);
    ytrans_kernel<<<BH, 256>>>(Y, yth, ytl);

    // fused attn1 + conv + bf16 split of O
    attn1_mma<<<dim3(NTOK / 128 / A1_TPB, BH), 256, A1_SMEM>>>(
        qbh, qbl, klh, kll, yth, ytl, v, res_k, Oh, Ol);

    tc_gemm<2><<<dim3(4, 256, 1), 256, TCG_SMEM>>>(Oh, Ol, woh, wol, D_, 1,
        nullptr, nullptr, nullptr, out, b_out, x, nullptr, nullptr, nullptr, nullptr);
}